// round 1
// baseline (speedup 1.0000x reference)
#include <cuda_runtime.h>
#include <math.h>

#define DIM 2048
#define NH 32
#define NKV 8
#define HD 64
#define BATCH 2
#define SEQ 2048
#define MROWS (BATCH*SEQ)   /* 4096 */
#define KVDIM (NKV*HD)      /* 512 */

// ---------------- scratch (static device allocations; no cudaMalloc) ----------------
__device__ float g_qlin[(size_t)MROWS * DIM];          // x @ Wq            (B,S,H*D)
__device__ float g_klin[(size_t)MROWS * KVDIM];        // x @ Wk            (B,S,KV*D)
__device__ float g_vlin[(size_t)MROWS * KVDIM];        // x @ Wv + bv       (B,S,KV*D)
__device__ float g_qt[(size_t)BATCH * NH * SEQ * HD];  // rope'd Q          (B,H,S,D)
__device__ float g_kt[(size_t)BATCH * NKV * SEQ * HD]; // rope'd K          (B,KV,S,D)
__device__ float g_vt[(size_t)BATCH * NKV * SEQ * HD]; // V                 (B,KV,S,D)
__device__ float g_attn[(size_t)MROWS * DIM];          // attention out     (B,S,H*D)
__device__ double g_theta[HD / 2];

// ---------------- RoPE angle table (double-precision base) ----------------
__global__ void theta_kernel() {
    int p = threadIdx.x;
    if (p < HD / 2) g_theta[p] = pow(10000.0, -(double)p / 32.0);
}

// ---------------- 128x128x8 register-blocked SGEMM, C = A@B (+bias) ----------------
// A: MxK row-major, B: KxN row-major, N % 128 == 0, M % 128 == 0, K % 8 == 0
__global__ void __launch_bounds__(256) sgemm128(
    const float* __restrict__ A, const float* __restrict__ B,
    const float* __restrict__ bias, float* __restrict__ C, int N, int K)
{
    __shared__ float As[8][128];
    __shared__ float Bs[8][128];
    const int t  = threadIdx.x;
    const int tx = t & 15, ty = t >> 4;
    const float* Ab = A + (size_t)blockIdx.y * 128 * K;
    const float* Bb = B + blockIdx.x * 128;
    const int arow = t >> 1, acol = (t & 1) * 4;
    const int brow = t >> 5, bcol = (t & 31) * 4;

    float acc[8][8];
    #pragma unroll
    for (int i = 0; i < 8; ++i)
        #pragma unroll
        for (int j = 0; j < 8; ++j) acc[i][j] = 0.f;

    for (int k0 = 0; k0 < K; k0 += 8) {
        float4 av = *(const float4*)(Ab + (size_t)arow * K + k0 + acol);
        As[acol + 0][arow] = av.x;
        As[acol + 1][arow] = av.y;
        As[acol + 2][arow] = av.z;
        As[acol + 3][arow] = av.w;
        *(float4*)(&Bs[brow][bcol]) =
            *(const float4*)(Bb + (size_t)(k0 + brow) * N + bcol);
        __syncthreads();
        #pragma unroll
        for (int k = 0; k < 8; ++k) {
            const float4 a0 = *(const float4*)(&As[k][ty * 8]);
            const float4 a1 = *(const float4*)(&As[k][ty * 8 + 4]);
            const float4 b0 = *(const float4*)(&Bs[k][tx * 8]);
            const float4 b1 = *(const float4*)(&Bs[k][tx * 8 + 4]);
            const float ra[8] = {a0.x, a0.y, a0.z, a0.w, a1.x, a1.y, a1.z, a1.w};
            const float rb[8] = {b0.x, b0.y, b0.z, b0.w, b1.x, b1.y, b1.z, b1.w};
            #pragma unroll
            for (int i = 0; i < 8; ++i)
                #pragma unroll
                for (int j = 0; j < 8; ++j)
                    acc[i][j] += ra[i] * rb[j];
        }
        __syncthreads();
    }

    const size_t crow0 = (size_t)blockIdx.y * 128 + ty * 8;
    const int    ccol0 = blockIdx.x * 128 + tx * 8;
    #pragma unroll
    for (int i = 0; i < 8; ++i) {
        float* crow = C + (crow0 + i) * N + ccol0;
        #pragma unroll
        for (int j = 0; j < 8; j += 4) {
            float4 v = make_float4(acc[i][j], acc[i][j+1], acc[i][j+2], acc[i][j+3]);
            if (bias) {
                v.x += bias[ccol0 + j + 0];
                v.y += bias[ccol0 + j + 1];
                v.z += bias[ccol0 + j + 2];
                v.w += bias[ccol0 + j + 3];
            }
            *(float4*)(crow + j) = v;
        }
    }
}

// ---------------- RoPE + layout transpose ----------------
// q_lin (B,S,H*D) -> g_qt (B,H,S,D), rope applied per interleaved pair
__global__ void rope_q_kernel(const float* __restrict__ in, float* __restrict__ out) {
    int idx = blockIdx.x * blockDim.x + threadIdx.x;   // over B*S*H*32 pairs = 2^22
    int p = idx & 31;
    int h = (idx >> 5) & 31;
    int s = (idx >> 10) & 2047;
    int b = idx >> 21;
    float ang = (float)((double)s * g_theta[p]);
    float sv, cv;
    sincosf(ang, &sv, &cv);
    const float2 x = *(const float2*)(in + ((size_t)(b * SEQ + s)) * DIM + h * HD + 2 * p);
    float2 r;
    r.x = x.x * cv - x.y * sv;
    r.y = x.x * sv + x.y * cv;
    *(float2*)(out + (((size_t)(b * NH + h)) * SEQ + s) * HD + 2 * p) = r;
}

// k_lin (B,S,KV*D) -> g_kt (B,KV,S,D)
__global__ void rope_k_kernel(const float* __restrict__ in, float* __restrict__ out) {
    int idx = blockIdx.x * blockDim.x + threadIdx.x;   // over B*S*KV*32 pairs = 2^20
    int p = idx & 31;
    int h = (idx >> 5) & 7;
    int s = (idx >> 8) & 2047;
    int b = idx >> 19;
    float ang = (float)((double)s * g_theta[p]);
    float sv, cv;
    sincosf(ang, &sv, &cv);
    const float2 x = *(const float2*)(in + ((size_t)(b * SEQ + s)) * KVDIM + h * HD + 2 * p);
    float2 r;
    r.x = x.x * cv - x.y * sv;
    r.y = x.x * sv + x.y * cv;
    *(float2*)(out + (((size_t)(b * NKV + h)) * SEQ + s) * HD + 2 * p) = r;
}

// v_lin (B,S,KV*D) -> g_vt (B,KV,S,D)
__global__ void transpose_v_kernel(const float* __restrict__ in, float* __restrict__ out) {
    int idx = blockIdx.x * blockDim.x + threadIdx.x;   // over B*S*KV*16 float4s = 2^19
    int d4 = idx & 15;
    int h  = (idx >> 4) & 7;
    int s  = (idx >> 7) & 2047;
    int b  = idx >> 18;
    const float4 v = *(const float4*)(in + ((size_t)(b * SEQ + s)) * KVDIM + h * HD + d4 * 4);
    *(float4*)(out + (((size_t)(b * NKV + h)) * SEQ + s) * HD + d4 * 4) = v;
}

// ---------------- causal flash attention, fp32, 64x64 tiles ----------------
// Q (B,H,S,D), K/V (B,KV,S,D) -> O (B,S,H*D).   256 threads, 4x4 micro-tiles.
__global__ void __launch_bounds__(256) flash_kernel(
    const float* __restrict__ Q, const float* __restrict__ K,
    const float* __restrict__ V, float* __restrict__ O)
{
    extern __shared__ float sm[];
    float* Qt = sm;              // [64][68]  Qt[d][r]  (pad 68 keeps 16B align, no conflicts)
    float* Ks = Qt + 64 * 68;    // [64][68]  Ks[d][c]
    float* Vs = Ks + 64 * 68;    // [64][64]  Vs[c][d]
    float* Ps = Vs + 64 * 64;    // [64][68]  Ps[c][r]

    const int qtile = blockIdx.x;
    const int h     = blockIdx.y;
    const int b     = blockIdx.z;
    const int kvh   = h >> 2;                      // GQA: 4 q heads per kv head
    const int t  = threadIdx.x;
    const int tx = t & 15, ty = t >> 4;
    const int r0 = ty * 4, c0 = tx * 4;

    const float* Qb = Q + (((size_t)(b * NH + h)) * SEQ + qtile * 64) * HD;
    const float* Kb = K + ((size_t)(b * NKV + kvh)) * SEQ * HD;
    const float* Vb = V + ((size_t)(b * NKV + kvh)) * SEQ * HD;

    // load Q tile transposed into smem
    for (int i = t * 4; i < 64 * 64; i += 1024) {
        int r = i >> 6, d = i & 63;
        float4 q4 = *(const float4*)(Qb + r * 64 + d);
        Qt[(d + 0) * 68 + r] = q4.x;
        Qt[(d + 1) * 68 + r] = q4.y;
        Qt[(d + 2) * 68 + r] = q4.z;
        Qt[(d + 3) * 68 + r] = q4.w;
    }

    float o[4][4];
    float m[4], lsum[4];
    #pragma unroll
    for (int i = 0; i < 4; ++i) {
        m[i] = -1e30f; lsum[i] = 0.f;
        #pragma unroll
        for (int j = 0; j < 4; ++j) o[i][j] = 0.f;
    }

    for (int kt = 0; kt <= qtile; ++kt) {
        __syncthreads();   // prior-iter consumers done (also covers Q transpose on iter 0)
        // load K (transposed) + V tiles
        for (int i = t * 4; i < 64 * 64; i += 1024) {
            int r = i >> 6, d = i & 63;
            float4 k4 = *(const float4*)(Kb + (size_t)(kt * 64 + r) * 64 + d);
            Ks[(d + 0) * 68 + r] = k4.x;
            Ks[(d + 1) * 68 + r] = k4.y;
            Ks[(d + 2) * 68 + r] = k4.z;
            Ks[(d + 3) * 68 + r] = k4.w;
            *(float4*)(Vs + r * 64 + d) = *(const float4*)(Vb + (size_t)(kt * 64 + r) * 64 + d);
        }
        __syncthreads();

        // scores: 4x4 per thread, outer product over d
        float s4[4][4];
        #pragma unroll
        for (int i = 0; i < 4; ++i)
            #pragma unroll
            for (int j = 0; j < 4; ++j) s4[i][j] = 0.f;

        #pragma unroll 8
        for (int d = 0; d < 64; ++d) {
            const float4 qa = *(const float4*)(Qt + d * 68 + r0);
            const float4 kb = *(const float4*)(Ks + d * 68 + c0);
            const float ra[4] = {qa.x, qa.y, qa.z, qa.w};
            const float rb[4] = {kb.x, kb.y, kb.z, kb.w};
            #pragma unroll
            for (int i = 0; i < 4; ++i)
                #pragma unroll
                for (int j = 0; j < 4; ++j)
                    s4[i][j] += ra[i] * rb[j];
        }

        // online softmax (row reduction over the 16 lanes sharing ty; lane = (ty&1)*16+tx)
        const bool diag = (kt == qtile);
        #pragma unroll
        for (int i = 0; i < 4; ++i) {
            const int qg = qtile * 64 + r0 + i;
            float rmax = -1e30f;
            #pragma unroll
            for (int j = 0; j < 4; ++j) {
                float v = s4[i][j] * 0.125f;            // 1/sqrt(64)
                if (diag && (kt * 64 + c0 + j) > qg) v = -1e30f;
                s4[i][j] = v;
                rmax = fmaxf(rmax, v);
            }
            rmax = fmaxf(rmax, __shfl_xor_sync(0xffffffffu, rmax, 8));
            rmax = fmaxf(rmax, __shfl_xor_sync(0xffffffffu, rmax, 4));
            rmax = fmaxf(rmax, __shfl_xor_sync(0xffffffffu, rmax, 2));
            rmax = fmaxf(rmax, __shfl_xor_sync(0xffffffffu, rmax, 1));
            const float mnew = fmaxf(m[i], rmax);
            const float corr = __expf(m[i] - mnew);
            float rsum = 0.f;
            #pragma unroll
            for (int j = 0; j < 4; ++j) {
                const float p = __expf(s4[i][j] - mnew);
                s4[i][j] = p;
                rsum += p;
            }
            rsum += __shfl_xor_sync(0xffffffffu, rsum, 8);
            rsum += __shfl_xor_sync(0xffffffffu, rsum, 4);
            rsum += __shfl_xor_sync(0xffffffffu, rsum, 2);
            rsum += __shfl_xor_sync(0xffffffffu, rsum, 1);
            lsum[i] = lsum[i] * corr + rsum;
            m[i] = mnew;
            #pragma unroll
            for (int j = 0; j < 4; ++j) o[i][j] *= corr;
        }

        // stage P (transposed) for the PV product
        #pragma unroll
        for (int i = 0; i < 4; ++i)
            #pragma unroll
            for (int j = 0; j < 4; ++j)
                Ps[(c0 + j) * 68 + (r0 + i)] = s4[i][j];
        __syncthreads();

        // O += P @ V   (thread: rows r0..r0+3, d-cols c0..c0+3)
        #pragma unroll 8
        for (int c = 0; c < 64; ++c) {
            const float4 pa = *(const float4*)(Ps + c * 68 + r0);
            const float4 vv = *(const float4*)(Vs + c * 64 + c0);
            const float pr[4] = {pa.x, pa.y, pa.z, pa.w};
            const float vr[4] = {vv.x, vv.y, vv.z, vv.w};
            #pragma unroll
            for (int i = 0; i < 4; ++i)
                #pragma unroll
                for (int j = 0; j < 4; ++j)
                    o[i][j] += pr[i] * vr[j];
        }
    }

    // epilogue: normalize and write (B,S,H*D)
    #pragma unroll
    for (int i = 0; i < 4; ++i) {
        const int qg = qtile * 64 + r0 + i;
        const float inv = 1.0f / lsum[i];
        float4 v = make_float4(o[i][0] * inv, o[i][1] * inv, o[i][2] * inv, o[i][3] * inv);
        *(float4*)(O + ((size_t)(b * SEQ) + qg) * DIM + h * HD + c0) = v;
    }
}

// ---------------- host launcher ----------------
extern "C" void kernel_launch(void* const* d_in, const int* in_sizes, int n_in,
                              void* d_out, int out_size) {
    (void)in_sizes; (void)n_in; (void)out_size;
    const float* x  = (const float*)d_in[0];
    const float* Wq = (const float*)d_in[1];
    const float* Wk = (const float*)d_in[2];
    const float* Wv = (const float*)d_in[3];
    const float* bv = (const float*)d_in[4];
    const float* Wo = (const float*)d_in[5];
    const float* bo = (const float*)d_in[6];
    // d_in[7] = mask: causality is computed analytically
    float* out = (float*)d_out;

    float *qlin, *klin, *vlin, *qt, *kt, *vt, *attn;
    cudaGetSymbolAddress((void**)&qlin, g_qlin);
    cudaGetSymbolAddress((void**)&klin, g_klin);
    cudaGetSymbolAddress((void**)&vlin, g_vlin);
    cudaGetSymbolAddress((void**)&qt,   g_qt);
    cudaGetSymbolAddress((void**)&kt,   g_kt);
    cudaGetSymbolAddress((void**)&vt,   g_vt);
    cudaGetSymbolAddress((void**)&attn, g_attn);

    theta_kernel<<<1, 32>>>();

    // QKV projections
    sgemm128<<<dim3(DIM / 128,   MROWS / 128), 256>>>(x, Wq, nullptr, qlin, DIM,   DIM);
    sgemm128<<<dim3(KVDIM / 128, MROWS / 128), 256>>>(x, Wk, nullptr, klin, KVDIM, DIM);
    sgemm128<<<dim3(KVDIM / 128, MROWS / 128), 256>>>(x, Wv, bv,      vlin, KVDIM, DIM);

    // RoPE + layout
    rope_q_kernel<<<(BATCH * SEQ * NH * 32) / 256, 256>>>(qlin, qt);
    rope_k_kernel<<<(BATCH * SEQ * NKV * 32) / 256, 256>>>(klin, kt);
    transpose_v_kernel<<<(BATCH * SEQ * NKV * 16) / 256, 256>>>(vlin, vt);

    // causal flash attention
    const int smem = (3 * 64 * 68 + 64 * 64) * sizeof(float);  // 68608 B
    cudaFuncSetAttribute(flash_kernel, cudaFuncAttributeMaxDynamicSharedMemorySize, smem);
    flash_kernel<<<dim3(SEQ / 64, NH, BATCH), 256, smem>>>(qt, kt, vt, attn);

    // output projection
    sgemm128<<<dim3(DIM / 128, MROWS / 128), 256>>>(attn, Wo, bo, out, DIM, DIM);
}

// round 3
// speedup vs baseline: 1.2407x; 1.2407x over previous
#include <cuda_runtime.h>
#include <math.h>
#include <stdint.h>

#define DIM 2048
#define NH 32
#define NKV 8
#define HD 64
#define BATCH 2
#define SEQ 2048
#define MROWS (BATCH*SEQ)   /* 4096 */
#define KVDIM (NKV*HD)      /* 512 */

// ---------------- scratch (static device allocations; no cudaMalloc) ----------------
__device__ float g_qlin[(size_t)MROWS * DIM];
__device__ float g_klin[(size_t)MROWS * KVDIM];
__device__ float g_vlin[(size_t)MROWS * KVDIM];
__device__ float g_qt[(size_t)BATCH * NH * SEQ * HD];
__device__ float g_kt[(size_t)BATCH * NKV * SEQ * HD];
__device__ float g_vt[(size_t)BATCH * NKV * SEQ * HD];
__device__ float g_attn[(size_t)MROWS * DIM];
__device__ float g_wt[(size_t)DIM * DIM];              // transposed weight scratch (reused)
__device__ double g_theta[HD / 2];

// ---------------- RoPE angle table ----------------
__global__ void theta_kernel() {
    int p = threadIdx.x;
    if (p < HD / 2) g_theta[p] = pow(10000.0, -(double)p / 32.0);
}

// ---------------- weight transpose: in R x C -> out C x R ----------------
__global__ void transpose_kernel(const float* __restrict__ in, float* __restrict__ out,
                                 int R, int Ccols) {
    __shared__ float tile[32][33];
    int bx = blockIdx.x * 32, by = blockIdx.y * 32;
    int x = bx + threadIdx.x;
    #pragma unroll
    for (int i = 0; i < 32; i += 8)
        tile[threadIdx.y + i][threadIdx.x] = in[(size_t)(by + threadIdx.y + i) * Ccols + x];
    __syncthreads();
    int ox = by + threadIdx.x;
    #pragma unroll
    for (int i = 0; i < 32; i += 8)
        out[(size_t)(bx + threadIdx.y + i) * R + ox] = tile[threadIdx.x][threadIdx.y + i];
}

// ================= mma.sync tf32 helpers (sm_80+ feature set; works at compute_103) ======
__device__ __forceinline__ void mma_tf32(float* d, const uint32_t* a, const uint32_t* b) {
    asm volatile(
        "mma.sync.aligned.m16n8k8.row.col.f32.tf32.tf32.f32 "
        "{%0,%1,%2,%3}, {%4,%5,%6,%7}, {%8,%9}, {%0,%1,%2,%3};\n"
        : "+f"(d[0]), "+f"(d[1]), "+f"(d[2]), "+f"(d[3])
        : "r"(a[0]), "r"(a[1]), "r"(a[2]), "r"(a[3]), "r"(b[0]), "r"(b[1]));
}
__device__ __forceinline__ void split_tf32(float x, uint32_t& hi, uint32_t& lo) {
    uint32_t h;
    asm("cvt.rna.tf32.f32 %0, %1;" : "=r"(h) : "f"(x));
    float r = x - __uint_as_float(h);
    uint32_t l;
    asm("cvt.rna.tf32.f32 %0, %1;" : "=r"(l) : "f"(r));
    hi = h; lo = l;
}

// ---------------- tensor-core tf32 GEMM with 3xTF32 split ----------------
// C[M,N] = A[M,K] @ Bt[N,K]^T (+bias). M%128==0, N%128==0, K%16==0.
// 128x128 tile, 8 warps in 4(m) x 2(n): warp tile 32x64. K-chunk 16, reg-prefetch.
#define GPAD 20   /* smem row stride (floats): conflict-free for the frag access pattern */

__global__ void __launch_bounds__(256) mma_gemm_tf32(
    const float* __restrict__ A, const float* __restrict__ Bt,
    const float* __restrict__ bias, float* __restrict__ C, int N, int K)
{
    __shared__ float As[128 * GPAD];
    __shared__ float Bs[128 * GPAD];

    const int t    = threadIdx.x;
    const int lane = t & 31;
    const int wid  = t >> 5;
    const int wr   = wid & 3;          // warp m index: rows wr*32..+31
    const int wc   = wid >> 2;         // warp n index: cols wc*64..+63
    const int qid  = lane >> 2;        // group id 0..7
    const int tid4 = lane & 3;         // thread-in-group 0..3

    const size_t m0 = (size_t)blockIdx.y * 128;
    const size_t n0 = (size_t)blockIdx.x * 128;
    const float* Ab = A  + m0 * K;
    const float* Bb = Bt + n0 * K;

    const int lrow = t >> 1;           // 0..127
    const int lcol = (t & 1) * 8;      // 0 or 8

    float acc[2][8][4];
    #pragma unroll
    for (int mf = 0; mf < 2; ++mf)
        #pragma unroll
        for (int nf = 0; nf < 8; ++nf)
            #pragma unroll
            for (int r = 0; r < 4; ++r) acc[mf][nf][r] = 0.f;

    const int nchunks = K / 16;

    // prefetch chunk 0
    float4 pa0 = *(const float4*)(Ab + (size_t)lrow * K + lcol);
    float4 pa1 = *(const float4*)(Ab + (size_t)lrow * K + lcol + 4);
    float4 pb0 = *(const float4*)(Bb + (size_t)lrow * K + lcol);
    float4 pb1 = *(const float4*)(Bb + (size_t)lrow * K + lcol + 4);

    for (int c = 0; c < nchunks; ++c) {
        *(float4*)(As + lrow * GPAD + lcol)     = pa0;
        *(float4*)(As + lrow * GPAD + lcol + 4) = pa1;
        *(float4*)(Bs + lrow * GPAD + lcol)     = pb0;
        *(float4*)(Bs + lrow * GPAD + lcol + 4) = pb1;
        __syncthreads();

        if (c + 1 < nchunks) {
            const int k0 = (c + 1) * 16;
            pa0 = *(const float4*)(Ab + (size_t)lrow * K + k0 + lcol);
            pa1 = *(const float4*)(Ab + (size_t)lrow * K + k0 + lcol + 4);
            pb0 = *(const float4*)(Bb + (size_t)lrow * K + k0 + lcol);
            pb1 = *(const float4*)(Bb + (size_t)lrow * K + k0 + lcol + 4);
        }

        #pragma unroll
        for (int ks = 0; ks < 16; ks += 8) {
            // A fragments (2 m-tiles), split hi/lo
            uint32_t ahi[2][4], alo[2][4];
            #pragma unroll
            for (int mf = 0; mf < 2; ++mf) {
                const int rb = wr * 32 + mf * 16 + qid;
                const float a0 = As[(rb    ) * GPAD + ks + tid4];
                const float a1 = As[(rb + 8) * GPAD + ks + tid4];
                const float a2 = As[(rb    ) * GPAD + ks + tid4 + 4];
                const float a3 = As[(rb + 8) * GPAD + ks + tid4 + 4];
                split_tf32(a0, ahi[mf][0], alo[mf][0]);
                split_tf32(a1, ahi[mf][1], alo[mf][1]);
                split_tf32(a2, ahi[mf][2], alo[mf][2]);
                split_tf32(a3, ahi[mf][3], alo[mf][3]);
            }
            // B fragments (8 n-tiles), split hi/lo, 3-term mma
            #pragma unroll
            for (int nf = 0; nf < 8; ++nf) {
                const int nb = wc * 64 + nf * 8 + qid;
                const float b0 = Bs[nb * GPAD + ks + tid4];
                const float b1 = Bs[nb * GPAD + ks + tid4 + 4];
                uint32_t bh[2], bl[2];
                split_tf32(b0, bh[0], bl[0]);
                split_tf32(b1, bh[1], bl[1]);
                #pragma unroll
                for (int mf = 0; mf < 2; ++mf) {
                    mma_tf32(acc[mf][nf], ahi[mf], bh);
                    mma_tf32(acc[mf][nf], alo[mf], bh);
                    mma_tf32(acc[mf][nf], ahi[mf], bl);
                }
            }
        }
        __syncthreads();
    }

    // epilogue: c0,c1 -> (row, col), (row, col+1); c2,c3 -> (row+8, ...)
    const int trow = qid;
    const int tcol = tid4 * 2;
    #pragma unroll
    for (int mf = 0; mf < 2; ++mf) {
        const size_t m = m0 + wr * 32 + mf * 16 + trow;
        #pragma unroll
        for (int nf = 0; nf < 8; ++nf) {
            const int ncol = (int)n0 + wc * 64 + nf * 8 + tcol;
            float2 v0 = make_float2(acc[mf][nf][0], acc[mf][nf][1]);
            float2 v1 = make_float2(acc[mf][nf][2], acc[mf][nf][3]);
            if (bias) {
                const float bx = bias[ncol], by = bias[ncol + 1];
                v0.x += bx; v0.y += by;
                v1.x += bx; v1.y += by;
            }
            *(float2*)(C + m * N + ncol)       = v0;
            *(float2*)(C + (m + 8) * N + ncol) = v1;
        }
    }
}

// ---------------- RoPE + layout transpose ----------------
__global__ void rope_q_kernel(const float* __restrict__ in, float* __restrict__ out) {
    int idx = blockIdx.x * blockDim.x + threadIdx.x;
    int p = idx & 31;
    int h = (idx >> 5) & 31;
    int s = (idx >> 10) & 2047;
    int b = idx >> 21;
    float ang = (float)((double)s * g_theta[p]);
    float sv, cv;
    sincosf(ang, &sv, &cv);
    const float2 x = *(const float2*)(in + ((size_t)(b * SEQ + s)) * DIM + h * HD + 2 * p);
    float2 r;
    r.x = x.x * cv - x.y * sv;
    r.y = x.x * sv + x.y * cv;
    *(float2*)(out + (((size_t)(b * NH + h)) * SEQ + s) * HD + 2 * p) = r;
}
__global__ void rope_k_kernel(const float* __restrict__ in, float* __restrict__ out) {
    int idx = blockIdx.x * blockDim.x + threadIdx.x;
    int p = idx & 31;
    int h = (idx >> 5) & 7;
    int s = (idx >> 8) & 2047;
    int b = idx >> 19;
    float ang = (float)((double)s * g_theta[p]);
    float sv, cv;
    sincosf(ang, &sv, &cv);
    const float2 x = *(const float2*)(in + ((size_t)(b * SEQ + s)) * KVDIM + h * HD + 2 * p);
    float2 r;
    r.x = x.x * cv - x.y * sv;
    r.y = x.x * sv + x.y * cv;
    *(float2*)(out + (((size_t)(b * NKV + h)) * SEQ + s) * HD + 2 * p) = r;
}
__global__ void transpose_v_kernel(const float* __restrict__ in, float* __restrict__ out) {
    int idx = blockIdx.x * blockDim.x + threadIdx.x;
    int d4 = idx & 15;
    int h  = (idx >> 4) & 7;
    int s  = (idx >> 7) & 2047;
    int b  = idx >> 18;
    const float4 v = *(const float4*)(in + ((size_t)(b * SEQ + s)) * KVDIM + h * HD + d4 * 4);
    *(float4*)(out + (((size_t)(b * NKV + h)) * SEQ + s) * HD + d4 * 4) = v;
}

// ---------------- causal flash attention, fp32, 64x64 tiles (unchanged) ----------------
__global__ void __launch_bounds__(256) flash_kernel(
    const float* __restrict__ Q, const float* __restrict__ K,
    const float* __restrict__ V, float* __restrict__ O)
{
    extern __shared__ float smf[];
    float* Qt = smf;
    float* Ks = Qt + 64 * 68;
    float* Vs = Ks + 64 * 68;
    float* Ps = Vs + 64 * 64;

    const int qtile = blockIdx.x;
    const int h     = blockIdx.y;
    const int b     = blockIdx.z;
    const int kvh   = h >> 2;
    const int t  = threadIdx.x;
    const int tx = t & 15, ty = t >> 4;
    const int r0 = ty * 4, c0 = tx * 4;

    const float* Qb = Q + (((size_t)(b * NH + h)) * SEQ + qtile * 64) * HD;
    const float* Kb = K + ((size_t)(b * NKV + kvh)) * SEQ * HD;
    const float* Vb = V + ((size_t)(b * NKV + kvh)) * SEQ * HD;

    for (int i = t * 4; i < 64 * 64; i += 1024) {
        int r = i >> 6, d = i & 63;
        float4 q4 = *(const float4*)(Qb + r * 64 + d);
        Qt[(d + 0) * 68 + r] = q4.x;
        Qt[(d + 1) * 68 + r] = q4.y;
        Qt[(d + 2) * 68 + r] = q4.z;
        Qt[(d + 3) * 68 + r] = q4.w;
    }

    float o[4][4];
    float m[4], lsum[4];
    #pragma unroll
    for (int i = 0; i < 4; ++i) {
        m[i] = -1e30f; lsum[i] = 0.f;
        #pragma unroll
        for (int j = 0; j < 4; ++j) o[i][j] = 0.f;
    }

    for (int kt = 0; kt <= qtile; ++kt) {
        __syncthreads();
        for (int i = t * 4; i < 64 * 64; i += 1024) {
            int r = i >> 6, d = i & 63;
            float4 k4 = *(const float4*)(Kb + (size_t)(kt * 64 + r) * 64 + d);
            Ks[(d + 0) * 68 + r] = k4.x;
            Ks[(d + 1) * 68 + r] = k4.y;
            Ks[(d + 2) * 68 + r] = k4.z;
            Ks[(d + 3) * 68 + r] = k4.w;
            *(float4*)(Vs + r * 64 + d) = *(const float4*)(Vb + (size_t)(kt * 64 + r) * 64 + d);
        }
        __syncthreads();

        float s4[4][4];
        #pragma unroll
        for (int i = 0; i < 4; ++i)
            #pragma unroll
            for (int j = 0; j < 4; ++j) s4[i][j] = 0.f;

        #pragma unroll 8
        for (int d = 0; d < 64; ++d) {
            const float4 qa = *(const float4*)(Qt + d * 68 + r0);
            const float4 kb = *(const float4*)(Ks + d * 68 + c0);
            const float ra[4] = {qa.x, qa.y, qa.z, qa.w};
            const float rb[4] = {kb.x, kb.y, kb.z, kb.w};
            #pragma unroll
            for (int i = 0; i < 4; ++i)
                #pragma unroll
                for (int j = 0; j < 4; ++j)
                    s4[i][j] += ra[i] * rb[j];
        }

        const bool diag = (kt == qtile);
        #pragma unroll
        for (int i = 0; i < 4; ++i) {
            const int qg = qtile * 64 + r0 + i;
            float rmax = -1e30f;
            #pragma unroll
            for (int j = 0; j < 4; ++j) {
                float v = s4[i][j] * 0.125f;
                if (diag && (kt * 64 + c0 + j) > qg) v = -1e30f;
                s4[i][j] = v;
                rmax = fmaxf(rmax, v);
            }
            rmax = fmaxf(rmax, __shfl_xor_sync(0xffffffffu, rmax, 8));
            rmax = fmaxf(rmax, __shfl_xor_sync(0xffffffffu, rmax, 4));
            rmax = fmaxf(rmax, __shfl_xor_sync(0xffffffffu, rmax, 2));
            rmax = fmaxf(rmax, __shfl_xor_sync(0xffffffffu, rmax, 1));
            const float mnew = fmaxf(m[i], rmax);
            const float corr = __expf(m[i] - mnew);
            float rsum = 0.f;
            #pragma unroll
            for (int j = 0; j < 4; ++j) {
                const float p = __expf(s4[i][j] - mnew);
                s4[i][j] = p;
                rsum += p;
            }
            rsum += __shfl_xor_sync(0xffffffffu, rsum, 8);
            rsum += __shfl_xor_sync(0xffffffffu, rsum, 4);
            rsum += __shfl_xor_sync(0xffffffffu, rsum, 2);
            rsum += __shfl_xor_sync(0xffffffffu, rsum, 1);
            lsum[i] = lsum[i] * corr + rsum;
            m[i] = mnew;
            #pragma unroll
            for (int j = 0; j < 4; ++j) o[i][j] *= corr;
        }

        #pragma unroll
        for (int i = 0; i < 4; ++i)
            #pragma unroll
            for (int j = 0; j < 4; ++j)
                Ps[(c0 + j) * 68 + (r0 + i)] = s4[i][j];
        __syncthreads();

        #pragma unroll 8
        for (int c = 0; c < 64; ++c) {
            const float4 pa = *(const float4*)(Ps + c * 68 + r0);
            const float4 vv = *(const float4*)(Vs + c * 64 + c0);
            const float pr[4] = {pa.x, pa.y, pa.z, pa.w};
            const float vr[4] = {vv.x, vv.y, vv.z, vv.w};
            #pragma unroll
            for (int i = 0; i < 4; ++i)
                #pragma unroll
                for (int j = 0; j < 4; ++j)
                    o[i][j] += pr[i] * vr[j];
        }
    }

    #pragma unroll
    for (int i = 0; i < 4; ++i) {
        const int qg = qtile * 64 + r0 + i;
        const float inv = 1.0f / lsum[i];
        float4 v = make_float4(o[i][0] * inv, o[i][1] * inv, o[i][2] * inv, o[i][3] * inv);
        *(float4*)(O + ((size_t)(b * SEQ) + qg) * DIM + h * HD + c0) = v;
    }
}

// ---------------- host launcher ----------------
extern "C" void kernel_launch(void* const* d_in, const int* in_sizes, int n_in,
                              void* d_out, int out_size) {
    (void)in_sizes; (void)n_in; (void)out_size;
    const float* x  = (const float*)d_in[0];
    const float* Wq = (const float*)d_in[1];
    const float* Wk = (const float*)d_in[2];
    const float* Wv = (const float*)d_in[3];
    const float* bv = (const float*)d_in[4];
    const float* Wo = (const float*)d_in[5];
    const float* bo = (const float*)d_in[6];
    float* out = (float*)d_out;

    float *qlin, *klin, *vlin, *qt, *kt, *vt, *attn, *wt;
    cudaGetSymbolAddress((void**)&qlin, g_qlin);
    cudaGetSymbolAddress((void**)&klin, g_klin);
    cudaGetSymbolAddress((void**)&vlin, g_vlin);
    cudaGetSymbolAddress((void**)&qt,   g_qt);
    cudaGetSymbolAddress((void**)&kt,   g_kt);
    cudaGetSymbolAddress((void**)&vt,   g_vt);
    cudaGetSymbolAddress((void**)&attn, g_attn);
    cudaGetSymbolAddress((void**)&wt,   g_wt);

    theta_kernel<<<1, 32>>>();

    // QKV projections on tensor cores (weights transposed into reused scratch first)
    transpose_kernel<<<dim3(DIM / 32, DIM / 32), dim3(32, 8)>>>(Wq, wt, DIM, DIM);
    mma_gemm_tf32<<<dim3(DIM / 128, MROWS / 128), 256>>>(x, wt, nullptr, qlin, DIM, DIM);
    transpose_kernel<<<dim3(KVDIM / 32, DIM / 32), dim3(32, 8)>>>(Wk, wt, DIM, KVDIM);
    mma_gemm_tf32<<<dim3(KVDIM / 128, MROWS / 128), 256>>>(x, wt, nullptr, klin, KVDIM, DIM);
    transpose_kernel<<<dim3(KVDIM / 32, DIM / 32), dim3(32, 8)>>>(Wv, wt, DIM, KVDIM);
    mma_gemm_tf32<<<dim3(KVDIM / 128, MROWS / 128), 256>>>(x, wt, bv, vlin, KVDIM, DIM);

    // RoPE + layout
    rope_q_kernel<<<(BATCH * SEQ * NH * 32) / 256, 256>>>(qlin, qt);
    rope_k_kernel<<<(BATCH * SEQ * NKV * 32) / 256, 256>>>(klin, kt);
    transpose_v_kernel<<<(BATCH * SEQ * NKV * 16) / 256, 256>>>(vlin, vt);

    // causal flash attention (fp32, unchanged this round)
    const int smem = (3 * 64 * 68 + 64 * 64) * sizeof(float);
    cudaFuncSetAttribute(flash_kernel, cudaFuncAttributeMaxDynamicSharedMemorySize, smem);
    flash_kernel<<<dim3(SEQ / 64, NH, BATCH), 256, smem>>>(qt, kt, vt, attn);

    // output projection on tensor cores
    transpose_kernel<<<dim3(DIM / 32, DIM / 32), dim3(32, 8)>>>(Wo, wt, DIM, DIM);
    mma_gemm_tf32<<<dim3(DIM / 128, MROWS / 128), 256>>>(attn, wt, bo, out, DIM, DIM);
}

// round 4
// speedup vs baseline: 1.5136x; 1.2200x over previous
#include <cuda_runtime.h>
#include <math.h>
#include <stdint.h>

#define DIM 2048
#define NH 32
#define NKV 8
#define HD 64
#define BATCH 2
#define SEQ 2048
#define MROWS (BATCH*SEQ)   /* 4096 */
#define KVDIM (NKV*HD)      /* 512 */

// ---------------- scratch (static device allocations; no cudaMalloc) ----------------
__device__ float g_qlin[(size_t)MROWS * DIM];
__device__ float g_klin[(size_t)MROWS * KVDIM];
__device__ float g_vlin[(size_t)MROWS * KVDIM];
__device__ float g_qt[(size_t)BATCH * NH * SEQ * HD];
__device__ float g_kt[(size_t)BATCH * NKV * SEQ * HD];
__device__ float g_vt[(size_t)BATCH * NKV * SEQ * HD];
__device__ float g_attn[(size_t)MROWS * DIM];
__device__ float g_wt[(size_t)DIM * DIM];              // transposed weight scratch (reused)
__device__ double g_theta[HD / 2];

// ---------------- RoPE angle table ----------------
__global__ void theta_kernel() {
    int p = threadIdx.x;
    if (p < HD / 2) g_theta[p] = pow(10000.0, -(double)p / 32.0);
}

// ---------------- weight transpose: in R x C -> out C x R ----------------
__global__ void transpose_kernel(const float* __restrict__ in, float* __restrict__ out,
                                 int R, int Ccols) {
    __shared__ float tile[32][33];
    int bx = blockIdx.x * 32, by = blockIdx.y * 32;
    int x = bx + threadIdx.x;
    #pragma unroll
    for (int i = 0; i < 32; i += 8)
        tile[threadIdx.y + i][threadIdx.x] = in[(size_t)(by + threadIdx.y + i) * Ccols + x];
    __syncthreads();
    int ox = by + threadIdx.x;
    #pragma unroll
    for (int i = 0; i < 32; i += 8)
        out[(size_t)(bx + threadIdx.y + i) * R + ox] = tile[threadIdx.x][threadIdx.y + i];
}

// ================= mma.sync tf32 helpers =================
__device__ __forceinline__ void mma_tf32(float* d, const uint32_t* a, const uint32_t* b) {
    asm volatile(
        "mma.sync.aligned.m16n8k8.row.col.f32.tf32.tf32.f32 "
        "{%0,%1,%2,%3}, {%4,%5,%6,%7}, {%8,%9}, {%0,%1,%2,%3};\n"
        : "+f"(d[0]), "+f"(d[1]), "+f"(d[2]), "+f"(d[3])
        : "r"(a[0]), "r"(a[1]), "r"(a[2]), "r"(a[3]), "r"(b[0]), "r"(b[1]));
}
__device__ __forceinline__ void split_tf32(float x, uint32_t& hi, uint32_t& lo) {
    uint32_t h;
    asm("cvt.rna.tf32.f32 %0, %1;" : "=r"(h) : "f"(x));
    float r = x - __uint_as_float(h);
    uint32_t l;
    asm("cvt.rna.tf32.f32 %0, %1;" : "=r"(l) : "f"(r));
    hi = h; lo = l;
}
__device__ __forceinline__ uint32_t cvt_tf32(float x) {
    uint32_t r;
    asm("cvt.rna.tf32.f32 %0, %1;" : "=r"(r) : "f"(x));
    return r;
}
// fast 2^y on the FMA pipe (y <= 0 expected; clamps below -120 to ~0)
__device__ __forceinline__ float exp2p(float y) {
    y = fmaxf(y, -120.f);
    int ki = __float2int_rn(y);
    float f = y - (float)ki;
    float p = 0.0013333558f;
    p = fmaf(p, f, 0.0096181291f);
    p = fmaf(p, f, 0.0555041087f);
    p = fmaf(p, f, 0.2402265070f);
    p = fmaf(p, f, 0.6931471806f);
    p = fmaf(p, f, 1.0f);
    return p * __int_as_float((ki + 127) << 23);
}

// ---------------- tensor-core tf32 GEMM with 3xTF32 split (unchanged from R3) ----------
#define GPAD 20

__global__ void __launch_bounds__(256) mma_gemm_tf32(
    const float* __restrict__ A, const float* __restrict__ Bt,
    const float* __restrict__ bias, float* __restrict__ C, int N, int K)
{
    __shared__ float As[128 * GPAD];
    __shared__ float Bs[128 * GPAD];

    const int t    = threadIdx.x;
    const int lane = t & 31;
    const int wid  = t >> 5;
    const int wr   = wid & 3;
    const int wc   = wid >> 2;
    const int qid  = lane >> 2;
    const int tid4 = lane & 3;

    const size_t m0 = (size_t)blockIdx.y * 128;
    const size_t n0 = (size_t)blockIdx.x * 128;
    const float* Ab = A  + m0 * K;
    const float* Bb = Bt + n0 * K;

    const int lrow = t >> 1;
    const int lcol = (t & 1) * 8;

    float acc[2][8][4];
    #pragma unroll
    for (int mf = 0; mf < 2; ++mf)
        #pragma unroll
        for (int nf = 0; nf < 8; ++nf)
            #pragma unroll
            for (int r = 0; r < 4; ++r) acc[mf][nf][r] = 0.f;

    const int nchunks = K / 16;

    float4 pa0 = *(const float4*)(Ab + (size_t)lrow * K + lcol);
    float4 pa1 = *(const float4*)(Ab + (size_t)lrow * K + lcol + 4);
    float4 pb0 = *(const float4*)(Bb + (size_t)lrow * K + lcol);
    float4 pb1 = *(const float4*)(Bb + (size_t)lrow * K + lcol + 4);

    for (int c = 0; c < nchunks; ++c) {
        *(float4*)(As + lrow * GPAD + lcol)     = pa0;
        *(float4*)(As + lrow * GPAD + lcol + 4) = pa1;
        *(float4*)(Bs + lrow * GPAD + lcol)     = pb0;
        *(float4*)(Bs + lrow * GPAD + lcol + 4) = pb1;
        __syncthreads();

        if (c + 1 < nchunks) {
            const int k0 = (c + 1) * 16;
            pa0 = *(const float4*)(Ab + (size_t)lrow * K + k0 + lcol);
            pa1 = *(const float4*)(Ab + (size_t)lrow * K + k0 + lcol + 4);
            pb0 = *(const float4*)(Bb + (size_t)lrow * K + k0 + lcol);
            pb1 = *(const float4*)(Bb + (size_t)lrow * K + k0 + lcol + 4);
        }

        #pragma unroll
        for (int ks = 0; ks < 16; ks += 8) {
            uint32_t ahi[2][4], alo[2][4];
            #pragma unroll
            for (int mf = 0; mf < 2; ++mf) {
                const int rb = wr * 32 + mf * 16 + qid;
                split_tf32(As[(rb    ) * GPAD + ks + tid4],     ahi[mf][0], alo[mf][0]);
                split_tf32(As[(rb + 8) * GPAD + ks + tid4],     ahi[mf][1], alo[mf][1]);
                split_tf32(As[(rb    ) * GPAD + ks + tid4 + 4], ahi[mf][2], alo[mf][2]);
                split_tf32(As[(rb + 8) * GPAD + ks + tid4 + 4], ahi[mf][3], alo[mf][3]);
            }
            #pragma unroll
            for (int nf = 0; nf < 8; ++nf) {
                const int nb = wc * 64 + nf * 8 + qid;
                uint32_t bh[2], bl[2];
                split_tf32(Bs[nb * GPAD + ks + tid4],     bh[0], bl[0]);
                split_tf32(Bs[nb * GPAD + ks + tid4 + 4], bh[1], bl[1]);
                #pragma unroll
                for (int mf = 0; mf < 2; ++mf) {
                    mma_tf32(acc[mf][nf], ahi[mf], bh);
                    mma_tf32(acc[mf][nf], alo[mf], bh);
                    mma_tf32(acc[mf][nf], ahi[mf], bl);
                }
            }
        }
        __syncthreads();
    }

    const int trow = qid;
    const int tcol = tid4 * 2;
    #pragma unroll
    for (int mf = 0; mf < 2; ++mf) {
        const size_t m = m0 + wr * 32 + mf * 16 + trow;
        #pragma unroll
        for (int nf = 0; nf < 8; ++nf) {
            const int ncol = (int)n0 + wc * 64 + nf * 8 + tcol;
            float2 v0 = make_float2(acc[mf][nf][0], acc[mf][nf][1]);
            float2 v1 = make_float2(acc[mf][nf][2], acc[mf][nf][3]);
            if (bias) {
                const float bx = bias[ncol], by = bias[ncol + 1];
                v0.x += bx; v0.y += by;
                v1.x += bx; v1.y += by;
            }
            *(float2*)(C + m * N + ncol)       = v0;
            *(float2*)(C + (m + 8) * N + ncol) = v1;
        }
    }
}

// ---------------- RoPE + layout transpose ----------------
__global__ void rope_q_kernel(const float* __restrict__ in, float* __restrict__ out) {
    int idx = blockIdx.x * blockDim.x + threadIdx.x;
    int p = idx & 31;
    int h = (idx >> 5) & 31;
    int s = (idx >> 10) & 2047;
    int b = idx >> 21;
    float ang = (float)((double)s * g_theta[p]);
    float sv, cv;
    sincosf(ang, &sv, &cv);
    const float2 x = *(const float2*)(in + ((size_t)(b * SEQ + s)) * DIM + h * HD + 2 * p);
    float2 r;
    r.x = x.x * cv - x.y * sv;
    r.y = x.x * sv + x.y * cv;
    *(float2*)(out + (((size_t)(b * NH + h)) * SEQ + s) * HD + 2 * p) = r;
}
__global__ void rope_k_kernel(const float* __restrict__ in, float* __restrict__ out) {
    int idx = blockIdx.x * blockDim.x + threadIdx.x;
    int p = idx & 31;
    int h = (idx >> 5) & 7;
    int s = (idx >> 8) & 2047;
    int b = idx >> 19;
    float ang = (float)((double)s * g_theta[p]);
    float sv, cv;
    sincosf(ang, &sv, &cv);
    const float2 x = *(const float2*)(in + ((size_t)(b * SEQ + s)) * KVDIM + h * HD + 2 * p);
    float2 r;
    r.x = x.x * cv - x.y * sv;
    r.y = x.x * sv + x.y * cv;
    *(float2*)(out + (((size_t)(b * NKV + h)) * SEQ + s) * HD + 2 * p) = r;
}
__global__ void transpose_v_kernel(const float* __restrict__ in, float* __restrict__ out) {
    int idx = blockIdx.x * blockDim.x + threadIdx.x;
    int d4 = idx & 15;
    int h  = (idx >> 4) & 7;
    int s  = (idx >> 7) & 2047;
    int b  = idx >> 18;
    const float4 v = *(const float4*)(in + ((size_t)(b * SEQ + s)) * KVDIM + h * HD + d4 * 4);
    *(float4*)(out + (((size_t)(b * NKV + h)) * SEQ + s) * HD + d4 * 4) = v;
}

// ---------------- tensor-core causal flash attention ----------------
// Q tile 128 rows/CTA, KV tiles of 64. 8 warps; warp w owns rows w*16..w*16+15
// (full width) => softmax entirely warp-local. Scores: (Qhi+Qlo) x K(tf32).
// PV: (Phi+Plo) x V(tf32). exp via FMA-pipe poly (no MUFU).
#define FQ 128
#define FK 64
#define QPAD 68
#define KPAD 68
#define VPAD 72
#define PPAD 76
#define FLASH_SMEM ((FQ*QPAD + FK*KPAD + FK*VPAD + FQ*PPAD) * 4)

__global__ void __launch_bounds__(256) flash_mma_kernel(
    const float* __restrict__ Q, const float* __restrict__ K,
    const float* __restrict__ V, float* __restrict__ O)
{
    extern __shared__ float sm[];
    float* Qs = sm;                       // [128][QPAD]
    float* Ks = Qs + FQ * QPAD;           // [64][KPAD]
    float* Vs = Ks + FK * KPAD;           // [64][VPAD]
    float* Ps = Vs + FK * VPAD;           // [128][PPAD]

    const int qt  = (SEQ / FQ - 1) - blockIdx.x;   // heavy CTAs first
    const int h   = blockIdx.y;
    const int b   = blockIdx.z;
    const int kvh = h >> 2;
    const int t    = threadIdx.x;
    const int lane = t & 31;
    const int w    = t >> 5;
    const int qid  = lane >> 2;
    const int tid4 = lane & 3;
    const int q0   = qt * FQ;
    const int wrow = w * 16;

    const float* Qb = Q + (((size_t)(b * NH + h)) * SEQ + q0) * HD;
    const float* Kb = K + ((size_t)(b * NKV + kvh)) * SEQ * HD;
    const float* Vb = V + ((size_t)(b * NKV + kvh)) * SEQ * HD;

    #pragma unroll
    for (int i = t * 4; i < FQ * HD; i += 1024) {
        const int r = i >> 6, c = i & 63;
        *(float4*)(Qs + r * QPAD + c) = *(const float4*)(Qb + r * HD + c);
    }

    float oacc[8][4];
    #pragma unroll
    for (int nf = 0; nf < 8; ++nf)
        #pragma unroll
        for (int j = 0; j < 4; ++j) oacc[nf][j] = 0.f;
    float m[2] = {-1e30f, -1e30f};
    float l[2] = {0.f, 0.f};

    const int row_a = q0 + wrow + qid;       // rows owned by this thread
    const int row_b = row_a + 8;
    const float SC = 0.125f * 1.4426950408889634f;   // scale * log2(e)

    const int ntiles = (q0 + FQ) / FK;
    for (int kt = 0; kt < ntiles; ++kt) {
        __syncthreads();
        #pragma unroll
        for (int i = t * 4; i < FK * HD; i += 1024) {
            const int r = i >> 6, c = i & 63;
            *(float4*)(Ks + r * KPAD + c) = *(const float4*)(Kb + (size_t)(kt * FK + r) * HD + c);
            *(float4*)(Vs + r * VPAD + c) = *(const float4*)(Vb + (size_t)(kt * FK + r) * HD + c);
        }
        __syncthreads();

        // ---- scores S = Q K^T  (Q split hi/lo, K truncated tf32) ----
        float sacc[8][4];
        #pragma unroll
        for (int nf = 0; nf < 8; ++nf)
            #pragma unroll
            for (int j = 0; j < 4; ++j) sacc[nf][j] = 0.f;

        #pragma unroll
        for (int ks = 0; ks < 8; ++ks) {
            const int k0 = ks * 8;
            const float* qp = Qs + (wrow + qid) * QPAD + k0 + tid4;
            uint32_t ah[4], al[4];
            split_tf32(qp[0],            ah[0], al[0]);
            split_tf32(qp[8 * QPAD],     ah[1], al[1]);
            split_tf32(qp[4],            ah[2], al[2]);
            split_tf32(qp[8 * QPAD + 4], ah[3], al[3]);
            #pragma unroll
            for (int nf = 0; nf < 8; ++nf) {
                const float* kp = Ks + (nf * 8 + qid) * KPAD + k0 + tid4;
                uint32_t bh[2];
                bh[0] = cvt_tf32(kp[0]);
                bh[1] = cvt_tf32(kp[4]);
                mma_tf32(sacc[nf], ah, bh);
                mma_tf32(sacc[nf], al, bh);
            }
        }

        // ---- mask + scale into log2 domain; row max ----
        const bool need_mask = (kt * FK + FK - 1) > row_a;
        float tmax[2] = {-1e30f, -1e30f};
        #pragma unroll
        for (int nf = 0; nf < 8; ++nf) {
            const int colbase = kt * FK + nf * 8 + tid4 * 2;
            #pragma unroll
            for (int j = 0; j < 4; ++j) {
                const int col = colbase + (j & 1);
                const int row = (j < 2) ? row_a : row_b;
                float v = sacc[nf][j] * SC;
                if (need_mask && col > row) v = -1e30f;
                sacc[nf][j] = v;
                const int hh = j >> 1;
                tmax[hh] = fmaxf(tmax[hh], v);
            }
        }

        // ---- online softmax (warp-local; reduce across tid4 group = lane bits 0,1) --
        float corr[2];
        #pragma unroll
        for (int hh = 0; hh < 2; ++hh) {
            tmax[hh] = fmaxf(tmax[hh], __shfl_xor_sync(0xffffffffu, tmax[hh], 1));
            tmax[hh] = fmaxf(tmax[hh], __shfl_xor_sync(0xffffffffu, tmax[hh], 2));
            const float mnew = fmaxf(m[hh], tmax[hh]);
            corr[hh] = exp2p(m[hh] - mnew);
            m[hh] = mnew;
            l[hh] *= corr[hh];
        }
        #pragma unroll
        for (int nf = 0; nf < 8; ++nf) {
            oacc[nf][0] *= corr[0]; oacc[nf][1] *= corr[0];
            oacc[nf][2] *= corr[1]; oacc[nf][3] *= corr[1];
        }
        float rsum[2] = {0.f, 0.f};
        #pragma unroll
        for (int nf = 0; nf < 8; ++nf) {
            #pragma unroll
            for (int j = 0; j < 4; ++j) {
                const int hh = j >> 1;
                const float p = exp2p(sacc[nf][j] - m[hh]);
                sacc[nf][j] = p;
                rsum[hh] += p;
            }
        }
        #pragma unroll
        for (int hh = 0; hh < 2; ++hh) {
            rsum[hh] += __shfl_xor_sync(0xffffffffu, rsum[hh], 1);
            rsum[hh] += __shfl_xor_sync(0xffffffffu, rsum[hh], 2);
            l[hh] += rsum[hh];
        }

        // ---- stage P (warp-private rows) ----
        #pragma unroll
        for (int nf = 0; nf < 8; ++nf) {
            const int pc = nf * 8 + tid4 * 2;
            *(float2*)(Ps + (wrow + qid) * PPAD + pc)     = make_float2(sacc[nf][0], sacc[nf][1]);
            *(float2*)(Ps + (wrow + qid + 8) * PPAD + pc) = make_float2(sacc[nf][2], sacc[nf][3]);
        }
        __syncwarp();

        // ---- O += P V  (P split hi/lo, V truncated tf32) ----
        #pragma unroll
        for (int ks = 0; ks < 8; ++ks) {
            const int k0 = ks * 8;
            const float* pp = Ps + (wrow + qid) * PPAD + k0 + tid4;
            uint32_t ah[4], al[4];
            split_tf32(pp[0],            ah[0], al[0]);
            split_tf32(pp[8 * PPAD],     ah[1], al[1]);
            split_tf32(pp[4],            ah[2], al[2]);
            split_tf32(pp[8 * PPAD + 4], ah[3], al[3]);
            #pragma unroll
            for (int nf = 0; nf < 8; ++nf) {
                uint32_t bb[2];
                bb[0] = cvt_tf32(Vs[(k0 + tid4)     * VPAD + nf * 8 + qid]);
                bb[1] = cvt_tf32(Vs[(k0 + tid4 + 4) * VPAD + nf * 8 + qid]);
                mma_tf32(oacc[nf], ah, bb);
                mma_tf32(oacc[nf], al, bb);
            }
        }
    }

    // ---- epilogue ----
    const float inv_a = 1.0f / l[0];
    const float inv_b = 1.0f / l[1];
    float* Oa = O + ((size_t)(b * SEQ) + row_a) * DIM + h * HD;
    float* Ob = Oa + 8 * DIM;
    #pragma unroll
    for (int nf = 0; nf < 8; ++nf) {
        const int col = nf * 8 + tid4 * 2;
        *(float2*)(Oa + col) = make_float2(oacc[nf][0] * inv_a, oacc[nf][1] * inv_a);
        *(float2*)(Ob + col) = make_float2(oacc[nf][2] * inv_b, oacc[nf][3] * inv_b);
    }
}

// ---------------- host launcher ----------------
extern "C" void kernel_launch(void* const* d_in, const int* in_sizes, int n_in,
                              void* d_out, int out_size) {
    (void)in_sizes; (void)n_in; (void)out_size;
    const float* x  = (const float*)d_in[0];
    const float* Wq = (const float*)d_in[1];
    const float* Wk = (const float*)d_in[2];
    const float* Wv = (const float*)d_in[3];
    const float* bv = (const float*)d_in[4];
    const float* Wo = (const float*)d_in[5];
    const float* bo = (const float*)d_in[6];
    float* out = (float*)d_out;

    float *qlin, *klin, *vlin, *qt, *kt, *vt, *attn, *wt;
    cudaGetSymbolAddress((void**)&qlin, g_qlin);
    cudaGetSymbolAddress((void**)&klin, g_klin);
    cudaGetSymbolAddress((void**)&vlin, g_vlin);
    cudaGetSymbolAddress((void**)&qt,   g_qt);
    cudaGetSymbolAddress((void**)&kt,   g_kt);
    cudaGetSymbolAddress((void**)&vt,   g_vt);
    cudaGetSymbolAddress((void**)&attn, g_attn);
    cudaGetSymbolAddress((void**)&wt,   g_wt);

    theta_kernel<<<1, 32>>>();

    transpose_kernel<<<dim3(DIM / 32, DIM / 32), dim3(32, 8)>>>(Wq, wt, DIM, DIM);
    mma_gemm_tf32<<<dim3(DIM / 128, MROWS / 128), 256>>>(x, wt, nullptr, qlin, DIM, DIM);
    transpose_kernel<<<dim3(KVDIM / 32, DIM / 32), dim3(32, 8)>>>(Wk, wt, DIM, KVDIM);
    mma_gemm_tf32<<<dim3(KVDIM / 128, MROWS / 128), 256>>>(x, wt, nullptr, klin, KVDIM, DIM);
    transpose_kernel<<<dim3(KVDIM / 32, DIM / 32), dim3(32, 8)>>>(Wv, wt, DIM, KVDIM);
    mma_gemm_tf32<<<dim3(KVDIM / 128, MROWS / 128), 256>>>(x, wt, bv, vlin, KVDIM, DIM);

    rope_q_kernel<<<(BATCH * SEQ * NH * 32) / 256, 256>>>(qlin, qt);
    rope_k_kernel<<<(BATCH * SEQ * NKV * 32) / 256, 256>>>(klin, kt);
    transpose_v_kernel<<<(BATCH * SEQ * NKV * 16) / 256, 256>>>(vlin, vt);

    cudaFuncSetAttribute(flash_mma_kernel, cudaFuncAttributeMaxDynamicSharedMemorySize, FLASH_SMEM);
    flash_mma_kernel<<<dim3(SEQ / FQ, NH, BATCH), 256, FLASH_SMEM>>>(qt, kt, vt, attn);

    transpose_kernel<<<dim3(DIM / 32, DIM / 32), dim3(32, 8)>>>(Wo, wt, DIM, DIM);
    mma_gemm_tf32<<<dim3(DIM / 128, MROWS / 128), 256>>>(attn, wt, bo, out, DIM, DIM);
}

// round 5
// speedup vs baseline: 2.0757x; 1.3713x over previous
#include <cuda_runtime.h>
#include <cuda_bf16.h>
#include <math.h>
#include <stdint.h>

#define DIM 2048
#define NH 32
#define NKV 8
#define HD 64
#define BATCH 2
#define SEQ 2048
#define MROWS (BATCH*SEQ)   /* 4096 */
#define KVDIM (NKV*HD)      /* 512 */

// ---------------- scratch (static device allocations; no cudaMalloc) ----------------
__device__ float g_qlin[(size_t)MROWS * DIM];
__device__ float g_klin[(size_t)MROWS * KVDIM];
__device__ float g_vlin[(size_t)MROWS * KVDIM];
__device__ float g_qt[(size_t)BATCH * NH * SEQ * HD];
__device__ float g_kt[(size_t)BATCH * NKV * SEQ * HD];
__device__ float g_vt[(size_t)BATCH * NKV * SEQ * HD];
__device__ float g_attn[(size_t)MROWS * DIM];
__device__ __nv_bfloat16 g_ah[(size_t)MROWS * DIM];   // A hi (x or attn)
__device__ __nv_bfloat16 g_al[(size_t)MROWS * DIM];   // A lo
__device__ __nv_bfloat16 g_bh[(size_t)DIM * DIM];     // B^T hi (weights)
__device__ __nv_bfloat16 g_bl[(size_t)DIM * DIM];     // B^T lo
__device__ double g_theta[HD / 2];

// ---------------- RoPE angle table ----------------
__global__ void theta_kernel() {
    int p = threadIdx.x;
    if (p < HD / 2) g_theta[p] = pow(10000.0, -(double)p / 32.0);
}

// ---------------- bf16 hi/lo split helpers ----------------
__device__ __forceinline__ void bf16_split(float x, __nv_bfloat16& h, __nv_bfloat16& l) {
    h = __float2bfloat16(x);
    l = __float2bfloat16(x - __bfloat162float(h));
}

// elementwise split: fp32[n] -> bf16 hi[n], lo[n]   (n % 1024 == 0)
__global__ void split_kernel(const float* __restrict__ in,
                             __nv_bfloat16* __restrict__ oh,
                             __nv_bfloat16* __restrict__ ol) {
    const int i = blockIdx.x * blockDim.x + threadIdx.x;
    const float4 v = *(const float4*)(in + (size_t)i * 4);
    __nv_bfloat16 h[4], l[4];
    bf16_split(v.x, h[0], l[0]);
    bf16_split(v.y, h[1], l[1]);
    bf16_split(v.z, h[2], l[2]);
    bf16_split(v.w, h[3], l[3]);
    *(uint2*)(oh + (size_t)i * 4) = *(uint2*)h;
    *(uint2*)(ol + (size_t)i * 4) = *(uint2*)l;
}

// weight transpose + split: in R x C fp32 -> out C x R bf16 hi/lo
__global__ void transpose_split_kernel(const float* __restrict__ in,
                                       __nv_bfloat16* __restrict__ oh,
                                       __nv_bfloat16* __restrict__ ol,
                                       int R, int Ccols) {
    __shared__ float tile[32][33];
    int bx = blockIdx.x * 32, by = blockIdx.y * 32;
    int x = bx + threadIdx.x;
    #pragma unroll
    for (int i = 0; i < 32; i += 8)
        tile[threadIdx.y + i][threadIdx.x] = in[(size_t)(by + threadIdx.y + i) * Ccols + x];
    __syncthreads();
    int ox = by + threadIdx.x;
    #pragma unroll
    for (int i = 0; i < 32; i += 8) {
        const float v = tile[threadIdx.x][threadIdx.y + i];
        __nv_bfloat16 h, l;
        bf16_split(v, h, l);
        const size_t o = (size_t)(bx + threadIdx.y + i) * R + ox;
        oh[o] = h;
        ol[o] = l;
    }
}

// ================= mma.sync helpers =================
__device__ __forceinline__ void mma_bf16(float* d, const uint32_t* a, const uint32_t* b) {
    asm volatile(
        "mma.sync.aligned.m16n8k16.row.col.f32.bf16.bf16.f32 "
        "{%0,%1,%2,%3}, {%4,%5,%6,%7}, {%8,%9}, {%0,%1,%2,%3};\n"
        : "+f"(d[0]), "+f"(d[1]), "+f"(d[2]), "+f"(d[3])
        : "r"(a[0]), "r"(a[1]), "r"(a[2]), "r"(a[3]), "r"(b[0]), "r"(b[1]));
}
__device__ __forceinline__ void mma_tf32(float* d, const uint32_t* a, const uint32_t* b) {
    asm volatile(
        "mma.sync.aligned.m16n8k8.row.col.f32.tf32.tf32.f32 "
        "{%0,%1,%2,%3}, {%4,%5,%6,%7}, {%8,%9}, {%0,%1,%2,%3};\n"
        : "+f"(d[0]), "+f"(d[1]), "+f"(d[2]), "+f"(d[3])
        : "r"(a[0]), "r"(a[1]), "r"(a[2]), "r"(a[3]), "r"(b[0]), "r"(b[1]));
}
__device__ __forceinline__ void split_tf32(float x, uint32_t& hi, uint32_t& lo) {
    uint32_t h;
    asm("cvt.rna.tf32.f32 %0, %1;" : "=r"(h) : "f"(x));
    float r = x - __uint_as_float(h);
    uint32_t l;
    asm("cvt.rna.tf32.f32 %0, %1;" : "=r"(l) : "f"(r));
    hi = h; lo = l;
}
__device__ __forceinline__ uint32_t cvt_tf32(float x) {
    uint32_t r;
    asm("cvt.rna.tf32.f32 %0, %1;" : "=r"(r) : "f"(x));
    return r;
}
// fast 2^y on the FMA pipe
__device__ __forceinline__ float exp2p(float y) {
    y = fmaxf(y, -120.f);
    int ki = __float2int_rn(y);
    float f = y - (float)ki;
    float p = 0.0013333558f;
    p = fmaf(p, f, 0.0096181291f);
    p = fmaf(p, f, 0.0555041087f);
    p = fmaf(p, f, 0.2402265070f);
    p = fmaf(p, f, 0.6931471806f);
    p = fmaf(p, f, 1.0f);
    return p * __int_as_float((ki + 127) << 23);
}

// ---------------- tensor-core bf16 GEMM with 3-term split ----------------
// C[M,N] = A[M,K] @ Bt[N,K]^T (+bias), operands pre-split bf16 hi/lo, K-major.
// 128x128 tile, 8 warps 4(m)x2(n), warp tile 32x64. K-chunk 32, reg prefetch.
#define BPAD 40   /* bf16 row stride for 32-wide chunk: conflict-free (stride 80B = 20 banks) */

__global__ void __launch_bounds__(256) mma_gemm_bf16(
    const __nv_bfloat16* __restrict__ Ah, const __nv_bfloat16* __restrict__ Al,
    const __nv_bfloat16* __restrict__ Bh, const __nv_bfloat16* __restrict__ Bl,
    const float* __restrict__ bias, float* __restrict__ C, int N, int K)
{
    __shared__ __nv_bfloat16 sAh[128 * BPAD];
    __shared__ __nv_bfloat16 sAl[128 * BPAD];
    __shared__ __nv_bfloat16 sBh[128 * BPAD];
    __shared__ __nv_bfloat16 sBl[128 * BPAD];

    const int t    = threadIdx.x;
    const int lane = t & 31;
    const int wid  = t >> 5;
    const int wr   = wid & 3;
    const int wc   = wid >> 2;
    const int qid  = lane >> 2;
    const int tid4 = lane & 3;

    const size_t m0 = (size_t)blockIdx.y * 128;
    const size_t n0 = (size_t)blockIdx.x * 128;
    const __nv_bfloat16* Abh = Ah + m0 * K;
    const __nv_bfloat16* Abl = Al + m0 * K;
    const __nv_bfloat16* Bbh = Bh + n0 * K;
    const __nv_bfloat16* Bbl = Bl + n0 * K;

    // each thread loads 2 x uint4 (16 bf16) per array per chunk: row t>>1, cols (t&1)*16 + {0,8}
    const int lrow = t >> 1;
    const int lc0  = (t & 1) * 16;

    float acc[2][8][4];
    #pragma unroll
    for (int mf = 0; mf < 2; ++mf)
        #pragma unroll
        for (int nf = 0; nf < 8; ++nf)
            #pragma unroll
            for (int r = 0; r < 4; ++r) acc[mf][nf][r] = 0.f;

    const int nchunks = K / 32;

    uint4 p[8];
    {
        const size_t ro = (size_t)lrow * K + lc0;
        p[0] = *(const uint4*)(Abh + ro);     p[1] = *(const uint4*)(Abh + ro + 8);
        p[2] = *(const uint4*)(Abl + ro);     p[3] = *(const uint4*)(Abl + ro + 8);
        p[4] = *(const uint4*)(Bbh + ro);     p[5] = *(const uint4*)(Bbh + ro + 8);
        p[6] = *(const uint4*)(Bbl + ro);     p[7] = *(const uint4*)(Bbl + ro + 8);
    }

    for (int c = 0; c < nchunks; ++c) {
        const int so = lrow * BPAD + lc0;
        *(uint4*)(sAh + so) = p[0];  *(uint4*)(sAh + so + 8) = p[1];
        *(uint4*)(sAl + so) = p[2];  *(uint4*)(sAl + so + 8) = p[3];
        *(uint4*)(sBh + so) = p[4];  *(uint4*)(sBh + so + 8) = p[5];
        *(uint4*)(sBl + so) = p[6];  *(uint4*)(sBl + so + 8) = p[7];
        __syncthreads();

        if (c + 1 < nchunks) {
            const size_t ro = (size_t)lrow * K + (c + 1) * 32 + lc0;
            p[0] = *(const uint4*)(Abh + ro);     p[1] = *(const uint4*)(Abh + ro + 8);
            p[2] = *(const uint4*)(Abl + ro);     p[3] = *(const uint4*)(Abl + ro + 8);
            p[4] = *(const uint4*)(Bbh + ro);     p[5] = *(const uint4*)(Bbh + ro + 8);
            p[6] = *(const uint4*)(Bbl + ro);     p[7] = *(const uint4*)(Bbl + ro + 8);
        }

        #pragma unroll
        for (int ks = 0; ks < 2; ++ks) {     // two k16 steps per chunk
            const int k0 = ks * 16;
            uint32_t ah[2][4], al[2][4];
            #pragma unroll
            for (int mf = 0; mf < 2; ++mf) {
                const int rb = wr * 32 + mf * 16 + qid;
                const __nv_bfloat16* aph = sAh + rb * BPAD + k0 + tid4 * 2;
                const __nv_bfloat16* apl = sAl + rb * BPAD + k0 + tid4 * 2;
                ah[mf][0] = *(const uint32_t*)(aph);
                ah[mf][1] = *(const uint32_t*)(aph + 8 * BPAD);
                ah[mf][2] = *(const uint32_t*)(aph + 8);
                ah[mf][3] = *(const uint32_t*)(aph + 8 * BPAD + 8);
                al[mf][0] = *(const uint32_t*)(apl);
                al[mf][1] = *(const uint32_t*)(apl + 8 * BPAD);
                al[mf][2] = *(const uint32_t*)(apl + 8);
                al[mf][3] = *(const uint32_t*)(apl + 8 * BPAD + 8);
            }
            #pragma unroll
            for (int nf = 0; nf < 8; ++nf) {
                const int nb = wc * 64 + nf * 8 + qid;
                const __nv_bfloat16* bph = sBh + nb * BPAD + k0 + tid4 * 2;
                const __nv_bfloat16* bpl = sBl + nb * BPAD + k0 + tid4 * 2;
                uint32_t bh[2], bl[2];
                bh[0] = *(const uint32_t*)(bph);
                bh[1] = *(const uint32_t*)(bph + 8);
                bl[0] = *(const uint32_t*)(bpl);
                bl[1] = *(const uint32_t*)(bpl + 8);
                #pragma unroll
                for (int mf = 0; mf < 2; ++mf) {
                    mma_bf16(acc[mf][nf], ah[mf], bh);
                    mma_bf16(acc[mf][nf], ah[mf], bl);
                    mma_bf16(acc[mf][nf], al[mf], bh);
                }
            }
        }
        __syncthreads();
    }

    const int trow = qid;
    const int tcol = tid4 * 2;
    #pragma unroll
    for (int mf = 0; mf < 2; ++mf) {
        const size_t m = m0 + wr * 32 + mf * 16 + trow;
        #pragma unroll
        for (int nf = 0; nf < 8; ++nf) {
            const int ncol = (int)n0 + wc * 64 + nf * 8 + tcol;
            float2 v0 = make_float2(acc[mf][nf][0], acc[mf][nf][1]);
            float2 v1 = make_float2(acc[mf][nf][2], acc[mf][nf][3]);
            if (bias) {
                const float bx = bias[ncol], by = bias[ncol + 1];
                v0.x += bx; v0.y += by;
                v1.x += bx; v1.y += by;
            }
            *(float2*)(C + m * N + ncol)       = v0;
            *(float2*)(C + (m + 8) * N + ncol) = v1;
        }
    }
}

// ---------------- RoPE + layout transpose ----------------
__global__ void rope_q_kernel(const float* __restrict__ in, float* __restrict__ out) {
    int idx = blockIdx.x * blockDim.x + threadIdx.x;
    int p = idx & 31;
    int h = (idx >> 5) & 31;
    int s = (idx >> 10) & 2047;
    int b = idx >> 21;
    float ang = (float)((double)s * g_theta[p]);
    float sv, cv;
    sincosf(ang, &sv, &cv);
    const float2 x = *(const float2*)(in + ((size_t)(b * SEQ + s)) * DIM + h * HD + 2 * p);
    float2 r;
    r.x = x.x * cv - x.y * sv;
    r.y = x.x * sv + x.y * cv;
    *(float2*)(out + (((size_t)(b * NH + h)) * SEQ + s) * HD + 2 * p) = r;
}
__global__ void rope_k_kernel(const float* __restrict__ in, float* __restrict__ out) {
    int idx = blockIdx.x * blockDim.x + threadIdx.x;
    int p = idx & 31;
    int h = (idx >> 5) & 7;
    int s = (idx >> 8) & 2047;
    int b = idx >> 19;
    float ang = (float)((double)s * g_theta[p]);
    float sv, cv;
    sincosf(ang, &sv, &cv);
    const float2 x = *(const float2*)(in + ((size_t)(b * SEQ + s)) * KVDIM + h * HD + 2 * p);
    float2 r;
    r.x = x.x * cv - x.y * sv;
    r.y = x.x * sv + x.y * cv;
    *(float2*)(out + (((size_t)(b * NKV + h)) * SEQ + s) * HD + 2 * p) = r;
}
__global__ void transpose_v_kernel(const float* __restrict__ in, float* __restrict__ out) {
    int idx = blockIdx.x * blockDim.x + threadIdx.x;
    int d4 = idx & 15;
    int h  = (idx >> 4) & 7;
    int s  = (idx >> 7) & 2047;
    int b  = idx >> 18;
    const float4 v = *(const float4*)(in + ((size_t)(b * SEQ + s)) * KVDIM + h * HD + d4 * 4);
    *(float4*)(out + (((size_t)(b * NKV + h)) * SEQ + s) * HD + d4 * 4) = v;
}

// ---------------- tensor-core causal flash attention (unchanged from R4) ----------------
#define FQ 128
#define FK 64
#define QPAD 68
#define KPAD 68
#define VPAD 72
#define PPAD 76
#define FLASH_SMEM ((FQ*QPAD + FK*KPAD + FK*VPAD + FQ*PPAD) * 4)

__global__ void __launch_bounds__(256) flash_mma_kernel(
    const float* __restrict__ Q, const float* __restrict__ K,
    const float* __restrict__ V, float* __restrict__ O)
{
    extern __shared__ float sm[];
    float* Qs = sm;
    float* Ks = Qs + FQ * QPAD;
    float* Vs = Ks + FK * KPAD;
    float* Ps = Vs + FK * VPAD;

    const int qt  = (SEQ / FQ - 1) - blockIdx.x;
    const int h   = blockIdx.y;
    const int b   = blockIdx.z;
    const int kvh = h >> 2;
    const int t    = threadIdx.x;
    const int lane = t & 31;
    const int w    = t >> 5;
    const int qid  = lane >> 2;
    const int tid4 = lane & 3;
    const int q0   = qt * FQ;
    const int wrow = w * 16;

    const float* Qb = Q + (((size_t)(b * NH + h)) * SEQ + q0) * HD;
    const float* Kb = K + ((size_t)(b * NKV + kvh)) * SEQ * HD;
    const float* Vb = V + ((size_t)(b * NKV + kvh)) * SEQ * HD;

    #pragma unroll
    for (int i = t * 4; i < FQ * HD; i += 1024) {
        const int r = i >> 6, c = i & 63;
        *(float4*)(Qs + r * QPAD + c) = *(const float4*)(Qb + r * HD + c);
    }

    float oacc[8][4];
    #pragma unroll
    for (int nf = 0; nf < 8; ++nf)
        #pragma unroll
        for (int j = 0; j < 4; ++j) oacc[nf][j] = 0.f;
    float m[2] = {-1e30f, -1e30f};
    float l[2] = {0.f, 0.f};

    const int row_a = q0 + wrow + qid;
    const int row_b = row_a + 8;
    const float SC = 0.125f * 1.4426950408889634f;

    const int ntiles = (q0 + FQ) / FK;
    for (int kt = 0; kt < ntiles; ++kt) {
        __syncthreads();
        #pragma unroll
        for (int i = t * 4; i < FK * HD; i += 1024) {
            const int r = i >> 6, c = i & 63;
            *(float4*)(Ks + r * KPAD + c) = *(const float4*)(Kb + (size_t)(kt * FK + r) * HD + c);
            *(float4*)(Vs + r * VPAD + c) = *(const float4*)(Vb + (size_t)(kt * FK + r) * HD + c);
        }
        __syncthreads();

        float sacc[8][4];
        #pragma unroll
        for (int nf = 0; nf < 8; ++nf)
            #pragma unroll
            for (int j = 0; j < 4; ++j) sacc[nf][j] = 0.f;

        #pragma unroll
        for (int ks = 0; ks < 8; ++ks) {
            const int k0 = ks * 8;
            const float* qp = Qs + (wrow + qid) * QPAD + k0 + tid4;
            uint32_t ah[4], al[4];
            split_tf32(qp[0],            ah[0], al[0]);
            split_tf32(qp[8 * QPAD],     ah[1], al[1]);
            split_tf32(qp[4],            ah[2], al[2]);
            split_tf32(qp[8 * QPAD + 4], ah[3], al[3]);
            #pragma unroll
            for (int nf = 0; nf < 8; ++nf) {
                const float* kp = Ks + (nf * 8 + qid) * KPAD + k0 + tid4;
                uint32_t bh[2];
                bh[0] = cvt_tf32(kp[0]);
                bh[1] = cvt_tf32(kp[4]);
                mma_tf32(sacc[nf], ah, bh);
                mma_tf32(sacc[nf], al, bh);
            }
        }

        const bool need_mask = (kt * FK + FK - 1) > row_a;
        float tmax[2] = {-1e30f, -1e30f};
        #pragma unroll
        for (int nf = 0; nf < 8; ++nf) {
            const int colbase = kt * FK + nf * 8 + tid4 * 2;
            #pragma unroll
            for (int j = 0; j < 4; ++j) {
                const int col = colbase + (j & 1);
                const int row = (j < 2) ? row_a : row_b;
                float v = sacc[nf][j] * SC;
                if (need_mask && col > row) v = -1e30f;
                sacc[nf][j] = v;
                const int hh = j >> 1;
                tmax[hh] = fmaxf(tmax[hh], v);
            }
        }

        float corr[2];
        #pragma unroll
        for (int hh = 0; hh < 2; ++hh) {
            tmax[hh] = fmaxf(tmax[hh], __shfl_xor_sync(0xffffffffu, tmax[hh], 1));
            tmax[hh] = fmaxf(tmax[hh], __shfl_xor_sync(0xffffffffu, tmax[hh], 2));
            const float mnew = fmaxf(m[hh], tmax[hh]);
            corr[hh] = exp2p(m[hh] - mnew);
            m[hh] = mnew;
            l[hh] *= corr[hh];
        }
        #pragma unroll
        for (int nf = 0; nf < 8; ++nf) {
            oacc[nf][0] *= corr[0]; oacc[nf][1] *= corr[0];
            oacc[nf][2] *= corr[1]; oacc[nf][3] *= corr[1];
        }
        float rsum[2] = {0.f, 0.f};
        #pragma unroll
        for (int nf = 0; nf < 8; ++nf) {
            #pragma unroll
            for (int j = 0; j < 4; ++j) {
                const int hh = j >> 1;
                const float p = exp2p(sacc[nf][j] - m[hh]);
                sacc[nf][j] = p;
                rsum[hh] += p;
            }
        }
        #pragma unroll
        for (int hh = 0; hh < 2; ++hh) {
            rsum[hh] += __shfl_xor_sync(0xffffffffu, rsum[hh], 1);
            rsum[hh] += __shfl_xor_sync(0xffffffffu, rsum[hh], 2);
            l[hh] += rsum[hh];
        }

        #pragma unroll
        for (int nf = 0; nf < 8; ++nf) {
            const int pc = nf * 8 + tid4 * 2;
            *(float2*)(Ps + (wrow + qid) * PPAD + pc)     = make_float2(sacc[nf][0], sacc[nf][1]);
            *(float2*)(Ps + (wrow + qid + 8) * PPAD + pc) = make_float2(sacc[nf][2], sacc[nf][3]);
        }
        __syncwarp();

        #pragma unroll
        for (int ks = 0; ks < 8; ++ks) {
            const int k0 = ks * 8;
            const float* pp = Ps + (wrow + qid) * PPAD + k0 + tid4;
            uint32_t ah[4], al[4];
            split_tf32(pp[0],            ah[0], al[0]);
            split_tf32(pp[8 * PPAD],     ah[1], al[1]);
            split_tf32(pp[4],            ah[2], al[2]);
            split_tf32(pp[8 * PPAD + 4], ah[3], al[3]);
            #pragma unroll
            for (int nf = 0; nf < 8; ++nf) {
                uint32_t bb[2];
                bb[0] = cvt_tf32(Vs[(k0 + tid4)     * VPAD + nf * 8 + qid]);
                bb[1] = cvt_tf32(Vs[(k0 + tid4 + 4) * VPAD + nf * 8 + qid]);
                mma_tf32(oacc[nf], ah, bb);
                mma_tf32(oacc[nf], al, bb);
            }
        }
    }

    const float inv_a = 1.0f / l[0];
    const float inv_b = 1.0f / l[1];
    float* Oa = O + ((size_t)(b * SEQ) + row_a) * DIM + h * HD;
    float* Ob = Oa + 8 * DIM;
    #pragma unroll
    for (int nf = 0; nf < 8; ++nf) {
        const int col = nf * 8 + tid4 * 2;
        *(float2*)(Oa + col) = make_float2(oacc[nf][0] * inv_a, oacc[nf][1] * inv_a);
        *(float2*)(Ob + col) = make_float2(oacc[nf][2] * inv_b, oacc[nf][3] * inv_b);
    }
}

// ---------------- host launcher ----------------
extern "C" void kernel_launch(void* const* d_in, const int* in_sizes, int n_in,
                              void* d_out, int out_size) {
    (void)in_sizes; (void)n_in; (void)out_size;
    const float* x  = (const float*)d_in[0];
    const float* Wq = (const float*)d_in[1];
    const float* Wk = (const float*)d_in[2];
    const float* Wv = (const float*)d_in[3];
    const float* bv = (const float*)d_in[4];
    const float* Wo = (const float*)d_in[5];
    const float* bo = (const float*)d_in[6];
    float* out = (float*)d_out;

    float *qlin, *klin, *vlin, *qt, *kt, *vt, *attn;
    __nv_bfloat16 *ah, *al, *bh, *bl;
    cudaGetSymbolAddress((void**)&qlin, g_qlin);
    cudaGetSymbolAddress((void**)&klin, g_klin);
    cudaGetSymbolAddress((void**)&vlin, g_vlin);
    cudaGetSymbolAddress((void**)&qt,   g_qt);
    cudaGetSymbolAddress((void**)&kt,   g_kt);
    cudaGetSymbolAddress((void**)&vt,   g_vt);
    cudaGetSymbolAddress((void**)&attn, g_attn);
    cudaGetSymbolAddress((void**)&ah,   g_ah);
    cudaGetSymbolAddress((void**)&al,   g_al);
    cudaGetSymbolAddress((void**)&bh,   g_bh);
    cudaGetSymbolAddress((void**)&bl,   g_bl);

    theta_kernel<<<1, 32>>>();

    // split activations once (reused by Q,K,V projections)
    split_kernel<<<(MROWS * DIM) / 1024, 256>>>(x, ah, al);

    transpose_split_kernel<<<dim3(DIM / 32, DIM / 32), dim3(32, 8)>>>(Wq, bh, bl, DIM, DIM);
    mma_gemm_bf16<<<dim3(DIM / 128, MROWS / 128), 256>>>(ah, al, bh, bl, nullptr, qlin, DIM, DIM);
    transpose_split_kernel<<<dim3(KVDIM / 32, DIM / 32), dim3(32, 8)>>>(Wk, bh, bl, DIM, KVDIM);
    mma_gemm_bf16<<<dim3(KVDIM / 128, MROWS / 128), 256>>>(ah, al, bh, bl, nullptr, klin, KVDIM, DIM);
    transpose_split_kernel<<<dim3(KVDIM / 32, DIM / 32), dim3(32, 8)>>>(Wv, bh, bl, DIM, KVDIM);
    mma_gemm_bf16<<<dim3(KVDIM / 128, MROWS / 128), 256>>>(ah, al, bh, bl, bv, vlin, KVDIM, DIM);

    rope_q_kernel<<<(BATCH * SEQ * NH * 32) / 256, 256>>>(qlin, qt);
    rope_k_kernel<<<(BATCH * SEQ * NKV * 32) / 256, 256>>>(klin, kt);
    transpose_v_kernel<<<(BATCH * SEQ * NKV * 16) / 256, 256>>>(vlin, vt);

    cudaFuncSetAttribute(flash_mma_kernel, cudaFuncAttributeMaxDynamicSharedMemorySize, FLASH_SMEM);
    flash_mma_kernel<<<dim3(SEQ / FQ, NH, BATCH), 256, FLASH_SMEM>>>(qt, kt, vt, attn);

    // output projection: split attn, then bf16 GEMM
    split_kernel<<<(MROWS * DIM) / 1024, 256>>>(attn, ah, al);
    transpose_split_kernel<<<dim3(DIM / 32, DIM / 32), dim3(32, 8)>>>(Wo, bh, bl, DIM, DIM);
    mma_gemm_bf16<<<dim3(DIM / 128, MROWS / 128), 256>>>(ah, al, bh, bl, bo, out, DIM, DIM);
}

// round 6
// speedup vs baseline: 2.3851x; 1.1490x over previous
#include <cuda_runtime.h>
#include <cuda_bf16.h>
#include <math.h>
#include <stdint.h>

#define DIM 2048
#define NH 32
#define NKV 8
#define HD 64
#define BATCH 2
#define SEQ 2048
#define MROWS (BATCH*SEQ)   /* 4096 */
#define KVDIM (NKV*HD)      /* 512 */

// ---------------- scratch (static device allocations; no cudaMalloc) ----------------
__device__ float g_qlin[(size_t)MROWS * DIM];
__device__ float g_kvlin[(size_t)MROWS * 2 * KVDIM];   // [m][0:512)=k, [512:1024)=v
__device__ float g_qt[(size_t)BATCH * NH * SEQ * HD];
__device__ float g_kt[(size_t)BATCH * NKV * SEQ * HD];
__device__ float g_vt[(size_t)BATCH * NKV * SEQ * HD];
__device__ float g_attn[(size_t)MROWS * DIM];
__device__ float g_biaskv[2 * KVDIM];
__device__ __align__(16) __nv_bfloat16 g_ah[(size_t)MROWS * DIM];   // A hi (x or attn)
__device__ __align__(16) __nv_bfloat16 g_al[(size_t)MROWS * DIM];   // A lo
__device__ __align__(16) __nv_bfloat16 g_bh[(size_t)DIM * DIM];     // B^T hi (weights)
__device__ __align__(16) __nv_bfloat16 g_bl[(size_t)DIM * DIM];     // B^T lo
__device__ double g_theta[HD / 2];

// ---------------- RoPE angle table ----------------
__global__ void theta_kernel() {
    int p = threadIdx.x;
    if (p < HD / 2) g_theta[p] = pow(10000.0, -(double)p / 32.0);
}

// combined kv bias: [0:512)=0 (k), [512:1024)=bv
__global__ void biaskv_kernel(const float* __restrict__ bv) {
    int i = blockIdx.x * blockDim.x + threadIdx.x;
    g_biaskv[i] = (i < KVDIM) ? 0.f : bv[i - KVDIM];
}

// ---------------- bf16 hi/lo split helpers ----------------
__device__ __forceinline__ void bf16_split(float x, __nv_bfloat16& h, __nv_bfloat16& l) {
    h = __float2bfloat16(x);
    l = __float2bfloat16(x - __bfloat162float(h));
}

__global__ void split_kernel(const float* __restrict__ in,
                             __nv_bfloat16* __restrict__ oh,
                             __nv_bfloat16* __restrict__ ol) {
    const int i = blockIdx.x * blockDim.x + threadIdx.x;
    const float4 v = *(const float4*)(in + (size_t)i * 4);
    __nv_bfloat16 h[4], l[4];
    bf16_split(v.x, h[0], l[0]);
    bf16_split(v.y, h[1], l[1]);
    bf16_split(v.z, h[2], l[2]);
    bf16_split(v.w, h[3], l[3]);
    *(uint2*)(oh + (size_t)i * 4) = *(uint2*)h;
    *(uint2*)(ol + (size_t)i * 4) = *(uint2*)l;
}

// weight transpose + split: in R x C fp32 -> out C x R bf16 hi/lo
__global__ void transpose_split_kernel(const float* __restrict__ in,
                                       __nv_bfloat16* __restrict__ oh,
                                       __nv_bfloat16* __restrict__ ol,
                                       int R, int Ccols) {
    __shared__ float tile[32][33];
    int bx = blockIdx.x * 32, by = blockIdx.y * 32;
    int x = bx + threadIdx.x;
    #pragma unroll
    for (int i = 0; i < 32; i += 8)
        tile[threadIdx.y + i][threadIdx.x] = in[(size_t)(by + threadIdx.y + i) * Ccols + x];
    __syncthreads();
    int ox = by + threadIdx.x;
    #pragma unroll
    for (int i = 0; i < 32; i += 8) {
        const float v = tile[threadIdx.x][threadIdx.y + i];
        __nv_bfloat16 h, l;
        bf16_split(v, h, l);
        const size_t o = (size_t)(bx + threadIdx.y + i) * R + ox;
        oh[o] = h;
        ol[o] = l;
    }
}

// ================= mma.sync / async helpers =================
__device__ __forceinline__ uint32_t smem_u32(const void* p) {
    uint32_t a;
    asm("{ .reg .u64 t; cvta.to.shared.u64 t, %1; cvt.u32.u64 %0, t; }" : "=r"(a) : "l"(p));
    return a;
}
__device__ __forceinline__ void cp16(uint32_t dst, const void* src) {
    asm volatile("cp.async.cg.shared.global [%0], [%1], 16;" :: "r"(dst), "l"(src));
}
#define CP_COMMIT() asm volatile("cp.async.commit_group;" ::: "memory")
#define CP_WAIT1()  asm volatile("cp.async.wait_group 1;" ::: "memory")

__device__ __forceinline__ void ldsm4(uint32_t* r, uint32_t addr) {
    asm volatile("ldmatrix.sync.aligned.m8n8.x4.shared.b16 {%0,%1,%2,%3}, [%4];"
                 : "=r"(r[0]), "=r"(r[1]), "=r"(r[2]), "=r"(r[3]) : "r"(addr));
}
__device__ __forceinline__ void mma_bf16(float* d, const uint32_t* a, const uint32_t* b) {
    asm volatile(
        "mma.sync.aligned.m16n8k16.row.col.f32.bf16.bf16.f32 "
        "{%0,%1,%2,%3}, {%4,%5,%6,%7}, {%8,%9}, {%0,%1,%2,%3};\n"
        : "+f"(d[0]), "+f"(d[1]), "+f"(d[2]), "+f"(d[3])
        : "r"(a[0]), "r"(a[1]), "r"(a[2]), "r"(a[3]), "r"(b[0]), "r"(b[1]));
}
__device__ __forceinline__ void mma_tf32(float* d, const uint32_t* a, const uint32_t* b) {
    asm volatile(
        "mma.sync.aligned.m16n8k8.row.col.f32.tf32.tf32.f32 "
        "{%0,%1,%2,%3}, {%4,%5,%6,%7}, {%8,%9}, {%0,%1,%2,%3};\n"
        : "+f"(d[0]), "+f"(d[1]), "+f"(d[2]), "+f"(d[3])
        : "r"(a[0]), "r"(a[1]), "r"(a[2]), "r"(a[3]), "r"(b[0]), "r"(b[1]));
}
__device__ __forceinline__ void split_tf32(float x, uint32_t& hi, uint32_t& lo) {
    uint32_t h;
    asm("cvt.rna.tf32.f32 %0, %1;" : "=r"(h) : "f"(x));
    float r = x - __uint_as_float(h);
    uint32_t l;
    asm("cvt.rna.tf32.f32 %0, %1;" : "=r"(l) : "f"(r));
    hi = h; lo = l;
}
__device__ __forceinline__ uint32_t cvt_tf32(float x) {
    uint32_t r;
    asm("cvt.rna.tf32.f32 %0, %1;" : "=r"(r) : "f"(x));
    return r;
}
__device__ __forceinline__ float exp2p(float y) {
    y = fmaxf(y, -120.f);
    int ki = __float2int_rn(y);
    float f = y - (float)ki;
    float p = 0.0013333558f;
    p = fmaf(p, f, 0.0096181291f);
    p = fmaf(p, f, 0.0555041087f);
    p = fmaf(p, f, 0.2402265070f);
    p = fmaf(p, f, 0.6931471806f);
    p = fmaf(p, f, 1.0f);
    return p * __int_as_float((ki + 127) << 23);
}

// ---------------- bf16 3-term GEMM: ldmatrix + cp.async double buffer ----------------
// C[M,N] = A[M,K] @ Bt[N,K]^T (+bias), pre-split bf16 hi/lo, K-major. K-chunk 32.
#define BPAD 40
#define G_ARRB (128 * BPAD * 2)     /* 10240 B per array */
#define G_BUFB (4 * G_ARRB)         /* 40960 B per buffer */
#define G_SMEM (2 * G_BUFB)         /* 81920 B */

__global__ void __launch_bounds__(256, 2) mma_gemm_bf16(
    const __nv_bfloat16* __restrict__ Ah, const __nv_bfloat16* __restrict__ Al,
    const __nv_bfloat16* __restrict__ Bh, const __nv_bfloat16* __restrict__ Bl,
    const float* __restrict__ bias, float* __restrict__ C, int N, int K)
{
    extern __shared__ char smem[];
    const uint32_t smbase = smem_u32(smem);

    const int t    = threadIdx.x;
    const int lane = t & 31;
    const int wid  = t >> 5;
    const int wr   = wid & 3;
    const int wc   = wid >> 2;
    const int qid  = lane >> 2;
    const int tid4 = lane & 3;

    const size_t m0 = (size_t)blockIdx.y * 128;
    const size_t n0 = (size_t)blockIdx.x * 128;

    // cp.async assignment: 64 threads per array, 8 x 16B each per chunk
    const int g   = t >> 6;
    const int sub = t & 63;
    const __nv_bfloat16* gbase =
        (g == 0) ? Ah + m0 * K : (g == 1) ? Al + m0 * K :
        (g == 2) ? Bh + n0 * K : Bl + n0 * K;
    const uint32_t sm_arr = smbase + g * G_ARRB;

    // ldmatrix per-lane addresses (byte offsets within array)
    const uint32_t a_off = (uint32_t)(((wr * 32 + (lane & 15)) * BPAD + ((lane >> 4) << 3)) * 2);
    const uint32_t b_off = (uint32_t)(((wc * 64 + (lane & 7) + ((lane & 16) >> 1)) * BPAD + (lane & 8)) * 2);

    float acc[2][8][4];
    #pragma unroll
    for (int mf = 0; mf < 2; ++mf)
        #pragma unroll
        for (int nf = 0; nf < 8; ++nf)
            #pragma unroll
            for (int r = 0; r < 4; ++r) acc[mf][nf][r] = 0.f;

    const int nchunks = K / 32;

    // prologue: chunk 0 -> buffer 0
    #pragma unroll
    for (int i = 0; i < 8; ++i) {
        const int idx = sub + i * 64;
        const int row = idx >> 2, col = (idx & 3) * 8;
        cp16(sm_arr + (uint32_t)((row * BPAD + col) * 2), gbase + (size_t)row * K + col);
    }
    CP_COMMIT();

    for (int c = 0; c < nchunks; ++c) {
        const int buf = c & 1;
        // issue next chunk into other buffer (empty group if none: keeps count uniform)
        if (c + 1 < nchunks) {
            const uint32_t dst = sm_arr + (uint32_t)((c + 1) & 1) * G_BUFB;
            const __nv_bfloat16* src = gbase + (c + 1) * 32;
            #pragma unroll
            for (int i = 0; i < 8; ++i) {
                const int idx = sub + i * 64;
                const int row = idx >> 2, col = (idx & 3) * 8;
                cp16(dst + (uint32_t)((row * BPAD + col) * 2), src + (size_t)row * K + col);
            }
        }
        CP_COMMIT();
        CP_WAIT1();          // chunk c complete
        __syncthreads();

        const uint32_t sb = smbase + (uint32_t)buf * G_BUFB;
        #pragma unroll
        for (int ks = 0; ks < 2; ++ks) {
            const uint32_t kb = (uint32_t)(ks * 32);   // 16 bf16 = 32 bytes
            uint32_t ah[2][4], al[2][4];
            #pragma unroll
            for (int mf = 0; mf < 2; ++mf) {
                const uint32_t ro = (uint32_t)(mf * 16 * BPAD * 2);
                ldsm4(ah[mf], sb + 0 * G_ARRB + a_off + ro + kb);
                ldsm4(al[mf], sb + 1 * G_ARRB + a_off + ro + kb);
            }
            uint32_t bh[8][2], bl[8][2];
            #pragma unroll
            for (int p = 0; p < 4; ++p) {
                const uint32_t ro = (uint32_t)(p * 16 * BPAD * 2);
                uint32_t r[4];
                ldsm4(r, sb + 2 * G_ARRB + b_off + ro + kb);
                bh[2 * p][0] = r[0]; bh[2 * p][1] = r[1];
                bh[2 * p + 1][0] = r[2]; bh[2 * p + 1][1] = r[3];
                ldsm4(r, sb + 3 * G_ARRB + b_off + ro + kb);
                bl[2 * p][0] = r[0]; bl[2 * p][1] = r[1];
                bl[2 * p + 1][0] = r[2]; bl[2 * p + 1][1] = r[3];
            }
            #pragma unroll
            for (int nf = 0; nf < 8; ++nf)
                #pragma unroll
                for (int mf = 0; mf < 2; ++mf) {
                    mma_bf16(acc[mf][nf], ah[mf], bh[nf]);
                    mma_bf16(acc[mf][nf], ah[mf], bl[nf]);
                    mma_bf16(acc[mf][nf], al[mf], bh[nf]);
                }
        }
        __syncthreads();     // all warps done with buf before it is refilled
    }

    const int trow = qid;
    const int tcol = tid4 * 2;
    #pragma unroll
    for (int mf = 0; mf < 2; ++mf) {
        const size_t m = m0 + wr * 32 + mf * 16 + trow;
        #pragma unroll
        for (int nf = 0; nf < 8; ++nf) {
            const int ncol = (int)n0 + wc * 64 + nf * 8 + tcol;
            float2 v0 = make_float2(acc[mf][nf][0], acc[mf][nf][1]);
            float2 v1 = make_float2(acc[mf][nf][2], acc[mf][nf][3]);
            if (bias) {
                const float bx = bias[ncol], by = bias[ncol + 1];
                v0.x += bx; v0.y += by;
                v1.x += bx; v1.y += by;
            }
            *(float2*)(C + m * N + ncol)       = v0;
            *(float2*)(C + (m + 8) * N + ncol) = v1;
        }
    }
}

// ---------------- RoPE + layout transpose ----------------
__global__ void rope_q_kernel(const float* __restrict__ in, float* __restrict__ out) {
    int idx = blockIdx.x * blockDim.x + threadIdx.x;
    int p = idx & 31;
    int h = (idx >> 5) & 31;
    int s = (idx >> 10) & 2047;
    int b = idx >> 21;
    float ang = (float)((double)s * g_theta[p]);
    float sv, cv;
    sincosf(ang, &sv, &cv);
    const float2 x = *(const float2*)(in + ((size_t)(b * SEQ + s)) * DIM + h * HD + 2 * p);
    float2 r;
    r.x = x.x * cv - x.y * sv;
    r.y = x.x * sv + x.y * cv;
    *(float2*)(out + (((size_t)(b * NH + h)) * SEQ + s) * HD + 2 * p) = r;
}
// reads k from kvlin [m][0:512)
__global__ void rope_k_kernel(const float* __restrict__ in, float* __restrict__ out) {
    int idx = blockIdx.x * blockDim.x + threadIdx.x;
    int p = idx & 31;
    int h = (idx >> 5) & 7;
    int s = (idx >> 8) & 2047;
    int b = idx >> 19;
    float ang = (float)((double)s * g_theta[p]);
    float sv, cv;
    sincosf(ang, &sv, &cv);
    const float2 x = *(const float2*)(in + ((size_t)(b * SEQ + s)) * (2 * KVDIM) + h * HD + 2 * p);
    float2 r;
    r.x = x.x * cv - x.y * sv;
    r.y = x.x * sv + x.y * cv;
    *(float2*)(out + (((size_t)(b * NKV + h)) * SEQ + s) * HD + 2 * p) = r;
}
// reads v from kvlin [m][512:1024)
__global__ void transpose_v_kernel(const float* __restrict__ in, float* __restrict__ out) {
    int idx = blockIdx.x * blockDim.x + threadIdx.x;
    int d4 = idx & 15;
    int h  = (idx >> 4) & 7;
    int s  = (idx >> 7) & 2047;
    int b  = idx >> 18;
    const float4 v = *(const float4*)(in + ((size_t)(b * SEQ + s)) * (2 * KVDIM) + KVDIM + h * HD + d4 * 4);
    *(float4*)(out + (((size_t)(b * NKV + h)) * SEQ + s) * HD + d4 * 4) = v;
}

// ---------------- tensor-core causal flash attention (unchanged from R4/R5) ----------------
#define FQ 128
#define FK 64
#define QPAD 68
#define KPAD 68
#define VPAD 72
#define PPAD 76
#define FLASH_SMEM ((FQ*QPAD + FK*KPAD + FK*VPAD + FQ*PPAD) * 4)

__global__ void __launch_bounds__(256) flash_mma_kernel(
    const float* __restrict__ Q, const float* __restrict__ K,
    const float* __restrict__ V, float* __restrict__ O)
{
    extern __shared__ float sm[];
    float* Qs = sm;
    float* Ks = Qs + FQ * QPAD;
    float* Vs = Ks + FK * KPAD;
    float* Ps = Vs + FK * VPAD;

    const int qt  = (SEQ / FQ - 1) - blockIdx.x;
    const int h   = blockIdx.y;
    const int b   = blockIdx.z;
    const int kvh = h >> 2;
    const int t    = threadIdx.x;
    const int lane = t & 31;
    const int w    = t >> 5;
    const int qid  = lane >> 2;
    const int tid4 = lane & 3;
    const int q0   = qt * FQ;
    const int wrow = w * 16;

    const float* Qb = Q + (((size_t)(b * NH + h)) * SEQ + q0) * HD;
    const float* Kb = K + ((size_t)(b * NKV + kvh)) * SEQ * HD;
    const float* Vb = V + ((size_t)(b * NKV + kvh)) * SEQ * HD;

    #pragma unroll
    for (int i = t * 4; i < FQ * HD; i += 1024) {
        const int r = i >> 6, c = i & 63;
        *(float4*)(Qs + r * QPAD + c) = *(const float4*)(Qb + r * HD + c);
    }

    float oacc[8][4];
    #pragma unroll
    for (int nf = 0; nf < 8; ++nf)
        #pragma unroll
        for (int j = 0; j < 4; ++j) oacc[nf][j] = 0.f;
    float m[2] = {-1e30f, -1e30f};
    float l[2] = {0.f, 0.f};

    const int row_a = q0 + wrow + qid;
    const int row_b = row_a + 8;
    const float SC = 0.125f * 1.4426950408889634f;

    const int ntiles = (q0 + FQ) / FK;
    for (int kt = 0; kt < ntiles; ++kt) {
        __syncthreads();
        #pragma unroll
        for (int i = t * 4; i < FK * HD; i += 1024) {
            const int r = i >> 6, c = i & 63;
            *(float4*)(Ks + r * KPAD + c) = *(const float4*)(Kb + (size_t)(kt * FK + r) * HD + c);
            *(float4*)(Vs + r * VPAD + c) = *(const float4*)(Vb + (size_t)(kt * FK + r) * HD + c);
        }
        __syncthreads();

        float sacc[8][4];
        #pragma unroll
        for (int nf = 0; nf < 8; ++nf)
            #pragma unroll
            for (int j = 0; j < 4; ++j) sacc[nf][j] = 0.f;

        #pragma unroll
        for (int ks = 0; ks < 8; ++ks) {
            const int k0 = ks * 8;
            const float* qp = Qs + (wrow + qid) * QPAD + k0 + tid4;
            uint32_t ah[4], al[4];
            split_tf32(qp[0],            ah[0], al[0]);
            split_tf32(qp[8 * QPAD],     ah[1], al[1]);
            split_tf32(qp[4],            ah[2], al[2]);
            split_tf32(qp[8 * QPAD + 4], ah[3], al[3]);
            #pragma unroll
            for (int nf = 0; nf < 8; ++nf) {
                const float* kp = Ks + (nf * 8 + qid) * KPAD + k0 + tid4;
                uint32_t bh[2];
                bh[0] = cvt_tf32(kp[0]);
                bh[1] = cvt_tf32(kp[4]);
                mma_tf32(sacc[nf], ah, bh);
                mma_tf32(sacc[nf], al, bh);
            }
        }

        const bool need_mask = (kt * FK + FK - 1) > row_a;
        float tmax[2] = {-1e30f, -1e30f};
        #pragma unroll
        for (int nf = 0; nf < 8; ++nf) {
            const int colbase = kt * FK + nf * 8 + tid4 * 2;
            #pragma unroll
            for (int j = 0; j < 4; ++j) {
                const int col = colbase + (j & 1);
                const int row = (j < 2) ? row_a : row_b;
                float v = sacc[nf][j] * SC;
                if (need_mask && col > row) v = -1e30f;
                sacc[nf][j] = v;
                const int hh = j >> 1;
                tmax[hh] = fmaxf(tmax[hh], v);
            }
        }

        float corr[2];
        #pragma unroll
        for (int hh = 0; hh < 2; ++hh) {
            tmax[hh] = fmaxf(tmax[hh], __shfl_xor_sync(0xffffffffu, tmax[hh], 1));
            tmax[hh] = fmaxf(tmax[hh], __shfl_xor_sync(0xffffffffu, tmax[hh], 2));
            const float mnew = fmaxf(m[hh], tmax[hh]);
            corr[hh] = exp2p(m[hh] - mnew);
            m[hh] = mnew;
            l[hh] *= corr[hh];
        }
        #pragma unroll
        for (int nf = 0; nf < 8; ++nf) {
            oacc[nf][0] *= corr[0]; oacc[nf][1] *= corr[0];
            oacc[nf][2] *= corr[1]; oacc[nf][3] *= corr[1];
        }
        float rsum[2] = {0.f, 0.f};
        #pragma unroll
        for (int nf = 0; nf < 8; ++nf) {
            #pragma unroll
            for (int j = 0; j < 4; ++j) {
                const int hh = j >> 1;
                const float p = exp2p(sacc[nf][j] - m[hh]);
                sacc[nf][j] = p;
                rsum[hh] += p;
            }
        }
        #pragma unroll
        for (int hh = 0; hh < 2; ++hh) {
            rsum[hh] += __shfl_xor_sync(0xffffffffu, rsum[hh], 1);
            rsum[hh] += __shfl_xor_sync(0xffffffffu, rsum[hh], 2);
            l[hh] += rsum[hh];
        }

        #pragma unroll
        for (int nf = 0; nf < 8; ++nf) {
            const int pc = nf * 8 + tid4 * 2;
            *(float2*)(Ps + (wrow + qid) * PPAD + pc)     = make_float2(sacc[nf][0], sacc[nf][1]);
            *(float2*)(Ps + (wrow + qid + 8) * PPAD + pc) = make_float2(sacc[nf][2], sacc[nf][3]);
        }
        __syncwarp();

        #pragma unroll
        for (int ks = 0; ks < 8; ++ks) {
            const int k0 = ks * 8;
            const float* pp = Ps + (wrow + qid) * PPAD + k0 + tid4;
            uint32_t ah[4], al[4];
            split_tf32(pp[0],            ah[0], al[0]);
            split_tf32(pp[8 * PPAD],     ah[1], al[1]);
            split_tf32(pp[4],            ah[2], al[2]);
            split_tf32(pp[8 * PPAD + 4], ah[3], al[3]);
            #pragma unroll
            for (int nf = 0; nf < 8; ++nf) {
                uint32_t bb[2];
                bb[0] = cvt_tf32(Vs[(k0 + tid4)     * VPAD + nf * 8 + qid]);
                bb[1] = cvt_tf32(Vs[(k0 + tid4 + 4) * VPAD + nf * 8 + qid]);
                mma_tf32(oacc[nf], ah, bb);
                mma_tf32(oacc[nf], al, bb);
            }
        }
    }

    const float inv_a = 1.0f / l[0];
    const float inv_b = 1.0f / l[1];
    float* Oa = O + ((size_t)(b * SEQ) + row_a) * DIM + h * HD;
    float* Ob = Oa + 8 * DIM;
    #pragma unroll
    for (int nf = 0; nf < 8; ++nf) {
        const int col = nf * 8 + tid4 * 2;
        *(float2*)(Oa + col) = make_float2(oacc[nf][0] * inv_a, oacc[nf][1] * inv_a);
        *(float2*)(Ob + col) = make_float2(oacc[nf][2] * inv_b, oacc[nf][3] * inv_b);
    }
}

// ---------------- host launcher ----------------
extern "C" void kernel_launch(void* const* d_in, const int* in_sizes, int n_in,
                              void* d_out, int out_size) {
    (void)in_sizes; (void)n_in; (void)out_size;
    const float* x  = (const float*)d_in[0];
    const float* Wq = (const float*)d_in[1];
    const float* Wk = (const float*)d_in[2];
    const float* Wv = (const float*)d_in[3];
    const float* bv = (const float*)d_in[4];
    const float* Wo = (const float*)d_in[5];
    const float* bo = (const float*)d_in[6];
    float* out = (float*)d_out;

    float *qlin, *kvlin, *qt, *kt, *vt, *attn, *biaskv;
    __nv_bfloat16 *ah, *al, *bh, *bl;
    cudaGetSymbolAddress((void**)&qlin,  g_qlin);
    cudaGetSymbolAddress((void**)&kvlin, g_kvlin);
    cudaGetSymbolAddress((void**)&qt,    g_qt);
    cudaGetSymbolAddress((void**)&kt,    g_kt);
    cudaGetSymbolAddress((void**)&vt,    g_vt);
    cudaGetSymbolAddress((void**)&attn,  g_attn);
    cudaGetSymbolAddress((void**)&biaskv, g_biaskv);
    cudaGetSymbolAddress((void**)&ah,    g_ah);
    cudaGetSymbolAddress((void**)&al,    g_al);
    cudaGetSymbolAddress((void**)&bh,    g_bh);
    cudaGetSymbolAddress((void**)&bl,    g_bl);

    cudaFuncSetAttribute(mma_gemm_bf16, cudaFuncAttributeMaxDynamicSharedMemorySize, G_SMEM);
    cudaFuncSetAttribute(flash_mma_kernel, cudaFuncAttributeMaxDynamicSharedMemorySize, FLASH_SMEM);

    theta_kernel<<<1, 32>>>();
    biaskv_kernel<<<(2 * KVDIM) / 256, 256>>>(bv);

    // split activations once (reused by Q and KV projections)
    split_kernel<<<(MROWS * DIM) / 1024, 256>>>(x, ah, al);

    // Q projection
    transpose_split_kernel<<<dim3(DIM / 32, DIM / 32), dim3(32, 8)>>>(Wq, bh, bl, DIM, DIM);
    mma_gemm_bf16<<<dim3(DIM / 128, MROWS / 128), 256, G_SMEM>>>(ah, al, bh, bl, nullptr, qlin, DIM, DIM);

    // fused K+V projection (N = 1024)
    transpose_split_kernel<<<dim3(KVDIM / 32, DIM / 32), dim3(32, 8)>>>(Wk, bh, bl, DIM, KVDIM);
    transpose_split_kernel<<<dim3(KVDIM / 32, DIM / 32), dim3(32, 8)>>>(
        Wv, bh + (size_t)KVDIM * DIM, bl + (size_t)KVDIM * DIM, DIM, KVDIM);
    mma_gemm_bf16<<<dim3((2 * KVDIM) / 128, MROWS / 128), 256, G_SMEM>>>(
        ah, al, bh, bl, biaskv, kvlin, 2 * KVDIM, DIM);

    rope_q_kernel<<<(BATCH * SEQ * NH * 32) / 256, 256>>>(qlin, qt);
    rope_k_kernel<<<(BATCH * SEQ * NKV * 32) / 256, 256>>>(kvlin, kt);
    transpose_v_kernel<<<(BATCH * SEQ * NKV * 16) / 256, 256>>>(kvlin, vt);

    flash_mma_kernel<<<dim3(SEQ / FQ, NH, BATCH), 256, FLASH_SMEM>>>(qt, kt, vt, attn);

    // output projection
    split_kernel<<<(MROWS * DIM) / 1024, 256>>>(attn, ah, al);
    transpose_split_kernel<<<dim3(DIM / 32, DIM / 32), dim3(32, 8)>>>(Wo, bh, bl, DIM, DIM);
    mma_gemm_bf16<<<dim3(DIM / 128, MROWS / 128), 256, G_SMEM>>>(ah, al, bh, bl, bo, out, DIM, DIM);
}

// round 7
// speedup vs baseline: 2.5202x; 1.0566x over previous
#include <cuda_runtime.h>
#include <cuda_bf16.h>
#include <math.h>
#include <stdint.h>

#define DIM 2048
#define NH 32
#define NKV 8
#define HD 64
#define BATCH 2
#define SEQ 2048
#define MROWS (BATCH*SEQ)   /* 4096 */
#define KVDIM (NKV*HD)      /* 512 */

// ---------------- scratch (static device allocations; no cudaMalloc) ----------------
__device__ float g_qlin[(size_t)MROWS * DIM];
__device__ float g_kvlin[(size_t)MROWS * 2 * KVDIM];   // [m][0:512)=k, [512:1024)=v
__device__ float g_attn[(size_t)MROWS * DIM];
__device__ float g_biaskv[2 * KVDIM];
__device__ __align__(16) __nv_bfloat16 g_ah[(size_t)MROWS * DIM];
__device__ __align__(16) __nv_bfloat16 g_al[(size_t)MROWS * DIM];
__device__ __align__(16) __nv_bfloat16 g_bh[(size_t)DIM * DIM];
__device__ __align__(16) __nv_bfloat16 g_bl[(size_t)DIM * DIM];
// flash operands, pre-split bf16 hi/lo
__device__ __align__(16) __nv_bfloat16 g_qh[(size_t)BATCH * NH * SEQ * HD];
__device__ __align__(16) __nv_bfloat16 g_ql[(size_t)BATCH * NH * SEQ * HD];
__device__ __align__(16) __nv_bfloat16 g_kh[(size_t)BATCH * NKV * SEQ * HD];
__device__ __align__(16) __nv_bfloat16 g_kl[(size_t)BATCH * NKV * SEQ * HD];
__device__ __align__(16) __nv_bfloat16 g_vth[(size_t)BATCH * NKV * HD * SEQ];  // [b,kv,d,s]
__device__ __align__(16) __nv_bfloat16 g_vtl[(size_t)BATCH * NKV * HD * SEQ];
__device__ double g_theta[HD / 2];

// ---------------- RoPE angle table ----------------
__global__ void theta_kernel() {
    int p = threadIdx.x;
    if (p < HD / 2) g_theta[p] = pow(10000.0, -(double)p / 32.0);
}

__global__ void biaskv_kernel(const float* __restrict__ bv) {
    int i = blockIdx.x * blockDim.x + threadIdx.x;
    g_biaskv[i] = (i < KVDIM) ? 0.f : bv[i - KVDIM];
}

// ---------------- bf16 hi/lo split helpers ----------------
__device__ __forceinline__ void bf16_split(float x, __nv_bfloat16& h, __nv_bfloat16& l) {
    h = __float2bfloat16(x);
    l = __float2bfloat16(x - __bfloat162float(h));
}

__global__ void split_kernel(const float* __restrict__ in,
                             __nv_bfloat16* __restrict__ oh,
                             __nv_bfloat16* __restrict__ ol) {
    const int i = blockIdx.x * blockDim.x + threadIdx.x;
    const float4 v = *(const float4*)(in + (size_t)i * 4);
    __nv_bfloat16 h[4], l[4];
    bf16_split(v.x, h[0], l[0]);
    bf16_split(v.y, h[1], l[1]);
    bf16_split(v.z, h[2], l[2]);
    bf16_split(v.w, h[3], l[3]);
    *(uint2*)(oh + (size_t)i * 4) = *(uint2*)h;
    *(uint2*)(ol + (size_t)i * 4) = *(uint2*)l;
}

__global__ void transpose_split_kernel(const float* __restrict__ in,
                                       __nv_bfloat16* __restrict__ oh,
                                       __nv_bfloat16* __restrict__ ol,
                                       int R, int Ccols) {
    __shared__ float tile[32][33];
    int bx = blockIdx.x * 32, by = blockIdx.y * 32;
    int x = bx + threadIdx.x;
    #pragma unroll
    for (int i = 0; i < 32; i += 8)
        tile[threadIdx.y + i][threadIdx.x] = in[(size_t)(by + threadIdx.y + i) * Ccols + x];
    __syncthreads();
    int ox = by + threadIdx.x;
    #pragma unroll
    for (int i = 0; i < 32; i += 8) {
        const float v = tile[threadIdx.x][threadIdx.y + i];
        __nv_bfloat16 h, l;
        bf16_split(v, h, l);
        const size_t o = (size_t)(bx + threadIdx.y + i) * R + ox;
        oh[o] = h;
        ol[o] = l;
    }
}

// ================= mma.sync / async helpers =================
__device__ __forceinline__ uint32_t smem_u32(const void* p) {
    uint32_t a;
    asm("{ .reg .u64 t; cvta.to.shared.u64 t, %1; cvt.u32.u64 %0, t; }" : "=r"(a) : "l"(p));
    return a;
}
__device__ __forceinline__ void cp16(uint32_t dst, const void* src) {
    asm volatile("cp.async.cg.shared.global [%0], [%1], 16;" :: "r"(dst), "l"(src));
}
#define CP_COMMIT() asm volatile("cp.async.commit_group;" ::: "memory")
#define CP_WAIT1()  asm volatile("cp.async.wait_group 1;" ::: "memory")

__device__ __forceinline__ void ldsm4(uint32_t* r, uint32_t addr) {
    asm volatile("ldmatrix.sync.aligned.m8n8.x4.shared.b16 {%0,%1,%2,%3}, [%4];"
                 : "=r"(r[0]), "=r"(r[1]), "=r"(r[2]), "=r"(r[3]) : "r"(addr));
}
__device__ __forceinline__ void mma_bf16(float* d, const uint32_t* a, const uint32_t* b) {
    asm volatile(
        "mma.sync.aligned.m16n8k16.row.col.f32.bf16.bf16.f32 "
        "{%0,%1,%2,%3}, {%4,%5,%6,%7}, {%8,%9}, {%0,%1,%2,%3};\n"
        : "+f"(d[0]), "+f"(d[1]), "+f"(d[2]), "+f"(d[3])
        : "r"(a[0]), "r"(a[1]), "r"(a[2]), "r"(a[3]), "r"(b[0]), "r"(b[1]));
}
__device__ __forceinline__ uint32_t pack_bf2(float x0, float x1) {
    __nv_bfloat162 v = __floats2bfloat162_rn(x0, x1);
    return *(uint32_t*)&v;
}
__device__ __forceinline__ float exp2p(float y) {
    y = fmaxf(y, -120.f);
    int ki = __float2int_rn(y);
    float f = y - (float)ki;
    float p = 0.0013333558f;
    p = fmaf(p, f, 0.0096181291f);
    p = fmaf(p, f, 0.0555041087f);
    p = fmaf(p, f, 0.2402265070f);
    p = fmaf(p, f, 0.6931471806f);
    p = fmaf(p, f, 1.0f);
    return p * __int_as_float((ki + 127) << 23);
}

// ---------------- bf16 3-term GEMM (unchanged from R6) ----------------
#define BPAD 40
#define G_ARRB (128 * BPAD * 2)
#define G_BUFB (4 * G_ARRB)
#define G_SMEM (2 * G_BUFB)

__global__ void __launch_bounds__(256, 2) mma_gemm_bf16(
    const __nv_bfloat16* __restrict__ Ah, const __nv_bfloat16* __restrict__ Al,
    const __nv_bfloat16* __restrict__ Bh, const __nv_bfloat16* __restrict__ Bl,
    const float* __restrict__ bias, float* __restrict__ C, int N, int K)
{
    extern __shared__ char smem[];
    const uint32_t smbase = smem_u32(smem);

    const int t    = threadIdx.x;
    const int lane = t & 31;
    const int wid  = t >> 5;
    const int wr   = wid & 3;
    const int wc   = wid >> 2;
    const int qid  = lane >> 2;
    const int tid4 = lane & 3;

    const size_t m0 = (size_t)blockIdx.y * 128;
    const size_t n0 = (size_t)blockIdx.x * 128;

    const int g   = t >> 6;
    const int sub = t & 63;
    const __nv_bfloat16* gbase =
        (g == 0) ? Ah + m0 * K : (g == 1) ? Al + m0 * K :
        (g == 2) ? Bh + n0 * K : Bl + n0 * K;
    const uint32_t sm_arr = smbase + g * G_ARRB;

    const uint32_t a_off = (uint32_t)(((wr * 32 + (lane & 15)) * BPAD + ((lane >> 4) << 3)) * 2);
    const uint32_t b_off = (uint32_t)(((wc * 64 + (lane & 7) + ((lane & 16) >> 1)) * BPAD + (lane & 8)) * 2);

    float acc[2][8][4];
    #pragma unroll
    for (int mf = 0; mf < 2; ++mf)
        #pragma unroll
        for (int nf = 0; nf < 8; ++nf)
            #pragma unroll
            for (int r = 0; r < 4; ++r) acc[mf][nf][r] = 0.f;

    const int nchunks = K / 32;

    #pragma unroll
    for (int i = 0; i < 8; ++i) {
        const int idx = sub + i * 64;
        const int row = idx >> 2, col = (idx & 3) * 8;
        cp16(sm_arr + (uint32_t)((row * BPAD + col) * 2), gbase + (size_t)row * K + col);
    }
    CP_COMMIT();

    for (int c = 0; c < nchunks; ++c) {
        const int buf = c & 1;
        if (c + 1 < nchunks) {
            const uint32_t dst = sm_arr + (uint32_t)((c + 1) & 1) * G_BUFB;
            const __nv_bfloat16* src = gbase + (c + 1) * 32;
            #pragma unroll
            for (int i = 0; i < 8; ++i) {
                const int idx = sub + i * 64;
                const int row = idx >> 2, col = (idx & 3) * 8;
                cp16(dst + (uint32_t)((row * BPAD + col) * 2), src + (size_t)row * K + col);
            }
        }
        CP_COMMIT();
        CP_WAIT1();
        __syncthreads();

        const uint32_t sb = smbase + (uint32_t)buf * G_BUFB;
        #pragma unroll
        for (int ks = 0; ks < 2; ++ks) {
            const uint32_t kb = (uint32_t)(ks * 32);
            uint32_t ah[2][4], al[2][4];
            #pragma unroll
            for (int mf = 0; mf < 2; ++mf) {
                const uint32_t ro = (uint32_t)(mf * 16 * BPAD * 2);
                ldsm4(ah[mf], sb + 0 * G_ARRB + a_off + ro + kb);
                ldsm4(al[mf], sb + 1 * G_ARRB + a_off + ro + kb);
            }
            uint32_t bh[8][2], bl[8][2];
            #pragma unroll
            for (int p = 0; p < 4; ++p) {
                const uint32_t ro = (uint32_t)(p * 16 * BPAD * 2);
                uint32_t r[4];
                ldsm4(r, sb + 2 * G_ARRB + b_off + ro + kb);
                bh[2 * p][0] = r[0]; bh[2 * p][1] = r[1];
                bh[2 * p + 1][0] = r[2]; bh[2 * p + 1][1] = r[3];
                ldsm4(r, sb + 3 * G_ARRB + b_off + ro + kb);
                bl[2 * p][0] = r[0]; bl[2 * p][1] = r[1];
                bl[2 * p + 1][0] = r[2]; bl[2 * p + 1][1] = r[3];
            }
            #pragma unroll
            for (int nf = 0; nf < 8; ++nf)
                #pragma unroll
                for (int mf = 0; mf < 2; ++mf) {
                    mma_bf16(acc[mf][nf], ah[mf], bh[nf]);
                    mma_bf16(acc[mf][nf], ah[mf], bl[nf]);
                    mma_bf16(acc[mf][nf], al[mf], bh[nf]);
                }
        }
        __syncthreads();
    }

    const int trow = qid;
    const int tcol = tid4 * 2;
    #pragma unroll
    for (int mf = 0; mf < 2; ++mf) {
        const size_t m = m0 + wr * 32 + mf * 16 + trow;
        #pragma unroll
        for (int nf = 0; nf < 8; ++nf) {
            const int ncol = (int)n0 + wc * 64 + nf * 8 + tcol;
            float2 v0 = make_float2(acc[mf][nf][0], acc[mf][nf][1]);
            float2 v1 = make_float2(acc[mf][nf][2], acc[mf][nf][3]);
            if (bias) {
                const float bx = bias[ncol], by = bias[ncol + 1];
                v0.x += bx; v0.y += by;
                v1.x += bx; v1.y += by;
            }
            *(float2*)(C + m * N + ncol)       = v0;
            *(float2*)(C + (m + 8) * N + ncol) = v1;
        }
    }
}

// ---------------- RoPE -> bf16 hi/lo ----------------
__global__ void rope_q_kernel(const float* __restrict__ in,
                              __nv_bfloat16* __restrict__ oh,
                              __nv_bfloat16* __restrict__ ol) {
    int idx = blockIdx.x * blockDim.x + threadIdx.x;
    int p = idx & 31;
    int h = (idx >> 5) & 31;
    int s = (idx >> 10) & 2047;
    int b = idx >> 21;
    float ang = (float)((double)s * g_theta[p]);
    float sv, cv;
    sincosf(ang, &sv, &cv);
    const float2 x = *(const float2*)(in + ((size_t)(b * SEQ + s)) * DIM + h * HD + 2 * p);
    float rx = x.x * cv - x.y * sv;
    float ry = x.x * sv + x.y * cv;
    __nv_bfloat16 hx, lx, hy, ly;
    bf16_split(rx, hx, lx);
    bf16_split(ry, hy, ly);
    const size_t o = (((size_t)(b * NH + h)) * SEQ + s) * HD + 2 * p;
    __nv_bfloat162 vh; vh.x = hx; vh.y = hy;
    __nv_bfloat162 vl; vl.x = lx; vl.y = ly;
    *(__nv_bfloat162*)(oh + o) = vh;
    *(__nv_bfloat162*)(ol + o) = vl;
}
__global__ void rope_k_kernel(const float* __restrict__ in,
                              __nv_bfloat16* __restrict__ oh,
                              __nv_bfloat16* __restrict__ ol) {
    int idx = blockIdx.x * blockDim.x + threadIdx.x;
    int p = idx & 31;
    int h = (idx >> 5) & 7;
    int s = (idx >> 8) & 2047;
    int b = idx >> 19;
    float ang = (float)((double)s * g_theta[p]);
    float sv, cv;
    sincosf(ang, &sv, &cv);
    const float2 x = *(const float2*)(in + ((size_t)(b * SEQ + s)) * (2 * KVDIM) + h * HD + 2 * p);
    float rx = x.x * cv - x.y * sv;
    float ry = x.x * sv + x.y * cv;
    __nv_bfloat16 hx, lx, hy, ly;
    bf16_split(rx, hx, lx);
    bf16_split(ry, hy, ly);
    const size_t o = (((size_t)(b * NKV + h)) * SEQ + s) * HD + 2 * p;
    __nv_bfloat162 vh; vh.x = hx; vh.y = hy;
    __nv_bfloat162 vl; vl.x = lx; vl.y = ly;
    *(__nv_bfloat162*)(oh + o) = vh;
    *(__nv_bfloat162*)(ol + o) = vl;
}

// V: kvlin [b,s,512+kv*64+d] -> transposed bf16 hi/lo [b,kv,d,s]
__global__ void transpose_v_kernel(const float* __restrict__ in,
                                   __nv_bfloat16* __restrict__ oh,
                                   __nv_bfloat16* __restrict__ ol) {
    __shared__ float tile[32][33];
    const int s0 = blockIdx.x * 32;
    const int d0 = blockIdx.y * 32;
    const int bk = blockIdx.z;                    // b*NKV + kv
    const int b  = bk >> 3, kv = bk & 7;
    const int tx = threadIdx.x, ty = threadIdx.y;
    const float* src = in + ((size_t)(b * SEQ)) * (2 * KVDIM) + KVDIM + kv * HD;
    #pragma unroll
    for (int i = 0; i < 32; i += 8)
        tile[ty + i][tx] = src[(size_t)(s0 + ty + i) * (2 * KVDIM) + d0 + tx];
    __syncthreads();
    const size_t obase = ((size_t)bk * HD + d0) * SEQ + s0;
    #pragma unroll
    for (int i = 0; i < 32; i += 8) {
        const float v = tile[tx][ty + i];
        __nv_bfloat16 h, l;
        bf16_split(v, h, l);
        oh[obase + (size_t)(ty + i) * SEQ + tx] = h;
        ol[obase + (size_t)(ty + i) * SEQ + tx] = l;
    }
}

// ---------------- flash attention v2: bf16 mma, ldmatrix, cp.async ----------------
// Q tile 128 rows/CTA, KV tiles 64. 8 warps, warp w owns q rows w*16..+15.
// QK: 3-term (Qhi+Qlo)x(Khi+Klo); PV: 3-term with P packed in registers.
#define FQ 128
#define FK 64
#define SP 72                          /* bf16 row stride: 144B, conflict-free */
#define F_ARR (64 * SP * 2)            /* 9216 B per array */
#define F_BUF (4 * F_ARR)              /* Kh Kl Vth Vtl */
#define F_SMEM (2 * F_BUF)             /* 73728 B */
#define F_QARR (FQ * SP * 2)           /* 18432 B (staged in buf region, prologue only) */

__global__ void __launch_bounds__(256) flash_mma_kernel(
    const __nv_bfloat16* __restrict__ Qh, const __nv_bfloat16* __restrict__ Ql,
    const __nv_bfloat16* __restrict__ Kh, const __nv_bfloat16* __restrict__ Kl,
    const __nv_bfloat16* __restrict__ Vth, const __nv_bfloat16* __restrict__ Vtl,
    float* __restrict__ O)
{
    extern __shared__ char smem[];
    const uint32_t smbase = smem_u32(smem);

    const int qt  = (SEQ / FQ - 1) - blockIdx.x;
    const int h   = blockIdx.y;
    const int b   = blockIdx.z;
    const int kvh = h >> 2;
    const int t    = threadIdx.x;
    const int lane = t & 31;
    const int w    = t >> 5;
    const int qid  = lane >> 2;
    const int tid4 = lane & 3;
    const int q0   = qt * FQ;
    const int wrow = w * 16;

    const __nv_bfloat16* Qhb = Qh + (((size_t)(b * NH + h)) * SEQ + q0) * HD;
    const __nv_bfloat16* Qlb = Ql + (((size_t)(b * NH + h)) * SEQ + q0) * HD;
    const __nv_bfloat16* Khb = Kh + ((size_t)(b * NKV + kvh)) * SEQ * HD;
    const __nv_bfloat16* Klb = Kl + ((size_t)(b * NKV + kvh)) * SEQ * HD;
    const __nv_bfloat16* Vhb = Vth + ((size_t)(b * NKV + kvh)) * HD * SEQ;
    const __nv_bfloat16* Vlb = Vtl + ((size_t)(b * NKV + kvh)) * HD * SEQ;

    // ---- stage Q (hi at 0, lo at F_QARR), extract fragments, release smem ----
    #pragma unroll
    for (int i = 0; i < 4; ++i) {
        const int idx = t + i * 256;          // 0..1023
        const int r = idx >> 3, c = (idx & 7) * 8;
        *(uint4*)(smem + (r * SP + c) * 2)          = *(const uint4*)(Qhb + (size_t)r * HD + c);
        *(uint4*)(smem + F_QARR + (r * SP + c) * 2) = *(const uint4*)(Qlb + (size_t)r * HD + c);
    }
    __syncthreads();

    uint32_t qfh[4][4], qfl[4][4];
    const uint32_t a_off = (uint32_t)(((wrow + (lane & 15)) * SP + ((lane >> 4) << 3)) * 2);
    #pragma unroll
    for (int g2 = 0; g2 < 4; ++g2) {
        ldsm4(qfh[g2], smbase + a_off + (uint32_t)(g2 * 32));
        ldsm4(qfl[g2], smbase + F_QARR + a_off + (uint32_t)(g2 * 32));
    }
    __syncthreads();

    // ---- cp.async assignment: 64 threads per array (0=Kh 1=Kl 2=Vth 3=Vtl) ----
    const int ga  = t >> 6;
    const int sub = t & 63;
    const __nv_bfloat16* gsrc = (ga == 0) ? Khb : (ga == 1) ? Klb : (ga == 2) ? Vhb : Vlb;
    const bool isK = (ga < 2);

    const uint32_t b_off = (uint32_t)((((lane & 7) + ((lane & 16) >> 1)) * SP + (lane & 8)) * 2);

    float oacc[8][4];
    #pragma unroll
    for (int nf = 0; nf < 8; ++nf)
        #pragma unroll
        for (int j = 0; j < 4; ++j) oacc[nf][j] = 0.f;
    float m[2] = {-1e30f, -1e30f};
    float l[2] = {0.f, 0.f};

    const int row_a = q0 + wrow + qid;
    const int row_b = row_a + 8;
    const float SC = 0.125f * 1.4426950408889634f;

    const int ntiles = (q0 + FQ) / FK;

    // prologue: tile 0 -> buf0
    #pragma unroll
    for (int i = 0; i < 8; ++i) {
        const int idx = sub + i * 64;
        const int row = idx >> 3, col = (idx & 7) * 8;
        const __nv_bfloat16* s = isK ? (gsrc + (size_t)row * HD + col)
                                     : (gsrc + (size_t)row * SEQ + col);
        cp16(smbase + (uint32_t)(ga * F_ARR) + (uint32_t)((row * SP + col) * 2), s);
    }
    CP_COMMIT();

    for (int kt = 0; kt < ntiles; ++kt) {
        if (kt + 1 < ntiles) {
            const uint32_t dst = smbase + (uint32_t)(((kt + 1) & 1) * F_BUF) + (uint32_t)(ga * F_ARR);
            #pragma unroll
            for (int i = 0; i < 8; ++i) {
                const int idx = sub + i * 64;
                const int row = idx >> 3, col = (idx & 7) * 8;
                const __nv_bfloat16* s = isK
                    ? (gsrc + (size_t)((kt + 1) * FK + row) * HD + col)
                    : (gsrc + (size_t)row * SEQ + (kt + 1) * FK + col);
                cp16(dst + (uint32_t)((row * SP + col) * 2), s);
            }
        }
        CP_COMMIT();
        CP_WAIT1();
        __syncthreads();

        const uint32_t sb = smbase + (uint32_t)((kt & 1) * F_BUF);

        // ---- scores ----
        float sacc[8][4];
        #pragma unroll
        for (int nf = 0; nf < 8; ++nf)
            #pragma unroll
            for (int j = 0; j < 4; ++j) sacc[nf][j] = 0.f;

        #pragma unroll
        for (int g2 = 0; g2 < 4; ++g2) {
            const uint32_t kb = (uint32_t)(g2 * 32);
            uint32_t bh[8][2], bl[8][2];
            #pragma unroll
            for (int p = 0; p < 4; ++p) {
                const uint32_t ro = (uint32_t)(p * 16 * SP * 2);
                uint32_t r[4];
                ldsm4(r, sb + 0 * F_ARR + b_off + ro + kb);
                bh[2 * p][0] = r[0]; bh[2 * p][1] = r[1];
                bh[2 * p + 1][0] = r[2]; bh[2 * p + 1][1] = r[3];
                ldsm4(r, sb + 1 * F_ARR + b_off + ro + kb);
                bl[2 * p][0] = r[0]; bl[2 * p][1] = r[1];
                bl[2 * p + 1][0] = r[2]; bl[2 * p + 1][1] = r[3];
            }
            #pragma unroll
            for (int nf = 0; nf < 8; ++nf) {
                mma_bf16(sacc[nf], qfh[g2], bh[nf]);
                mma_bf16(sacc[nf], qfl[g2], bh[nf]);
                mma_bf16(sacc[nf], qfh[g2], bl[nf]);
            }
        }

        // ---- mask + scale (log2 domain) + row max ----
        const bool need_mask = (kt * FK + FK - 1) > row_a;
        float tmax[2] = {-1e30f, -1e30f};
        #pragma unroll
        for (int nf = 0; nf < 8; ++nf) {
            const int colbase = kt * FK + nf * 8 + tid4 * 2;
            #pragma unroll
            for (int j = 0; j < 4; ++j) {
                const int col = colbase + (j & 1);
                const int row = (j < 2) ? row_a : row_b;
                float v = sacc[nf][j] * SC;
                if (need_mask && col > row) v = -1e30f;
                sacc[nf][j] = v;
                tmax[j >> 1] = fmaxf(tmax[j >> 1], v);
            }
        }

        float corr[2];
        #pragma unroll
        for (int hh = 0; hh < 2; ++hh) {
            tmax[hh] = fmaxf(tmax[hh], __shfl_xor_sync(0xffffffffu, tmax[hh], 1));
            tmax[hh] = fmaxf(tmax[hh], __shfl_xor_sync(0xffffffffu, tmax[hh], 2));
            const float mnew = fmaxf(m[hh], tmax[hh]);
            corr[hh] = exp2p(m[hh] - mnew);
            m[hh] = mnew;
            l[hh] *= corr[hh];
        }
        #pragma unroll
        for (int nf = 0; nf < 8; ++nf) {
            oacc[nf][0] *= corr[0]; oacc[nf][1] *= corr[0];
            oacc[nf][2] *= corr[1]; oacc[nf][3] *= corr[1];
        }
        float rsum[2] = {0.f, 0.f};
        #pragma unroll
        for (int nf = 0; nf < 8; ++nf) {
            #pragma unroll
            for (int j = 0; j < 4; ++j) {
                const float p = exp2p(sacc[nf][j] - m[j >> 1]);
                sacc[nf][j] = p;
                rsum[j >> 1] += p;
            }
        }
        #pragma unroll
        for (int hh = 0; hh < 2; ++hh) {
            rsum[hh] += __shfl_xor_sync(0xffffffffu, rsum[hh], 1);
            rsum[hh] += __shfl_xor_sync(0xffffffffu, rsum[hh], 2);
            l[hh] += rsum[hh];
        }

        // ---- build P a-fragments in registers (hi/lo) ----
        // k16 group g2 <- score tiles nf=2g2 (k 0..7) and nf=2g2+1 (k 8..15)
        uint32_t pfh[4][4], pfl[4][4];
        #pragma unroll
        for (int g2 = 0; g2 < 4; ++g2) {
            const float* s0 = sacc[2 * g2];
            const float* s1 = sacc[2 * g2 + 1];
            float h00 = __bfloat162float(__float2bfloat16(s0[0]));
            float h01 = __bfloat162float(__float2bfloat16(s0[1]));
            float h02 = __bfloat162float(__float2bfloat16(s0[2]));
            float h03 = __bfloat162float(__float2bfloat16(s0[3]));
            float h10 = __bfloat162float(__float2bfloat16(s1[0]));
            float h11 = __bfloat162float(__float2bfloat16(s1[1]));
            float h12 = __bfloat162float(__float2bfloat16(s1[2]));
            float h13 = __bfloat162float(__float2bfloat16(s1[3]));
            pfh[g2][0] = pack_bf2(h00, h01);
            pfh[g2][1] = pack_bf2(h02, h03);
            pfh[g2][2] = pack_bf2(h10, h11);
            pfh[g2][3] = pack_bf2(h12, h13);
            pfl[g2][0] = pack_bf2(s0[0] - h00, s0[1] - h01);
            pfl[g2][1] = pack_bf2(s0[2] - h02, s0[3] - h03);
            pfl[g2][2] = pack_bf2(s1[0] - h10, s1[1] - h11);
            pfl[g2][3] = pack_bf2(s1[2] - h12, s1[3] - h13);
        }

        // ---- O += P V  (Vt is [d][key]: B-operand K-major over keys) ----
        #pragma unroll
        for (int g2 = 0; g2 < 4; ++g2) {
            const uint32_t kb = (uint32_t)(g2 * 32);
            uint32_t vh[8][2], vl[8][2];
            #pragma unroll
            for (int p = 0; p < 4; ++p) {
                const uint32_t ro = (uint32_t)(p * 16 * SP * 2);
                uint32_t r[4];
                ldsm4(r, sb + 2 * F_ARR + b_off + ro + kb);
                vh[2 * p][0] = r[0]; vh[2 * p][1] = r[1];
                vh[2 * p + 1][0] = r[2]; vh[2 * p + 1][1] = r[3];
                ldsm4(r, sb + 3 * F_ARR + b_off + ro + kb);
                vl[2 * p][0] = r[0]; vl[2 * p][1] = r[1];
                vl[2 * p + 1][0] = r[2]; vl[2 * p + 1][1] = r[3];
            }
            #pragma unroll
            for (int nf = 0; nf < 8; ++nf) {
                mma_bf16(oacc[nf], pfh[g2], vh[nf]);
                mma_bf16(oacc[nf], pfl[g2], vh[nf]);
                mma_bf16(oacc[nf], pfh[g2], vl[nf]);
            }
        }
        __syncthreads();
    }

    // ---- epilogue ----
    const float inv_a = 1.0f / l[0];
    const float inv_b = 1.0f / l[1];
    float* Oa = O + ((size_t)(b * SEQ) + row_a) * DIM + h * HD;
    float* Ob = Oa + 8 * DIM;
    #pragma unroll
    for (int nf = 0; nf < 8; ++nf) {
        const int col = nf * 8 + tid4 * 2;
        *(float2*)(Oa + col) = make_float2(oacc[nf][0] * inv_a, oacc[nf][1] * inv_a);
        *(float2*)(Ob + col) = make_float2(oacc[nf][2] * inv_b, oacc[nf][3] * inv_b);
    }
}

// ---------------- host launcher ----------------
extern "C" void kernel_launch(void* const* d_in, const int* in_sizes, int n_in,
                              void* d_out, int out_size) {
    (void)in_sizes; (void)n_in; (void)out_size;
    const float* x  = (const float*)d_in[0];
    const float* Wq = (const float*)d_in[1];
    const float* Wk = (const float*)d_in[2];
    const float* Wv = (const float*)d_in[3];
    const float* bv = (const float*)d_in[4];
    const float* Wo = (const float*)d_in[5];
    const float* bo = (const float*)d_in[6];
    float* out = (float*)d_out;

    float *qlin, *kvlin, *attn, *biaskv;
    __nv_bfloat16 *ah, *al, *bh, *bl, *qh, *ql, *kh, *kl, *vth, *vtl;
    cudaGetSymbolAddress((void**)&qlin,  g_qlin);
    cudaGetSymbolAddress((void**)&kvlin, g_kvlin);
    cudaGetSymbolAddress((void**)&attn,  g_attn);
    cudaGetSymbolAddress((void**)&biaskv, g_biaskv);
    cudaGetSymbolAddress((void**)&ah,    g_ah);
    cudaGetSymbolAddress((void**)&al,    g_al);
    cudaGetSymbolAddress((void**)&bh,    g_bh);
    cudaGetSymbolAddress((void**)&bl,    g_bl);
    cudaGetSymbolAddress((void**)&qh,    g_qh);
    cudaGetSymbolAddress((void**)&ql,    g_ql);
    cudaGetSymbolAddress((void**)&kh,    g_kh);
    cudaGetSymbolAddress((void**)&kl,    g_kl);
    cudaGetSymbolAddress((void**)&vth,   g_vth);
    cudaGetSymbolAddress((void**)&vtl,   g_vtl);

    cudaFuncSetAttribute(mma_gemm_bf16, cudaFuncAttributeMaxDynamicSharedMemorySize, G_SMEM);
    cudaFuncSetAttribute(flash_mma_kernel, cudaFuncAttributeMaxDynamicSharedMemorySize, F_SMEM);

    theta_kernel<<<1, 32>>>();
    biaskv_kernel<<<(2 * KVDIM) / 256, 256>>>(bv);

    split_kernel<<<(MROWS * DIM) / 1024, 256>>>(x, ah, al);

    transpose_split_kernel<<<dim3(DIM / 32, DIM / 32), dim3(32, 8)>>>(Wq, bh, bl, DIM, DIM);
    mma_gemm_bf16<<<dim3(DIM / 128, MROWS / 128), 256, G_SMEM>>>(ah, al, bh, bl, nullptr, qlin, DIM, DIM);

    transpose_split_kernel<<<dim3(KVDIM / 32, DIM / 32), dim3(32, 8)>>>(Wk, bh, bl, DIM, KVDIM);
    transpose_split_kernel<<<dim3(KVDIM / 32, DIM / 32), dim3(32, 8)>>>(
        Wv, bh + (size_t)KVDIM * DIM, bl + (size_t)KVDIM * DIM, DIM, KVDIM);
    mma_gemm_bf16<<<dim3((2 * KVDIM) / 128, MROWS / 128), 256, G_SMEM>>>(
        ah, al, bh, bl, biaskv, kvlin, 2 * KVDIM, DIM);

    rope_q_kernel<<<(BATCH * SEQ * NH * 32) / 256, 256>>>(qlin, qh, ql);
    rope_k_kernel<<<(BATCH * SEQ * NKV * 32) / 256, 256>>>(kvlin, kh, kl);
    transpose_v_kernel<<<dim3(SEQ / 32, HD / 32, BATCH * NKV), dim3(32, 8)>>>(kvlin, vth, vtl);

    flash_mma_kernel<<<dim3(SEQ / FQ, NH, BATCH), 256, F_SMEM>>>(qh, ql, kh, kl, vth, vtl, attn);

    split_kernel<<<(MROWS * DIM) / 1024, 256>>>(attn, ah, al);
    transpose_split_kernel<<<dim3(DIM / 32, DIM / 32), dim3(32, 8)>>>(Wo, bh, bl, DIM, DIM);
    mma_gemm_bf16<<<dim3(DIM / 128, MROWS / 128), 256, G_SMEM>>>(ah, al, bh, bl, bo, out, DIM, DIM);
}

// round 8
// speedup vs baseline: 2.8102x; 1.1151x over previous
#include <cuda_runtime.h>
#include <cuda_bf16.h>
#include <math.h>
#include <stdint.h>

#define DIM 2048
#define NH 32
#define NKV 8
#define HD 64
#define BATCH 2
#define SEQ 2048
#define MROWS (BATCH*SEQ)   /* 4096 */
#define KVDIM (NKV*HD)      /* 512 */
#define NQKV (DIM + 2*KVDIM) /* 3072 */

// ---------------- scratch (static device allocations; no cudaMalloc) ----------------
__device__ float g_qkvlin[(size_t)MROWS * NQKV];   // merged q|k|v projection output
__device__ float g_biasqkv[NQKV];
__device__ __align__(16) __nv_bfloat16 g_ah[(size_t)MROWS * DIM];
__device__ __align__(16) __nv_bfloat16 g_al[(size_t)MROWS * DIM];
__device__ __align__(16) __nv_bfloat16 g_bh[(size_t)NQKV * DIM];
__device__ __align__(16) __nv_bfloat16 g_bl[(size_t)NQKV * DIM];
// flash operands, pre-split bf16 hi/lo
__device__ __align__(16) __nv_bfloat16 g_qh[(size_t)BATCH * NH * SEQ * HD];
__device__ __align__(16) __nv_bfloat16 g_ql[(size_t)BATCH * NH * SEQ * HD];
__device__ __align__(16) __nv_bfloat16 g_kh[(size_t)BATCH * NKV * SEQ * HD];
__device__ __align__(16) __nv_bfloat16 g_kl[(size_t)BATCH * NKV * SEQ * HD];
__device__ __align__(16) __nv_bfloat16 g_vth[(size_t)BATCH * NKV * HD * SEQ];  // [b,kv,d,s]
__device__ __align__(16) __nv_bfloat16 g_vtl[(size_t)BATCH * NKV * HD * SEQ];
__device__ double g_theta[HD / 2];
__device__ float2 g_cs[(size_t)SEQ * (HD / 2)];    // cos/sin table

// ---------------- RoPE tables ----------------
__global__ void theta_kernel() {
    int p = threadIdx.x;
    if (p < HD / 2) g_theta[p] = pow(10000.0, -(double)p / 32.0);
}
__global__ void sincos_kernel() {
    int idx = blockIdx.x * blockDim.x + threadIdx.x;   // SEQ*32
    int s = idx >> 5, p = idx & 31;
    float ang = (float)((double)s * g_theta[p]);
    float sv, cv;
    sincosf(ang, &sv, &cv);
    g_cs[idx] = make_float2(cv, sv);
}
__global__ void biasqkv_kernel(const float* __restrict__ bv) {
    int i = blockIdx.x * blockDim.x + threadIdx.x;
    g_biasqkv[i] = (i < DIM + KVDIM) ? 0.f : bv[i - (DIM + KVDIM)];
}

// ---------------- bf16 hi/lo split helpers ----------------
__device__ __forceinline__ void bf16_split(float x, __nv_bfloat16& h, __nv_bfloat16& l) {
    h = __float2bfloat16(x);
    l = __float2bfloat16(x - __bfloat162float(h));
}

__global__ void split_kernel(const float* __restrict__ in,
                             __nv_bfloat16* __restrict__ oh,
                             __nv_bfloat16* __restrict__ ol) {
    const int i = blockIdx.x * blockDim.x + threadIdx.x;
    const float4 v = *(const float4*)(in + (size_t)i * 4);
    __nv_bfloat16 h[4], l[4];
    bf16_split(v.x, h[0], l[0]);
    bf16_split(v.y, h[1], l[1]);
    bf16_split(v.z, h[2], l[2]);
    bf16_split(v.w, h[3], l[3]);
    *(uint2*)(oh + (size_t)i * 4) = *(uint2*)h;
    *(uint2*)(ol + (size_t)i * 4) = *(uint2*)l;
}

__global__ void transpose_split_kernel(const float* __restrict__ in,
                                       __nv_bfloat16* __restrict__ oh,
                                       __nv_bfloat16* __restrict__ ol,
                                       int R, int Ccols) {
    __shared__ float tile[32][33];
    int bx = blockIdx.x * 32, by = blockIdx.y * 32;
    int x = bx + threadIdx.x;
    #pragma unroll
    for (int i = 0; i < 32; i += 8)
        tile[threadIdx.y + i][threadIdx.x] = in[(size_t)(by + threadIdx.y + i) * Ccols + x];
    __syncthreads();
    int ox = by + threadIdx.x;
    #pragma unroll
    for (int i = 0; i < 32; i += 8) {
        const float v = tile[threadIdx.x][threadIdx.y + i];
        __nv_bfloat16 h, l;
        bf16_split(v, h, l);
        const size_t o = (size_t)(bx + threadIdx.y + i) * R + ox;
        oh[o] = h;
        ol[o] = l;
    }
}

// ================= mma.sync / async helpers =================
__device__ __forceinline__ uint32_t smem_u32(const void* p) {
    uint32_t a;
    asm("{ .reg .u64 t; cvta.to.shared.u64 t, %1; cvt.u32.u64 %0, t; }" : "=r"(a) : "l"(p));
    return a;
}
__device__ __forceinline__ void cp16(uint32_t dst, const void* src) {
    asm volatile("cp.async.cg.shared.global [%0], [%1], 16;" :: "r"(dst), "l"(src));
}
#define CP_COMMIT() asm volatile("cp.async.commit_group;" ::: "memory")
#define CP_WAIT1()  asm volatile("cp.async.wait_group 1;" ::: "memory")

__device__ __forceinline__ void ldsm4(uint32_t* r, uint32_t addr) {
    asm volatile("ldmatrix.sync.aligned.m8n8.x4.shared.b16 {%0,%1,%2,%3}, [%4];"
                 : "=r"(r[0]), "=r"(r[1]), "=r"(r[2]), "=r"(r[3]) : "r"(addr));
}
__device__ __forceinline__ void mma_bf16(float* d, const uint32_t* a, const uint32_t* b) {
    asm volatile(
        "mma.sync.aligned.m16n8k16.row.col.f32.bf16.bf16.f32 "
        "{%0,%1,%2,%3}, {%4,%5,%6,%7}, {%8,%9}, {%0,%1,%2,%3};\n"
        : "+f"(d[0]), "+f"(d[1]), "+f"(d[2]), "+f"(d[3])
        : "r"(a[0]), "r"(a[1]), "r"(a[2]), "r"(a[3]), "r"(b[0]), "r"(b[1]));
}
__device__ __forceinline__ uint32_t pack_bf2(float x0, float x1) {
    __nv_bfloat162 v = __floats2bfloat162_rn(x0, x1);
    return *(uint32_t*)&v;
}
__device__ __forceinline__ float exp2p(float y) {
    y = fmaxf(y, -120.f);
    int ki = __float2int_rn(y);
    float f = y - (float)ki;
    float p = 0.0013333558f;
    p = fmaf(p, f, 0.0096181291f);
    p = fmaf(p, f, 0.0555041087f);
    p = fmaf(p, f, 0.2402265070f);
    p = fmaf(p, f, 0.6931471806f);
    p = fmaf(p, f, 1.0f);
    return p * __int_as_float((ki + 127) << 23);
}

// ---------------- bf16 3-term GEMM (unchanged from R6/R7) ----------------
#define BPAD 40
#define G_ARRB (128 * BPAD * 2)
#define G_BUFB (4 * G_ARRB)
#define G_SMEM (2 * G_BUFB)

__global__ void __launch_bounds__(256, 2) mma_gemm_bf16(
    const __nv_bfloat16* __restrict__ Ah, const __nv_bfloat16* __restrict__ Al,
    const __nv_bfloat16* __restrict__ Bh, const __nv_bfloat16* __restrict__ Bl,
    const float* __restrict__ bias, float* __restrict__ C, int N, int K)
{
    extern __shared__ char smem[];
    const uint32_t smbase = smem_u32(smem);

    const int t    = threadIdx.x;
    const int lane = t & 31;
    const int wid  = t >> 5;
    const int wr   = wid & 3;
    const int wc   = wid >> 2;
    const int qid  = lane >> 2;
    const int tid4 = lane & 3;

    const size_t m0 = (size_t)blockIdx.y * 128;
    const size_t n0 = (size_t)blockIdx.x * 128;

    const int g   = t >> 6;
    const int sub = t & 63;
    const __nv_bfloat16* gbase =
        (g == 0) ? Ah + m0 * K : (g == 1) ? Al + m0 * K :
        (g == 2) ? Bh + n0 * K : Bl + n0 * K;
    const uint32_t sm_arr = smbase + g * G_ARRB;

    const uint32_t a_off = (uint32_t)(((wr * 32 + (lane & 15)) * BPAD + ((lane >> 4) << 3)) * 2);
    const uint32_t b_off = (uint32_t)(((wc * 64 + (lane & 7) + ((lane & 16) >> 1)) * BPAD + (lane & 8)) * 2);

    float acc[2][8][4];
    #pragma unroll
    for (int mf = 0; mf < 2; ++mf)
        #pragma unroll
        for (int nf = 0; nf < 8; ++nf)
            #pragma unroll
            for (int r = 0; r < 4; ++r) acc[mf][nf][r] = 0.f;

    const int nchunks = K / 32;

    #pragma unroll
    for (int i = 0; i < 8; ++i) {
        const int idx = sub + i * 64;
        const int row = idx >> 2, col = (idx & 3) * 8;
        cp16(sm_arr + (uint32_t)((row * BPAD + col) * 2), gbase + (size_t)row * K + col);
    }
    CP_COMMIT();

    for (int c = 0; c < nchunks; ++c) {
        const int buf = c & 1;
        if (c + 1 < nchunks) {
            const uint32_t dst = sm_arr + (uint32_t)((c + 1) & 1) * G_BUFB;
            const __nv_bfloat16* src = gbase + (c + 1) * 32;
            #pragma unroll
            for (int i = 0; i < 8; ++i) {
                const int idx = sub + i * 64;
                const int row = idx >> 2, col = (idx & 3) * 8;
                cp16(dst + (uint32_t)((row * BPAD + col) * 2), src + (size_t)row * K + col);
            }
        }
        CP_COMMIT();
        CP_WAIT1();
        __syncthreads();

        const uint32_t sb = smbase + (uint32_t)buf * G_BUFB;
        #pragma unroll
        for (int ks = 0; ks < 2; ++ks) {
            const uint32_t kb = (uint32_t)(ks * 32);
            uint32_t ah[2][4], al[2][4];
            #pragma unroll
            for (int mf = 0; mf < 2; ++mf) {
                const uint32_t ro = (uint32_t)(mf * 16 * BPAD * 2);
                ldsm4(ah[mf], sb + 0 * G_ARRB + a_off + ro + kb);
                ldsm4(al[mf], sb + 1 * G_ARRB + a_off + ro + kb);
            }
            uint32_t bh[8][2], bl[8][2];
            #pragma unroll
            for (int p = 0; p < 4; ++p) {
                const uint32_t ro = (uint32_t)(p * 16 * BPAD * 2);
                uint32_t r[4];
                ldsm4(r, sb + 2 * G_ARRB + b_off + ro + kb);
                bh[2 * p][0] = r[0]; bh[2 * p][1] = r[1];
                bh[2 * p + 1][0] = r[2]; bh[2 * p + 1][1] = r[3];
                ldsm4(r, sb + 3 * G_ARRB + b_off + ro + kb);
                bl[2 * p][0] = r[0]; bl[2 * p][1] = r[1];
                bl[2 * p + 1][0] = r[2]; bl[2 * p + 1][1] = r[3];
            }
            #pragma unroll
            for (int nf = 0; nf < 8; ++nf)
                #pragma unroll
                for (int mf = 0; mf < 2; ++mf) {
                    mma_bf16(acc[mf][nf], ah[mf], bh[nf]);
                    mma_bf16(acc[mf][nf], ah[mf], bl[nf]);
                    mma_bf16(acc[mf][nf], al[mf], bh[nf]);
                }
        }
        __syncthreads();
    }

    const int trow = qid;
    const int tcol = tid4 * 2;
    #pragma unroll
    for (int mf = 0; mf < 2; ++mf) {
        const size_t m = m0 + wr * 32 + mf * 16 + trow;
        #pragma unroll
        for (int nf = 0; nf < 8; ++nf) {
            const int ncol = (int)n0 + wc * 64 + nf * 8 + tcol;
            float2 v0 = make_float2(acc[mf][nf][0], acc[mf][nf][1]);
            float2 v1 = make_float2(acc[mf][nf][2], acc[mf][nf][3]);
            if (bias) {
                const float bx = bias[ncol], by = bias[ncol + 1];
                v0.x += bx; v0.y += by;
                v1.x += bx; v1.y += by;
            }
            *(float2*)(C + m * N + ncol)       = v0;
            *(float2*)(C + (m + 8) * N + ncol) = v1;
        }
    }
}

// ---------------- RoPE -> bf16 hi/lo (table-driven, merged-input) ----------------
__global__ void rope_q_kernel(const float* __restrict__ in,
                              __nv_bfloat16* __restrict__ oh,
                              __nv_bfloat16* __restrict__ ol) {
    int idx = blockIdx.x * blockDim.x + threadIdx.x;
    int p = idx & 31;
    int h = (idx >> 5) & 31;
    int s = (idx >> 10) & 2047;
    int b = idx >> 21;
    const float2 cs = g_cs[s * 32 + p];
    const float2 x = *(const float2*)(in + ((size_t)(b * SEQ + s)) * NQKV + h * HD + 2 * p);
    float rx = x.x * cs.x - x.y * cs.y;
    float ry = x.x * cs.y + x.y * cs.x;
    __nv_bfloat16 hx, lx, hy, ly;
    bf16_split(rx, hx, lx);
    bf16_split(ry, hy, ly);
    const size_t o = (((size_t)(b * NH + h)) * SEQ + s) * HD + 2 * p;
    __nv_bfloat162 vh; vh.x = hx; vh.y = hy;
    __nv_bfloat162 vl; vl.x = lx; vl.y = ly;
    *(__nv_bfloat162*)(oh + o) = vh;
    *(__nv_bfloat162*)(ol + o) = vl;
}
__global__ void rope_k_kernel(const float* __restrict__ in,
                              __nv_bfloat16* __restrict__ oh,
                              __nv_bfloat16* __restrict__ ol) {
    int idx = blockIdx.x * blockDim.x + threadIdx.x;
    int p = idx & 31;
    int h = (idx >> 5) & 7;
    int s = (idx >> 8) & 2047;
    int b = idx >> 19;
    const float2 cs = g_cs[s * 32 + p];
    const float2 x = *(const float2*)(in + ((size_t)(b * SEQ + s)) * NQKV + DIM + h * HD + 2 * p);
    float rx = x.x * cs.x - x.y * cs.y;
    float ry = x.x * cs.y + x.y * cs.x;
    __nv_bfloat16 hx, lx, hy, ly;
    bf16_split(rx, hx, lx);
    bf16_split(ry, hy, ly);
    const size_t o = (((size_t)(b * NKV + h)) * SEQ + s) * HD + 2 * p;
    __nv_bfloat162 vh; vh.x = hx; vh.y = hy;
    __nv_bfloat162 vl; vl.x = lx; vl.y = ly;
    *(__nv_bfloat162*)(oh + o) = vh;
    *(__nv_bfloat162*)(ol + o) = vl;
}

// V: qkvlin [b,s, 2560 + kv*64 + d] -> transposed bf16 hi/lo [b,kv,d,s]
__global__ void transpose_v_kernel(const float* __restrict__ in,
                                   __nv_bfloat16* __restrict__ oh,
                                   __nv_bfloat16* __restrict__ ol) {
    __shared__ float tile[32][33];
    const int s0 = blockIdx.x * 32;
    const int d0 = blockIdx.y * 32;
    const int bk = blockIdx.z;
    const int b  = bk >> 3, kv = bk & 7;
    const int tx = threadIdx.x, ty = threadIdx.y;
    const float* src = in + ((size_t)(b * SEQ)) * NQKV + (DIM + KVDIM) + kv * HD;
    #pragma unroll
    for (int i = 0; i < 32; i += 8)
        tile[ty + i][tx] = src[(size_t)(s0 + ty + i) * NQKV + d0 + tx];
    __syncthreads();
    const size_t obase = ((size_t)bk * HD + d0) * SEQ + s0;
    #pragma unroll
    for (int i = 0; i < 32; i += 8) {
        const float v = tile[tx][ty + i];
        __nv_bfloat16 h, l;
        bf16_split(v, h, l);
        oh[obase + (size_t)(ty + i) * SEQ + tx] = h;
        ol[obase + (size_t)(ty + i) * SEQ + tx] = l;
    }
}

// ---------------- flash attention v3: Q resident in smem, 2 CTAs/SM ----------------
// Q tile 128/CTA, KV tiles 64. 8 warps; QK & PV 3-term bf16. Epilogue writes
// pre-split ah/al for the O-projection.
#define FQ 128
#define FK 64
#define SP 72
#define F_QARR (FQ * SP * 2)           /* 18432 B (Qh; Ql at +F_QARR) */
#define QOFF   (2 * F_QARR)            /* 36864 */
#define F_ARR  (FK * SP * 2)           /* 9216 B per K/V array */
#define F_BUF  (4 * F_ARR)             /* Kh Kl Vth Vtl = 36864 */
#define F_SMEM (QOFF + 2 * F_BUF)      /* 110592 B -> 2 CTAs/SM */

__global__ void __launch_bounds__(256, 2) flash_mma_kernel(
    const __nv_bfloat16* __restrict__ Qh, const __nv_bfloat16* __restrict__ Ql,
    const __nv_bfloat16* __restrict__ Kh, const __nv_bfloat16* __restrict__ Kl,
    const __nv_bfloat16* __restrict__ Vth, const __nv_bfloat16* __restrict__ Vtl,
    __nv_bfloat16* __restrict__ Oh, __nv_bfloat16* __restrict__ Ol)
{
    extern __shared__ char smem[];
    const uint32_t smbase = smem_u32(smem);

    const int qt  = (SEQ / FQ - 1) - blockIdx.x;
    const int h   = blockIdx.y;
    const int b   = blockIdx.z;
    const int kvh = h >> 2;
    const int t    = threadIdx.x;
    const int lane = t & 31;
    const int w    = t >> 5;
    const int qid  = lane >> 2;
    const int tid4 = lane & 3;
    const int q0   = qt * FQ;
    const int wrow = w * 16;

    const __nv_bfloat16* Qhb = Qh + (((size_t)(b * NH + h)) * SEQ + q0) * HD;
    const __nv_bfloat16* Qlb = Ql + (((size_t)(b * NH + h)) * SEQ + q0) * HD;
    const __nv_bfloat16* Khb = Kh + ((size_t)(b * NKV + kvh)) * SEQ * HD;
    const __nv_bfloat16* Klb = Kl + ((size_t)(b * NKV + kvh)) * SEQ * HD;
    const __nv_bfloat16* Vhb = Vth + ((size_t)(b * NKV + kvh)) * HD * SEQ;
    const __nv_bfloat16* Vlb = Vtl + ((size_t)(b * NKV + kvh)) * HD * SEQ;

    // ---- stage Q permanently in smem (hi at 0, lo at F_QARR) ----
    #pragma unroll
    for (int i = 0; i < 4; ++i) {
        const int idx = t + i * 256;
        const int r = idx >> 3, c = (idx & 7) * 8;
        *(uint4*)(smem + (r * SP + c) * 2)          = *(const uint4*)(Qhb + (size_t)r * HD + c);
        *(uint4*)(smem + F_QARR + (r * SP + c) * 2) = *(const uint4*)(Qlb + (size_t)r * HD + c);
    }
    __syncthreads();

    const uint32_t a_off = (uint32_t)(((wrow + (lane & 15)) * SP + ((lane >> 4) << 3)) * 2);
    const uint32_t b_off = (uint32_t)((((lane & 7) + ((lane & 16) >> 1)) * SP + (lane & 8)) * 2);

    // ---- cp.async: 64 threads per array (0=Kh 1=Kl 2=Vth 3=Vtl) ----
    const int ga  = t >> 6;
    const int sub = t & 63;
    const __nv_bfloat16* gsrc = (ga == 0) ? Khb : (ga == 1) ? Klb : (ga == 2) ? Vhb : Vlb;
    const bool isK = (ga < 2);

    float oacc[8][4];
    #pragma unroll
    for (int nf = 0; nf < 8; ++nf)
        #pragma unroll
        for (int j = 0; j < 4; ++j) oacc[nf][j] = 0.f;
    float m[2] = {-1e30f, -1e30f};
    float l[2] = {0.f, 0.f};

    const int row_a = q0 + wrow + qid;
    const int row_b = row_a + 8;
    const float SC = 0.125f * 1.4426950408889634f;

    const int ntiles = (q0 + FQ) / FK;

    #pragma unroll
    for (int i = 0; i < 8; ++i) {
        const int idx = sub + i * 64;
        const int row = idx >> 3, col = (idx & 7) * 8;
        const __nv_bfloat16* s = isK ? (gsrc + (size_t)row * HD + col)
                                     : (gsrc + (size_t)row * SEQ + col);
        cp16(smbase + QOFF + (uint32_t)(ga * F_ARR) + (uint32_t)((row * SP + col) * 2), s);
    }
    CP_COMMIT();

    for (int kt = 0; kt < ntiles; ++kt) {
        if (kt + 1 < ntiles) {
            const uint32_t dst = smbase + QOFF + (uint32_t)(((kt + 1) & 1) * F_BUF) + (uint32_t)(ga * F_ARR);
            #pragma unroll
            for (int i = 0; i < 8; ++i) {
                const int idx = sub + i * 64;
                const int row = idx >> 3, col = (idx & 7) * 8;
                const __nv_bfloat16* s = isK
                    ? (gsrc + (size_t)((kt + 1) * FK + row) * HD + col)
                    : (gsrc + (size_t)row * SEQ + (kt + 1) * FK + col);
                cp16(dst + (uint32_t)((row * SP + col) * 2), s);
            }
        }
        CP_COMMIT();
        CP_WAIT1();
        __syncthreads();

        const uint32_t sb = smbase + QOFF + (uint32_t)((kt & 1) * F_BUF);

        // ---- scores (Q frags reloaded from resident smem per g2) ----
        float sacc[8][4];
        #pragma unroll
        for (int nf = 0; nf < 8; ++nf)
            #pragma unroll
            for (int j = 0; j < 4; ++j) sacc[nf][j] = 0.f;

        #pragma unroll
        for (int g2 = 0; g2 < 4; ++g2) {
            const uint32_t kb = (uint32_t)(g2 * 32);
            uint32_t qh4[4], ql4[4];
            ldsm4(qh4, smbase + a_off + kb);
            ldsm4(ql4, smbase + F_QARR + a_off + kb);
            uint32_t bh[8][2], bl[8][2];
            #pragma unroll
            for (int p = 0; p < 4; ++p) {
                const uint32_t ro = (uint32_t)(p * 16 * SP * 2);
                uint32_t r[4];
                ldsm4(r, sb + 0 * F_ARR + b_off + ro + kb);
                bh[2 * p][0] = r[0]; bh[2 * p][1] = r[1];
                bh[2 * p + 1][0] = r[2]; bh[2 * p + 1][1] = r[3];
                ldsm4(r, sb + 1 * F_ARR + b_off + ro + kb);
                bl[2 * p][0] = r[0]; bl[2 * p][1] = r[1];
                bl[2 * p + 1][0] = r[2]; bl[2 * p + 1][1] = r[3];
            }
            #pragma unroll
            for (int nf = 0; nf < 8; ++nf) {
                mma_bf16(sacc[nf], qh4, bh[nf]);
                mma_bf16(sacc[nf], ql4, bh[nf]);
                mma_bf16(sacc[nf], qh4, bl[nf]);
            }
        }

        // ---- mask + scale (log2 domain) + row max ----
        const bool need_mask = (kt * FK + FK - 1) > row_a;
        float tmax[2] = {-1e30f, -1e30f};
        #pragma unroll
        for (int nf = 0; nf < 8; ++nf) {
            const int colbase = kt * FK + nf * 8 + tid4 * 2;
            #pragma unroll
            for (int j = 0; j < 4; ++j) {
                const int col = colbase + (j & 1);
                const int row = (j < 2) ? row_a : row_b;
                float v = sacc[nf][j] * SC;
                if (need_mask && col > row) v = -1e30f;
                sacc[nf][j] = v;
                tmax[j >> 1] = fmaxf(tmax[j >> 1], v);
            }
        }

        float corr[2];
        #pragma unroll
        for (int hh = 0; hh < 2; ++hh) {
            tmax[hh] = fmaxf(tmax[hh], __shfl_xor_sync(0xffffffffu, tmax[hh], 1));
            tmax[hh] = fmaxf(tmax[hh], __shfl_xor_sync(0xffffffffu, tmax[hh], 2));
            const float mnew = fmaxf(m[hh], tmax[hh]);
            corr[hh] = exp2p(m[hh] - mnew);
            m[hh] = mnew;
            l[hh] *= corr[hh];
        }
        #pragma unroll
        for (int nf = 0; nf < 8; ++nf) {
            oacc[nf][0] *= corr[0]; oacc[nf][1] *= corr[0];
            oacc[nf][2] *= corr[1]; oacc[nf][3] *= corr[1];
        }
        float rsum[2] = {0.f, 0.f};
        #pragma unroll
        for (int nf = 0; nf < 8; ++nf) {
            #pragma unroll
            for (int j = 0; j < 4; ++j) {
                const float p = exp2p(sacc[nf][j] - m[j >> 1]);
                sacc[nf][j] = p;
                rsum[j >> 1] += p;
            }
        }
        #pragma unroll
        for (int hh = 0; hh < 2; ++hh) {
            rsum[hh] += __shfl_xor_sync(0xffffffffu, rsum[hh], 1);
            rsum[hh] += __shfl_xor_sync(0xffffffffu, rsum[hh], 2);
            l[hh] += rsum[hh];
        }

        // ---- build P a-fragments in registers (hi/lo) ----
        uint32_t pfh[4][4], pfl[4][4];
        #pragma unroll
        for (int g2 = 0; g2 < 4; ++g2) {
            const float* s0 = sacc[2 * g2];
            const float* s1 = sacc[2 * g2 + 1];
            float h00 = __bfloat162float(__float2bfloat16(s0[0]));
            float h01 = __bfloat162float(__float2bfloat16(s0[1]));
            float h02 = __bfloat162float(__float2bfloat16(s0[2]));
            float h03 = __bfloat162float(__float2bfloat16(s0[3]));
            float h10 = __bfloat162float(__float2bfloat16(s1[0]));
            float h11 = __bfloat162float(__float2bfloat16(s1[1]));
            float h12 = __bfloat162float(__float2bfloat16(s1[2]));
            float h13 = __bfloat162float(__float2bfloat16(s1[3]));
            pfh[g2][0] = pack_bf2(h00, h01);
            pfh[g2][1] = pack_bf2(h02, h03);
            pfh[g2][2] = pack_bf2(h10, h11);
            pfh[g2][3] = pack_bf2(h12, h13);
            pfl[g2][0] = pack_bf2(s0[0] - h00, s0[1] - h01);
            pfl[g2][1] = pack_bf2(s0[2] - h02, s0[3] - h03);
            pfl[g2][2] = pack_bf2(s1[0] - h10, s1[1] - h11);
            pfl[g2][3] = pack_bf2(s1[2] - h12, s1[3] - h13);
        }

        // ---- O += P V ----
        #pragma unroll
        for (int g2 = 0; g2 < 4; ++g2) {
            const uint32_t kb = (uint32_t)(g2 * 32);
            uint32_t vh[8][2], vl[8][2];
            #pragma unroll
            for (int p = 0; p < 4; ++p) {
                const uint32_t ro = (uint32_t)(p * 16 * SP * 2);
                uint32_t r[4];
                ldsm4(r, sb + 2 * F_ARR + b_off + ro + kb);
                vh[2 * p][0] = r[0]; vh[2 * p][1] = r[1];
                vh[2 * p + 1][0] = r[2]; vh[2 * p + 1][1] = r[3];
                ldsm4(r, sb + 3 * F_ARR + b_off + ro + kb);
                vl[2 * p][0] = r[0]; vl[2 * p][1] = r[1];
                vl[2 * p + 1][0] = r[2]; vl[2 * p + 1][1] = r[3];
            }
            #pragma unroll
            for (int nf = 0; nf < 8; ++nf) {
                mma_bf16(oacc[nf], pfh[g2], vh[nf]);
                mma_bf16(oacc[nf], pfl[g2], vh[nf]);
                mma_bf16(oacc[nf], pfh[g2], vl[nf]);
            }
        }
        __syncthreads();
    }

    // ---- epilogue: normalized output, pre-split bf16 hi/lo for O-projection ----
    const float inv_a = 1.0f / l[0];
    const float inv_b = 1.0f / l[1];
    const size_t rA = ((size_t)(b * SEQ) + row_a) * DIM + h * HD;
    const size_t rB = rA + 8 * DIM;
    #pragma unroll
    for (int nf = 0; nf < 8; ++nf) {
        const int col = nf * 8 + tid4 * 2;
        float f0 = oacc[nf][0] * inv_a, f1 = oacc[nf][1] * inv_a;
        float f2 = oacc[nf][2] * inv_b, f3 = oacc[nf][3] * inv_b;
        __nv_bfloat16 h0, l0, h1, l1, h2, l2, h3, l3;
        bf16_split(f0, h0, l0);
        bf16_split(f1, h1, l1);
        bf16_split(f2, h2, l2);
        bf16_split(f3, h3, l3);
        __nv_bfloat162 vhA; vhA.x = h0; vhA.y = h1;
        __nv_bfloat162 vlA; vlA.x = l0; vlA.y = l1;
        __nv_bfloat162 vhB; vhB.x = h2; vhB.y = h3;
        __nv_bfloat162 vlB; vlB.x = l2; vlB.y = l3;
        *(__nv_bfloat162*)(Oh + rA + col) = vhA;
        *(__nv_bfloat162*)(Ol + rA + col) = vlA;
        *(__nv_bfloat162*)(Oh + rB + col) = vhB;
        *(__nv_bfloat162*)(Ol + rB + col) = vlB;
    }
}

// ---------------- host launcher ----------------
extern "C" void kernel_launch(void* const* d_in, const int* in_sizes, int n_in,
                              void* d_out, int out_size) {
    (void)in_sizes; (void)n_in; (void)out_size;
    const float* x  = (const float*)d_in[0];
    const float* Wq = (const float*)d_in[1];
    const float* Wk = (const float*)d_in[2];
    const float* Wv = (const float*)d_in[3];
    const float* bv = (const float*)d_in[4];
    const float* Wo = (const float*)d_in[5];
    const float* bo = (const float*)d_in[6];
    float* out = (float*)d_out;

    float *qkvlin, *biasqkv;
    __nv_bfloat16 *ah, *al, *bh, *bl, *qh, *ql, *kh, *kl, *vth, *vtl;
    cudaGetSymbolAddress((void**)&qkvlin,  g_qkvlin);
    cudaGetSymbolAddress((void**)&biasqkv, g_biasqkv);
    cudaGetSymbolAddress((void**)&ah,  g_ah);
    cudaGetSymbolAddress((void**)&al,  g_al);
    cudaGetSymbolAddress((void**)&bh,  g_bh);
    cudaGetSymbolAddress((void**)&bl,  g_bl);
    cudaGetSymbolAddress((void**)&qh,  g_qh);
    cudaGetSymbolAddress((void**)&ql,  g_ql);
    cudaGetSymbolAddress((void**)&kh,  g_kh);
    cudaGetSymbolAddress((void**)&kl,  g_kl);
    cudaGetSymbolAddress((void**)&vth, g_vth);
    cudaGetSymbolAddress((void**)&vtl, g_vtl);

    cudaFuncSetAttribute(mma_gemm_bf16, cudaFuncAttributeMaxDynamicSharedMemorySize, G_SMEM);
    cudaFuncSetAttribute(flash_mma_kernel, cudaFuncAttributeMaxDynamicSharedMemorySize, F_SMEM);

    theta_kernel<<<1, 32>>>();
    sincos_kernel<<<(SEQ * 32) / 256, 256>>>();
    biasqkv_kernel<<<NQKV / 256, 256>>>(bv);

    // split activations once
    split_kernel<<<(MROWS * DIM) / 1024, 256>>>(x, ah, al);

    // merged QKV projection (N = 3072)
    transpose_split_kernel<<<dim3(DIM / 32, DIM / 32), dim3(32, 8)>>>(Wq, bh, bl, DIM, DIM);
    transpose_split_kernel<<<dim3(KVDIM / 32, DIM / 32), dim3(32, 8)>>>(
        Wk, bh + (size_t)DIM * DIM, bl + (size_t)DIM * DIM, DIM, KVDIM);
    transpose_split_kernel<<<dim3(KVDIM / 32, DIM / 32), dim3(32, 8)>>>(
        Wv, bh + (size_t)(DIM + KVDIM) * DIM, bl + (size_t)(DIM + KVDIM) * DIM, DIM, KVDIM);
    mma_gemm_bf16<<<dim3(NQKV / 128, MROWS / 128), 256, G_SMEM>>>(
        ah, al, bh, bl, biasqkv, qkvlin, NQKV, DIM);

    rope_q_kernel<<<(BATCH * SEQ * NH * 32) / 256, 256>>>(qkvlin, qh, ql);
    rope_k_kernel<<<(BATCH * SEQ * NKV * 32) / 256, 256>>>(qkvlin, kh, kl);
    transpose_v_kernel<<<dim3(SEQ / 32, HD / 32, BATCH * NKV), dim3(32, 8)>>>(qkvlin, vth, vtl);

    // flash writes pre-split ah/al for the O projection
    flash_mma_kernel<<<dim3(SEQ / FQ, NH, BATCH), 256, F_SMEM>>>(
        qh, ql, kh, kl, vth, vtl, ah, al);

    transpose_split_kernel<<<dim3(DIM / 32, DIM / 32), dim3(32, 8)>>>(Wo, bh, bl, DIM, DIM);
    mma_gemm_bf16<<<dim3(DIM / 128, MROWS / 128), 256, G_SMEM>>>(ah, al, bh, bl, bo, out, DIM, DIM);
}

// round 9
// speedup vs baseline: 3.1242x; 1.1118x over previous
#include <cuda_runtime.h>
#include <cuda_bf16.h>
#include <cuda_fp16.h>
#include <math.h>
#include <stdint.h>

#define DIM 2048
#define NH 32
#define NKV 8
#define HD 64
#define BATCH 2
#define SEQ 2048
#define MROWS (BATCH*SEQ)   /* 4096 */
#define KVDIM (NKV*HD)      /* 512 */
#define NQKV (DIM + 2*KVDIM) /* 3072 */

// ---------------- scratch (static device allocations; no cudaMalloc) ----------------
__device__ float g_qkvlin[(size_t)MROWS * NQKV];   // merged q|k|v projection output
__device__ float g_biasqkv[NQKV];
__device__ __align__(16) __nv_bfloat16 g_ah[(size_t)MROWS * DIM];
__device__ __align__(16) __nv_bfloat16 g_al[(size_t)MROWS * DIM];
__device__ __align__(16) __nv_bfloat16 g_bh[(size_t)NQKV * DIM];
__device__ __align__(16) __nv_bfloat16 g_bl[(size_t)NQKV * DIM];
// flash operands: Q fp16 hi/lo; K,V fp16 hi only
__device__ __align__(16) __half g_qh[(size_t)BATCH * NH * SEQ * HD];
__device__ __align__(16) __half g_ql[(size_t)BATCH * NH * SEQ * HD];
__device__ __align__(16) __half g_kh[(size_t)BATCH * NKV * SEQ * HD];
__device__ __align__(16) __half g_vth[(size_t)BATCH * NKV * HD * SEQ];  // [b,kv,d,s]
__device__ double g_theta[HD / 2];
__device__ float2 g_cs[(size_t)SEQ * (HD / 2)];    // cos/sin table

// ---------------- RoPE tables ----------------
__global__ void theta_kernel() {
    int p = threadIdx.x;
    if (p < HD / 2) g_theta[p] = pow(10000.0, -(double)p / 32.0);
}
__global__ void sincos_kernel() {
    int idx = blockIdx.x * blockDim.x + threadIdx.x;   // SEQ*32
    int s = idx >> 5, p = idx & 31;
    float ang = (float)((double)s * g_theta[p]);
    float sv, cv;
    sincosf(ang, &sv, &cv);
    g_cs[idx] = make_float2(cv, sv);
}
__global__ void biasqkv_kernel(const float* __restrict__ bv) {
    int i = blockIdx.x * blockDim.x + threadIdx.x;
    g_biasqkv[i] = (i < DIM + KVDIM) ? 0.f : bv[i - (DIM + KVDIM)];
}

// ---------------- split helpers ----------------
__device__ __forceinline__ void bf16_split(float x, __nv_bfloat16& h, __nv_bfloat16& l) {
    h = __float2bfloat16(x);
    l = __float2bfloat16(x - __bfloat162float(h));
}
__device__ __forceinline__ void fp16_split(float x, __half& h, __half& l) {
    h = __float2half_rn(x);
    l = __float2half_rn(x - __half2float(h));
}

__global__ void split_kernel(const float* __restrict__ in,
                             __nv_bfloat16* __restrict__ oh,
                             __nv_bfloat16* __restrict__ ol) {
    const int i = blockIdx.x * blockDim.x + threadIdx.x;
    const float4 v = *(const float4*)(in + (size_t)i * 4);
    __nv_bfloat16 h[4], l[4];
    bf16_split(v.x, h[0], l[0]);
    bf16_split(v.y, h[1], l[1]);
    bf16_split(v.z, h[2], l[2]);
    bf16_split(v.w, h[3], l[3]);
    *(uint2*)(oh + (size_t)i * 4) = *(uint2*)h;
    *(uint2*)(ol + (size_t)i * 4) = *(uint2*)l;
}

__global__ void transpose_split_kernel(const float* __restrict__ in,
                                       __nv_bfloat16* __restrict__ oh,
                                       __nv_bfloat16* __restrict__ ol,
                                       int R, int Ccols) {
    __shared__ float tile[32][33];
    int bx = blockIdx.x * 32, by = blockIdx.y * 32;
    int x = bx + threadIdx.x;
    #pragma unroll
    for (int i = 0; i < 32; i += 8)
        tile[threadIdx.y + i][threadIdx.x] = in[(size_t)(by + threadIdx.y + i) * Ccols + x];
    __syncthreads();
    int ox = by + threadIdx.x;
    #pragma unroll
    for (int i = 0; i < 32; i += 8) {
        const float v = tile[threadIdx.x][threadIdx.y + i];
        __nv_bfloat16 h, l;
        bf16_split(v, h, l);
        const size_t o = (size_t)(bx + threadIdx.y + i) * R + ox;
        oh[o] = h;
        ol[o] = l;
    }
}

// ================= mma.sync / async helpers =================
__device__ __forceinline__ uint32_t smem_u32(const void* p) {
    uint32_t a;
    asm("{ .reg .u64 t; cvta.to.shared.u64 t, %1; cvt.u32.u64 %0, t; }" : "=r"(a) : "l"(p));
    return a;
}
__device__ __forceinline__ void cp16(uint32_t dst, const void* src) {
    asm volatile("cp.async.cg.shared.global [%0], [%1], 16;" :: "r"(dst), "l"(src));
}
#define CP_COMMIT() asm volatile("cp.async.commit_group;" ::: "memory")
#define CP_WAIT1()  asm volatile("cp.async.wait_group 1;" ::: "memory")

__device__ __forceinline__ void ldsm4(uint32_t* r, uint32_t addr) {
    asm volatile("ldmatrix.sync.aligned.m8n8.x4.shared.b16 {%0,%1,%2,%3}, [%4];"
                 : "=r"(r[0]), "=r"(r[1]), "=r"(r[2]), "=r"(r[3]) : "r"(addr));
}
__device__ __forceinline__ void mma_bf16(float* d, const uint32_t* a, const uint32_t* b) {
    asm volatile(
        "mma.sync.aligned.m16n8k16.row.col.f32.bf16.bf16.f32 "
        "{%0,%1,%2,%3}, {%4,%5,%6,%7}, {%8,%9}, {%0,%1,%2,%3};\n"
        : "+f"(d[0]), "+f"(d[1]), "+f"(d[2]), "+f"(d[3])
        : "r"(a[0]), "r"(a[1]), "r"(a[2]), "r"(a[3]), "r"(b[0]), "r"(b[1]));
}
__device__ __forceinline__ void mma_fp16(float* d, const uint32_t* a, const uint32_t* b) {
    asm volatile(
        "mma.sync.aligned.m16n8k16.row.col.f32.f16.f16.f32 "
        "{%0,%1,%2,%3}, {%4,%5,%6,%7}, {%8,%9}, {%0,%1,%2,%3};\n"
        : "+f"(d[0]), "+f"(d[1]), "+f"(d[2]), "+f"(d[3])
        : "r"(a[0]), "r"(a[1]), "r"(a[2]), "r"(a[3]), "r"(b[0]), "r"(b[1]));
}
__device__ __forceinline__ uint32_t pack_hf2(float x0, float x1) {
    __half2 v = __floats2half2_rn(x0, x1);
    return *(uint32_t*)&v;
}
__device__ __forceinline__ float exp2p(float y) {
    y = fmaxf(y, -120.f);
    int ki = __float2int_rn(y);
    float f = y - (float)ki;
    float p = 0.0013333558f;
    p = fmaf(p, f, 0.0096181291f);
    p = fmaf(p, f, 0.0555041087f);
    p = fmaf(p, f, 0.2402265070f);
    p = fmaf(p, f, 0.6931471806f);
    p = fmaf(p, f, 1.0f);
    return p * __int_as_float((ki + 127) << 23);
}

// ---------------- bf16 3-term GEMM (unchanged from R6-R8) ----------------
#define BPAD 40
#define G_ARRB (128 * BPAD * 2)
#define G_BUFB (4 * G_ARRB)
#define G_SMEM (2 * G_BUFB)

__global__ void __launch_bounds__(256, 2) mma_gemm_bf16(
    const __nv_bfloat16* __restrict__ Ah, const __nv_bfloat16* __restrict__ Al,
    const __nv_bfloat16* __restrict__ Bh, const __nv_bfloat16* __restrict__ Bl,
    const float* __restrict__ bias, float* __restrict__ C, int N, int K)
{
    extern __shared__ char smem[];
    const uint32_t smbase = smem_u32(smem);

    const int t    = threadIdx.x;
    const int lane = t & 31;
    const int wid  = t >> 5;
    const int wr   = wid & 3;
    const int wc   = wid >> 2;
    const int qid  = lane >> 2;
    const int tid4 = lane & 3;

    const size_t m0 = (size_t)blockIdx.y * 128;
    const size_t n0 = (size_t)blockIdx.x * 128;

    const int g   = t >> 6;
    const int sub = t & 63;
    const __nv_bfloat16* gbase =
        (g == 0) ? Ah + m0 * K : (g == 1) ? Al + m0 * K :
        (g == 2) ? Bh + n0 * K : Bl + n0 * K;
    const uint32_t sm_arr = smbase + g * G_ARRB;

    const uint32_t a_off = (uint32_t)(((wr * 32 + (lane & 15)) * BPAD + ((lane >> 4) << 3)) * 2);
    const uint32_t b_off = (uint32_t)(((wc * 64 + (lane & 7) + ((lane & 16) >> 1)) * BPAD + (lane & 8)) * 2);

    float acc[2][8][4];
    #pragma unroll
    for (int mf = 0; mf < 2; ++mf)
        #pragma unroll
        for (int nf = 0; nf < 8; ++nf)
            #pragma unroll
            for (int r = 0; r < 4; ++r) acc[mf][nf][r] = 0.f;

    const int nchunks = K / 32;

    #pragma unroll
    for (int i = 0; i < 8; ++i) {
        const int idx = sub + i * 64;
        const int row = idx >> 2, col = (idx & 3) * 8;
        cp16(sm_arr + (uint32_t)((row * BPAD + col) * 2), gbase + (size_t)row * K + col);
    }
    CP_COMMIT();

    for (int c = 0; c < nchunks; ++c) {
        const int buf = c & 1;
        if (c + 1 < nchunks) {
            const uint32_t dst = sm_arr + (uint32_t)((c + 1) & 1) * G_BUFB;
            const __nv_bfloat16* src = gbase + (c + 1) * 32;
            #pragma unroll
            for (int i = 0; i < 8; ++i) {
                const int idx = sub + i * 64;
                const int row = idx >> 2, col = (idx & 3) * 8;
                cp16(dst + (uint32_t)((row * BPAD + col) * 2), src + (size_t)row * K + col);
            }
        }
        CP_COMMIT();
        CP_WAIT1();
        __syncthreads();

        const uint32_t sb = smbase + (uint32_t)buf * G_BUFB;
        #pragma unroll
        for (int ks = 0; ks < 2; ++ks) {
            const uint32_t kb = (uint32_t)(ks * 32);
            uint32_t ah[2][4], al[2][4];
            #pragma unroll
            for (int mf = 0; mf < 2; ++mf) {
                const uint32_t ro = (uint32_t)(mf * 16 * BPAD * 2);
                ldsm4(ah[mf], sb + 0 * G_ARRB + a_off + ro + kb);
                ldsm4(al[mf], sb + 1 * G_ARRB + a_off + ro + kb);
            }
            uint32_t bh[8][2], bl[8][2];
            #pragma unroll
            for (int p = 0; p < 4; ++p) {
                const uint32_t ro = (uint32_t)(p * 16 * BPAD * 2);
                uint32_t r[4];
                ldsm4(r, sb + 2 * G_ARRB + b_off + ro + kb);
                bh[2 * p][0] = r[0]; bh[2 * p][1] = r[1];
                bh[2 * p + 1][0] = r[2]; bh[2 * p + 1][1] = r[3];
                ldsm4(r, sb + 3 * G_ARRB + b_off + ro + kb);
                bl[2 * p][0] = r[0]; bl[2 * p][1] = r[1];
                bl[2 * p + 1][0] = r[2]; bl[2 * p + 1][1] = r[3];
            }
            #pragma unroll
            for (int nf = 0; nf < 8; ++nf)
                #pragma unroll
                for (int mf = 0; mf < 2; ++mf) {
                    mma_bf16(acc[mf][nf], ah[mf], bh[nf]);
                    mma_bf16(acc[mf][nf], ah[mf], bl[nf]);
                    mma_bf16(acc[mf][nf], al[mf], bh[nf]);
                }
        }
        __syncthreads();
    }

    const int trow = qid;
    const int tcol = tid4 * 2;
    #pragma unroll
    for (int mf = 0; mf < 2; ++mf) {
        const size_t m = m0 + wr * 32 + mf * 16 + trow;
        #pragma unroll
        for (int nf = 0; nf < 8; ++nf) {
            const int ncol = (int)n0 + wc * 64 + nf * 8 + tcol;
            float2 v0 = make_float2(acc[mf][nf][0], acc[mf][nf][1]);
            float2 v1 = make_float2(acc[mf][nf][2], acc[mf][nf][3]);
            if (bias) {
                const float bx = bias[ncol], by = bias[ncol + 1];
                v0.x += bx; v0.y += by;
                v1.x += bx; v1.y += by;
            }
            *(float2*)(C + m * N + ncol)       = v0;
            *(float2*)(C + (m + 8) * N + ncol) = v1;
        }
    }
}

// ---------------- RoPE -> fp16 (Q hi/lo; K hi only) ----------------
__global__ void rope_q_kernel(const float* __restrict__ in,
                              __half* __restrict__ oh,
                              __half* __restrict__ ol) {
    int idx = blockIdx.x * blockDim.x + threadIdx.x;
    int p = idx & 31;
    int h = (idx >> 5) & 31;
    int s = (idx >> 10) & 2047;
    int b = idx >> 21;
    const float2 cs = g_cs[s * 32 + p];
    const float2 x = *(const float2*)(in + ((size_t)(b * SEQ + s)) * NQKV + h * HD + 2 * p);
    float rx = x.x * cs.x - x.y * cs.y;
    float ry = x.x * cs.y + x.y * cs.x;
    __half hx, lx, hy, ly;
    fp16_split(rx, hx, lx);
    fp16_split(ry, hy, ly);
    const size_t o = (((size_t)(b * NH + h)) * SEQ + s) * HD + 2 * p;
    __half2 vh; vh.x = hx; vh.y = hy;
    __half2 vl; vl.x = lx; vl.y = ly;
    *(__half2*)(oh + o) = vh;
    *(__half2*)(ol + o) = vl;
}
__global__ void rope_k_kernel(const float* __restrict__ in,
                              __half* __restrict__ oh) {
    int idx = blockIdx.x * blockDim.x + threadIdx.x;
    int p = idx & 31;
    int h = (idx >> 5) & 7;
    int s = (idx >> 8) & 2047;
    int b = idx >> 19;
    const float2 cs = g_cs[s * 32 + p];
    const float2 x = *(const float2*)(in + ((size_t)(b * SEQ + s)) * NQKV + DIM + h * HD + 2 * p);
    float rx = x.x * cs.x - x.y * cs.y;
    float ry = x.x * cs.y + x.y * cs.x;
    const size_t o = (((size_t)(b * NKV + h)) * SEQ + s) * HD + 2 * p;
    *(__half2*)(oh + o) = __floats2half2_rn(rx, ry);
}

// V: qkvlin [b,s, 2560 + kv*64 + d] -> transposed fp16 hi [b,kv,d,s]
__global__ void transpose_v_kernel(const float* __restrict__ in,
                                   __half* __restrict__ oh) {
    __shared__ float tile[32][33];
    const int s0 = blockIdx.x * 32;
    const int d0 = blockIdx.y * 32;
    const int bk = blockIdx.z;
    const int b  = bk >> 3, kv = bk & 7;
    const int tx = threadIdx.x, ty = threadIdx.y;
    const float* src = in + ((size_t)(b * SEQ)) * NQKV + (DIM + KVDIM) + kv * HD;
    #pragma unroll
    for (int i = 0; i < 32; i += 8)
        tile[ty + i][tx] = src[(size_t)(s0 + ty + i) * NQKV + d0 + tx];
    __syncthreads();
    const size_t obase = ((size_t)bk * HD + d0) * SEQ + s0;
    #pragma unroll
    for (int i = 0; i < 32; i += 8)
        oh[obase + (size_t)(ty + i) * SEQ + tx] = __float2half_rn(tile[tx][ty + i]);
}

// ---------------- flash attention v4: fp16 2-term, Q resident, 2 CTAs/SM ----------------
// QK = (Qh+Ql)*Kh (2 mma); PV = (Ph+Pl)*Vh (2 mma). K,V hi only.
#define FQ 128
#define FK 64
#define SP 72
#define F_QARR (FQ * SP * 2)           /* 18432 B (Qh; Ql at +F_QARR) */
#define QOFF   (2 * F_QARR)            /* 36864 */
#define F_ARR  (FK * SP * 2)           /* 9216 B per K/V array */
#define F_BUF  (2 * F_ARR)             /* Kh Vth = 18432 */
#define F_SMEM (QOFF + 2 * F_BUF)      /* 73728 B */

__global__ void __launch_bounds__(256, 2) flash_mma_kernel(
    const __half* __restrict__ Qh, const __half* __restrict__ Ql,
    const __half* __restrict__ Kh, const __half* __restrict__ Vth,
    __nv_bfloat16* __restrict__ Oh, __nv_bfloat16* __restrict__ Ol)
{
    extern __shared__ char smem[];
    const uint32_t smbase = smem_u32(smem);

    const int qt  = (SEQ / FQ - 1) - blockIdx.x;
    const int h   = blockIdx.y;
    const int b   = blockIdx.z;
    const int kvh = h >> 2;
    const int t    = threadIdx.x;
    const int lane = t & 31;
    const int w    = t >> 5;
    const int qid  = lane >> 2;
    const int tid4 = lane & 3;
    const int q0   = qt * FQ;
    const int wrow = w * 16;

    const __half* Qhb = Qh + (((size_t)(b * NH + h)) * SEQ + q0) * HD;
    const __half* Qlb = Ql + (((size_t)(b * NH + h)) * SEQ + q0) * HD;
    const __half* Khb = Kh + ((size_t)(b * NKV + kvh)) * SEQ * HD;
    const __half* Vhb = Vth + ((size_t)(b * NKV + kvh)) * HD * SEQ;

    // ---- stage Q permanently in smem (hi at 0, lo at F_QARR) ----
    #pragma unroll
    for (int i = 0; i < 4; ++i) {
        const int idx = t + i * 256;
        const int r = idx >> 3, c = (idx & 7) * 8;
        *(uint4*)(smem + (r * SP + c) * 2)          = *(const uint4*)(Qhb + (size_t)r * HD + c);
        *(uint4*)(smem + F_QARR + (r * SP + c) * 2) = *(const uint4*)(Qlb + (size_t)r * HD + c);
    }
    __syncthreads();

    const uint32_t a_off = (uint32_t)(((wrow + (lane & 15)) * SP + ((lane >> 4) << 3)) * 2);
    const uint32_t b_off = (uint32_t)((((lane & 7) + ((lane & 16) >> 1)) * SP + (lane & 8)) * 2);

    // ---- cp.async: 128 threads per array (0=Kh, 1=Vth) ----
    const int ga  = t >> 7;
    const int sub = t & 127;
    const __half* gsrc = (ga == 0) ? Khb : Vhb;
    const bool isK = (ga == 0);

    float oacc[8][4];
    #pragma unroll
    for (int nf = 0; nf < 8; ++nf)
        #pragma unroll
        for (int j = 0; j < 4; ++j) oacc[nf][j] = 0.f;
    float m[2] = {-1e30f, -1e30f};
    float l[2] = {0.f, 0.f};

    const int row_a = q0 + wrow + qid;
    const int row_b = row_a + 8;
    const float SC = 0.125f * 1.4426950408889634f;

    const int ntiles = (q0 + FQ) / FK;

    #pragma unroll
    for (int i = 0; i < 4; ++i) {
        const int idx = sub + i * 128;
        const int row = idx >> 3, col = (idx & 7) * 8;
        const __half* s = isK ? (gsrc + (size_t)row * HD + col)
                              : (gsrc + (size_t)row * SEQ + col);
        cp16(smbase + QOFF + (uint32_t)(ga * F_ARR) + (uint32_t)((row * SP + col) * 2), s);
    }
    CP_COMMIT();

    for (int kt = 0; kt < ntiles; ++kt) {
        if (kt + 1 < ntiles) {
            const uint32_t dst = smbase + QOFF + (uint32_t)(((kt + 1) & 1) * F_BUF) + (uint32_t)(ga * F_ARR);
            #pragma unroll
            for (int i = 0; i < 4; ++i) {
                const int idx = sub + i * 128;
                const int row = idx >> 3, col = (idx & 7) * 8;
                const __half* s = isK
                    ? (gsrc + (size_t)((kt + 1) * FK + row) * HD + col)
                    : (gsrc + (size_t)row * SEQ + (kt + 1) * FK + col);
                cp16(dst + (uint32_t)((row * SP + col) * 2), s);
            }
        }
        CP_COMMIT();
        CP_WAIT1();
        __syncthreads();

        const uint32_t sb = smbase + QOFF + (uint32_t)((kt & 1) * F_BUF);

        // ---- scores: (Qh+Ql) x Kh ----
        float sacc[8][4];
        #pragma unroll
        for (int nf = 0; nf < 8; ++nf)
            #pragma unroll
            for (int j = 0; j < 4; ++j) sacc[nf][j] = 0.f;

        #pragma unroll
        for (int g2 = 0; g2 < 4; ++g2) {
            const uint32_t kb = (uint32_t)(g2 * 32);
            uint32_t qh4[4], ql4[4];
            ldsm4(qh4, smbase + a_off + kb);
            ldsm4(ql4, smbase + F_QARR + a_off + kb);
            uint32_t bh[8][2];
            #pragma unroll
            for (int p = 0; p < 4; ++p) {
                const uint32_t ro = (uint32_t)(p * 16 * SP * 2);
                uint32_t r[4];
                ldsm4(r, sb + 0 * F_ARR + b_off + ro + kb);
                bh[2 * p][0] = r[0]; bh[2 * p][1] = r[1];
                bh[2 * p + 1][0] = r[2]; bh[2 * p + 1][1] = r[3];
            }
            #pragma unroll
            for (int nf = 0; nf < 8; ++nf) {
                mma_fp16(sacc[nf], qh4, bh[nf]);
                mma_fp16(sacc[nf], ql4, bh[nf]);
            }
        }

        // ---- mask + scale (log2 domain) + row max ----
        const bool need_mask = (kt * FK + FK - 1) > row_a;
        float tmax[2] = {-1e30f, -1e30f};
        #pragma unroll
        for (int nf = 0; nf < 8; ++nf) {
            const int colbase = kt * FK + nf * 8 + tid4 * 2;
            #pragma unroll
            for (int j = 0; j < 4; ++j) {
                const int col = colbase + (j & 1);
                const int row = (j < 2) ? row_a : row_b;
                float v = sacc[nf][j] * SC;
                if (need_mask && col > row) v = -1e30f;
                sacc[nf][j] = v;
                tmax[j >> 1] = fmaxf(tmax[j >> 1], v);
            }
        }

        float corr[2];
        #pragma unroll
        for (int hh = 0; hh < 2; ++hh) {
            tmax[hh] = fmaxf(tmax[hh], __shfl_xor_sync(0xffffffffu, tmax[hh], 1));
            tmax[hh] = fmaxf(tmax[hh], __shfl_xor_sync(0xffffffffu, tmax[hh], 2));
            const float mnew = fmaxf(m[hh], tmax[hh]);
            corr[hh] = exp2p(m[hh] - mnew);
            m[hh] = mnew;
            l[hh] *= corr[hh];
        }
        #pragma unroll
        for (int nf = 0; nf < 8; ++nf) {
            oacc[nf][0] *= corr[0]; oacc[nf][1] *= corr[0];
            oacc[nf][2] *= corr[1]; oacc[nf][3] *= corr[1];
        }
        float rsum[2] = {0.f, 0.f};
        #pragma unroll
        for (int nf = 0; nf < 8; ++nf) {
            #pragma unroll
            for (int j = 0; j < 4; ++j) {
                const float p = exp2p(sacc[nf][j] - m[j >> 1]);
                sacc[nf][j] = p;
                rsum[j >> 1] += p;
            }
        }
        #pragma unroll
        for (int hh = 0; hh < 2; ++hh) {
            rsum[hh] += __shfl_xor_sync(0xffffffffu, rsum[hh], 1);
            rsum[hh] += __shfl_xor_sync(0xffffffffu, rsum[hh], 2);
            l[hh] += rsum[hh];
        }

        // ---- build P a-fragments in registers (fp16 hi/lo) ----
        uint32_t pfh[4][4], pfl[4][4];
        #pragma unroll
        for (int g2 = 0; g2 < 4; ++g2) {
            const float* s0 = sacc[2 * g2];
            const float* s1 = sacc[2 * g2 + 1];
            float h00 = __half2float(__float2half_rn(s0[0]));
            float h01 = __half2float(__float2half_rn(s0[1]));
            float h02 = __half2float(__float2half_rn(s0[2]));
            float h03 = __half2float(__float2half_rn(s0[3]));
            float h10 = __half2float(__float2half_rn(s1[0]));
            float h11 = __half2float(__float2half_rn(s1[1]));
            float h12 = __half2float(__float2half_rn(s1[2]));
            float h13 = __half2float(__float2half_rn(s1[3]));
            pfh[g2][0] = pack_hf2(h00, h01);
            pfh[g2][1] = pack_hf2(h02, h03);
            pfh[g2][2] = pack_hf2(h10, h11);
            pfh[g2][3] = pack_hf2(h12, h13);
            pfl[g2][0] = pack_hf2(s0[0] - h00, s0[1] - h01);
            pfl[g2][1] = pack_hf2(s0[2] - h02, s0[3] - h03);
            pfl[g2][2] = pack_hf2(s1[0] - h10, s1[1] - h11);
            pfl[g2][3] = pack_hf2(s1[2] - h12, s1[3] - h13);
        }

        // ---- O += (Ph+Pl) x Vh ----
        #pragma unroll
        for (int g2 = 0; g2 < 4; ++g2) {
            const uint32_t kb = (uint32_t)(g2 * 32);
            uint32_t vh[8][2];
            #pragma unroll
            for (int p = 0; p < 4; ++p) {
                const uint32_t ro = (uint32_t)(p * 16 * SP * 2);
                uint32_t r[4];
                ldsm4(r, sb + 1 * F_ARR + b_off + ro + kb);
                vh[2 * p][0] = r[0]; vh[2 * p][1] = r[1];
                vh[2 * p + 1][0] = r[2]; vh[2 * p + 1][1] = r[3];
            }
            #pragma unroll
            for (int nf = 0; nf < 8; ++nf) {
                mma_fp16(oacc[nf], pfh[g2], vh[nf]);
                mma_fp16(oacc[nf], pfl[g2], vh[nf]);
            }
        }
        __syncthreads();
    }

    // ---- epilogue: normalized output, pre-split bf16 hi/lo for O-projection ----
    const float inv_a = 1.0f / l[0];
    const float inv_b = 1.0f / l[1];
    const size_t rA = ((size_t)(b * SEQ) + row_a) * DIM + h * HD;
    const size_t rB = rA + 8 * DIM;
    #pragma unroll
    for (int nf = 0; nf < 8; ++nf) {
        const int col = nf * 8 + tid4 * 2;
        float f0 = oacc[nf][0] * inv_a, f1 = oacc[nf][1] * inv_a;
        float f2 = oacc[nf][2] * inv_b, f3 = oacc[nf][3] * inv_b;
        __nv_bfloat16 h0, l0, h1, l1, h2, l2, h3, l3;
        bf16_split(f0, h0, l0);
        bf16_split(f1, h1, l1);
        bf16_split(f2, h2, l2);
        bf16_split(f3, h3, l3);
        __nv_bfloat162 vhA; vhA.x = h0; vhA.y = h1;
        __nv_bfloat162 vlA; vlA.x = l0; vlA.y = l1;
        __nv_bfloat162 vhB; vhB.x = h2; vhB.y = h3;
        __nv_bfloat162 vlB; vlB.x = l2; vlB.y = l3;
        *(__nv_bfloat162*)(Oh + rA + col) = vhA;
        *(__nv_bfloat162*)(Ol + rA + col) = vlA;
        *(__nv_bfloat162*)(Oh + rB + col) = vhB;
        *(__nv_bfloat162*)(Ol + rB + col) = vlB;
    }
}

// ---------------- host launcher ----------------
extern "C" void kernel_launch(void* const* d_in, const int* in_sizes, int n_in,
                              void* d_out, int out_size) {
    (void)in_sizes; (void)n_in; (void)out_size;
    const float* x  = (const float*)d_in[0];
    const float* Wq = (const float*)d_in[1];
    const float* Wk = (const float*)d_in[2];
    const float* Wv = (const float*)d_in[3];
    const float* bv = (const float*)d_in[4];
    const float* Wo = (const float*)d_in[5];
    const float* bo = (const float*)d_in[6];
    float* out = (float*)d_out;

    float *qkvlin, *biasqkv;
    __nv_bfloat16 *ah, *al, *bh, *bl;
    __half *qh, *ql, *kh, *vth;
    cudaGetSymbolAddress((void**)&qkvlin,  g_qkvlin);
    cudaGetSymbolAddress((void**)&biasqkv, g_biasqkv);
    cudaGetSymbolAddress((void**)&ah,  g_ah);
    cudaGetSymbolAddress((void**)&al,  g_al);
    cudaGetSymbolAddress((void**)&bh,  g_bh);
    cudaGetSymbolAddress((void**)&bl,  g_bl);
    cudaGetSymbolAddress((void**)&qh,  g_qh);
    cudaGetSymbolAddress((void**)&ql,  g_ql);
    cudaGetSymbolAddress((void**)&kh,  g_kh);
    cudaGetSymbolAddress((void**)&vth, g_vth);

    cudaFuncSetAttribute(mma_gemm_bf16, cudaFuncAttributeMaxDynamicSharedMemorySize, G_SMEM);
    cudaFuncSetAttribute(flash_mma_kernel, cudaFuncAttributeMaxDynamicSharedMemorySize, F_SMEM);

    theta_kernel<<<1, 32>>>();
    sincos_kernel<<<(SEQ * 32) / 256, 256>>>();
    biasqkv_kernel<<<NQKV / 256, 256>>>(bv);

    // split activations once
    split_kernel<<<(MROWS * DIM) / 1024, 256>>>(x, ah, al);

    // merged QKV projection (N = 3072)
    transpose_split_kernel<<<dim3(DIM / 32, DIM / 32), dim3(32, 8)>>>(Wq, bh, bl, DIM, DIM);
    transpose_split_kernel<<<dim3(KVDIM / 32, DIM / 32), dim3(32, 8)>>>(
        Wk, bh + (size_t)DIM * DIM, bl + (size_t)DIM * DIM, DIM, KVDIM);
    transpose_split_kernel<<<dim3(KVDIM / 32, DIM / 32), dim3(32, 8)>>>(
        Wv, bh + (size_t)(DIM + KVDIM) * DIM, bl + (size_t)(DIM + KVDIM) * DIM, DIM, KVDIM);
    mma_gemm_bf16<<<dim3(NQKV / 128, MROWS / 128), 256, G_SMEM>>>(
        ah, al, bh, bl, biasqkv, qkvlin, NQKV, DIM);

    rope_q_kernel<<<(BATCH * SEQ * NH * 32) / 256, 256>>>(qkvlin, qh, ql);
    rope_k_kernel<<<(BATCH * SEQ * NKV * 32) / 256, 256>>>(qkvlin, kh);
    transpose_v_kernel<<<dim3(SEQ / 32, HD / 32, BATCH * NKV), dim3(32, 8)>>>(qkvlin, vth);

    // flash writes pre-split ah/al for the O projection
    flash_mma_kernel<<<dim3(SEQ / FQ, NH, BATCH), 256, F_SMEM>>>(
        qh, ql, kh, vth, ah, al);

    transpose_split_kernel<<<dim3(DIM / 32, DIM / 32), dim3(32, 8)>>>(Wo, bh, bl, DIM, DIM);
    mma_gemm_bf16<<<dim3(DIM / 128, MROWS / 128), 256, G_SMEM>>>(ah, al, bh, bl, bo, out, DIM, DIM);
}

// round 10
// speedup vs baseline: 4.1899x; 1.3411x over previous
#include <cuda_runtime.h>
#include <cuda_bf16.h>
#include <cuda_fp16.h>
#include <math.h>
#include <stdint.h>

#define DIM 2048
#define NH 32
#define NKV 8
#define HD 64
#define BATCH 2
#define SEQ 2048
#define MROWS (BATCH*SEQ)   /* 4096 */
#define KVDIM (NKV*HD)      /* 512 */
#define NQKV (DIM + 2*KVDIM) /* 3072 */

// ---------------- scratch (static device allocations; no cudaMalloc) ----------------
__device__ float g_qkvlin[(size_t)MROWS * NQKV];
__device__ float g_biasqkv[NQKV];
// GEMM operands: activations fp16 hi/lo, weights fp16 hi only
__device__ __align__(16) __half g_ah[(size_t)MROWS * DIM];
__device__ __align__(16) __half g_al[(size_t)MROWS * DIM];
__device__ __align__(16) __half g_bh[(size_t)NQKV * DIM];
// flash operands: Q fp16 hi/lo; K,V fp16 hi only
__device__ __align__(16) __half g_qh[(size_t)BATCH * NH * SEQ * HD];
__device__ __align__(16) __half g_ql[(size_t)BATCH * NH * SEQ * HD];
__device__ __align__(16) __half g_kh[(size_t)BATCH * NKV * SEQ * HD];
__device__ __align__(16) __half g_vth[(size_t)BATCH * NKV * HD * SEQ];  // [b,kv,d,s]
__device__ double g_theta[HD / 2];
__device__ float2 g_cs[(size_t)SEQ * (HD / 2)];

// ---------------- RoPE tables ----------------
__global__ void theta_kernel() {
    int p = threadIdx.x;
    if (p < HD / 2) g_theta[p] = pow(10000.0, -(double)p / 32.0);
}
__global__ void sincos_kernel() {
    int idx = blockIdx.x * blockDim.x + threadIdx.x;
    int s = idx >> 5, p = idx & 31;
    float ang = (float)((double)s * g_theta[p]);
    float sv, cv;
    sincosf(ang, &sv, &cv);
    g_cs[idx] = make_float2(cv, sv);
}
__global__ void biasqkv_kernel(const float* __restrict__ bv) {
    int i = blockIdx.x * blockDim.x + threadIdx.x;
    g_biasqkv[i] = (i < DIM + KVDIM) ? 0.f : bv[i - (DIM + KVDIM)];
}

// ---------------- split helpers ----------------
__device__ __forceinline__ void fp16_split(float x, __half& h, __half& l) {
    h = __float2half_rn(x);
    l = __float2half_rn(x - __half2float(h));
}

// activations: fp32 -> fp16 hi/lo
__global__ void split_kernel(const float* __restrict__ in,
                             __half* __restrict__ oh,
                             __half* __restrict__ ol) {
    const int i = blockIdx.x * blockDim.x + threadIdx.x;
    const float4 v = *(const float4*)(in + (size_t)i * 4);
    __half h[4], l[4];
    fp16_split(v.x, h[0], l[0]);
    fp16_split(v.y, h[1], l[1]);
    fp16_split(v.z, h[2], l[2]);
    fp16_split(v.w, h[3], l[3]);
    *(uint2*)(oh + (size_t)i * 4) = *(uint2*)h;
    *(uint2*)(ol + (size_t)i * 4) = *(uint2*)l;
}

// weight transpose: in R x C fp32 -> out C x R fp16 (hi only)
__global__ void transpose_half_kernel(const float* __restrict__ in,
                                      __half* __restrict__ oh,
                                      int R, int Ccols) {
    __shared__ float tile[32][33];
    int bx = blockIdx.x * 32, by = blockIdx.y * 32;
    int x = bx + threadIdx.x;
    #pragma unroll
    for (int i = 0; i < 32; i += 8)
        tile[threadIdx.y + i][threadIdx.x] = in[(size_t)(by + threadIdx.y + i) * Ccols + x];
    __syncthreads();
    int ox = by + threadIdx.x;
    #pragma unroll
    for (int i = 0; i < 32; i += 8)
        oh[(size_t)(bx + threadIdx.y + i) * R + ox] = __float2half_rn(tile[threadIdx.x][threadIdx.y + i]);
}

// ================= mma.sync / async helpers =================
__device__ __forceinline__ uint32_t smem_u32(const void* p) {
    uint32_t a;
    asm("{ .reg .u64 t; cvta.to.shared.u64 t, %1; cvt.u32.u64 %0, t; }" : "=r"(a) : "l"(p));
    return a;
}
__device__ __forceinline__ void cp16(uint32_t dst, const void* src) {
    asm volatile("cp.async.cg.shared.global [%0], [%1], 16;" :: "r"(dst), "l"(src));
}
#define CP_COMMIT() asm volatile("cp.async.commit_group;" ::: "memory")
#define CP_WAIT1()  asm volatile("cp.async.wait_group 1;" ::: "memory")

__device__ __forceinline__ void ldsm4(uint32_t* r, uint32_t addr) {
    asm volatile("ldmatrix.sync.aligned.m8n8.x4.shared.b16 {%0,%1,%2,%3}, [%4];"
                 : "=r"(r[0]), "=r"(r[1]), "=r"(r[2]), "=r"(r[3]) : "r"(addr));
}
__device__ __forceinline__ void mma_fp16(float* d, const uint32_t* a, const uint32_t* b) {
    asm volatile(
        "mma.sync.aligned.m16n8k16.row.col.f32.f16.f16.f32 "
        "{%0,%1,%2,%3}, {%4,%5,%6,%7}, {%8,%9}, {%0,%1,%2,%3};\n"
        : "+f"(d[0]), "+f"(d[1]), "+f"(d[2]), "+f"(d[3])
        : "r"(a[0]), "r"(a[1]), "r"(a[2]), "r"(a[3]), "r"(b[0]), "r"(b[1]));
}
__device__ __forceinline__ uint32_t pack_hf2(float x0, float x1) {
    __half2 v = __floats2half2_rn(x0, x1);
    return *(uint32_t*)&v;
}
__device__ __forceinline__ float exp2p(float y) {
    y = fmaxf(y, -120.f);
    int ki = __float2int_rn(y);
    float f = y - (float)ki;
    float p = 0.0013333558f;
    p = fmaf(p, f, 0.0096181291f);
    p = fmaf(p, f, 0.0555041087f);
    p = fmaf(p, f, 0.2402265070f);
    p = fmaf(p, f, 0.6931471806f);
    p = fmaf(p, f, 1.0f);
    return p * __int_as_float((ki + 127) << 23);
}

// ---------------- fp16 2-term GEMM: C = (Ah+Al) @ Bh^T (+bias) ----------------
// K-chunk 32, double buffer, 3 smem arrays (Ah, Al, Bh).
#define BPAD 40
#define G_ARRB (128 * BPAD * 2)     /* 10240 B */
#define G_BUFB (3 * G_ARRB)         /* 30720 B */
#define G_SMEM (2 * G_BUFB)         /* 61440 B -> 2 CTAs/SM easily */

__global__ void __launch_bounds__(256, 2) mma_gemm_fp16(
    const __half* __restrict__ Ah, const __half* __restrict__ Al,
    const __half* __restrict__ Bh,
    const float* __restrict__ bias, float* __restrict__ C, int N, int K)
{
    extern __shared__ char smem[];
    const uint32_t smbase = smem_u32(smem);

    const int t    = threadIdx.x;
    const int lane = t & 31;
    const int wid  = t >> 5;
    const int wr   = wid & 3;
    const int wc   = wid >> 2;
    const int qid  = lane >> 2;
    const int tid4 = lane & 3;

    const size_t m0 = (size_t)blockIdx.y * 128;
    const size_t n0 = (size_t)blockIdx.x * 128;
    const __half* Abh = Ah + m0 * K;
    const __half* Abl = Al + m0 * K;
    const __half* Bbh = Bh + n0 * K;

    const uint32_t a_off = (uint32_t)(((wr * 32 + (lane & 15)) * BPAD + ((lane >> 4) << 3)) * 2);
    const uint32_t b_off = (uint32_t)(((wc * 64 + (lane & 7) + ((lane & 16) >> 1)) * BPAD + (lane & 8)) * 2);

    float acc[2][8][4];
    #pragma unroll
    for (int mf = 0; mf < 2; ++mf)
        #pragma unroll
        for (int nf = 0; nf < 8; ++nf)
            #pragma unroll
            for (int r = 0; r < 4; ++r) acc[mf][nf][r] = 0.f;

    const int nchunks = K / 32;

    // cp.async: 1536 x 16B per chunk (3 arrays x 512), 6 per thread
    #pragma unroll
    for (int i = 0; i < 6; ++i) {
        const int o = t + i * 256;
        const int arr = o >> 9;
        const int r = (o & 511) >> 2, c = (o & 3) * 8;
        const __half* src = ((arr == 0) ? Abh : (arr == 1) ? Abl : Bbh) + (size_t)r * K + c;
        cp16(smbase + (uint32_t)(arr * G_ARRB) + (uint32_t)((r * BPAD + c) * 2), src);
    }
    CP_COMMIT();

    for (int cch = 0; cch < nchunks; ++cch) {
        const int buf = cch & 1;
        if (cch + 1 < nchunks) {
            const uint32_t dst = smbase + (uint32_t)(((cch + 1) & 1) * G_BUFB);
            const int k0 = (cch + 1) * 32;
            #pragma unroll
            for (int i = 0; i < 6; ++i) {
                const int o = t + i * 256;
                const int arr = o >> 9;
                const int r = (o & 511) >> 2, c = (o & 3) * 8;
                const __half* src = ((arr == 0) ? Abh : (arr == 1) ? Abl : Bbh) + (size_t)r * K + k0 + c;
                cp16(dst + (uint32_t)(arr * G_ARRB) + (uint32_t)((r * BPAD + c) * 2), src);
            }
        }
        CP_COMMIT();
        CP_WAIT1();
        __syncthreads();

        const uint32_t sb = smbase + (uint32_t)buf * G_BUFB;
        #pragma unroll
        for (int ks = 0; ks < 2; ++ks) {
            const uint32_t kb = (uint32_t)(ks * 32);
            uint32_t ah[2][4], al[2][4];
            #pragma unroll
            for (int mf = 0; mf < 2; ++mf) {
                const uint32_t ro = (uint32_t)(mf * 16 * BPAD * 2);
                ldsm4(ah[mf], sb + 0 * G_ARRB + a_off + ro + kb);
                ldsm4(al[mf], sb + 1 * G_ARRB + a_off + ro + kb);
            }
            uint32_t bh[8][2];
            #pragma unroll
            for (int p = 0; p < 4; ++p) {
                const uint32_t ro = (uint32_t)(p * 16 * BPAD * 2);
                uint32_t r[4];
                ldsm4(r, sb + 2 * G_ARRB + b_off + ro + kb);
                bh[2 * p][0] = r[0]; bh[2 * p][1] = r[1];
                bh[2 * p + 1][0] = r[2]; bh[2 * p + 1][1] = r[3];
            }
            #pragma unroll
            for (int nf = 0; nf < 8; ++nf)
                #pragma unroll
                for (int mf = 0; mf < 2; ++mf) {
                    mma_fp16(acc[mf][nf], ah[mf], bh[nf]);
                    mma_fp16(acc[mf][nf], al[mf], bh[nf]);
                }
        }
        __syncthreads();
    }

    const int trow = qid;
    const int tcol = tid4 * 2;
    #pragma unroll
    for (int mf = 0; mf < 2; ++mf) {
        const size_t m = m0 + wr * 32 + mf * 16 + trow;
        #pragma unroll
        for (int nf = 0; nf < 8; ++nf) {
            const int ncol = (int)n0 + wc * 64 + nf * 8 + tcol;
            float2 v0 = make_float2(acc[mf][nf][0], acc[mf][nf][1]);
            float2 v1 = make_float2(acc[mf][nf][2], acc[mf][nf][3]);
            if (bias) {
                const float bx = bias[ncol], by = bias[ncol + 1];
                v0.x += bx; v0.y += by;
                v1.x += bx; v1.y += by;
            }
            *(float2*)(C + m * N + ncol)       = v0;
            *(float2*)(C + (m + 8) * N + ncol) = v1;
        }
    }
}

// ---------------- RoPE -> fp16 (Q hi/lo; K hi only) ----------------
__global__ void rope_q_kernel(const float* __restrict__ in,
                              __half* __restrict__ oh,
                              __half* __restrict__ ol) {
    int idx = blockIdx.x * blockDim.x + threadIdx.x;
    int p = idx & 31;
    int h = (idx >> 5) & 31;
    int s = (idx >> 10) & 2047;
    int b = idx >> 21;
    const float2 cs = g_cs[s * 32 + p];
    const float2 x = *(const float2*)(in + ((size_t)(b * SEQ + s)) * NQKV + h * HD + 2 * p);
    float rx = x.x * cs.x - x.y * cs.y;
    float ry = x.x * cs.y + x.y * cs.x;
    __half hx, lx, hy, ly;
    fp16_split(rx, hx, lx);
    fp16_split(ry, hy, ly);
    const size_t o = (((size_t)(b * NH + h)) * SEQ + s) * HD + 2 * p;
    __half2 vh; vh.x = hx; vh.y = hy;
    __half2 vl; vl.x = lx; vl.y = ly;
    *(__half2*)(oh + o) = vh;
    *(__half2*)(ol + o) = vl;
}
__global__ void rope_k_kernel(const float* __restrict__ in,
                              __half* __restrict__ oh) {
    int idx = blockIdx.x * blockDim.x + threadIdx.x;
    int p = idx & 31;
    int h = (idx >> 5) & 7;
    int s = (idx >> 8) & 2047;
    int b = idx >> 19;
    const float2 cs = g_cs[s * 32 + p];
    const float2 x = *(const float2*)(in + ((size_t)(b * SEQ + s)) * NQKV + DIM + h * HD + 2 * p);
    float rx = x.x * cs.x - x.y * cs.y;
    float ry = x.x * cs.y + x.y * cs.x;
    const size_t o = (((size_t)(b * NKV + h)) * SEQ + s) * HD + 2 * p;
    *(__half2*)(oh + o) = __floats2half2_rn(rx, ry);
}

// V: qkvlin [b,s, 2560 + kv*64 + d] -> transposed fp16 hi [b,kv,d,s]
__global__ void transpose_v_kernel(const float* __restrict__ in,
                                   __half* __restrict__ oh) {
    __shared__ float tile[32][33];
    const int s0 = blockIdx.x * 32;
    const int d0 = blockIdx.y * 32;
    const int bk = blockIdx.z;
    const int b  = bk >> 3, kv = bk & 7;
    const int tx = threadIdx.x, ty = threadIdx.y;
    const float* src = in + ((size_t)(b * SEQ)) * NQKV + (DIM + KVDIM) + kv * HD;
    #pragma unroll
    for (int i = 0; i < 32; i += 8)
        tile[ty + i][tx] = src[(size_t)(s0 + ty + i) * NQKV + d0 + tx];
    __syncthreads();
    const size_t obase = ((size_t)bk * HD + d0) * SEQ + s0;
    #pragma unroll
    for (int i = 0; i < 32; i += 8)
        oh[obase + (size_t)(ty + i) * SEQ + tx] = __float2half_rn(tile[tx][ty + i]);
}

// ---------------- flash attention v4 (unchanged math; epilogue now fp16 hi/lo) ------
#define FQ 128
#define FK 64
#define SP 72
#define F_QARR (FQ * SP * 2)
#define QOFF   (2 * F_QARR)
#define F_ARR  (FK * SP * 2)
#define F_BUF  (2 * F_ARR)
#define F_SMEM (QOFF + 2 * F_BUF)

__global__ void __launch_bounds__(256, 2) flash_mma_kernel(
    const __half* __restrict__ Qh, const __half* __restrict__ Ql,
    const __half* __restrict__ Kh, const __half* __restrict__ Vth,
    __half* __restrict__ Oh, __half* __restrict__ Ol)
{
    extern __shared__ char smem[];
    const uint32_t smbase = smem_u32(smem);

    const int qt  = (SEQ / FQ - 1) - blockIdx.x;
    const int h   = blockIdx.y;
    const int b   = blockIdx.z;
    const int kvh = h >> 2;
    const int t    = threadIdx.x;
    const int lane = t & 31;
    const int w    = t >> 5;
    const int qid  = lane >> 2;
    const int tid4 = lane & 3;
    const int q0   = qt * FQ;
    const int wrow = w * 16;

    const __half* Qhb = Qh + (((size_t)(b * NH + h)) * SEQ + q0) * HD;
    const __half* Qlb = Ql + (((size_t)(b * NH + h)) * SEQ + q0) * HD;
    const __half* Khb = Kh + ((size_t)(b * NKV + kvh)) * SEQ * HD;
    const __half* Vhb = Vth + ((size_t)(b * NKV + kvh)) * HD * SEQ;

    #pragma unroll
    for (int i = 0; i < 4; ++i) {
        const int idx = t + i * 256;
        const int r = idx >> 3, c = (idx & 7) * 8;
        *(uint4*)(smem + (r * SP + c) * 2)          = *(const uint4*)(Qhb + (size_t)r * HD + c);
        *(uint4*)(smem + F_QARR + (r * SP + c) * 2) = *(const uint4*)(Qlb + (size_t)r * HD + c);
    }
    __syncthreads();

    const uint32_t a_off = (uint32_t)(((wrow + (lane & 15)) * SP + ((lane >> 4) << 3)) * 2);
    const uint32_t b_off = (uint32_t)((((lane & 7) + ((lane & 16) >> 1)) * SP + (lane & 8)) * 2);

    const int ga  = t >> 7;
    const int sub = t & 127;
    const __half* gsrc = (ga == 0) ? Khb : Vhb;
    const bool isK = (ga == 0);

    float oacc[8][4];
    #pragma unroll
    for (int nf = 0; nf < 8; ++nf)
        #pragma unroll
        for (int j = 0; j < 4; ++j) oacc[nf][j] = 0.f;
    float m[2] = {-1e30f, -1e30f};
    float l[2] = {0.f, 0.f};

    const int row_a = q0 + wrow + qid;
    const int row_b = row_a + 8;
    const float SC = 0.125f * 1.4426950408889634f;

    const int ntiles = (q0 + FQ) / FK;

    #pragma unroll
    for (int i = 0; i < 4; ++i) {
        const int idx = sub + i * 128;
        const int row = idx >> 3, col = (idx & 7) * 8;
        const __half* s = isK ? (gsrc + (size_t)row * HD + col)
                              : (gsrc + (size_t)row * SEQ + col);
        cp16(smbase + QOFF + (uint32_t)(ga * F_ARR) + (uint32_t)((row * SP + col) * 2), s);
    }
    CP_COMMIT();

    for (int kt = 0; kt < ntiles; ++kt) {
        if (kt + 1 < ntiles) {
            const uint32_t dst = smbase + QOFF + (uint32_t)(((kt + 1) & 1) * F_BUF) + (uint32_t)(ga * F_ARR);
            #pragma unroll
            for (int i = 0; i < 4; ++i) {
                const int idx = sub + i * 128;
                const int row = idx >> 3, col = (idx & 7) * 8;
                const __half* s = isK
                    ? (gsrc + (size_t)((kt + 1) * FK + row) * HD + col)
                    : (gsrc + (size_t)row * SEQ + (kt + 1) * FK + col);
                cp16(dst + (uint32_t)((row * SP + col) * 2), s);
            }
        }
        CP_COMMIT();
        CP_WAIT1();
        __syncthreads();

        const uint32_t sb = smbase + QOFF + (uint32_t)((kt & 1) * F_BUF);

        float sacc[8][4];
        #pragma unroll
        for (int nf = 0; nf < 8; ++nf)
            #pragma unroll
            for (int j = 0; j < 4; ++j) sacc[nf][j] = 0.f;

        #pragma unroll
        for (int g2 = 0; g2 < 4; ++g2) {
            const uint32_t kb = (uint32_t)(g2 * 32);
            uint32_t qh4[4], ql4[4];
            ldsm4(qh4, smbase + a_off + kb);
            ldsm4(ql4, smbase + F_QARR + a_off + kb);
            uint32_t bh[8][2];
            #pragma unroll
            for (int p = 0; p < 4; ++p) {
                const uint32_t ro = (uint32_t)(p * 16 * SP * 2);
                uint32_t r[4];
                ldsm4(r, sb + 0 * F_ARR + b_off + ro + kb);
                bh[2 * p][0] = r[0]; bh[2 * p][1] = r[1];
                bh[2 * p + 1][0] = r[2]; bh[2 * p + 1][1] = r[3];
            }
            #pragma unroll
            for (int nf = 0; nf < 8; ++nf) {
                mma_fp16(sacc[nf], qh4, bh[nf]);
                mma_fp16(sacc[nf], ql4, bh[nf]);
            }
        }

        const bool need_mask = (kt * FK + FK - 1) > row_a;
        float tmax[2] = {-1e30f, -1e30f};
        #pragma unroll
        for (int nf = 0; nf < 8; ++nf) {
            const int colbase = kt * FK + nf * 8 + tid4 * 2;
            #pragma unroll
            for (int j = 0; j < 4; ++j) {
                const int col = colbase + (j & 1);
                const int row = (j < 2) ? row_a : row_b;
                float v = sacc[nf][j] * SC;
                if (need_mask && col > row) v = -1e30f;
                sacc[nf][j] = v;
                tmax[j >> 1] = fmaxf(tmax[j >> 1], v);
            }
        }

        float corr[2];
        #pragma unroll
        for (int hh = 0; hh < 2; ++hh) {
            tmax[hh] = fmaxf(tmax[hh], __shfl_xor_sync(0xffffffffu, tmax[hh], 1));
            tmax[hh] = fmaxf(tmax[hh], __shfl_xor_sync(0xffffffffu, tmax[hh], 2));
            const float mnew = fmaxf(m[hh], tmax[hh]);
            corr[hh] = exp2p(m[hh] - mnew);
            m[hh] = mnew;
            l[hh] *= corr[hh];
        }
        #pragma unroll
        for (int nf = 0; nf < 8; ++nf) {
            oacc[nf][0] *= corr[0]; oacc[nf][1] *= corr[0];
            oacc[nf][2] *= corr[1]; oacc[nf][3] *= corr[1];
        }
        float rsum[2] = {0.f, 0.f};
        #pragma unroll
        for (int nf = 0; nf < 8; ++nf) {
            #pragma unroll
            for (int j = 0; j < 4; ++j) {
                const float p = exp2p(sacc[nf][j] - m[j >> 1]);
                sacc[nf][j] = p;
                rsum[j >> 1] += p;
            }
        }
        #pragma unroll
        for (int hh = 0; hh < 2; ++hh) {
            rsum[hh] += __shfl_xor_sync(0xffffffffu, rsum[hh], 1);
            rsum[hh] += __shfl_xor_sync(0xffffffffu, rsum[hh], 2);
            l[hh] += rsum[hh];
        }

        uint32_t pfh[4][4], pfl[4][4];
        #pragma unroll
        for (int g2 = 0; g2 < 4; ++g2) {
            const float* s0 = sacc[2 * g2];
            const float* s1 = sacc[2 * g2 + 1];
            float h00 = __half2float(__float2half_rn(s0[0]));
            float h01 = __half2float(__float2half_rn(s0[1]));
            float h02 = __half2float(__float2half_rn(s0[2]));
            float h03 = __half2float(__float2half_rn(s0[3]));
            float h10 = __half2float(__float2half_rn(s1[0]));
            float h11 = __half2float(__float2half_rn(s1[1]));
            float h12 = __half2float(__float2half_rn(s1[2]));
            float h13 = __half2float(__float2half_rn(s1[3]));
            pfh[g2][0] = pack_hf2(h00, h01);
            pfh[g2][1] = pack_hf2(h02, h03);
            pfh[g2][2] = pack_hf2(h10, h11);
            pfh[g2][3] = pack_hf2(h12, h13);
            pfl[g2][0] = pack_hf2(s0[0] - h00, s0[1] - h01);
            pfl[g2][1] = pack_hf2(s0[2] - h02, s0[3] - h03);
            pfl[g2][2] = pack_hf2(s1[0] - h10, s1[1] - h11);
            pfl[g2][3] = pack_hf2(s1[2] - h12, s1[3] - h13);
        }

        #pragma unroll
        for (int g2 = 0; g2 < 4; ++g2) {
            const uint32_t kb = (uint32_t)(g2 * 32);
            uint32_t vh[8][2];
            #pragma unroll
            for (int p = 0; p < 4; ++p) {
                const uint32_t ro = (uint32_t)(p * 16 * SP * 2);
                uint32_t r[4];
                ldsm4(r, sb + 1 * F_ARR + b_off + ro + kb);
                vh[2 * p][0] = r[0]; vh[2 * p][1] = r[1];
                vh[2 * p + 1][0] = r[2]; vh[2 * p + 1][1] = r[3];
            }
            #pragma unroll
            for (int nf = 0; nf < 8; ++nf) {
                mma_fp16(oacc[nf], pfh[g2], vh[nf]);
                mma_fp16(oacc[nf], pfl[g2], vh[nf]);
            }
        }
        __syncthreads();
    }

    // ---- epilogue: normalized output, pre-split fp16 hi/lo for O-projection ----
    const float inv_a = 1.0f / l[0];
    const float inv_b = 1.0f / l[1];
    const size_t rA = ((size_t)(b * SEQ) + row_a) * DIM + h * HD;
    const size_t rB = rA + 8 * DIM;
    #pragma unroll
    for (int nf = 0; nf < 8; ++nf) {
        const int col = nf * 8 + tid4 * 2;
        float f0 = oacc[nf][0] * inv_a, f1 = oacc[nf][1] * inv_a;
        float f2 = oacc[nf][2] * inv_b, f3 = oacc[nf][3] * inv_b;
        __half h0, l0, h1, l1, h2, l2, h3, l3;
        fp16_split(f0, h0, l0);
        fp16_split(f1, h1, l1);
        fp16_split(f2, h2, l2);
        fp16_split(f3, h3, l3);
        __half2 vhA; vhA.x = h0; vhA.y = h1;
        __half2 vlA; vlA.x = l0; vlA.y = l1;
        __half2 vhB; vhB.x = h2; vhB.y = h3;
        __half2 vlB; vlB.x = l2; vlB.y = l3;
        *(__half2*)(Oh + rA + col) = vhA;
        *(__half2*)(Ol + rA + col) = vlA;
        *(__half2*)(Oh + rB + col) = vhB;
        *(__half2*)(Ol + rB + col) = vlB;
    }
}

// ---------------- host launcher ----------------
extern "C" void kernel_launch(void* const* d_in, const int* in_sizes, int n_in,
                              void* d_out, int out_size) {
    (void)in_sizes; (void)n_in; (void)out_size;
    const float* x  = (const float*)d_in[0];
    const float* Wq = (const float*)d_in[1];
    const float* Wk = (const float*)d_in[2];
    const float* Wv = (const float*)d_in[3];
    const float* bv = (const float*)d_in[4];
    const float* Wo = (const float*)d_in[5];
    const float* bo = (const float*)d_in[6];
    float* out = (float*)d_out;

    float *qkvlin, *biasqkv;
    __half *ah, *al, *bh, *qh, *ql, *kh, *vth;
    cudaGetSymbolAddress((void**)&qkvlin,  g_qkvlin);
    cudaGetSymbolAddress((void**)&biasqkv, g_biasqkv);
    cudaGetSymbolAddress((void**)&ah,  g_ah);
    cudaGetSymbolAddress((void**)&al,  g_al);
    cudaGetSymbolAddress((void**)&bh,  g_bh);
    cudaGetSymbolAddress((void**)&qh,  g_qh);
    cudaGetSymbolAddress((void**)&ql,  g_ql);
    cudaGetSymbolAddress((void**)&kh,  g_kh);
    cudaGetSymbolAddress((void**)&vth, g_vth);

    cudaFuncSetAttribute(mma_gemm_fp16, cudaFuncAttributeMaxDynamicSharedMemorySize, G_SMEM);
    cudaFuncSetAttribute(flash_mma_kernel, cudaFuncAttributeMaxDynamicSharedMemorySize, F_SMEM);

    theta_kernel<<<1, 32>>>();
    sincos_kernel<<<(SEQ * 32) / 256, 256>>>();
    biasqkv_kernel<<<NQKV / 256, 256>>>(bv);

    // split activations once (fp16 hi/lo)
    split_kernel<<<(MROWS * DIM) / 1024, 256>>>(x, ah, al);

    // merged QKV projection (N = 3072), weights fp16 hi only
    transpose_half_kernel<<<dim3(DIM / 32, DIM / 32), dim3(32, 8)>>>(Wq, bh, DIM, DIM);
    transpose_half_kernel<<<dim3(KVDIM / 32, DIM / 32), dim3(32, 8)>>>(
        Wk, bh + (size_t)DIM * DIM, DIM, KVDIM);
    transpose_half_kernel<<<dim3(KVDIM / 32, DIM / 32), dim3(32, 8)>>>(
        Wv, bh + (size_t)(DIM + KVDIM) * DIM, DIM, KVDIM);
    mma_gemm_fp16<<<dim3(NQKV / 128, MROWS / 128), 256, G_SMEM>>>(
        ah, al, bh, biasqkv, qkvlin, NQKV, DIM);

    rope_q_kernel<<<(BATCH * SEQ * NH * 32) / 256, 256>>>(qkvlin, qh, ql);
    rope_k_kernel<<<(BATCH * SEQ * NKV * 32) / 256, 256>>>(qkvlin, kh);
    transpose_v_kernel<<<dim3(SEQ / 32, HD / 32, BATCH * NKV), dim3(32, 8)>>>(qkvlin, vth);

    // flash writes pre-split fp16 ah/al for the O projection
    flash_mma_kernel<<<dim3(SEQ / FQ, NH, BATCH), 256, F_SMEM>>>(
        qh, ql, kh, vth, ah, al);

    transpose_half_kernel<<<dim3(DIM / 32, DIM / 32), dim3(32, 8)>>>(Wo, bh, DIM, DIM);
    mma_gemm_fp16<<<dim3(DIM / 128, MROWS / 128), 256, G_SMEM>>>(ah, al, bh, bo, out, DIM, DIM);
}

// round 11
// speedup vs baseline: 4.4109x; 1.0527x over previous
#include <cuda_runtime.h>
#include <cuda_fp16.h>
#include <math.h>
#include <stdint.h>

#define DIM 2048
#define NH 32
#define NKV 8
#define HD 64
#define BATCH 2
#define SEQ 2048
#define MROWS (BATCH*SEQ)   /* 4096 */
#define KVDIM (NKV*HD)      /* 512 */
#define NQKV (DIM + 2*KVDIM) /* 3072 */

// ---------------- scratch (static device allocations; no cudaMalloc) ----------------
// GEMM operands: activations fp16 hi/lo, weights fp16 hi only
__device__ __align__(16) __half g_ah[(size_t)MROWS * DIM];
__device__ __align__(16) __half g_al[(size_t)MROWS * DIM];
__device__ __align__(16) __half g_bh[(size_t)NQKV * DIM];
// flash operands: Q fp16 hi/lo; K,V fp16 hi only
__device__ __align__(16) __half g_qh[(size_t)BATCH * NH * SEQ * HD];
__device__ __align__(16) __half g_ql[(size_t)BATCH * NH * SEQ * HD];
__device__ __align__(16) __half g_kh[(size_t)BATCH * NKV * SEQ * HD];
__device__ __align__(16) __half g_vth[(size_t)BATCH * NKV * HD * SEQ];  // [b,kv,d,s]
__device__ float2 g_cs[(size_t)SEQ * (HD / 2)];

// ---------------- RoPE table (theta fused in) ----------------
__global__ void sincos_kernel() {
    int idx = blockIdx.x * blockDim.x + threadIdx.x;   // SEQ*32
    int s = idx >> 5, p = idx & 31;
    double theta = pow(10000.0, -(double)p / 32.0);
    float ang = (float)((double)s * theta);
    float sv, cv;
    sincosf(ang, &sv, &cv);
    g_cs[idx] = make_float2(cv, sv);
}

// ---------------- split helpers ----------------
__device__ __forceinline__ void fp16_split(float x, __half& h, __half& l) {
    h = __float2half_rn(x);
    l = __float2half_rn(x - __half2float(h));
}

// activations: fp32 -> fp16 hi/lo
__global__ void split_kernel(const float* __restrict__ in,
                             __half* __restrict__ oh,
                             __half* __restrict__ ol) {
    const int i = blockIdx.x * blockDim.x + threadIdx.x;
    const float4 v = *(const float4*)(in + (size_t)i * 4);
    __half h[4], l[4];
    fp16_split(v.x, h[0], l[0]);
    fp16_split(v.y, h[1], l[1]);
    fp16_split(v.z, h[2], l[2]);
    fp16_split(v.w, h[3], l[3]);
    *(uint2*)(oh + (size_t)i * 4) = *(uint2*)h;
    *(uint2*)(ol + (size_t)i * 4) = *(uint2*)l;
}

// weight transpose: in R x C fp32 -> out C x R fp16 (hi only)
__global__ void transpose_half_kernel(const float* __restrict__ in,
                                      __half* __restrict__ oh,
                                      int R, int Ccols) {
    __shared__ float tile[32][33];
    int bx = blockIdx.x * 32, by = blockIdx.y * 32;
    int x = bx + threadIdx.x;
    #pragma unroll
    for (int i = 0; i < 32; i += 8)
        tile[threadIdx.y + i][threadIdx.x] = in[(size_t)(by + threadIdx.y + i) * Ccols + x];
    __syncthreads();
    int ox = by + threadIdx.x;
    #pragma unroll
    for (int i = 0; i < 32; i += 8)
        oh[(size_t)(bx + threadIdx.y + i) * R + ox] = __float2half_rn(tile[threadIdx.x][threadIdx.y + i]);
}

// ================= mma.sync / async helpers =================
__device__ __forceinline__ uint32_t smem_u32(const void* p) {
    uint32_t a;
    asm("{ .reg .u64 t; cvta.to.shared.u64 t, %1; cvt.u32.u64 %0, t; }" : "=r"(a) : "l"(p));
    return a;
}
__device__ __forceinline__ void cp16(uint32_t dst, const void* src) {
    asm volatile("cp.async.cg.shared.global [%0], [%1], 16;" :: "r"(dst), "l"(src));
}
#define CP_COMMIT() asm volatile("cp.async.commit_group;" ::: "memory")
#define CP_WAIT1()  asm volatile("cp.async.wait_group 1;" ::: "memory")

__device__ __forceinline__ void ldsm4(uint32_t* r, uint32_t addr) {
    asm volatile("ldmatrix.sync.aligned.m8n8.x4.shared.b16 {%0,%1,%2,%3}, [%4];"
                 : "=r"(r[0]), "=r"(r[1]), "=r"(r[2]), "=r"(r[3]) : "r"(addr));
}
__device__ __forceinline__ void mma_fp16(float* d, const uint32_t* a, const uint32_t* b) {
    asm volatile(
        "mma.sync.aligned.m16n8k16.row.col.f32.f16.f16.f32 "
        "{%0,%1,%2,%3}, {%4,%5,%6,%7}, {%8,%9}, {%0,%1,%2,%3};\n"
        : "+f"(d[0]), "+f"(d[1]), "+f"(d[2]), "+f"(d[3])
        : "r"(a[0]), "r"(a[1]), "r"(a[2]), "r"(a[3]), "r"(b[0]), "r"(b[1]));
}
__device__ __forceinline__ uint32_t pack_hf2(float x0, float x1) {
    __half2 v = __floats2half2_rn(x0, x1);
    return *(uint32_t*)&v;
}
__device__ __forceinline__ float exp2p(float y) {
    y = fmaxf(y, -120.f);
    int ki = __float2int_rn(y);
    float f = y - (float)ki;
    float p = 0.0013333558f;
    p = fmaf(p, f, 0.0096181291f);
    p = fmaf(p, f, 0.0555041087f);
    p = fmaf(p, f, 0.2402265070f);
    p = fmaf(p, f, 0.6931471806f);
    p = fmaf(p, f, 1.0f);
    return p * __int_as_float((ki + 127) << 23);
}

// ---------------- fp16 2-term GEMM, 3-stage pipeline ----------------
// C = (Ah+Al) @ Bh^T. mode 0: +bias -> fp32 C. mode 1 (QKV): fused
// rope+split epilogue writing g_qh/g_ql/g_kh/g_vth directly (bias = bv for V).
#define BPAD 40
#define G_ARRB (128 * BPAD * 2)     /* 10240 B */
#define G_BUFB (3 * G_ARRB)         /* 30720 B per stage */
#define G_SMEM (3 * G_BUFB)         /* 92160 B, 3 stages */

__global__ void __launch_bounds__(256, 2) mma_gemm_fp16(
    const __half* __restrict__ Ah, const __half* __restrict__ Al,
    const __half* __restrict__ Bh,
    const float* __restrict__ bias, float* __restrict__ C, int N, int K,
    int qkv_mode)
{
    extern __shared__ char smem[];
    const uint32_t smbase = smem_u32(smem);

    const int t    = threadIdx.x;
    const int lane = t & 31;
    const int wid  = t >> 5;
    const int wr   = wid & 3;
    const int wc   = wid >> 2;
    const int qid  = lane >> 2;
    const int tid4 = lane & 3;

    const size_t m0 = (size_t)blockIdx.y * 128;
    const size_t n0 = (size_t)blockIdx.x * 128;
    const __half* Abh = Ah + m0 * K;
    const __half* Abl = Al + m0 * K;
    const __half* Bbh = Bh + n0 * K;

    const uint32_t a_off = (uint32_t)(((wr * 32 + (lane & 15)) * BPAD + ((lane >> 4) << 3)) * 2);
    const uint32_t b_off = (uint32_t)(((wc * 64 + (lane & 7) + ((lane & 16) >> 1)) * BPAD + (lane & 8)) * 2);

    float acc[2][8][4];
    #pragma unroll
    for (int mf = 0; mf < 2; ++mf)
        #pragma unroll
        for (int nf = 0; nf < 8; ++nf)
            #pragma unroll
            for (int r = 0; r < 4; ++r) acc[mf][nf][r] = 0.f;

    const int nchunks = K / 32;   // 64

    // prologue: chunks 0,1 -> stages 0,1
    #pragma unroll
    for (int pc = 0; pc < 2; ++pc) {
        const uint32_t dst = smbase + (uint32_t)(pc * G_BUFB);
        #pragma unroll
        for (int i = 0; i < 6; ++i) {
            const int o = t + i * 256;
            const int arr = o >> 9;
            const int r = (o & 511) >> 2, c = (o & 3) * 8;
            const __half* src = ((arr == 0) ? Abh : (arr == 1) ? Abl : Bbh) + (size_t)r * K + pc * 32 + c;
            cp16(dst + (uint32_t)(arr * G_ARRB) + (uint32_t)((r * BPAD + c) * 2), src);
        }
        CP_COMMIT();
    }

    for (int cch = 0; cch < nchunks; ++cch) {
        CP_WAIT1();
        __syncthreads();

        const uint32_t sb = smbase + (uint32_t)((cch % 3) * G_BUFB);
        #pragma unroll
        for (int ks = 0; ks < 2; ++ks) {
            const uint32_t kb = (uint32_t)(ks * 32);
            uint32_t ah[2][4], al[2][4];
            #pragma unroll
            for (int mf = 0; mf < 2; ++mf) {
                const uint32_t ro = (uint32_t)(mf * 16 * BPAD * 2);
                ldsm4(ah[mf], sb + 0 * G_ARRB + a_off + ro + kb);
                ldsm4(al[mf], sb + 1 * G_ARRB + a_off + ro + kb);
            }
            uint32_t bh[8][2];
            #pragma unroll
            for (int p = 0; p < 4; ++p) {
                const uint32_t ro = (uint32_t)(p * 16 * BPAD * 2);
                uint32_t r[4];
                ldsm4(r, sb + 2 * G_ARRB + b_off + ro + kb);
                bh[2 * p][0] = r[0]; bh[2 * p][1] = r[1];
                bh[2 * p + 1][0] = r[2]; bh[2 * p + 1][1] = r[3];
            }
            #pragma unroll
            for (int nf = 0; nf < 8; ++nf)
                #pragma unroll
                for (int mf = 0; mf < 2; ++mf) {
                    mma_fp16(acc[mf][nf], ah[mf], bh[nf]);
                    mma_fp16(acc[mf][nf], al[mf], bh[nf]);
                }
        }

        // issue chunk cch+2 into stage (cch+2)%3 (safe: all warps are past
        // the barrier above, hence done computing chunk cch-1)
        if (cch + 2 < nchunks) {
            const uint32_t dst = smbase + (uint32_t)(((cch + 2) % 3) * G_BUFB);
            const int k0 = (cch + 2) * 32;
            #pragma unroll
            for (int i = 0; i < 6; ++i) {
                const int o = t + i * 256;
                const int arr = o >> 9;
                const int r = (o & 511) >> 2, c = (o & 3) * 8;
                const __half* src = ((arr == 0) ? Abh : (arr == 1) ? Abl : Bbh) + (size_t)r * K + k0 + c;
                cp16(dst + (uint32_t)(arr * G_ARRB) + (uint32_t)((r * BPAD + c) * 2), src);
            }
        }
        CP_COMMIT();
    }

    // ---------------- epilogue ----------------
    const int trow = qid;
    const int tcol = tid4 * 2;
    if (!qkv_mode) {
        #pragma unroll
        for (int mf = 0; mf < 2; ++mf) {
            const size_t m = m0 + wr * 32 + mf * 16 + trow;
            #pragma unroll
            for (int nf = 0; nf < 8; ++nf) {
                const int ncol = (int)n0 + wc * 64 + nf * 8 + tcol;
                float2 v0 = make_float2(acc[mf][nf][0], acc[mf][nf][1]);
                float2 v1 = make_float2(acc[mf][nf][2], acc[mf][nf][3]);
                const float bx = bias[ncol], by = bias[ncol + 1];
                v0.x += bx; v0.y += by;
                v1.x += bx; v1.y += by;
                *(float2*)(C + m * N + ncol)       = v0;
                *(float2*)(C + (m + 8) * N + ncol) = v1;
            }
        }
        return;
    }

    // fused QKV epilogue: rope + fp16 split + layout, no fp32 intermediate
    #pragma unroll
    for (int mf = 0; mf < 2; ++mf) {
        const size_t m = m0 + wr * 32 + mf * 16 + trow;   // m and m+8 share batch
        const int b = (int)(m >> 11);
        const int s = (int)(m & 2047);
        #pragma unroll
        for (int nf = 0; nf < 8; ++nf) {
            const int ncol = (int)n0 + wc * 64 + nf * 8 + tcol;
            float2 v0 = make_float2(acc[mf][nf][0], acc[mf][nf][1]);   // row m
            float2 v1 = make_float2(acc[mf][nf][2], acc[mf][nf][3]);   // row m+8
            if (ncol < DIM) {
                // Q: rope + split hi/lo
                const int h = ncol >> 6, d = ncol & 63, p = d >> 1;
                const float2 c0 = g_cs[s * 32 + p];
                const float2 c1 = g_cs[(s + 8) * 32 + p];
                float r0x = v0.x * c0.x - v0.y * c0.y;
                float r0y = v0.x * c0.y + v0.y * c0.x;
                float r1x = v1.x * c1.x - v1.y * c1.y;
                float r1y = v1.x * c1.y + v1.y * c1.x;
                __half h0, l0, h1, l1, h2, l2, h3, l3;
                fp16_split(r0x, h0, l0);
                fp16_split(r0y, h1, l1);
                fp16_split(r1x, h2, l2);
                fp16_split(r1y, h3, l3);
                const size_t o0 = (((size_t)(b * NH + h)) * SEQ + s) * HD + d;
                const size_t o1 = o0 + 8 * HD;
                __half2 a0; a0.x = h0; a0.y = h1;
                __half2 b0; b0.x = l0; b0.y = l1;
                __half2 a1; a1.x = h2; a1.y = h3;
                __half2 b1; b1.x = l2; b1.y = l3;
                *(__half2*)(g_qh + o0) = a0;
                *(__half2*)(g_ql + o0) = b0;
                *(__half2*)(g_qh + o1) = a1;
                *(__half2*)(g_ql + o1) = b1;
            } else if (ncol < DIM + KVDIM) {
                // K: rope, hi only
                const int kc = ncol - DIM;
                const int kv = kc >> 6, d = kc & 63, p = d >> 1;
                const float2 c0 = g_cs[s * 32 + p];
                const float2 c1 = g_cs[(s + 8) * 32 + p];
                float r0x = v0.x * c0.x - v0.y * c0.y;
                float r0y = v0.x * c0.y + v0.y * c0.x;
                float r1x = v1.x * c1.x - v1.y * c1.y;
                float r1y = v1.x * c1.y + v1.y * c1.x;
                const size_t o0 = (((size_t)(b * NKV + kv)) * SEQ + s) * HD + d;
                const size_t o1 = o0 + 8 * HD;
                *(__half2*)(g_kh + o0) = __floats2half2_rn(r0x, r0y);
                *(__half2*)(g_kh + o1) = __floats2half2_rn(r1x, r1y);
            } else {
                // V: + bias, transposed [b,kv,d,s], hi only
                const int vc = ncol - DIM - KVDIM;
                const int kv = vc >> 6, d = vc & 63;
                const float bx = bias[vc], by = bias[vc + 1];
                const size_t base = ((size_t)(b * NKV + kv) * HD + d) * SEQ;
                g_vth[base + s]           = __float2half_rn(v0.x + bx);
                g_vth[base + SEQ + s]     = __float2half_rn(v0.y + by);
                g_vth[base + s + 8]       = __float2half_rn(v1.x + bx);
                g_vth[base + SEQ + s + 8] = __float2half_rn(v1.y + by);
            }
        }
    }
}

// ---------------- flash attention v5: 3-stage pipeline, Q resident, 2 CTAs/SM ------
#define FQ 128
#define FK 64
#define SP 72
#define F_QARR (FQ * SP * 2)           /* 18432 */
#define QOFF   (2 * F_QARR)            /* 36864 */
#define F_ARR  (FK * SP * 2)           /* 9216 per K/V array */
#define F_BUF  (2 * F_ARR)             /* Kh Vth = 18432 per stage */
#define F_SMEM (QOFF + 3 * F_BUF)      /* 92160 */

__global__ void __launch_bounds__(256, 2) flash_mma_kernel(
    const __half* __restrict__ Qh, const __half* __restrict__ Ql,
    const __half* __restrict__ Kh, const __half* __restrict__ Vth,
    __half* __restrict__ Oh, __half* __restrict__ Ol)
{
    extern __shared__ char smem[];
    const uint32_t smbase = smem_u32(smem);

    const int qt  = (SEQ / FQ - 1) - blockIdx.x;
    const int h   = blockIdx.y;
    const int b   = blockIdx.z;
    const int kvh = h >> 2;
    const int t    = threadIdx.x;
    const int lane = t & 31;
    const int w    = t >> 5;
    const int qid  = lane >> 2;
    const int tid4 = lane & 3;
    const int q0   = qt * FQ;
    const int wrow = w * 16;

    const __half* Qhb = Qh + (((size_t)(b * NH + h)) * SEQ + q0) * HD;
    const __half* Qlb = Ql + (((size_t)(b * NH + h)) * SEQ + q0) * HD;
    const __half* Khb = Kh + ((size_t)(b * NKV + kvh)) * SEQ * HD;
    const __half* Vhb = Vth + ((size_t)(b * NKV + kvh)) * HD * SEQ;

    #pragma unroll
    for (int i = 0; i < 4; ++i) {
        const int idx = t + i * 256;
        const int r = idx >> 3, c = (idx & 7) * 8;
        *(uint4*)(smem + (r * SP + c) * 2)          = *(const uint4*)(Qhb + (size_t)r * HD + c);
        *(uint4*)(smem + F_QARR + (r * SP + c) * 2) = *(const uint4*)(Qlb + (size_t)r * HD + c);
    }

    const uint32_t a_off = (uint32_t)(((wrow + (lane & 15)) * SP + ((lane >> 4) << 3)) * 2);
    const uint32_t b_off = (uint32_t)((((lane & 7) + ((lane & 16) >> 1)) * SP + (lane & 8)) * 2);

    const int ga  = t >> 7;
    const int sub = t & 127;
    const __half* gsrc = (ga == 0) ? Khb : Vhb;
    const bool isK = (ga == 0);

    float oacc[8][4];
    #pragma unroll
    for (int nf = 0; nf < 8; ++nf)
        #pragma unroll
        for (int j = 0; j < 4; ++j) oacc[nf][j] = 0.f;
    float m[2] = {-1e30f, -1e30f};
    float l[2] = {0.f, 0.f};

    const int row_a = q0 + wrow + qid;
    const int row_b = row_a + 8;
    const float SC = 0.125f * 1.4426950408889634f;

    const int ntiles = (q0 + FQ) / FK;   // >= 2

    // prologue: tiles 0,1 -> stages 0,1
    #pragma unroll
    for (int pt = 0; pt < 2; ++pt) {
        const uint32_t dst = smbase + QOFF + (uint32_t)(pt * F_BUF) + (uint32_t)(ga * F_ARR);
        #pragma unroll
        for (int i = 0; i < 4; ++i) {
            const int idx = sub + i * 128;
            const int row = idx >> 3, col = (idx & 7) * 8;
            const __half* s = isK ? (gsrc + (size_t)(pt * FK + row) * HD + col)
                                  : (gsrc + (size_t)row * SEQ + pt * FK + col);
            cp16(dst + (uint32_t)((row * SP + col) * 2), s);
        }
        CP_COMMIT();
    }
    __syncthreads();   // covers Q staging too (before first ldsm of Q)

    for (int kt = 0; kt < ntiles; ++kt) {
        CP_WAIT1();
        __syncthreads();

        const uint32_t sb = smbase + QOFF + (uint32_t)((kt % 3) * F_BUF);

        float sacc[8][4];
        #pragma unroll
        for (int nf = 0; nf < 8; ++nf)
            #pragma unroll
            for (int j = 0; j < 4; ++j) sacc[nf][j] = 0.f;

        #pragma unroll
        for (int g2 = 0; g2 < 4; ++g2) {
            const uint32_t kb = (uint32_t)(g2 * 32);
            uint32_t qh4[4], ql4[4];
            ldsm4(qh4, smbase + a_off + kb);
            ldsm4(ql4, smbase + F_QARR + a_off + kb);
            uint32_t bh[8][2];
            #pragma unroll
            for (int p = 0; p < 4; ++p) {
                const uint32_t ro = (uint32_t)(p * 16 * SP * 2);
                uint32_t r[4];
                ldsm4(r, sb + 0 * F_ARR + b_off + ro + kb);
                bh[2 * p][0] = r[0]; bh[2 * p][1] = r[1];
                bh[2 * p + 1][0] = r[2]; bh[2 * p + 1][1] = r[3];
            }
            #pragma unroll
            for (int nf = 0; nf < 8; ++nf) {
                mma_fp16(sacc[nf], qh4, bh[nf]);
                mma_fp16(sacc[nf], ql4, bh[nf]);
            }
        }

        const bool need_mask = (kt * FK + FK - 1) > row_a;
        float tmax[2] = {-1e30f, -1e30f};
        #pragma unroll
        for (int nf = 0; nf < 8; ++nf) {
            const int colbase = kt * FK + nf * 8 + tid4 * 2;
            #pragma unroll
            for (int j = 0; j < 4; ++j) {
                const int col = colbase + (j & 1);
                const int row = (j < 2) ? row_a : row_b;
                float v = sacc[nf][j] * SC;
                if (need_mask && col > row) v = -1e30f;
                sacc[nf][j] = v;
                tmax[j >> 1] = fmaxf(tmax[j >> 1], v);
            }
        }

        float corr[2];
        #pragma unroll
        for (int hh = 0; hh < 2; ++hh) {
            tmax[hh] = fmaxf(tmax[hh], __shfl_xor_sync(0xffffffffu, tmax[hh], 1));
            tmax[hh] = fmaxf(tmax[hh], __shfl_xor_sync(0xffffffffu, tmax[hh], 2));
            const float mnew = fmaxf(m[hh], tmax[hh]);
            corr[hh] = exp2p(m[hh] - mnew);
            m[hh] = mnew;
            l[hh] *= corr[hh];
        }
        #pragma unroll
        for (int nf = 0; nf < 8; ++nf) {
            oacc[nf][0] *= corr[0]; oacc[nf][1] *= corr[0];
            oacc[nf][2] *= corr[1]; oacc[nf][3] *= corr[1];
        }
        float rsum[2] = {0.f, 0.f};
        #pragma unroll
        for (int nf = 0; nf < 8; ++nf) {
            #pragma unroll
            for (int j = 0; j < 4; ++j) {
                const float p = exp2p(sacc[nf][j] - m[j >> 1]);
                sacc[nf][j] = p;
                rsum[j >> 1] += p;
            }
        }
        #pragma unroll
        for (int hh = 0; hh < 2; ++hh) {
            rsum[hh] += __shfl_xor_sync(0xffffffffu, rsum[hh], 1);
            rsum[hh] += __shfl_xor_sync(0xffffffffu, rsum[hh], 2);
            l[hh] += rsum[hh];
        }

        uint32_t pfh[4][4], pfl[4][4];
        #pragma unroll
        for (int g2 = 0; g2 < 4; ++g2) {
            const float* s0 = sacc[2 * g2];
            const float* s1 = sacc[2 * g2 + 1];
            float h00 = __half2float(__float2half_rn(s0[0]));
            float h01 = __half2float(__float2half_rn(s0[1]));
            float h02 = __half2float(__float2half_rn(s0[2]));
            float h03 = __half2float(__float2half_rn(s0[3]));
            float h10 = __half2float(__float2half_rn(s1[0]));
            float h11 = __half2float(__float2half_rn(s1[1]));
            float h12 = __half2float(__float2half_rn(s1[2]));
            float h13 = __half2float(__float2half_rn(s1[3]));
            pfh[g2][0] = pack_hf2(h00, h01);
            pfh[g2][1] = pack_hf2(h02, h03);
            pfh[g2][2] = pack_hf2(h10, h11);
            pfh[g2][3] = pack_hf2(h12, h13);
            pfl[g2][0] = pack_hf2(s0[0] - h00, s0[1] - h01);
            pfl[g2][1] = pack_hf2(s0[2] - h02, s0[3] - h03);
            pfl[g2][2] = pack_hf2(s1[0] - h10, s1[1] - h11);
            pfl[g2][3] = pack_hf2(s1[2] - h12, s1[3] - h13);
        }

        #pragma unroll
        for (int g2 = 0; g2 < 4; ++g2) {
            const uint32_t kb = (uint32_t)(g2 * 32);
            uint32_t vh[8][2];
            #pragma unroll
            for (int p = 0; p < 4; ++p) {
                const uint32_t ro = (uint32_t)(p * 16 * SP * 2);
                uint32_t r[4];
                ldsm4(r, sb + 1 * F_ARR + b_off + ro + kb);
                vh[2 * p][0] = r[0]; vh[2 * p][1] = r[1];
                vh[2 * p + 1][0] = r[2]; vh[2 * p + 1][1] = r[3];
            }
            #pragma unroll
            for (int nf = 0; nf < 8; ++nf) {
                mma_fp16(oacc[nf], pfh[g2], vh[nf]);
                mma_fp16(oacc[nf], pfl[g2], vh[nf]);
            }
        }

        // issue tile kt+2 into stage (kt+2)%3 (safe after top-of-loop barrier)
        if (kt + 2 < ntiles) {
            const uint32_t dst = smbase + QOFF + (uint32_t)(((kt + 2) % 3) * F_BUF) + (uint32_t)(ga * F_ARR);
            #pragma unroll
            for (int i = 0; i < 4; ++i) {
                const int idx = sub + i * 128;
                const int row = idx >> 3, col = (idx & 7) * 8;
                const __half* s = isK
                    ? (gsrc + (size_t)((kt + 2) * FK + row) * HD + col)
                    : (gsrc + (size_t)row * SEQ + (kt + 2) * FK + col);
                cp16(dst + (uint32_t)((row * SP + col) * 2), s);
            }
        }
        CP_COMMIT();
    }

    // ---- epilogue: normalized output, pre-split fp16 hi/lo for O-projection ----
    const float inv_a = 1.0f / l[0];
    const float inv_b = 1.0f / l[1];
    const size_t rA = ((size_t)(b * SEQ) + row_a) * DIM + h * HD;
    const size_t rB = rA + 8 * DIM;
    #pragma unroll
    for (int nf = 0; nf < 8; ++nf) {
        const int col = nf * 8 + tid4 * 2;
        float f0 = oacc[nf][0] * inv_a, f1 = oacc[nf][1] * inv_a;
        float f2 = oacc[nf][2] * inv_b, f3 = oacc[nf][3] * inv_b;
        __half h0, l0, h1, l1, h2, l2, h3, l3;
        fp16_split(f0, h0, l0);
        fp16_split(f1, h1, l1);
        fp16_split(f2, h2, l2);
        fp16_split(f3, h3, l3);
        __half2 vhA; vhA.x = h0; vhA.y = h1;
        __half2 vlA; vlA.x = l0; vlA.y = l1;
        __half2 vhB; vhB.x = h2; vhB.y = h3;
        __half2 vlB; vlB.x = l2; vlB.y = l3;
        *(__half2*)(Oh + rA + col) = vhA;
        *(__half2*)(Ol + rA + col) = vlA;
        *(__half2*)(Oh + rB + col) = vhB;
        *(__half2*)(Ol + rB + col) = vlB;
    }
}

// ---------------- host launcher ----------------
extern "C" void kernel_launch(void* const* d_in, const int* in_sizes, int n_in,
                              void* d_out, int out_size) {
    (void)in_sizes; (void)n_in; (void)out_size;
    const float* x  = (const float*)d_in[0];
    const float* Wq = (const float*)d_in[1];
    const float* Wk = (const float*)d_in[2];
    const float* Wv = (const float*)d_in[3];
    const float* bv = (const float*)d_in[4];
    const float* Wo = (const float*)d_in[5];
    const float* bo = (const float*)d_in[6];
    float* out = (float*)d_out;

    __half *ah, *al, *bh, *qh, *ql, *kh, *vth;
    cudaGetSymbolAddress((void**)&ah,  g_ah);
    cudaGetSymbolAddress((void**)&al,  g_al);
    cudaGetSymbolAddress((void**)&bh,  g_bh);
    cudaGetSymbolAddress((void**)&qh,  g_qh);
    cudaGetSymbolAddress((void**)&ql,  g_ql);
    cudaGetSymbolAddress((void**)&kh,  g_kh);
    cudaGetSymbolAddress((void**)&vth, g_vth);

    cudaFuncSetAttribute(mma_gemm_fp16, cudaFuncAttributeMaxDynamicSharedMemorySize, G_SMEM);
    cudaFuncSetAttribute(flash_mma_kernel, cudaFuncAttributeMaxDynamicSharedMemorySize, F_SMEM);

    sincos_kernel<<<(SEQ * 32) / 256, 256>>>();

    // split activations once (fp16 hi/lo)
    split_kernel<<<(MROWS * DIM) / 1024, 256>>>(x, ah, al);

    // merged QKV projection (N = 3072), fused rope/split/transpose epilogue
    transpose_half_kernel<<<dim3(DIM / 32, DIM / 32), dim3(32, 8)>>>(Wq, bh, DIM, DIM);
    transpose_half_kernel<<<dim3(KVDIM / 32, DIM / 32), dim3(32, 8)>>>(
        Wk, bh + (size_t)DIM * DIM, DIM, KVDIM);
    transpose_half_kernel<<<dim3(KVDIM / 32, DIM / 32), dim3(32, 8)>>>(
        Wv, bh + (size_t)(DIM + KVDIM) * DIM, DIM, KVDIM);
    mma_gemm_fp16<<<dim3(NQKV / 128, MROWS / 128), 256, G_SMEM>>>(
        ah, al, bh, bv, nullptr, NQKV, DIM, 1);

    // flash writes pre-split fp16 ah/al for the O projection
    flash_mma_kernel<<<dim3(SEQ / FQ, NH, BATCH), 256, F_SMEM>>>(
        qh, ql, kh, vth, ah, al);

    transpose_half_kernel<<<dim3(DIM / 32, DIM / 32), dim3(32, 8)>>>(Wo, bh, DIM, DIM);
    mma_gemm_fp16<<<dim3(DIM / 128, MROWS / 128), 256, G_SMEM>>>(
        ah, al, bh, bo, out, DIM, DIM, 0);
}

// round 12
// speedup vs baseline: 4.8159x; 1.0918x over previous
#include <cuda_runtime.h>
#include <cuda_fp16.h>
#include <math.h>
#include <stdint.h>

#define DIM 2048
#define NH 32
#define NKV 8
#define HD 64
#define BATCH 2
#define SEQ 2048
#define MROWS (BATCH*SEQ)   /* 4096 */
#define KVDIM (NKV*HD)      /* 512 */
#define NQKV (DIM + 2*KVDIM) /* 3072 */

// ---------------- scratch (static device allocations; no cudaMalloc) ----------------
// GEMM operands: activations fp16 hi/lo, weights fp16 hi only
__device__ __align__(16) __half g_ah[(size_t)MROWS * DIM];
__device__ __align__(16) __half g_al[(size_t)MROWS * DIM];
__device__ __align__(16) __half g_bh[(size_t)NQKV * DIM];
// flash operands: Q fp16 hi/lo; K,V fp16 hi only
__device__ __align__(16) __half g_qh[(size_t)BATCH * NH * SEQ * HD];
__device__ __align__(16) __half g_ql[(size_t)BATCH * NH * SEQ * HD];
__device__ __align__(16) __half g_kh[(size_t)BATCH * NKV * SEQ * HD];
__device__ __align__(16) __half g_vth[(size_t)BATCH * NKV * HD * SEQ];  // [b,kv,d,s]
__device__ float2 g_cs[(size_t)SEQ * (HD / 2)];

// ---------------- RoPE table ----------------
__global__ void sincos_kernel() {
    int idx = blockIdx.x * blockDim.x + threadIdx.x;   // SEQ*32
    int s = idx >> 5, p = idx & 31;
    double theta = pow(10000.0, -(double)p / 32.0);
    float ang = (float)((double)s * theta);
    float sv, cv;
    sincosf(ang, &sv, &cv);
    g_cs[idx] = make_float2(cv, sv);
}

// ---------------- split helpers ----------------
__device__ __forceinline__ void fp16_split(float x, __half& h, __half& l) {
    h = __float2half_rn(x);
    l = __float2half_rn(x - __half2float(h));
}

// activations: fp32 -> fp16 hi/lo
__global__ void split_kernel(const float* __restrict__ in,
                             __half* __restrict__ oh,
                             __half* __restrict__ ol) {
    const int i = blockIdx.x * blockDim.x + threadIdx.x;
    const float4 v = *(const float4*)(in + (size_t)i * 4);
    __half h[4], l[4];
    fp16_split(v.x, h[0], l[0]);
    fp16_split(v.y, h[1], l[1]);
    fp16_split(v.z, h[2], l[2]);
    fp16_split(v.w, h[3], l[3]);
    *(uint2*)(oh + (size_t)i * 4) = *(uint2*)h;
    *(uint2*)(ol + (size_t)i * 4) = *(uint2*)l;
}

// weight transpose: in R x C fp32 -> out C x R fp16 (hi only)
__global__ void transpose_half_kernel(const float* __restrict__ in,
                                      __half* __restrict__ oh,
                                      int R, int Ccols) {
    __shared__ float tile[32][33];
    int bx = blockIdx.x * 32, by = blockIdx.y * 32;
    int x = bx + threadIdx.x;
    #pragma unroll
    for (int i = 0; i < 32; i += 8)
        tile[threadIdx.y + i][threadIdx.x] = in[(size_t)(by + threadIdx.y + i) * Ccols + x];
    __syncthreads();
    int ox = by + threadIdx.x;
    #pragma unroll
    for (int i = 0; i < 32; i += 8)
        oh[(size_t)(bx + threadIdx.y + i) * R + ox] = __float2half_rn(tile[threadIdx.x][threadIdx.y + i]);
}

// ================= mma.sync / async helpers =================
__device__ __forceinline__ uint32_t smem_u32(const void* p) {
    uint32_t a;
    asm("{ .reg .u64 t; cvta.to.shared.u64 t, %1; cvt.u32.u64 %0, t; }" : "=r"(a) : "l"(p));
    return a;
}
__device__ __forceinline__ void cp16(uint32_t dst, const void* src) {
    asm volatile("cp.async.cg.shared.global [%0], [%1], 16;" :: "r"(dst), "l"(src));
}
#define CP_COMMIT() asm volatile("cp.async.commit_group;" ::: "memory")
#define CP_WAIT1()  asm volatile("cp.async.wait_group 1;" ::: "memory")

__device__ __forceinline__ void ldsm4(uint32_t* r, uint32_t addr) {
    asm volatile("ldmatrix.sync.aligned.m8n8.x4.shared.b16 {%0,%1,%2,%3}, [%4];"
                 : "=r"(r[0]), "=r"(r[1]), "=r"(r[2]), "=r"(r[3]) : "r"(addr));
}
__device__ __forceinline__ void mma_fp16(float* d, const uint32_t* a, const uint32_t* b) {
    asm volatile(
        "mma.sync.aligned.m16n8k16.row.col.f32.f16.f16.f32 "
        "{%0,%1,%2,%3}, {%4,%5,%6,%7}, {%8,%9}, {%0,%1,%2,%3};\n"
        : "+f"(d[0]), "+f"(d[1]), "+f"(d[2]), "+f"(d[3])
        : "r"(a[0]), "r"(a[1]), "r"(a[2]), "r"(a[3]), "r"(b[0]), "r"(b[1]));
}
__device__ __forceinline__ uint32_t pack_hf2(float x0, float x1) {
    __half2 v = __floats2half2_rn(x0, x1);
    return *(uint32_t*)&v;
}
__device__ __forceinline__ float exp2p(float y) {
    y = fmaxf(y, -120.f);
    int ki = __float2int_rn(y);
    float f = y - (float)ki;
    float p = 0.0013333558f;
    p = fmaf(p, f, 0.0096181291f);
    p = fmaf(p, f, 0.0555041087f);
    p = fmaf(p, f, 0.2402265070f);
    p = fmaf(p, f, 0.6931471806f);
    p = fmaf(p, f, 1.0f);
    return p * __int_as_float((ki + 127) << 23);
}

// ---------------- fp16 GEMM, 3-stage pipeline ----------------
// C = (Ah [+ Al]) @ Bh^T. qkv_mode 1: fused rope/split epilogue (bias = bv).
// two_term 0: single-term A (O-projection; Al ignored).
#define BPAD 40
#define G_ARRB (128 * BPAD * 2)     /* 10240 B */
#define G_BUFB (3 * G_ARRB)         /* 30720 B per stage */
#define G_SMEM (3 * G_BUFB)         /* 92160 B, 3 stages */

__global__ void __launch_bounds__(256, 2) mma_gemm_fp16(
    const __half* __restrict__ Ah, const __half* __restrict__ Al,
    const __half* __restrict__ Bh,
    const float* __restrict__ bias, float* __restrict__ C, int N, int K,
    int qkv_mode, int two_term)
{
    extern __shared__ char smem[];
    const uint32_t smbase = smem_u32(smem);

    const int t    = threadIdx.x;
    const int lane = t & 31;
    const int wid  = t >> 5;
    const int wr   = wid & 3;
    const int wc   = wid >> 2;
    const int qid  = lane >> 2;
    const int tid4 = lane & 3;

    const size_t m0 = (size_t)blockIdx.y * 128;
    const size_t n0 = (size_t)blockIdx.x * 128;
    const __half* Abh = Ah + m0 * K;
    const __half* Abl = Al + m0 * K;
    const __half* Bbh = Bh + n0 * K;

    const uint32_t a_off = (uint32_t)(((wr * 32 + (lane & 15)) * BPAD + ((lane >> 4) << 3)) * 2);
    const uint32_t b_off = (uint32_t)(((wc * 64 + (lane & 7) + ((lane & 16) >> 1)) * BPAD + (lane & 8)) * 2);

    float acc[2][8][4];
    #pragma unroll
    for (int mf = 0; mf < 2; ++mf)
        #pragma unroll
        for (int nf = 0; nf < 8; ++nf)
            #pragma unroll
            for (int r = 0; r < 4; ++r) acc[mf][nf][r] = 0.f;

    const int nchunks = K / 32;   // 64

    // prologue: chunks 0,1 -> stages 0,1
    #pragma unroll
    for (int pc = 0; pc < 2; ++pc) {
        const uint32_t dst = smbase + (uint32_t)(pc * G_BUFB);
        #pragma unroll
        for (int i = 0; i < 6; ++i) {
            const int o = t + i * 256;
            const int arr = o >> 9;
            if (arr == 1 && !two_term) continue;
            const int r = (o & 511) >> 2, c = (o & 3) * 8;
            const __half* src = ((arr == 0) ? Abh : (arr == 1) ? Abl : Bbh) + (size_t)r * K + pc * 32 + c;
            cp16(dst + (uint32_t)(arr * G_ARRB) + (uint32_t)((r * BPAD + c) * 2), src);
        }
        CP_COMMIT();
    }

    for (int cch = 0; cch < nchunks; ++cch) {
        CP_WAIT1();
        __syncthreads();

        const uint32_t sb = smbase + (uint32_t)((cch % 3) * G_BUFB);
        #pragma unroll
        for (int ks = 0; ks < 2; ++ks) {
            const uint32_t kb = (uint32_t)(ks * 32);
            uint32_t ah[2][4], al[2][4];
            #pragma unroll
            for (int mf = 0; mf < 2; ++mf) {
                const uint32_t ro = (uint32_t)(mf * 16 * BPAD * 2);
                ldsm4(ah[mf], sb + 0 * G_ARRB + a_off + ro + kb);
                if (two_term) ldsm4(al[mf], sb + 1 * G_ARRB + a_off + ro + kb);
            }
            uint32_t bh[8][2];
            #pragma unroll
            for (int p = 0; p < 4; ++p) {
                const uint32_t ro = (uint32_t)(p * 16 * BPAD * 2);
                uint32_t r[4];
                ldsm4(r, sb + 2 * G_ARRB + b_off + ro + kb);
                bh[2 * p][0] = r[0]; bh[2 * p][1] = r[1];
                bh[2 * p + 1][0] = r[2]; bh[2 * p + 1][1] = r[3];
            }
            #pragma unroll
            for (int nf = 0; nf < 8; ++nf)
                #pragma unroll
                for (int mf = 0; mf < 2; ++mf) {
                    mma_fp16(acc[mf][nf], ah[mf], bh[nf]);
                    if (two_term) mma_fp16(acc[mf][nf], al[mf], bh[nf]);
                }
        }

        // issue chunk cch+2 into stage (cch+2)%3
        if (cch + 2 < nchunks) {
            const uint32_t dst = smbase + (uint32_t)(((cch + 2) % 3) * G_BUFB);
            const int k0 = (cch + 2) * 32;
            #pragma unroll
            for (int i = 0; i < 6; ++i) {
                const int o = t + i * 256;
                const int arr = o >> 9;
                if (arr == 1 && !two_term) continue;
                const int r = (o & 511) >> 2, c = (o & 3) * 8;
                const __half* src = ((arr == 0) ? Abh : (arr == 1) ? Abl : Bbh) + (size_t)r * K + k0 + c;
                cp16(dst + (uint32_t)(arr * G_ARRB) + (uint32_t)((r * BPAD + c) * 2), src);
            }
        }
        CP_COMMIT();
    }

    // ---------------- epilogue ----------------
    const int trow = qid;
    const int tcol = tid4 * 2;
    if (!qkv_mode) {
        #pragma unroll
        for (int mf = 0; mf < 2; ++mf) {
            const size_t m = m0 + wr * 32 + mf * 16 + trow;
            #pragma unroll
            for (int nf = 0; nf < 8; ++nf) {
                const int ncol = (int)n0 + wc * 64 + nf * 8 + tcol;
                float2 v0 = make_float2(acc[mf][nf][0], acc[mf][nf][1]);
                float2 v1 = make_float2(acc[mf][nf][2], acc[mf][nf][3]);
                const float bx = bias[ncol], by = bias[ncol + 1];
                v0.x += bx; v0.y += by;
                v1.x += bx; v1.y += by;
                *(float2*)(C + m * N + ncol)       = v0;
                *(float2*)(C + (m + 8) * N + ncol) = v1;
            }
        }
        return;
    }

    // fused QKV epilogue: rope + fp16 split + layout
    #pragma unroll
    for (int mf = 0; mf < 2; ++mf) {
        const size_t m = m0 + wr * 32 + mf * 16 + trow;
        const int b = (int)(m >> 11);
        const int s = (int)(m & 2047);
        #pragma unroll
        for (int nf = 0; nf < 8; ++nf) {
            const int ncol = (int)n0 + wc * 64 + nf * 8 + tcol;
            float2 v0 = make_float2(acc[mf][nf][0], acc[mf][nf][1]);
            float2 v1 = make_float2(acc[mf][nf][2], acc[mf][nf][3]);
            if (ncol < DIM) {
                const int h = ncol >> 6, d = ncol & 63, p = d >> 1;
                const float2 c0 = g_cs[s * 32 + p];
                const float2 c1 = g_cs[(s + 8) * 32 + p];
                float r0x = v0.x * c0.x - v0.y * c0.y;
                float r0y = v0.x * c0.y + v0.y * c0.x;
                float r1x = v1.x * c1.x - v1.y * c1.y;
                float r1y = v1.x * c1.y + v1.y * c1.x;
                __half h0, l0, h1, l1, h2, l2, h3, l3;
                fp16_split(r0x, h0, l0);
                fp16_split(r0y, h1, l1);
                fp16_split(r1x, h2, l2);
                fp16_split(r1y, h3, l3);
                const size_t o0 = (((size_t)(b * NH + h)) * SEQ + s) * HD + d;
                const size_t o1 = o0 + 8 * HD;
                __half2 a0; a0.x = h0; a0.y = h1;
                __half2 b0; b0.x = l0; b0.y = l1;
                __half2 a1; a1.x = h2; a1.y = h3;
                __half2 b1; b1.x = l2; b1.y = l3;
                *(__half2*)(g_qh + o0) = a0;
                *(__half2*)(g_ql + o0) = b0;
                *(__half2*)(g_qh + o1) = a1;
                *(__half2*)(g_ql + o1) = b1;
            } else if (ncol < DIM + KVDIM) {
                const int kc = ncol - DIM;
                const int kv = kc >> 6, d = kc & 63, p = d >> 1;
                const float2 c0 = g_cs[s * 32 + p];
                const float2 c1 = g_cs[(s + 8) * 32 + p];
                float r0x = v0.x * c0.x - v0.y * c0.y;
                float r0y = v0.x * c0.y + v0.y * c0.x;
                float r1x = v1.x * c1.x - v1.y * c1.y;
                float r1y = v1.x * c1.y + v1.y * c1.x;
                const size_t o0 = (((size_t)(b * NKV + kv)) * SEQ + s) * HD + d;
                const size_t o1 = o0 + 8 * HD;
                *(__half2*)(g_kh + o0) = __floats2half2_rn(r0x, r0y);
                *(__half2*)(g_kh + o1) = __floats2half2_rn(r1x, r1y);
            } else {
                const int vc = ncol - DIM - KVDIM;
                const int kv = vc >> 6, d = vc & 63;
                const float bx = bias[vc], by = bias[vc + 1];
                const size_t base = ((size_t)(b * NKV + kv) * HD + d) * SEQ;
                g_vth[base + s]           = __float2half_rn(v0.x + bx);
                g_vth[base + SEQ + s]     = __float2half_rn(v0.y + by);
                g_vth[base + s + 8]       = __float2half_rn(v1.x + bx);
                g_vth[base + SEQ + s + 8] = __float2half_rn(v1.y + by);
            }
        }
    }
}

// ---------------- flash attention v5: 3-stage pipeline, Q resident, 2 CTAs/SM ------
// Epilogue now writes single fp16 (O-projection uses 1-term A).
#define FQ 128
#define FK 64
#define SP 72
#define F_QARR (FQ * SP * 2)           /* 18432 */
#define QOFF   (2 * F_QARR)            /* 36864 */
#define F_ARR  (FK * SP * 2)           /* 9216 per K/V array */
#define F_BUF  (2 * F_ARR)             /* Kh Vth = 18432 per stage */
#define F_SMEM (QOFF + 3 * F_BUF)      /* 92160 */

__global__ void __launch_bounds__(256, 2) flash_mma_kernel(
    const __half* __restrict__ Qh, const __half* __restrict__ Ql,
    const __half* __restrict__ Kh, const __half* __restrict__ Vth,
    __half* __restrict__ Oh)
{
    extern __shared__ char smem[];
    const uint32_t smbase = smem_u32(smem);

    const int qt  = (SEQ / FQ - 1) - blockIdx.x;
    const int h   = blockIdx.y;
    const int b   = blockIdx.z;
    const int kvh = h >> 2;
    const int t    = threadIdx.x;
    const int lane = t & 31;
    const int w    = t >> 5;
    const int qid  = lane >> 2;
    const int tid4 = lane & 3;
    const int q0   = qt * FQ;
    const int wrow = w * 16;

    const __half* Qhb = Qh + (((size_t)(b * NH + h)) * SEQ + q0) * HD;
    const __half* Qlb = Ql + (((size_t)(b * NH + h)) * SEQ + q0) * HD;
    const __half* Khb = Kh + ((size_t)(b * NKV + kvh)) * SEQ * HD;
    const __half* Vhb = Vth + ((size_t)(b * NKV + kvh)) * HD * SEQ;

    #pragma unroll
    for (int i = 0; i < 4; ++i) {
        const int idx = t + i * 256;
        const int r = idx >> 3, c = (idx & 7) * 8;
        *(uint4*)(smem + (r * SP + c) * 2)          = *(const uint4*)(Qhb + (size_t)r * HD + c);
        *(uint4*)(smem + F_QARR + (r * SP + c) * 2) = *(const uint4*)(Qlb + (size_t)r * HD + c);
    }

    const uint32_t a_off = (uint32_t)(((wrow + (lane & 15)) * SP + ((lane >> 4) << 3)) * 2);
    const uint32_t b_off = (uint32_t)((((lane & 7) + ((lane & 16) >> 1)) * SP + (lane & 8)) * 2);

    const int ga  = t >> 7;
    const int sub = t & 127;
    const __half* gsrc = (ga == 0) ? Khb : Vhb;
    const bool isK = (ga == 0);

    float oacc[8][4];
    #pragma unroll
    for (int nf = 0; nf < 8; ++nf)
        #pragma unroll
        for (int j = 0; j < 4; ++j) oacc[nf][j] = 0.f;
    float m[2] = {-1e30f, -1e30f};
    float l[2] = {0.f, 0.f};

    const int row_a = q0 + wrow + qid;
    const int row_b = row_a + 8;
    const float SC = 0.125f * 1.4426950408889634f;

    const int ntiles = (q0 + FQ) / FK;   // >= 2

    #pragma unroll
    for (int pt = 0; pt < 2; ++pt) {
        const uint32_t dst = smbase + QOFF + (uint32_t)(pt * F_BUF) + (uint32_t)(ga * F_ARR);
        #pragma unroll
        for (int i = 0; i < 4; ++i) {
            const int idx = sub + i * 128;
            const int row = idx >> 3, col = (idx & 7) * 8;
            const __half* s = isK ? (gsrc + (size_t)(pt * FK + row) * HD + col)
                                  : (gsrc + (size_t)row * SEQ + pt * FK + col);
            cp16(dst + (uint32_t)((row * SP + col) * 2), s);
        }
        CP_COMMIT();
    }
    __syncthreads();

    for (int kt = 0; kt < ntiles; ++kt) {
        CP_WAIT1();
        __syncthreads();

        const uint32_t sb = smbase + QOFF + (uint32_t)((kt % 3) * F_BUF);

        float sacc[8][4];
        #pragma unroll
        for (int nf = 0; nf < 8; ++nf)
            #pragma unroll
            for (int j = 0; j < 4; ++j) sacc[nf][j] = 0.f;

        #pragma unroll
        for (int g2 = 0; g2 < 4; ++g2) {
            const uint32_t kb = (uint32_t)(g2 * 32);
            uint32_t qh4[4], ql4[4];
            ldsm4(qh4, smbase + a_off + kb);
            ldsm4(ql4, smbase + F_QARR + a_off + kb);
            uint32_t bh[8][2];
            #pragma unroll
            for (int p = 0; p < 4; ++p) {
                const uint32_t ro = (uint32_t)(p * 16 * SP * 2);
                uint32_t r[4];
                ldsm4(r, sb + 0 * F_ARR + b_off + ro + kb);
                bh[2 * p][0] = r[0]; bh[2 * p][1] = r[1];
                bh[2 * p + 1][0] = r[2]; bh[2 * p + 1][1] = r[3];
            }
            #pragma unroll
            for (int nf = 0; nf < 8; ++nf) {
                mma_fp16(sacc[nf], qh4, bh[nf]);
                mma_fp16(sacc[nf], ql4, bh[nf]);
            }
        }

        const bool need_mask = (kt * FK + FK - 1) > row_a;
        float tmax[2] = {-1e30f, -1e30f};
        #pragma unroll
        for (int nf = 0; nf < 8; ++nf) {
            const int colbase = kt * FK + nf * 8 + tid4 * 2;
            #pragma unroll
            for (int j = 0; j < 4; ++j) {
                const int col = colbase + (j & 1);
                const int row = (j < 2) ? row_a : row_b;
                float v = sacc[nf][j] * SC;
                if (need_mask && col > row) v = -1e30f;
                sacc[nf][j] = v;
                tmax[j >> 1] = fmaxf(tmax[j >> 1], v);
            }
        }

        float corr[2];
        #pragma unroll
        for (int hh = 0; hh < 2; ++hh) {
            tmax[hh] = fmaxf(tmax[hh], __shfl_xor_sync(0xffffffffu, tmax[hh], 1));
            tmax[hh] = fmaxf(tmax[hh], __shfl_xor_sync(0xffffffffu, tmax[hh], 2));
            const float mnew = fmaxf(m[hh], tmax[hh]);
            corr[hh] = exp2p(m[hh] - mnew);
            m[hh] = mnew;
            l[hh] *= corr[hh];
        }
        #pragma unroll
        for (int nf = 0; nf < 8; ++nf) {
            oacc[nf][0] *= corr[0]; oacc[nf][1] *= corr[0];
            oacc[nf][2] *= corr[1]; oacc[nf][3] *= corr[1];
        }
        float rsum[2] = {0.f, 0.f};
        #pragma unroll
        for (int nf = 0; nf < 8; ++nf) {
            #pragma unroll
            for (int j = 0; j < 4; ++j) {
                const float p = exp2p(sacc[nf][j] - m[j >> 1]);
                sacc[nf][j] = p;
                rsum[j >> 1] += p;
            }
        }
        #pragma unroll
        for (int hh = 0; hh < 2; ++hh) {
            rsum[hh] += __shfl_xor_sync(0xffffffffu, rsum[hh], 1);
            rsum[hh] += __shfl_xor_sync(0xffffffffu, rsum[hh], 2);
            l[hh] += rsum[hh];
        }

        uint32_t pfh[4][4], pfl[4][4];
        #pragma unroll
        for (int g2 = 0; g2 < 4; ++g2) {
            const float* s0 = sacc[2 * g2];
            const float* s1 = sacc[2 * g2 + 1];
            float h00 = __half2float(__float2half_rn(s0[0]));
            float h01 = __half2float(__float2half_rn(s0[1]));
            float h02 = __half2float(__float2half_rn(s0[2]));
            float h03 = __half2float(__float2half_rn(s0[3]));
            float h10 = __half2float(__float2half_rn(s1[0]));
            float h11 = __half2float(__float2half_rn(s1[1]));
            float h12 = __half2float(__float2half_rn(s1[2]));
            float h13 = __half2float(__float2half_rn(s1[3]));
            pfh[g2][0] = pack_hf2(h00, h01);
            pfh[g2][1] = pack_hf2(h02, h03);
            pfh[g2][2] = pack_hf2(h10, h11);
            pfh[g2][3] = pack_hf2(h12, h13);
            pfl[g2][0] = pack_hf2(s0[0] - h00, s0[1] - h01);
            pfl[g2][1] = pack_hf2(s0[2] - h02, s0[3] - h03);
            pfl[g2][2] = pack_hf2(s1[0] - h10, s1[1] - h11);
            pfl[g2][3] = pack_hf2(s1[2] - h12, s1[3] - h13);
        }

        #pragma unroll
        for (int g2 = 0; g2 < 4; ++g2) {
            const uint32_t kb = (uint32_t)(g2 * 32);
            uint32_t vh[8][2];
            #pragma unroll
            for (int p = 0; p < 4; ++p) {
                const uint32_t ro = (uint32_t)(p * 16 * SP * 2);
                uint32_t r[4];
                ldsm4(r, sb + 1 * F_ARR + b_off + ro + kb);
                vh[2 * p][0] = r[0]; vh[2 * p][1] = r[1];
                vh[2 * p + 1][0] = r[2]; vh[2 * p + 1][1] = r[3];
            }
            #pragma unroll
            for (int nf = 0; nf < 8; ++nf) {
                mma_fp16(oacc[nf], pfh[g2], vh[nf]);
                mma_fp16(oacc[nf], pfl[g2], vh[nf]);
            }
        }

        if (kt + 2 < ntiles) {
            const uint32_t dst = smbase + QOFF + (uint32_t)(((kt + 2) % 3) * F_BUF) + (uint32_t)(ga * F_ARR);
            #pragma unroll
            for (int i = 0; i < 4; ++i) {
                const int idx = sub + i * 128;
                const int row = idx >> 3, col = (idx & 7) * 8;
                const __half* s = isK
                    ? (gsrc + (size_t)((kt + 2) * FK + row) * HD + col)
                    : (gsrc + (size_t)row * SEQ + (kt + 2) * FK + col);
                cp16(dst + (uint32_t)((row * SP + col) * 2), s);
            }
        }
        CP_COMMIT();
    }

    // ---- epilogue: normalized output, single fp16 (O-projection is 1-term) ----
    const float inv_a = 1.0f / l[0];
    const float inv_b = 1.0f / l[1];
    const size_t rA = ((size_t)(b * SEQ) + row_a) * DIM + h * HD;
    const size_t rB = rA + 8 * DIM;
    #pragma unroll
    for (int nf = 0; nf < 8; ++nf) {
        const int col = nf * 8 + tid4 * 2;
        *(__half2*)(Oh + rA + col) = __floats2half2_rn(oacc[nf][0] * inv_a, oacc[nf][1] * inv_a);
        *(__half2*)(Oh + rB + col) = __floats2half2_rn(oacc[nf][2] * inv_b, oacc[nf][3] * inv_b);
    }
}

// ---------------- host launcher ----------------
extern "C" void kernel_launch(void* const* d_in, const int* in_sizes, int n_in,
                              void* d_out, int out_size) {
    (void)in_sizes; (void)n_in; (void)out_size;
    const float* x  = (const float*)d_in[0];
    const float* Wq = (const float*)d_in[1];
    const float* Wk = (const float*)d_in[2];
    const float* Wv = (const float*)d_in[3];
    const float* bv = (const float*)d_in[4];
    const float* Wo = (const float*)d_in[5];
    const float* bo = (const float*)d_in[6];
    float* out = (float*)d_out;

    __half *ah, *al, *bh, *qh, *ql, *kh, *vth;
    cudaGetSymbolAddress((void**)&ah,  g_ah);
    cudaGetSymbolAddress((void**)&al,  g_al);
    cudaGetSymbolAddress((void**)&bh,  g_bh);
    cudaGetSymbolAddress((void**)&qh,  g_qh);
    cudaGetSymbolAddress((void**)&ql,  g_ql);
    cudaGetSymbolAddress((void**)&kh,  g_kh);
    cudaGetSymbolAddress((void**)&vth, g_vth);

    cudaFuncSetAttribute(mma_gemm_fp16, cudaFuncAttributeMaxDynamicSharedMemorySize, G_SMEM);
    cudaFuncSetAttribute(flash_mma_kernel, cudaFuncAttributeMaxDynamicSharedMemorySize, F_SMEM);

    sincos_kernel<<<(SEQ * 32) / 256, 256>>>();

    // split activations once (fp16 hi/lo)
    split_kernel<<<(MROWS * DIM) / 1024, 256>>>(x, ah, al);

    // merged QKV projection (N = 3072), 2-term, fused rope/split epilogue
    transpose_half_kernel<<<dim3(DIM / 32, DIM / 32), dim3(32, 8)>>>(Wq, bh, DIM, DIM);
    transpose_half_kernel<<<dim3(KVDIM / 32, DIM / 32), dim3(32, 8)>>>(
        Wk, bh + (size_t)DIM * DIM, DIM, KVDIM);
    transpose_half_kernel<<<dim3(KVDIM / 32, DIM / 32), dim3(32, 8)>>>(
        Wv, bh + (size_t)(DIM + KVDIM) * DIM, DIM, KVDIM);
    mma_gemm_fp16<<<dim3(NQKV / 128, MROWS / 128), 256, G_SMEM>>>(
        ah, al, bh, bv, nullptr, NQKV, DIM, 1, 1);

    // flash writes single fp16 ah for the O projection
    flash_mma_kernel<<<dim3(SEQ / FQ, NH, BATCH), 256, F_SMEM>>>(
        qh, ql, kh, vth, ah);

    // O projection: 1-term A
    transpose_half_kernel<<<dim3(DIM / 32, DIM / 32), dim3(32, 8)>>>(Wo, bh, DIM, DIM);
    mma_gemm_fp16<<<dim3(DIM / 128, MROWS / 128), 256, G_SMEM>>>(
        ah, al, bh, bo, out, DIM, DIM, 0, 0);
}

// round 13
// speedup vs baseline: 5.0999x; 1.0590x over previous
#include <cuda_runtime.h>
#include <cuda_fp16.h>
#include <math.h>
#include <stdint.h>

#define DIM 2048
#define NH 32
#define NKV 8
#define HD 64
#define BATCH 2
#define SEQ 2048
#define MROWS (BATCH*SEQ)   /* 4096 */
#define KVDIM (NKV*HD)      /* 512 */
#define NQKV (DIM + 2*KVDIM) /* 3072 */

// ---------------- scratch (static device allocations; no cudaMalloc) ----------------
// GEMM operands: activations fp16 hi/lo, weights fp16 hi only
__device__ __align__(16) __half g_ah[(size_t)MROWS * DIM];
__device__ __align__(16) __half g_al[(size_t)MROWS * DIM];
__device__ __align__(16) __half g_bh[(size_t)NQKV * DIM];    // Wq|Wk|Wv transposed
__device__ __align__(16) __half g_bho[(size_t)DIM * DIM];    // Wo transposed
// flash operands: all fp16 hi only (error budget validated R9-R12)
__device__ __align__(16) __half g_qh[(size_t)BATCH * NH * SEQ * HD];
__device__ __align__(16) __half g_kh[(size_t)BATCH * NKV * SEQ * HD];
__device__ __align__(16) __half g_vth[(size_t)BATCH * NKV * HD * SEQ];  // [b,kv,d,s]
__device__ float2 g_cs[(size_t)SEQ * (HD / 2)];

// ---------------- split helpers ----------------
__device__ __forceinline__ void fp16_split(float x, __half& h, __half& l) {
    h = __float2half_rn(x);
    l = __float2half_rn(x - __half2float(h));
}

// fused prep: split x -> ah/al (blocks 0..8191), sincos table (blocks 8192..8447)
#define SPLIT_BLOCKS ((MROWS * DIM) / 1024)   /* 8192 */
__global__ void prep_kernel(const float* __restrict__ in,
                            __half* __restrict__ oh,
                            __half* __restrict__ ol) {
    const int bid = blockIdx.x;
    if (bid < SPLIT_BLOCKS) {
        const int i = bid * 256 + threadIdx.x;
        const float4 v = *(const float4*)(in + (size_t)i * 4);
        __half h[4], l[4];
        fp16_split(v.x, h[0], l[0]);
        fp16_split(v.y, h[1], l[1]);
        fp16_split(v.z, h[2], l[2]);
        fp16_split(v.w, h[3], l[3]);
        *(uint2*)(oh + (size_t)i * 4) = *(uint2*)h;
        *(uint2*)(ol + (size_t)i * 4) = *(uint2*)l;
    } else {
        const int idx = (bid - SPLIT_BLOCKS) * 256 + threadIdx.x;   // SEQ*32
        const int s = idx >> 5, p = idx & 31;
        double theta = pow(10000.0, -(double)p / 32.0);
        float ang = (float)((double)s * theta);
        float sv, cv;
        sincosf(ang, &sv, &cv);
        g_cs[idx] = make_float2(cv, sv);
    }
}

// batched weight transpose: z selects {Wq, Wk, Wv, Wo}; fp32 RxC -> fp16 CxR
__global__ void transpose_all_kernel(const float* __restrict__ Wq,
                                     const float* __restrict__ Wk,
                                     const float* __restrict__ Wv,
                                     const float* __restrict__ Wo) {
    __shared__ float tile[32][33];
    const int z = blockIdx.z;
    const int nx = (z == 1 || z == 2) ? (KVDIM / 32) : (DIM / 32);
    if (blockIdx.x >= nx) return;
    const float* in = (z == 0) ? Wq : (z == 1) ? Wk : (z == 2) ? Wv : Wo;
    __half* out = (z == 0) ? g_bh
                : (z == 1) ? g_bh + (size_t)DIM * DIM
                : (z == 2) ? g_bh + (size_t)(DIM + KVDIM) * DIM
                : g_bho;
    const int Ccols = (z == 1 || z == 2) ? KVDIM : DIM;
    const int R = DIM;
    int bx = blockIdx.x * 32, by = blockIdx.y * 32;
    int x = bx + threadIdx.x;
    #pragma unroll
    for (int i = 0; i < 32; i += 8)
        tile[threadIdx.y + i][threadIdx.x] = in[(size_t)(by + threadIdx.y + i) * Ccols + x];
    __syncthreads();
    int ox = by + threadIdx.x;
    #pragma unroll
    for (int i = 0; i < 32; i += 8)
        out[(size_t)(bx + threadIdx.y + i) * R + ox] = __float2half_rn(tile[threadIdx.x][threadIdx.y + i]);
}

// ================= mma.sync / async helpers =================
__device__ __forceinline__ uint32_t smem_u32(const void* p) {
    uint32_t a;
    asm("{ .reg .u64 t; cvta.to.shared.u64 t, %1; cvt.u32.u64 %0, t; }" : "=r"(a) : "l"(p));
    return a;
}
__device__ __forceinline__ void cp16(uint32_t dst, const void* src) {
    asm volatile("cp.async.cg.shared.global [%0], [%1], 16;" :: "r"(dst), "l"(src));
}
#define CP_COMMIT() asm volatile("cp.async.commit_group;" ::: "memory")
#define CP_WAIT1()  asm volatile("cp.async.wait_group 1;" ::: "memory")

__device__ __forceinline__ void ldsm4(uint32_t* r, uint32_t addr) {
    asm volatile("ldmatrix.sync.aligned.m8n8.x4.shared.b16 {%0,%1,%2,%3}, [%4];"
                 : "=r"(r[0]), "=r"(r[1]), "=r"(r[2]), "=r"(r[3]) : "r"(addr));
}
__device__ __forceinline__ void mma_fp16(float* d, const uint32_t* a, const uint32_t* b) {
    asm volatile(
        "mma.sync.aligned.m16n8k16.row.col.f32.f16.f16.f32 "
        "{%0,%1,%2,%3}, {%4,%5,%6,%7}, {%8,%9}, {%0,%1,%2,%3};\n"
        : "+f"(d[0]), "+f"(d[1]), "+f"(d[2]), "+f"(d[3])
        : "r"(a[0]), "r"(a[1]), "r"(a[2]), "r"(a[3]), "r"(b[0]), "r"(b[1]));
}
__device__ __forceinline__ uint32_t pack_hf2(float x0, float x1) {
    __half2 v = __floats2half2_rn(x0, x1);
    return *(uint32_t*)&v;
}
__device__ __forceinline__ float exp2p(float y) {
    y = fmaxf(y, -120.f);
    int ki = __float2int_rn(y);
    float f = y - (float)ki;
    float p = 0.0013333558f;
    p = fmaf(p, f, 0.0096181291f);
    p = fmaf(p, f, 0.0555041087f);
    p = fmaf(p, f, 0.2402265070f);
    p = fmaf(p, f, 0.6931471806f);
    p = fmaf(p, f, 1.0f);
    return p * __int_as_float((ki + 127) << 23);
}

// ---------------- fp16 GEMM, 3-stage pipeline ----------------
// C = (Ah [+ Al]) @ Bh^T. qkv_mode 1: fused rope epilogue (bias = bv).
// two_term 0: single-term A (O-projection; Al ignored).
#define BPAD 40
#define G_ARRB (128 * BPAD * 2)     /* 10240 B */
#define G_BUFB (3 * G_ARRB)         /* 30720 B per stage */
#define G_SMEM (3 * G_BUFB)         /* 92160 B, 3 stages */

__global__ void __launch_bounds__(256, 2) mma_gemm_fp16(
    const __half* __restrict__ Ah, const __half* __restrict__ Al,
    const __half* __restrict__ Bh,
    const float* __restrict__ bias, float* __restrict__ C, int N, int K,
    int qkv_mode, int two_term)
{
    extern __shared__ char smem[];
    const uint32_t smbase = smem_u32(smem);

    const int t    = threadIdx.x;
    const int lane = t & 31;
    const int wid  = t >> 5;
    const int wr   = wid & 3;
    const int wc   = wid >> 2;
    const int qid  = lane >> 2;
    const int tid4 = lane & 3;

    const size_t m0 = (size_t)blockIdx.y * 128;
    const size_t n0 = (size_t)blockIdx.x * 128;
    const __half* Abh = Ah + m0 * K;
    const __half* Abl = Al + m0 * K;
    const __half* Bbh = Bh + n0 * K;

    const uint32_t a_off = (uint32_t)(((wr * 32 + (lane & 15)) * BPAD + ((lane >> 4) << 3)) * 2);
    const uint32_t b_off = (uint32_t)(((wc * 64 + (lane & 7) + ((lane & 16) >> 1)) * BPAD + (lane & 8)) * 2);

    float acc[2][8][4];
    #pragma unroll
    for (int mf = 0; mf < 2; ++mf)
        #pragma unroll
        for (int nf = 0; nf < 8; ++nf)
            #pragma unroll
            for (int r = 0; r < 4; ++r) acc[mf][nf][r] = 0.f;

    const int nchunks = K / 32;   // 64

    // prologue: chunks 0,1 -> stages 0,1
    #pragma unroll
    for (int pc = 0; pc < 2; ++pc) {
        const uint32_t dst = smbase + (uint32_t)(pc * G_BUFB);
        #pragma unroll
        for (int i = 0; i < 6; ++i) {
            const int o = t + i * 256;
            const int arr = o >> 9;
            if (arr == 1 && !two_term) continue;
            const int r = (o & 511) >> 2, c = (o & 3) * 8;
            const __half* src = ((arr == 0) ? Abh : (arr == 1) ? Abl : Bbh) + (size_t)r * K + pc * 32 + c;
            cp16(dst + (uint32_t)(arr * G_ARRB) + (uint32_t)((r * BPAD + c) * 2), src);
        }
        CP_COMMIT();
    }

    for (int cch = 0; cch < nchunks; ++cch) {
        CP_WAIT1();
        __syncthreads();

        const uint32_t sb = smbase + (uint32_t)((cch % 3) * G_BUFB);
        #pragma unroll
        for (int ks = 0; ks < 2; ++ks) {
            const uint32_t kb = (uint32_t)(ks * 32);
            uint32_t ah[2][4], al[2][4];
            #pragma unroll
            for (int mf = 0; mf < 2; ++mf) {
                const uint32_t ro = (uint32_t)(mf * 16 * BPAD * 2);
                ldsm4(ah[mf], sb + 0 * G_ARRB + a_off + ro + kb);
                if (two_term) ldsm4(al[mf], sb + 1 * G_ARRB + a_off + ro + kb);
            }
            uint32_t bh[8][2];
            #pragma unroll
            for (int p = 0; p < 4; ++p) {
                const uint32_t ro = (uint32_t)(p * 16 * BPAD * 2);
                uint32_t r[4];
                ldsm4(r, sb + 2 * G_ARRB + b_off + ro + kb);
                bh[2 * p][0] = r[0]; bh[2 * p][1] = r[1];
                bh[2 * p + 1][0] = r[2]; bh[2 * p + 1][1] = r[3];
            }
            #pragma unroll
            for (int nf = 0; nf < 8; ++nf)
                #pragma unroll
                for (int mf = 0; mf < 2; ++mf) {
                    mma_fp16(acc[mf][nf], ah[mf], bh[nf]);
                    if (two_term) mma_fp16(acc[mf][nf], al[mf], bh[nf]);
                }
        }

        if (cch + 2 < nchunks) {
            const uint32_t dst = smbase + (uint32_t)(((cch + 2) % 3) * G_BUFB);
            const int k0 = (cch + 2) * 32;
            #pragma unroll
            for (int i = 0; i < 6; ++i) {
                const int o = t + i * 256;
                const int arr = o >> 9;
                if (arr == 1 && !two_term) continue;
                const int r = (o & 511) >> 2, c = (o & 3) * 8;
                const __half* src = ((arr == 0) ? Abh : (arr == 1) ? Abl : Bbh) + (size_t)r * K + k0 + c;
                cp16(dst + (uint32_t)(arr * G_ARRB) + (uint32_t)((r * BPAD + c) * 2), src);
            }
        }
        CP_COMMIT();
    }

    // ---------------- epilogue ----------------
    const int trow = qid;
    const int tcol = tid4 * 2;
    if (!qkv_mode) {
        #pragma unroll
        for (int mf = 0; mf < 2; ++mf) {
            const size_t m = m0 + wr * 32 + mf * 16 + trow;
            #pragma unroll
            for (int nf = 0; nf < 8; ++nf) {
                const int ncol = (int)n0 + wc * 64 + nf * 8 + tcol;
                float2 v0 = make_float2(acc[mf][nf][0], acc[mf][nf][1]);
                float2 v1 = make_float2(acc[mf][nf][2], acc[mf][nf][3]);
                const float bx = bias[ncol], by = bias[ncol + 1];
                v0.x += bx; v0.y += by;
                v1.x += bx; v1.y += by;
                *(float2*)(C + m * N + ncol)       = v0;
                *(float2*)(C + (m + 8) * N + ncol) = v1;
            }
        }
        return;
    }

    // fused QKV epilogue: rope + fp16 + layout (all hi-only now)
    #pragma unroll
    for (int mf = 0; mf < 2; ++mf) {
        const size_t m = m0 + wr * 32 + mf * 16 + trow;
        const int b = (int)(m >> 11);
        const int s = (int)(m & 2047);
        #pragma unroll
        for (int nf = 0; nf < 8; ++nf) {
            const int ncol = (int)n0 + wc * 64 + nf * 8 + tcol;
            float2 v0 = make_float2(acc[mf][nf][0], acc[mf][nf][1]);
            float2 v1 = make_float2(acc[mf][nf][2], acc[mf][nf][3]);
            if (ncol < DIM + KVDIM) {
                // Q or K: rope, hi only
                const bool isQ = (ncol < DIM);
                const int cc = isQ ? ncol : (ncol - DIM);
                const int hh = cc >> 6, d = cc & 63, p = d >> 1;
                const float2 c0 = g_cs[s * 32 + p];
                const float2 c1 = g_cs[(s + 8) * 32 + p];
                float r0x = v0.x * c0.x - v0.y * c0.y;
                float r0y = v0.x * c0.y + v0.y * c0.x;
                float r1x = v1.x * c1.x - v1.y * c1.y;
                float r1y = v1.x * c1.y + v1.y * c1.x;
                __half* dst = isQ ? g_qh : g_kh;
                const int nheads = isQ ? NH : NKV;
                const size_t o0 = (((size_t)(b * nheads + hh)) * SEQ + s) * HD + d;
                const size_t o1 = o0 + 8 * HD;
                *(__half2*)(dst + o0) = __floats2half2_rn(r0x, r0y);
                *(__half2*)(dst + o1) = __floats2half2_rn(r1x, r1y);
            } else {
                const int vc = ncol - DIM - KVDIM;
                const int kv = vc >> 6, d = vc & 63;
                const float bx = bias[vc], by = bias[vc + 1];
                const size_t base = ((size_t)(b * NKV + kv) * HD + d) * SEQ;
                g_vth[base + s]           = __float2half_rn(v0.x + bx);
                g_vth[base + SEQ + s]     = __float2half_rn(v0.y + by);
                g_vth[base + s + 8]       = __float2half_rn(v1.x + bx);
                g_vth[base + SEQ + s + 8] = __float2half_rn(v1.y + by);
            }
        }
    }
}

// ---------------- flash attention v6: fully 1-term fp16, 3-stage pipeline ----------
#define FQ 128
#define FK 64
#define SP 72
#define F_QARR (FQ * SP * 2)           /* 18432 (Qh only) */
#define QOFF   F_QARR
#define F_ARR  (FK * SP * 2)           /* 9216 per K/V array */
#define F_BUF  (2 * F_ARR)             /* Kh Vth = 18432 per stage */
#define F_SMEM (QOFF + 3 * F_BUF)      /* 73728 */

__global__ void __launch_bounds__(256, 2) flash_mma_kernel(
    const __half* __restrict__ Qh,
    const __half* __restrict__ Kh, const __half* __restrict__ Vth,
    __half* __restrict__ Oh)
{
    extern __shared__ char smem[];
    const uint32_t smbase = smem_u32(smem);

    const int qt  = (SEQ / FQ - 1) - blockIdx.x;
    const int h   = blockIdx.y;
    const int b   = blockIdx.z;
    const int kvh = h >> 2;
    const int t    = threadIdx.x;
    const int lane = t & 31;
    const int w    = t >> 5;
    const int qid  = lane >> 2;
    const int tid4 = lane & 3;
    const int q0   = qt * FQ;
    const int wrow = w * 16;

    const __half* Qhb = Qh + (((size_t)(b * NH + h)) * SEQ + q0) * HD;
    const __half* Khb = Kh + ((size_t)(b * NKV + kvh)) * SEQ * HD;
    const __half* Vhb = Vth + ((size_t)(b * NKV + kvh)) * HD * SEQ;

    // stage Q (hi only) permanently in smem
    #pragma unroll
    for (int i = 0; i < 4; ++i) {
        const int idx = t + i * 256;
        const int r = idx >> 3, c = (idx & 7) * 8;
        *(uint4*)(smem + (r * SP + c) * 2) = *(const uint4*)(Qhb + (size_t)r * HD + c);
    }

    const uint32_t a_off = (uint32_t)(((wrow + (lane & 15)) * SP + ((lane >> 4) << 3)) * 2);
    const uint32_t b_off = (uint32_t)((((lane & 7) + ((lane & 16) >> 1)) * SP + (lane & 8)) * 2);

    const int ga  = t >> 7;
    const int sub = t & 127;
    const __half* gsrc = (ga == 0) ? Khb : Vhb;
    const bool isK = (ga == 0);

    float oacc[8][4];
    #pragma unroll
    for (int nf = 0; nf < 8; ++nf)
        #pragma unroll
        for (int j = 0; j < 4; ++j) oacc[nf][j] = 0.f;
    float m[2] = {-1e30f, -1e30f};
    float l[2] = {0.f, 0.f};

    const int row_a = q0 + wrow + qid;
    const int row_b = row_a + 8;
    const float SC = 0.125f * 1.4426950408889634f;

    const int ntiles = (q0 + FQ) / FK;   // >= 2

    #pragma unroll
    for (int pt = 0; pt < 2; ++pt) {
        const uint32_t dst = smbase + QOFF + (uint32_t)(pt * F_BUF) + (uint32_t)(ga * F_ARR);
        #pragma unroll
        for (int i = 0; i < 4; ++i) {
            const int idx = sub + i * 128;
            const int row = idx >> 3, col = (idx & 7) * 8;
            const __half* s = isK ? (gsrc + (size_t)(pt * FK + row) * HD + col)
                                  : (gsrc + (size_t)row * SEQ + pt * FK + col);
            cp16(dst + (uint32_t)((row * SP + col) * 2), s);
        }
        CP_COMMIT();
    }
    __syncthreads();   // Q staging + stage-0 visible ordering

    for (int kt = 0; kt < ntiles; ++kt) {
        CP_WAIT1();
        __syncthreads();

        const uint32_t sb = smbase + QOFF + (uint32_t)((kt % 3) * F_BUF);

        float sacc[8][4];
        #pragma unroll
        for (int nf = 0; nf < 8; ++nf)
            #pragma unroll
            for (int j = 0; j < 4; ++j) sacc[nf][j] = 0.f;

        #pragma unroll
        for (int g2 = 0; g2 < 4; ++g2) {
            const uint32_t kb = (uint32_t)(g2 * 32);
            uint32_t qh4[4];
            ldsm4(qh4, smbase + a_off + kb);
            uint32_t bh[8][2];
            #pragma unroll
            for (int p = 0; p < 4; ++p) {
                const uint32_t ro = (uint32_t)(p * 16 * SP * 2);
                uint32_t r[4];
                ldsm4(r, sb + 0 * F_ARR + b_off + ro + kb);
                bh[2 * p][0] = r[0]; bh[2 * p][1] = r[1];
                bh[2 * p + 1][0] = r[2]; bh[2 * p + 1][1] = r[3];
            }
            #pragma unroll
            for (int nf = 0; nf < 8; ++nf)
                mma_fp16(sacc[nf], qh4, bh[nf]);
        }

        const bool need_mask = (kt * FK + FK - 1) > row_a;
        float tmax[2] = {-1e30f, -1e30f};
        #pragma unroll
        for (int nf = 0; nf < 8; ++nf) {
            const int colbase = kt * FK + nf * 8 + tid4 * 2;
            #pragma unroll
            for (int j = 0; j < 4; ++j) {
                const int col = colbase + (j & 1);
                const int row = (j < 2) ? row_a : row_b;
                float v = sacc[nf][j] * SC;
                if (need_mask && col > row) v = -1e30f;
                sacc[nf][j] = v;
                tmax[j >> 1] = fmaxf(tmax[j >> 1], v);
            }
        }

        float corr[2];
        #pragma unroll
        for (int hh = 0; hh < 2; ++hh) {
            tmax[hh] = fmaxf(tmax[hh], __shfl_xor_sync(0xffffffffu, tmax[hh], 1));
            tmax[hh] = fmaxf(tmax[hh], __shfl_xor_sync(0xffffffffu, tmax[hh], 2));
            const float mnew = fmaxf(m[hh], tmax[hh]);
            corr[hh] = exp2p(m[hh] - mnew);
            m[hh] = mnew;
            l[hh] *= corr[hh];
        }
        #pragma unroll
        for (int nf = 0; nf < 8; ++nf) {
            oacc[nf][0] *= corr[0]; oacc[nf][1] *= corr[0];
            oacc[nf][2] *= corr[1]; oacc[nf][3] *= corr[1];
        }
        float rsum[2] = {0.f, 0.f};
        #pragma unroll
        for (int nf = 0; nf < 8; ++nf) {
            #pragma unroll
            for (int j = 0; j < 4; ++j) {
                const float p = exp2p(sacc[nf][j] - m[j >> 1]);
                sacc[nf][j] = p;
                rsum[j >> 1] += p;
            }
        }
        #pragma unroll
        for (int hh = 0; hh < 2; ++hh) {
            rsum[hh] += __shfl_xor_sync(0xffffffffu, rsum[hh], 1);
            rsum[hh] += __shfl_xor_sync(0xffffffffu, rsum[hh], 2);
            l[hh] += rsum[hh];
        }

        // P a-fragments, hi only
        uint32_t pfh[4][4];
        #pragma unroll
        for (int g2 = 0; g2 < 4; ++g2) {
            const float* s0 = sacc[2 * g2];
            const float* s1 = sacc[2 * g2 + 1];
            pfh[g2][0] = pack_hf2(s0[0], s0[1]);
            pfh[g2][1] = pack_hf2(s0[2], s0[3]);
            pfh[g2][2] = pack_hf2(s1[0], s1[1]);
            pfh[g2][3] = pack_hf2(s1[2], s1[3]);
        }

        #pragma unroll
        for (int g2 = 0; g2 < 4; ++g2) {
            const uint32_t kb = (uint32_t)(g2 * 32);
            uint32_t vh[8][2];
            #pragma unroll
            for (int p = 0; p < 4; ++p) {
                const uint32_t ro = (uint32_t)(p * 16 * SP * 2);
                uint32_t r[4];
                ldsm4(r, sb + 1 * F_ARR + b_off + ro + kb);
                vh[2 * p][0] = r[0]; vh[2 * p][1] = r[1];
                vh[2 * p + 1][0] = r[2]; vh[2 * p + 1][1] = r[3];
            }
            #pragma unroll
            for (int nf = 0; nf < 8; ++nf)
                mma_fp16(oacc[nf], pfh[g2], vh[nf]);
        }

        if (kt + 2 < ntiles) {
            const uint32_t dst = smbase + QOFF + (uint32_t)(((kt + 2) % 3) * F_BUF) + (uint32_t)(ga * F_ARR);
            #pragma unroll
            for (int i = 0; i < 4; ++i) {
                const int idx = sub + i * 128;
                const int row = idx >> 3, col = (idx & 7) * 8;
                const __half* s = isK
                    ? (gsrc + (size_t)((kt + 2) * FK + row) * HD + col)
                    : (gsrc + (size_t)row * SEQ + (kt + 2) * FK + col);
                cp16(dst + (uint32_t)((row * SP + col) * 2), s);
            }
        }
        CP_COMMIT();
    }

    // epilogue: normalized output, single fp16 for the 1-term O-projection
    const float inv_a = 1.0f / l[0];
    const float inv_b = 1.0f / l[1];
    const size_t rA = ((size_t)(b * SEQ) + row_a) * DIM + h * HD;
    const size_t rB = rA + 8 * DIM;
    #pragma unroll
    for (int nf = 0; nf < 8; ++nf) {
        const int col = nf * 8 + tid4 * 2;
        *(__half2*)(Oh + rA + col) = __floats2half2_rn(oacc[nf][0] * inv_a, oacc[nf][1] * inv_a);
        *(__half2*)(Oh + rB + col) = __floats2half2_rn(oacc[nf][2] * inv_b, oacc[nf][3] * inv_b);
    }
}

// ---------------- host launcher ----------------
extern "C" void kernel_launch(void* const* d_in, const int* in_sizes, int n_in,
                              void* d_out, int out_size) {
    (void)in_sizes; (void)n_in; (void)out_size;
    const float* x  = (const float*)d_in[0];
    const float* Wq = (const float*)d_in[1];
    const float* Wk = (const float*)d_in[2];
    const float* Wv = (const float*)d_in[3];
    const float* bv = (const float*)d_in[4];
    const float* Wo = (const float*)d_in[5];
    const float* bo = (const float*)d_in[6];
    float* out = (float*)d_out;

    __half *ah, *al, *bh, *bho, *qh, *kh, *vth;
    cudaGetSymbolAddress((void**)&ah,  g_ah);
    cudaGetSymbolAddress((void**)&al,  g_al);
    cudaGetSymbolAddress((void**)&bh,  g_bh);
    cudaGetSymbolAddress((void**)&bho, g_bho);
    cudaGetSymbolAddress((void**)&qh,  g_qh);
    cudaGetSymbolAddress((void**)&kh,  g_kh);
    cudaGetSymbolAddress((void**)&vth, g_vth);

    cudaFuncSetAttribute(mma_gemm_fp16, cudaFuncAttributeMaxDynamicSharedMemorySize, G_SMEM);
    cudaFuncSetAttribute(flash_mma_kernel, cudaFuncAttributeMaxDynamicSharedMemorySize, F_SMEM);

    // fused prep: x split + sincos table (one launch)
    prep_kernel<<<SPLIT_BLOCKS + (SEQ * 32) / 256, 256>>>(x, ah, al);

    // all weight transposes in one launch
    transpose_all_kernel<<<dim3(DIM / 32, DIM / 32, 4), dim3(32, 8)>>>(Wq, Wk, Wv, Wo);

    // merged QKV projection (N = 3072), 2-term, fused rope epilogue
    mma_gemm_fp16<<<dim3(NQKV / 128, MROWS / 128), 256, G_SMEM>>>(
        ah, al, bh, bv, nullptr, NQKV, DIM, 1, 1);

    // flash (fully 1-term) writes fp16 ah for the O projection
    flash_mma_kernel<<<dim3(SEQ / FQ, NH, BATCH), 256, F_SMEM>>>(qh, kh, vth, ah);

    // O projection: 1-term A
    mma_gemm_fp16<<<dim3(DIM / 128, MROWS / 128), 256, G_SMEM>>>(
        ah, al, bho, bo, out, DIM, DIM, 0, 0);
}

// round 14
// speedup vs baseline: 5.1815x; 1.0160x over previous
#include <cuda_runtime.h>
#include <cuda_fp16.h>
#include <math.h>
#include <stdint.h>

#define DIM 2048
#define NH 32
#define NKV 8
#define HD 64
#define BATCH 2
#define SEQ 2048
#define MROWS (BATCH*SEQ)   /* 4096 */
#define KVDIM (NKV*HD)      /* 512 */
#define NQKV (DIM + 2*KVDIM) /* 3072 */

// ---------------- scratch (static device allocations; no cudaMalloc) ----------------
__device__ __align__(16) __half g_ah[(size_t)MROWS * DIM];
__device__ __align__(16) __half g_al[(size_t)MROWS * DIM];
__device__ __align__(16) __half g_bh[(size_t)NQKV * DIM];    // Wq|Wk|Wv transposed
__device__ __align__(16) __half g_bho[(size_t)DIM * DIM];    // Wo transposed
// flash operands: all fp16 hi only; Q pre-scaled by 0.125*log2(e)
__device__ __align__(16) __half g_qh[(size_t)BATCH * NH * SEQ * HD];
__device__ __align__(16) __half g_kh[(size_t)BATCH * NKV * SEQ * HD];
__device__ __align__(16) __half g_vth[(size_t)BATCH * NKV * HD * SEQ];  // [b,kv,d,s]
__device__ float2 g_cs[(size_t)SEQ * (HD / 2)];

#define QSCALE 0.18033688011112042f   /* 0.125 * log2(e) */

// ---------------- split helpers ----------------
__device__ __forceinline__ void fp16_split(float x, __half& h, __half& l) {
    h = __float2half_rn(x);
    l = __float2half_rn(x - __half2float(h));
}

// fused prep: split x -> ah/al (blocks 0..8191), sincos table (blocks 8192..8447)
#define SPLIT_BLOCKS ((MROWS * DIM) / 1024)   /* 8192 */
__global__ void prep_kernel(const float* __restrict__ in,
                            __half* __restrict__ oh,
                            __half* __restrict__ ol) {
    const int bid = blockIdx.x;
    if (bid < SPLIT_BLOCKS) {
        const int i = bid * 256 + threadIdx.x;
        const float4 v = *(const float4*)(in + (size_t)i * 4);
        __half h[4], l[4];
        fp16_split(v.x, h[0], l[0]);
        fp16_split(v.y, h[1], l[1]);
        fp16_split(v.z, h[2], l[2]);
        fp16_split(v.w, h[3], l[3]);
        *(uint2*)(oh + (size_t)i * 4) = *(uint2*)h;
        *(uint2*)(ol + (size_t)i * 4) = *(uint2*)l;
    } else {
        const int idx = (bid - SPLIT_BLOCKS) * 256 + threadIdx.x;   // SEQ*32
        const int s = idx >> 5, p = idx & 31;
        double theta = pow(10000.0, -(double)p / 32.0);
        float ang = (float)((double)s * theta);
        float sv, cv;
        sincosf(ang, &sv, &cv);
        g_cs[idx] = make_float2(cv, sv);
    }
}

// batched weight transpose: z selects {Wq, Wk, Wv, Wo}; fp32 RxC -> fp16 CxR
__global__ void transpose_all_kernel(const float* __restrict__ Wq,
                                     const float* __restrict__ Wk,
                                     const float* __restrict__ Wv,
                                     const float* __restrict__ Wo) {
    __shared__ float tile[32][33];
    const int z = blockIdx.z;
    const int nx = (z == 1 || z == 2) ? (KVDIM / 32) : (DIM / 32);
    if (blockIdx.x >= nx) return;
    const float* in = (z == 0) ? Wq : (z == 1) ? Wk : (z == 2) ? Wv : Wo;
    __half* out = (z == 0) ? g_bh
                : (z == 1) ? g_bh + (size_t)DIM * DIM
                : (z == 2) ? g_bh + (size_t)(DIM + KVDIM) * DIM
                : g_bho;
    const int Ccols = (z == 1 || z == 2) ? KVDIM : DIM;
    const int R = DIM;
    int bx = blockIdx.x * 32, by = blockIdx.y * 32;
    int x = bx + threadIdx.x;
    #pragma unroll
    for (int i = 0; i < 32; i += 8)
        tile[threadIdx.y + i][threadIdx.x] = in[(size_t)(by + threadIdx.y + i) * Ccols + x];
    __syncthreads();
    int ox = by + threadIdx.x;
    #pragma unroll
    for (int i = 0; i < 32; i += 8)
        out[(size_t)(bx + threadIdx.y + i) * R + ox] = __float2half_rn(tile[threadIdx.x][threadIdx.y + i]);
}

// ================= mma.sync / async helpers =================
__device__ __forceinline__ uint32_t smem_u32(const void* p) {
    uint32_t a;
    asm("{ .reg .u64 t; cvta.to.shared.u64 t, %1; cvt.u32.u64 %0, t; }" : "=r"(a) : "l"(p));
    return a;
}
__device__ __forceinline__ void cp16(uint32_t dst, const void* src) {
    asm volatile("cp.async.cg.shared.global [%0], [%1], 16;" :: "r"(dst), "l"(src));
}
#define CP_COMMIT() asm volatile("cp.async.commit_group;" ::: "memory")
#define CP_WAIT1()  asm volatile("cp.async.wait_group 1;" ::: "memory")

__device__ __forceinline__ void ldsm4(uint32_t* r, uint32_t addr) {
    asm volatile("ldmatrix.sync.aligned.m8n8.x4.shared.b16 {%0,%1,%2,%3}, [%4];"
                 : "=r"(r[0]), "=r"(r[1]), "=r"(r[2]), "=r"(r[3]) : "r"(addr));
}
__device__ __forceinline__ void mma_fp16(float* d, const uint32_t* a, const uint32_t* b) {
    asm volatile(
        "mma.sync.aligned.m16n8k16.row.col.f32.f16.f16.f32 "
        "{%0,%1,%2,%3}, {%4,%5,%6,%7}, {%8,%9}, {%0,%1,%2,%3};\n"
        : "+f"(d[0]), "+f"(d[1]), "+f"(d[2]), "+f"(d[3])
        : "r"(a[0]), "r"(a[1]), "r"(a[2]), "r"(a[3]), "r"(b[0]), "r"(b[1]));
}
__device__ __forceinline__ uint32_t pack_hf2(float x0, float x1) {
    __half2 v = __floats2half2_rn(x0, x1);
    return *(uint32_t*)&v;
}
// degree-4 2^y (err ~4e-5; P is fp16-rounded at 2.4e-4, so invisible)
__device__ __forceinline__ float exp2p(float y) {
    y = fmaxf(y, -120.f);
    int ki = __float2int_rn(y);
    float f = y - (float)ki;
    float p = 0.0096181291f;
    p = fmaf(p, f, 0.0555041087f);
    p = fmaf(p, f, 0.2402265070f);
    p = fmaf(p, f, 0.6931471806f);
    p = fmaf(p, f, 1.0f);
    return p * __int_as_float((ki + 127) << 23);
}

// ---------------- fp16 GEMM, 3-stage pipeline ----------------
#define BPAD 40
#define G_ARRB (128 * BPAD * 2)     /* 10240 B */
#define G_BUFB (3 * G_ARRB)         /* 30720 B per stage */
#define G_SMEM (3 * G_BUFB)         /* 92160 B, 3 stages */

__global__ void __launch_bounds__(256, 2) mma_gemm_fp16(
    const __half* __restrict__ Ah, const __half* __restrict__ Al,
    const __half* __restrict__ Bh,
    const float* __restrict__ bias, float* __restrict__ C, int N, int K,
    int qkv_mode, int two_term)
{
    extern __shared__ char smem[];
    const uint32_t smbase = smem_u32(smem);

    const int t    = threadIdx.x;
    const int lane = t & 31;
    const int wid  = t >> 5;
    const int wr   = wid & 3;
    const int wc   = wid >> 2;
    const int qid  = lane >> 2;
    const int tid4 = lane & 3;

    const size_t m0 = (size_t)blockIdx.y * 128;
    const size_t n0 = (size_t)blockIdx.x * 128;
    const __half* Abh = Ah + m0 * K;
    const __half* Abl = Al + m0 * K;
    const __half* Bbh = Bh + n0 * K;

    const uint32_t a_off = (uint32_t)(((wr * 32 + (lane & 15)) * BPAD + ((lane >> 4) << 3)) * 2);
    const uint32_t b_off = (uint32_t)(((wc * 64 + (lane & 7) + ((lane & 16) >> 1)) * BPAD + (lane & 8)) * 2);

    float acc[2][8][4];
    #pragma unroll
    for (int mf = 0; mf < 2; ++mf)
        #pragma unroll
        for (int nf = 0; nf < 8; ++nf)
            #pragma unroll
            for (int r = 0; r < 4; ++r) acc[mf][nf][r] = 0.f;

    const int nchunks = K / 32;   // 64

    #pragma unroll
    for (int pc = 0; pc < 2; ++pc) {
        const uint32_t dst = smbase + (uint32_t)(pc * G_BUFB);
        #pragma unroll
        for (int i = 0; i < 6; ++i) {
            const int o = t + i * 256;
            const int arr = o >> 9;
            if (arr == 1 && !two_term) continue;
            const int r = (o & 511) >> 2, c = (o & 3) * 8;
            const __half* src = ((arr == 0) ? Abh : (arr == 1) ? Abl : Bbh) + (size_t)r * K + pc * 32 + c;
            cp16(dst + (uint32_t)(arr * G_ARRB) + (uint32_t)((r * BPAD + c) * 2), src);
        }
        CP_COMMIT();
    }

    for (int cch = 0; cch < nchunks; ++cch) {
        CP_WAIT1();
        __syncthreads();

        const uint32_t sb = smbase + (uint32_t)((cch % 3) * G_BUFB);
        #pragma unroll
        for (int ks = 0; ks < 2; ++ks) {
            const uint32_t kb = (uint32_t)(ks * 32);
            uint32_t ah[2][4], al[2][4];
            #pragma unroll
            for (int mf = 0; mf < 2; ++mf) {
                const uint32_t ro = (uint32_t)(mf * 16 * BPAD * 2);
                ldsm4(ah[mf], sb + 0 * G_ARRB + a_off + ro + kb);
                if (two_term) ldsm4(al[mf], sb + 1 * G_ARRB + a_off + ro + kb);
            }
            uint32_t bh[8][2];
            #pragma unroll
            for (int p = 0; p < 4; ++p) {
                const uint32_t ro = (uint32_t)(p * 16 * BPAD * 2);
                uint32_t r[4];
                ldsm4(r, sb + 2 * G_ARRB + b_off + ro + kb);
                bh[2 * p][0] = r[0]; bh[2 * p][1] = r[1];
                bh[2 * p + 1][0] = r[2]; bh[2 * p + 1][1] = r[3];
            }
            #pragma unroll
            for (int nf = 0; nf < 8; ++nf)
                #pragma unroll
                for (int mf = 0; mf < 2; ++mf) {
                    mma_fp16(acc[mf][nf], ah[mf], bh[nf]);
                    if (two_term) mma_fp16(acc[mf][nf], al[mf], bh[nf]);
                }
        }

        if (cch + 2 < nchunks) {
            const uint32_t dst = smbase + (uint32_t)(((cch + 2) % 3) * G_BUFB);
            const int k0 = (cch + 2) * 32;
            #pragma unroll
            for (int i = 0; i < 6; ++i) {
                const int o = t + i * 256;
                const int arr = o >> 9;
                if (arr == 1 && !two_term) continue;
                const int r = (o & 511) >> 2, c = (o & 3) * 8;
                const __half* src = ((arr == 0) ? Abh : (arr == 1) ? Abl : Bbh) + (size_t)r * K + k0 + c;
                cp16(dst + (uint32_t)(arr * G_ARRB) + (uint32_t)((r * BPAD + c) * 2), src);
            }
        }
        CP_COMMIT();
    }

    // ---------------- epilogue ----------------
    const int trow = qid;
    const int tcol = tid4 * 2;
    if (!qkv_mode) {
        #pragma unroll
        for (int mf = 0; mf < 2; ++mf) {
            const size_t m = m0 + wr * 32 + mf * 16 + trow;
            #pragma unroll
            for (int nf = 0; nf < 8; ++nf) {
                const int ncol = (int)n0 + wc * 64 + nf * 8 + tcol;
                float2 v0 = make_float2(acc[mf][nf][0], acc[mf][nf][1]);
                float2 v1 = make_float2(acc[mf][nf][2], acc[mf][nf][3]);
                const float bx = bias[ncol], by = bias[ncol + 1];
                v0.x += bx; v0.y += by;
                v1.x += bx; v1.y += by;
                *(float2*)(C + m * N + ncol)       = v0;
                *(float2*)(C + (m + 8) * N + ncol) = v1;
            }
        }
        return;
    }

    // fused QKV epilogue: rope + fp16 + layout (Q pre-scaled by QSCALE)
    #pragma unroll
    for (int mf = 0; mf < 2; ++mf) {
        const size_t m = m0 + wr * 32 + mf * 16 + trow;
        const int b = (int)(m >> 11);
        const int s = (int)(m & 2047);
        #pragma unroll
        for (int nf = 0; nf < 8; ++nf) {
            const int ncol = (int)n0 + wc * 64 + nf * 8 + tcol;
            float2 v0 = make_float2(acc[mf][nf][0], acc[mf][nf][1]);
            float2 v1 = make_float2(acc[mf][nf][2], acc[mf][nf][3]);
            if (ncol < DIM + KVDIM) {
                const bool isQ = (ncol < DIM);
                const int cc = isQ ? ncol : (ncol - DIM);
                const int hh = cc >> 6, d = cc & 63, p = d >> 1;
                const float2 c0 = g_cs[s * 32 + p];
                const float2 c1 = g_cs[(s + 8) * 32 + p];
                float r0x = v0.x * c0.x - v0.y * c0.y;
                float r0y = v0.x * c0.y + v0.y * c0.x;
                float r1x = v1.x * c1.x - v1.y * c1.y;
                float r1y = v1.x * c1.y + v1.y * c1.x;
                if (isQ) {   // fold softmax scale * log2(e) into Q
                    r0x *= QSCALE; r0y *= QSCALE;
                    r1x *= QSCALE; r1y *= QSCALE;
                }
                __half* dst = isQ ? g_qh : g_kh;
                const int nheads = isQ ? NH : NKV;
                const size_t o0 = (((size_t)(b * nheads + hh)) * SEQ + s) * HD + d;
                const size_t o1 = o0 + 8 * HD;
                *(__half2*)(dst + o0) = __floats2half2_rn(r0x, r0y);
                *(__half2*)(dst + o1) = __floats2half2_rn(r1x, r1y);
            } else {
                const int vc = ncol - DIM - KVDIM;
                const int kv = vc >> 6, d = vc & 63;
                const float bx = bias[vc], by = bias[vc + 1];
                const size_t base = ((size_t)(b * NKV + kv) * HD + d) * SEQ;
                g_vth[base + s]           = __float2half_rn(v0.x + bx);
                g_vth[base + SEQ + s]     = __float2half_rn(v0.y + by);
                g_vth[base + s + 8]       = __float2half_rn(v1.x + bx);
                g_vth[base + SEQ + s + 8] = __float2half_rn(v1.y + by);
            }
        }
    }
}

// ---------------- flash attention v7: 1-term fp16, masked fast-path ----------------
#define FQ 128
#define FK 64
#define SP 72
#define F_QARR (FQ * SP * 2)           /* 18432 (Qh only) */
#define QOFF   F_QARR
#define F_ARR  (FK * SP * 2)           /* 9216 per K/V array */
#define F_BUF  (2 * F_ARR)             /* Kh Vth = 18432 per stage */
#define F_SMEM (QOFF + 3 * F_BUF)      /* 73728 */

__global__ void __launch_bounds__(256, 2) flash_mma_kernel(
    const __half* __restrict__ Qh,
    const __half* __restrict__ Kh, const __half* __restrict__ Vth,
    __half* __restrict__ Oh)
{
    extern __shared__ char smem[];
    const uint32_t smbase = smem_u32(smem);

    const int qt  = (SEQ / FQ - 1) - blockIdx.x;
    const int h   = blockIdx.y;
    const int b   = blockIdx.z;
    const int kvh = h >> 2;
    const int t    = threadIdx.x;
    const int lane = t & 31;
    const int w    = t >> 5;
    const int qid  = lane >> 2;
    const int tid4 = lane & 3;
    const int q0   = qt * FQ;
    const int wrow = w * 16;

    const __half* Qhb = Qh + (((size_t)(b * NH + h)) * SEQ + q0) * HD;
    const __half* Khb = Kh + ((size_t)(b * NKV + kvh)) * SEQ * HD;
    const __half* Vhb = Vth + ((size_t)(b * NKV + kvh)) * HD * SEQ;

    #pragma unroll
    for (int i = 0; i < 4; ++i) {
        const int idx = t + i * 256;
        const int r = idx >> 3, c = (idx & 7) * 8;
        *(uint4*)(smem + (r * SP + c) * 2) = *(const uint4*)(Qhb + (size_t)r * HD + c);
    }

    const uint32_t a_off = (uint32_t)(((wrow + (lane & 15)) * SP + ((lane >> 4) << 3)) * 2);
    const uint32_t b_off = (uint32_t)((((lane & 7) + ((lane & 16) >> 1)) * SP + (lane & 8)) * 2);

    const int ga  = t >> 7;
    const int sub = t & 127;
    const __half* gsrc = (ga == 0) ? Khb : Vhb;
    const bool isK = (ga == 0);

    float oacc[8][4];
    #pragma unroll
    for (int nf = 0; nf < 8; ++nf)
        #pragma unroll
        for (int j = 0; j < 4; ++j) oacc[nf][j] = 0.f;
    float m[2] = {-1e30f, -1e30f};
    float l[2] = {0.f, 0.f};

    const int row_a = q0 + wrow + qid;
    const int row_b = row_a + 8;

    const int ntiles = (q0 + FQ) / FK;   // = q0/64 + 2
    const int qdiag  = q0 / FK;          // first tile that can touch the diagonal

    #pragma unroll
    for (int pt = 0; pt < 2; ++pt) {
        const uint32_t dst = smbase + QOFF + (uint32_t)(pt * F_BUF) + (uint32_t)(ga * F_ARR);
        #pragma unroll
        for (int i = 0; i < 4; ++i) {
            const int idx = sub + i * 128;
            const int row = idx >> 3, col = (idx & 7) * 8;
            const __half* s = isK ? (gsrc + (size_t)(pt * FK + row) * HD + col)
                                  : (gsrc + (size_t)row * SEQ + pt * FK + col);
            cp16(dst + (uint32_t)((row * SP + col) * 2), s);
        }
        CP_COMMIT();
    }
    __syncthreads();

    for (int kt = 0; kt < ntiles; ++kt) {
        CP_WAIT1();
        __syncthreads();

        const uint32_t sb = smbase + QOFF + (uint32_t)((kt % 3) * F_BUF);

        float sacc[8][4];
        #pragma unroll
        for (int nf = 0; nf < 8; ++nf)
            #pragma unroll
            for (int j = 0; j < 4; ++j) sacc[nf][j] = 0.f;

        #pragma unroll
        for (int g2 = 0; g2 < 4; ++g2) {
            const uint32_t kb = (uint32_t)(g2 * 32);
            uint32_t qh4[4];
            ldsm4(qh4, smbase + a_off + kb);
            uint32_t bh[8][2];
            #pragma unroll
            for (int p = 0; p < 4; ++p) {
                const uint32_t ro = (uint32_t)(p * 16 * SP * 2);
                uint32_t r[4];
                ldsm4(r, sb + 0 * F_ARR + b_off + ro + kb);
                bh[2 * p][0] = r[0]; bh[2 * p][1] = r[1];
                bh[2 * p + 1][0] = r[2]; bh[2 * p + 1][1] = r[3];
            }
            #pragma unroll
            for (int nf = 0; nf < 8; ++nf)
                mma_fp16(sacc[nf], qh4, bh[nf]);
        }

        // scores already scaled (QSCALE folded into Q). Mask only near diagonal.
        float tmax[2] = {-1e30f, -1e30f};
        if (kt >= qdiag) {
            #pragma unroll
            for (int nf = 0; nf < 8; ++nf) {
                const int colbase = kt * FK + nf * 8 + tid4 * 2;
                #pragma unroll
                for (int j = 0; j < 4; ++j) {
                    const int col = colbase + (j & 1);
                    const int row = (j < 2) ? row_a : row_b;
                    float v = sacc[nf][j];
                    if (col > row) v = -1e30f;
                    sacc[nf][j] = v;
                    tmax[j >> 1] = fmaxf(tmax[j >> 1], v);
                }
            }
        } else {
            #pragma unroll
            for (int nf = 0; nf < 8; ++nf)
                #pragma unroll
                for (int j = 0; j < 4; ++j)
                    tmax[j >> 1] = fmaxf(tmax[j >> 1], sacc[nf][j]);
        }

        float corr[2];
        #pragma unroll
        for (int hh = 0; hh < 2; ++hh) {
            tmax[hh] = fmaxf(tmax[hh], __shfl_xor_sync(0xffffffffu, tmax[hh], 1));
            tmax[hh] = fmaxf(tmax[hh], __shfl_xor_sync(0xffffffffu, tmax[hh], 2));
            const float mnew = fmaxf(m[hh], tmax[hh]);
            corr[hh] = exp2p(m[hh] - mnew);
            m[hh] = mnew;
            l[hh] *= corr[hh];
        }
        #pragma unroll
        for (int nf = 0; nf < 8; ++nf) {
            oacc[nf][0] *= corr[0]; oacc[nf][1] *= corr[0];
            oacc[nf][2] *= corr[1]; oacc[nf][3] *= corr[1];
        }
        float rsum[2] = {0.f, 0.f};
        #pragma unroll
        for (int nf = 0; nf < 8; ++nf) {
            #pragma unroll
            for (int j = 0; j < 4; ++j) {
                const float p = exp2p(sacc[nf][j] - m[j >> 1]);
                sacc[nf][j] = p;
                rsum[j >> 1] += p;
            }
        }
        #pragma unroll
        for (int hh = 0; hh < 2; ++hh) {
            rsum[hh] += __shfl_xor_sync(0xffffffffu, rsum[hh], 1);
            rsum[hh] += __shfl_xor_sync(0xffffffffu, rsum[hh], 2);
            l[hh] += rsum[hh];
        }

        uint32_t pfh[4][4];
        #pragma unroll
        for (int g2 = 0; g2 < 4; ++g2) {
            const float* s0 = sacc[2 * g2];
            const float* s1 = sacc[2 * g2 + 1];
            pfh[g2][0] = pack_hf2(s0[0], s0[1]);
            pfh[g2][1] = pack_hf2(s0[2], s0[3]);
            pfh[g2][2] = pack_hf2(s1[0], s1[1]);
            pfh[g2][3] = pack_hf2(s1[2], s1[3]);
        }

        #pragma unroll
        for (int g2 = 0; g2 < 4; ++g2) {
            const uint32_t kb = (uint32_t)(g2 * 32);
            uint32_t vh[8][2];
            #pragma unroll
            for (int p = 0; p < 4; ++p) {
                const uint32_t ro = (uint32_t)(p * 16 * SP * 2);
                uint32_t r[4];
                ldsm4(r, sb + 1 * F_ARR + b_off + ro + kb);
                vh[2 * p][0] = r[0]; vh[2 * p][1] = r[1];
                vh[2 * p + 1][0] = r[2]; vh[2 * p + 1][1] = r[3];
            }
            #pragma unroll
            for (int nf = 0; nf < 8; ++nf)
                mma_fp16(oacc[nf], pfh[g2], vh[nf]);
        }

        if (kt + 2 < ntiles) {
            const uint32_t dst = smbase + QOFF + (uint32_t)(((kt + 2) % 3) * F_BUF) + (uint32_t)(ga * F_ARR);
            #pragma unroll
            for (int i = 0; i < 4; ++i) {
                const int idx = sub + i * 128;
                const int row = idx >> 3, col = (idx & 7) * 8;
                const __half* s = isK
                    ? (gsrc + (size_t)((kt + 2) * FK + row) * HD + col)
                    : (gsrc + (size_t)row * SEQ + (kt + 2) * FK + col);
                cp16(dst + (uint32_t)((row * SP + col) * 2), s);
            }
        }
        CP_COMMIT();
    }

    const float inv_a = 1.0f / l[0];
    const float inv_b = 1.0f / l[1];
    const size_t rA = ((size_t)(b * SEQ) + row_a) * DIM + h * HD;
    const size_t rB = rA + 8 * DIM;
    #pragma unroll
    for (int nf = 0; nf < 8; ++nf) {
        const int col = nf * 8 + tid4 * 2;
        *(__half2*)(Oh + rA + col) = __floats2half2_rn(oacc[nf][0] * inv_a, oacc[nf][1] * inv_a);
        *(__half2*)(Oh + rB + col) = __floats2half2_rn(oacc[nf][2] * inv_b, oacc[nf][3] * inv_b);
    }
}

// ---------------- host launcher ----------------
extern "C" void kernel_launch(void* const* d_in, const int* in_sizes, int n_in,
                              void* d_out, int out_size) {
    (void)in_sizes; (void)n_in; (void)out_size;
    const float* x  = (const float*)d_in[0];
    const float* Wq = (const float*)d_in[1];
    const float* Wk = (const float*)d_in[2];
    const float* Wv = (const float*)d_in[3];
    const float* bv = (const float*)d_in[4];
    const float* Wo = (const float*)d_in[5];
    const float* bo = (const float*)d_in[6];
    float* out = (float*)d_out;

    __half *ah, *al, *bh, *bho, *qh, *kh, *vth;
    cudaGetSymbolAddress((void**)&ah,  g_ah);
    cudaGetSymbolAddress((void**)&al,  g_al);
    cudaGetSymbolAddress((void**)&bh,  g_bh);
    cudaGetSymbolAddress((void**)&bho, g_bho);
    cudaGetSymbolAddress((void**)&qh,  g_qh);
    cudaGetSymbolAddress((void**)&kh,  g_kh);
    cudaGetSymbolAddress((void**)&vth, g_vth);

    cudaFuncSetAttribute(mma_gemm_fp16, cudaFuncAttributeMaxDynamicSharedMemorySize, G_SMEM);
    cudaFuncSetAttribute(flash_mma_kernel, cudaFuncAttributeMaxDynamicSharedMemorySize, F_SMEM);

    prep_kernel<<<SPLIT_BLOCKS + (SEQ * 32) / 256, 256>>>(x, ah, al);
    transpose_all_kernel<<<dim3(DIM / 32, DIM / 32, 4), dim3(32, 8)>>>(Wq, Wk, Wv, Wo);

    mma_gemm_fp16<<<dim3(NQKV / 128, MROWS / 128), 256, G_SMEM>>>(
        ah, al, bh, bv, nullptr, NQKV, DIM, 1, 1);

    flash_mma_kernel<<<dim3(SEQ / FQ, NH, BATCH), 256, F_SMEM>>>(qh, kh, vth, ah);

    mma_gemm_fp16<<<dim3(DIM / 128, MROWS / 128), 256, G_SMEM>>>(
        ah, al, bho, bo, out, DIM, DIM, 0, 0);
}

// round 15
// speedup vs baseline: 6.7225x; 1.2974x over previous
#include <cuda_runtime.h>
#include <cuda_fp16.h>
#include <math.h>
#include <stdint.h>

#define DIM 2048
#define NH 32
#define NKV 8
#define HD 64
#define BATCH 2
#define SEQ 2048
#define MROWS (BATCH*SEQ)   /* 4096 */
#define KVDIM (NKV*HD)      /* 512 */
#define NQKV (DIM + 2*KVDIM) /* 3072 */

// ---------------- scratch (static device allocations; no cudaMalloc) ----------------
__device__ __align__(16) __half g_ah[(size_t)MROWS * DIM];   // activations fp16
__device__ __align__(16) __half g_bh[(size_t)NQKV * DIM];    // Wq|Wk|Wv transposed
__device__ __align__(16) __half g_bho[(size_t)DIM * DIM];    // Wo transposed
// flash operands: fp16; Q pre-scaled by 0.125*log2(e)
__device__ __align__(16) __half g_qh[(size_t)BATCH * NH * SEQ * HD];
__device__ __align__(16) __half g_kh[(size_t)BATCH * NKV * SEQ * HD];
__device__ __align__(16) __half g_vth[(size_t)BATCH * NKV * HD * SEQ];  // [b,kv,d,s]
__device__ float2 g_cs[(size_t)SEQ * (HD / 2)];

#define QSCALE 0.18033688011112042f   /* 0.125 * log2(e) */

// fused prep: x -> fp16 (blocks 0..8191), sincos table (rest)
#define SPLIT_BLOCKS ((MROWS * DIM) / 1024)   /* 8192 */
__global__ void prep_kernel(const float* __restrict__ in, __half* __restrict__ oh) {
    const int bid = blockIdx.x;
    if (bid < SPLIT_BLOCKS) {
        const int i = bid * 256 + threadIdx.x;
        const float4 v = *(const float4*)(in + (size_t)i * 4);
        __half h[4];
        h[0] = __float2half_rn(v.x);
        h[1] = __float2half_rn(v.y);
        h[2] = __float2half_rn(v.z);
        h[3] = __float2half_rn(v.w);
        *(uint2*)(oh + (size_t)i * 4) = *(uint2*)h;
    } else {
        const int idx = (bid - SPLIT_BLOCKS) * 256 + threadIdx.x;   // SEQ*32
        const int s = idx >> 5, p = idx & 31;
        double theta = pow(10000.0, -(double)p / 32.0);
        float ang = (float)((double)s * theta);
        float sv, cv;
        sincosf(ang, &sv, &cv);
        g_cs[idx] = make_float2(cv, sv);
    }
}

// batched weight transpose: z selects {Wq, Wk, Wv, Wo}; fp32 RxC -> fp16 CxR
__global__ void transpose_all_kernel(const float* __restrict__ Wq,
                                     const float* __restrict__ Wk,
                                     const float* __restrict__ Wv,
                                     const float* __restrict__ Wo) {
    __shared__ float tile[32][33];
    const int z = blockIdx.z;
    const int nx = (z == 1 || z == 2) ? (KVDIM / 32) : (DIM / 32);
    if (blockIdx.x >= nx) return;
    const float* in = (z == 0) ? Wq : (z == 1) ? Wk : (z == 2) ? Wv : Wo;
    __half* out = (z == 0) ? g_bh
                : (z == 1) ? g_bh + (size_t)DIM * DIM
                : (z == 2) ? g_bh + (size_t)(DIM + KVDIM) * DIM
                : g_bho;
    const int Ccols = (z == 1 || z == 2) ? KVDIM : DIM;
    const int R = DIM;
    int bx = blockIdx.x * 32, by = blockIdx.y * 32;
    int x = bx + threadIdx.x;
    #pragma unroll
    for (int i = 0; i < 32; i += 8)
        tile[threadIdx.y + i][threadIdx.x] = in[(size_t)(by + threadIdx.y + i) * Ccols + x];
    __syncthreads();
    int ox = by + threadIdx.x;
    #pragma unroll
    for (int i = 0; i < 32; i += 8)
        out[(size_t)(bx + threadIdx.y + i) * R + ox] = __float2half_rn(tile[threadIdx.x][threadIdx.y + i]);
}

// ================= mma.sync / async helpers =================
__device__ __forceinline__ uint32_t smem_u32(const void* p) {
    uint32_t a;
    asm("{ .reg .u64 t; cvta.to.shared.u64 t, %1; cvt.u32.u64 %0, t; }" : "=r"(a) : "l"(p));
    return a;
}
__device__ __forceinline__ void cp16(uint32_t dst, const void* src) {
    asm volatile("cp.async.cg.shared.global [%0], [%1], 16;" :: "r"(dst), "l"(src));
}
#define CP_COMMIT() asm volatile("cp.async.commit_group;" ::: "memory")
#define CP_WAIT1()  asm volatile("cp.async.wait_group 1;" ::: "memory")

__device__ __forceinline__ void ldsm4(uint32_t* r, uint32_t addr) {
    asm volatile("ldmatrix.sync.aligned.m8n8.x4.shared.b16 {%0,%1,%2,%3}, [%4];"
                 : "=r"(r[0]), "=r"(r[1]), "=r"(r[2]), "=r"(r[3]) : "r"(addr));
}
__device__ __forceinline__ void mma_fp16(float* d, const uint32_t* a, const uint32_t* b) {
    asm volatile(
        "mma.sync.aligned.m16n8k16.row.col.f32.f16.f16.f32 "
        "{%0,%1,%2,%3}, {%4,%5,%6,%7}, {%8,%9}, {%0,%1,%2,%3};\n"
        : "+f"(d[0]), "+f"(d[1]), "+f"(d[2]), "+f"(d[3])
        : "r"(a[0]), "r"(a[1]), "r"(a[2]), "r"(a[3]), "r"(b[0]), "r"(b[1]));
}
__device__ __forceinline__ uint32_t pack_hf2(float x0, float x1) {
    __half2 v = __floats2half2_rn(x0, x1);
    return *(uint32_t*)&v;
}
// degree-4 2^y
__device__ __forceinline__ float exp2p(float y) {
    y = fmaxf(y, -120.f);
    int ki = __float2int_rn(y);
    float f = y - (float)ki;
    float p = 0.0096181291f;
    p = fmaf(p, f, 0.0555041087f);
    p = fmaf(p, f, 0.2402265070f);
    p = fmaf(p, f, 0.6931471806f);
    p = fmaf(p, f, 1.0f);
    return p * __int_as_float((ki + 127) << 23);
}

// ---------------- fp16 1-term GEMM, 3-stage pipeline ----------------
// C = Ah @ Bh^T. qkv_mode 1: fused rope epilogue (bias = bv for V).
#define BPAD 40
#define G_ARRB (128 * BPAD * 2)     /* 10240 B */
#define G_BUFB (2 * G_ARRB)         /* 20480 B per stage (A, B) */
#define G_SMEM (3 * G_BUFB)         /* 61440 B, 3 stages */

__global__ void __launch_bounds__(256, 2) mma_gemm_fp16(
    const __half* __restrict__ Ah, const __half* __restrict__ Bh,
    const float* __restrict__ bias, float* __restrict__ C, int N, int K,
    int qkv_mode)
{
    extern __shared__ char smem[];
    const uint32_t smbase = smem_u32(smem);

    const int t    = threadIdx.x;
    const int lane = t & 31;
    const int wid  = t >> 5;
    const int wr   = wid & 3;
    const int wc   = wid >> 2;
    const int qid  = lane >> 2;
    const int tid4 = lane & 3;

    const size_t m0 = (size_t)blockIdx.y * 128;
    const size_t n0 = (size_t)blockIdx.x * 128;
    const __half* Abh = Ah + m0 * K;
    const __half* Bbh = Bh + n0 * K;

    const uint32_t a_off = (uint32_t)(((wr * 32 + (lane & 15)) * BPAD + ((lane >> 4) << 3)) * 2);
    const uint32_t b_off = (uint32_t)(((wc * 64 + (lane & 7) + ((lane & 16) >> 1)) * BPAD + (lane & 8)) * 2);

    float acc[2][8][4];
    #pragma unroll
    for (int mf = 0; mf < 2; ++mf)
        #pragma unroll
        for (int nf = 0; nf < 8; ++nf)
            #pragma unroll
            for (int r = 0; r < 4; ++r) acc[mf][nf][r] = 0.f;

    const int nchunks = K / 32;   // 64

    // prologue: chunks 0,1 -> stages 0,1 (2 arrays x 512 x 16B = 4 per thread)
    #pragma unroll
    for (int pc = 0; pc < 2; ++pc) {
        const uint32_t dst = smbase + (uint32_t)(pc * G_BUFB);
        #pragma unroll
        for (int i = 0; i < 4; ++i) {
            const int o = t + i * 256;
            const int arr = o >> 9;
            const int r = (o & 511) >> 2, c = (o & 3) * 8;
            const __half* src = ((arr == 0) ? Abh : Bbh) + (size_t)r * K + pc * 32 + c;
            cp16(dst + (uint32_t)(arr * G_ARRB) + (uint32_t)((r * BPAD + c) * 2), src);
        }
        CP_COMMIT();
    }

    for (int cch = 0; cch < nchunks; ++cch) {
        CP_WAIT1();
        __syncthreads();

        const uint32_t sb = smbase + (uint32_t)((cch % 3) * G_BUFB);
        #pragma unroll
        for (int ks = 0; ks < 2; ++ks) {
            const uint32_t kb = (uint32_t)(ks * 32);
            uint32_t ah[2][4];
            #pragma unroll
            for (int mf = 0; mf < 2; ++mf) {
                const uint32_t ro = (uint32_t)(mf * 16 * BPAD * 2);
                ldsm4(ah[mf], sb + a_off + ro + kb);
            }
            uint32_t bh[8][2];
            #pragma unroll
            for (int p = 0; p < 4; ++p) {
                const uint32_t ro = (uint32_t)(p * 16 * BPAD * 2);
                uint32_t r[4];
                ldsm4(r, sb + G_ARRB + b_off + ro + kb);
                bh[2 * p][0] = r[0]; bh[2 * p][1] = r[1];
                bh[2 * p + 1][0] = r[2]; bh[2 * p + 1][1] = r[3];
            }
            #pragma unroll
            for (int nf = 0; nf < 8; ++nf)
                #pragma unroll
                for (int mf = 0; mf < 2; ++mf)
                    mma_fp16(acc[mf][nf], ah[mf], bh[nf]);
        }

        if (cch + 2 < nchunks) {
            const uint32_t dst = smbase + (uint32_t)(((cch + 2) % 3) * G_BUFB);
            const int k0 = (cch + 2) * 32;
            #pragma unroll
            for (int i = 0; i < 4; ++i) {
                const int o = t + i * 256;
                const int arr = o >> 9;
                const int r = (o & 511) >> 2, c = (o & 3) * 8;
                const __half* src = ((arr == 0) ? Abh : Bbh) + (size_t)r * K + k0 + c;
                cp16(dst + (uint32_t)(arr * G_ARRB) + (uint32_t)((r * BPAD + c) * 2), src);
            }
        }
        CP_COMMIT();
    }

    // ---------------- epilogue ----------------
    const int trow = qid;
    const int tcol = tid4 * 2;
    if (!qkv_mode) {
        #pragma unroll
        for (int mf = 0; mf < 2; ++mf) {
            const size_t m = m0 + wr * 32 + mf * 16 + trow;
            #pragma unroll
            for (int nf = 0; nf < 8; ++nf) {
                const int ncol = (int)n0 + wc * 64 + nf * 8 + tcol;
                float2 v0 = make_float2(acc[mf][nf][0], acc[mf][nf][1]);
                float2 v1 = make_float2(acc[mf][nf][2], acc[mf][nf][3]);
                const float bx = bias[ncol], by = bias[ncol + 1];
                v0.x += bx; v0.y += by;
                v1.x += bx; v1.y += by;
                *(float2*)(C + m * N + ncol)       = v0;
                *(float2*)(C + (m + 8) * N + ncol) = v1;
            }
        }
        return;
    }

    // fused QKV epilogue: rope + fp16 + layout (Q pre-scaled by QSCALE)
    #pragma unroll
    for (int mf = 0; mf < 2; ++mf) {
        const size_t m = m0 + wr * 32 + mf * 16 + trow;
        const int b = (int)(m >> 11);
        const int s = (int)(m & 2047);
        #pragma unroll
        for (int nf = 0; nf < 8; ++nf) {
            const int ncol = (int)n0 + wc * 64 + nf * 8 + tcol;
            float2 v0 = make_float2(acc[mf][nf][0], acc[mf][nf][1]);
            float2 v1 = make_float2(acc[mf][nf][2], acc[mf][nf][3]);
            if (ncol < DIM + KVDIM) {
                const bool isQ = (ncol < DIM);
                const int cc = isQ ? ncol : (ncol - DIM);
                const int hh = cc >> 6, d = cc & 63, p = d >> 1;
                const float2 c0 = g_cs[s * 32 + p];
                const float2 c1 = g_cs[(s + 8) * 32 + p];
                float r0x = v0.x * c0.x - v0.y * c0.y;
                float r0y = v0.x * c0.y + v0.y * c0.x;
                float r1x = v1.x * c1.x - v1.y * c1.y;
                float r1y = v1.x * c1.y + v1.y * c1.x;
                if (isQ) {
                    r0x *= QSCALE; r0y *= QSCALE;
                    r1x *= QSCALE; r1y *= QSCALE;
                }
                __half* dst = isQ ? g_qh : g_kh;
                const int nheads = isQ ? NH : NKV;
                const size_t o0 = (((size_t)(b * nheads + hh)) * SEQ + s) * HD + d;
                const size_t o1 = o0 + 8 * HD;
                *(__half2*)(dst + o0) = __floats2half2_rn(r0x, r0y);
                *(__half2*)(dst + o1) = __floats2half2_rn(r1x, r1y);
            } else {
                const int vc = ncol - DIM - KVDIM;
                const int kv = vc >> 6, d = vc & 63;
                const float bx = bias[vc], by = bias[vc + 1];
                const size_t base = ((size_t)(b * NKV + kv) * HD + d) * SEQ;
                g_vth[base + s]           = __float2half_rn(v0.x + bx);
                g_vth[base + SEQ + s]     = __float2half_rn(v0.y + by);
                g_vth[base + s + 8]       = __float2half_rn(v1.x + bx);
                g_vth[base + SEQ + s + 8] = __float2half_rn(v1.y + by);
            }
        }
    }
}

// ---------------- flash attention v7 (unchanged from R14) ----------------
#define FQ 128
#define FK 64
#define SP 72
#define F_QARR (FQ * SP * 2)
#define QOFF   F_QARR
#define F_ARR  (FK * SP * 2)
#define F_BUF  (2 * F_ARR)
#define F_SMEM (QOFF + 3 * F_BUF)

__global__ void __launch_bounds__(256, 2) flash_mma_kernel(
    const __half* __restrict__ Qh,
    const __half* __restrict__ Kh, const __half* __restrict__ Vth,
    __half* __restrict__ Oh)
{
    extern __shared__ char smem[];
    const uint32_t smbase = smem_u32(smem);

    const int qt  = (SEQ / FQ - 1) - blockIdx.x;
    const int h   = blockIdx.y;
    const int b   = blockIdx.z;
    const int kvh = h >> 2;
    const int t    = threadIdx.x;
    const int lane = t & 31;
    const int w    = t >> 5;
    const int qid  = lane >> 2;
    const int tid4 = lane & 3;
    const int q0   = qt * FQ;
    const int wrow = w * 16;

    const __half* Qhb = Qh + (((size_t)(b * NH + h)) * SEQ + q0) * HD;
    const __half* Khb = Kh + ((size_t)(b * NKV + kvh)) * SEQ * HD;
    const __half* Vhb = Vth + ((size_t)(b * NKV + kvh)) * HD * SEQ;

    #pragma unroll
    for (int i = 0; i < 4; ++i) {
        const int idx = t + i * 256;
        const int r = idx >> 3, c = (idx & 7) * 8;
        *(uint4*)(smem + (r * SP + c) * 2) = *(const uint4*)(Qhb + (size_t)r * HD + c);
    }

    const uint32_t a_off = (uint32_t)(((wrow + (lane & 15)) * SP + ((lane >> 4) << 3)) * 2);
    const uint32_t b_off = (uint32_t)((((lane & 7) + ((lane & 16) >> 1)) * SP + (lane & 8)) * 2);

    const int ga  = t >> 7;
    const int sub = t & 127;
    const __half* gsrc = (ga == 0) ? Khb : Vhb;
    const bool isK = (ga == 0);

    float oacc[8][4];
    #pragma unroll
    for (int nf = 0; nf < 8; ++nf)
        #pragma unroll
        for (int j = 0; j < 4; ++j) oacc[nf][j] = 0.f;
    float m[2] = {-1e30f, -1e30f};
    float l[2] = {0.f, 0.f};

    const int row_a = q0 + wrow + qid;
    const int row_b = row_a + 8;

    const int ntiles = (q0 + FQ) / FK;
    const int qdiag  = q0 / FK;

    #pragma unroll
    for (int pt = 0; pt < 2; ++pt) {
        const uint32_t dst = smbase + QOFF + (uint32_t)(pt * F_BUF) + (uint32_t)(ga * F_ARR);
        #pragma unroll
        for (int i = 0; i < 4; ++i) {
            const int idx = sub + i * 128;
            const int row = idx >> 3, col = (idx & 7) * 8;
            const __half* s = isK ? (gsrc + (size_t)(pt * FK + row) * HD + col)
                                  : (gsrc + (size_t)row * SEQ + pt * FK + col);
            cp16(dst + (uint32_t)((row * SP + col) * 2), s);
        }
        CP_COMMIT();
    }
    __syncthreads();

    for (int kt = 0; kt < ntiles; ++kt) {
        CP_WAIT1();
        __syncthreads();

        const uint32_t sb = smbase + QOFF + (uint32_t)((kt % 3) * F_BUF);

        float sacc[8][4];
        #pragma unroll
        for (int nf = 0; nf < 8; ++nf)
            #pragma unroll
            for (int j = 0; j < 4; ++j) sacc[nf][j] = 0.f;

        #pragma unroll
        for (int g2 = 0; g2 < 4; ++g2) {
            const uint32_t kb = (uint32_t)(g2 * 32);
            uint32_t qh4[4];
            ldsm4(qh4, smbase + a_off + kb);
            uint32_t bh[8][2];
            #pragma unroll
            for (int p = 0; p < 4; ++p) {
                const uint32_t ro = (uint32_t)(p * 16 * SP * 2);
                uint32_t r[4];
                ldsm4(r, sb + 0 * F_ARR + b_off + ro + kb);
                bh[2 * p][0] = r[0]; bh[2 * p][1] = r[1];
                bh[2 * p + 1][0] = r[2]; bh[2 * p + 1][1] = r[3];
            }
            #pragma unroll
            for (int nf = 0; nf < 8; ++nf)
                mma_fp16(sacc[nf], qh4, bh[nf]);
        }

        float tmax[2] = {-1e30f, -1e30f};
        if (kt >= qdiag) {
            #pragma unroll
            for (int nf = 0; nf < 8; ++nf) {
                const int colbase = kt * FK + nf * 8 + tid4 * 2;
                #pragma unroll
                for (int j = 0; j < 4; ++j) {
                    const int col = colbase + (j & 1);
                    const int row = (j < 2) ? row_a : row_b;
                    float v = sacc[nf][j];
                    if (col > row) v = -1e30f;
                    sacc[nf][j] = v;
                    tmax[j >> 1] = fmaxf(tmax[j >> 1], v);
                }
            }
        } else {
            #pragma unroll
            for (int nf = 0; nf < 8; ++nf)
                #pragma unroll
                for (int j = 0; j < 4; ++j)
                    tmax[j >> 1] = fmaxf(tmax[j >> 1], sacc[nf][j]);
        }

        float corr[2];
        #pragma unroll
        for (int hh = 0; hh < 2; ++hh) {
            tmax[hh] = fmaxf(tmax[hh], __shfl_xor_sync(0xffffffffu, tmax[hh], 1));
            tmax[hh] = fmaxf(tmax[hh], __shfl_xor_sync(0xffffffffu, tmax[hh], 2));
            const float mnew = fmaxf(m[hh], tmax[hh]);
            corr[hh] = exp2p(m[hh] - mnew);
            m[hh] = mnew;
            l[hh] *= corr[hh];
        }
        #pragma unroll
        for (int nf = 0; nf < 8; ++nf) {
            oacc[nf][0] *= corr[0]; oacc[nf][1] *= corr[0];
            oacc[nf][2] *= corr[1]; oacc[nf][3] *= corr[1];
        }
        float rsum[2] = {0.f, 0.f};
        #pragma unroll
        for (int nf = 0; nf < 8; ++nf) {
            #pragma unroll
            for (int j = 0; j < 4; ++j) {
                const float p = exp2p(sacc[nf][j] - m[j >> 1]);
                sacc[nf][j] = p;
                rsum[j >> 1] += p;
            }
        }
        #pragma unroll
        for (int hh = 0; hh < 2; ++hh) {
            rsum[hh] += __shfl_xor_sync(0xffffffffu, rsum[hh], 1);
            rsum[hh] += __shfl_xor_sync(0xffffffffu, rsum[hh], 2);
            l[hh] += rsum[hh];
        }

        uint32_t pfh[4][4];
        #pragma unroll
        for (int g2 = 0; g2 < 4; ++g2) {
            const float* s0 = sacc[2 * g2];
            const float* s1 = sacc[2 * g2 + 1];
            pfh[g2][0] = pack_hf2(s0[0], s0[1]);
            pfh[g2][1] = pack_hf2(s0[2], s0[3]);
            pfh[g2][2] = pack_hf2(s1[0], s1[1]);
            pfh[g2][3] = pack_hf2(s1[2], s1[3]);
        }

        #pragma unroll
        for (int g2 = 0; g2 < 4; ++g2) {
            const uint32_t kb = (uint32_t)(g2 * 32);
            uint32_t vh[8][2];
            #pragma unroll
            for (int p = 0; p < 4; ++p) {
                const uint32_t ro = (uint32_t)(p * 16 * SP * 2);
                uint32_t r[4];
                ldsm4(r, sb + 1 * F_ARR + b_off + ro + kb);
                vh[2 * p][0] = r[0]; vh[2 * p][1] = r[1];
                vh[2 * p + 1][0] = r[2]; vh[2 * p + 1][1] = r[3];
            }
            #pragma unroll
            for (int nf = 0; nf < 8; ++nf)
                mma_fp16(oacc[nf], pfh[g2], vh[nf]);
        }

        if (kt + 2 < ntiles) {
            const uint32_t dst = smbase + QOFF + (uint32_t)(((kt + 2) % 3) * F_BUF) + (uint32_t)(ga * F_ARR);
            #pragma unroll
            for (int i = 0; i < 4; ++i) {
                const int idx = sub + i * 128;
                const int row = idx >> 3, col = (idx & 7) * 8;
                const __half* s = isK
                    ? (gsrc + (size_t)((kt + 2) * FK + row) * HD + col)
                    : (gsrc + (size_t)row * SEQ + (kt + 2) * FK + col);
                cp16(dst + (uint32_t)((row * SP + col) * 2), s);
            }
        }
        CP_COMMIT();
    }

    const float inv_a = 1.0f / l[0];
    const float inv_b = 1.0f / l[1];
    const size_t rA = ((size_t)(b * SEQ) + row_a) * DIM + h * HD;
    const size_t rB = rA + 8 * DIM;
    #pragma unroll
    for (int nf = 0; nf < 8; ++nf) {
        const int col = nf * 8 + tid4 * 2;
        *(__half2*)(Oh + rA + col) = __floats2half2_rn(oacc[nf][0] * inv_a, oacc[nf][1] * inv_a);
        *(__half2*)(Oh + rB + col) = __floats2half2_rn(oacc[nf][2] * inv_b, oacc[nf][3] * inv_b);
    }
}

// ---------------- host launcher ----------------
extern "C" void kernel_launch(void* const* d_in, const int* in_sizes, int n_in,
                              void* d_out, int out_size) {
    (void)in_sizes; (void)n_in; (void)out_size;
    const float* x  = (const float*)d_in[0];
    const float* Wq = (const float*)d_in[1];
    const float* Wk = (const float*)d_in[2];
    const float* Wv = (const float*)d_in[3];
    const float* bv = (const float*)d_in[4];
    const float* Wo = (const float*)d_in[5];
    const float* bo = (const float*)d_in[6];
    float* out = (float*)d_out;

    __half *ah, *bh, *bho, *qh, *kh, *vth;
    cudaGetSymbolAddress((void**)&ah,  g_ah);
    cudaGetSymbolAddress((void**)&bh,  g_bh);
    cudaGetSymbolAddress((void**)&bho, g_bho);
    cudaGetSymbolAddress((void**)&qh,  g_qh);
    cudaGetSymbolAddress((void**)&kh,  g_kh);
    cudaGetSymbolAddress((void**)&vth, g_vth);

    cudaFuncSetAttribute(mma_gemm_fp16, cudaFuncAttributeMaxDynamicSharedMemorySize, G_SMEM);
    cudaFuncSetAttribute(flash_mma_kernel, cudaFuncAttributeMaxDynamicSharedMemorySize, F_SMEM);

    prep_kernel<<<SPLIT_BLOCKS + (SEQ * 32) / 256, 256>>>(x, ah);
    transpose_all_kernel<<<dim3(DIM / 32, DIM / 32, 4), dim3(32, 8)>>>(Wq, Wk, Wv, Wo);

    // merged QKV projection (N = 3072), 1-term, fused rope epilogue
    mma_gemm_fp16<<<dim3(NQKV / 128, MROWS / 128), 256, G_SMEM>>>(
        ah, bh, bv, nullptr, NQKV, DIM, 1);

    // flash writes fp16 ah for the O projection
    flash_mma_kernel<<<dim3(SEQ / FQ, NH, BATCH), 256, F_SMEM>>>(qh, kh, vth, ah);

    // O projection: 1-term
    mma_gemm_fp16<<<dim3(DIM / 128, MROWS / 128), 256, G_SMEM>>>(
        ah, bho, bo, out, DIM, DIM, 0);
}

// round 16
// speedup vs baseline: 7.5122x; 1.1175x over previous
#include <cuda_runtime.h>
#include <cuda_fp16.h>
#include <math.h>
#include <stdint.h>

#define DIM 2048
#define NH 32
#define NKV 8
#define HD 64
#define BATCH 2
#define SEQ 2048
#define MROWS (BATCH*SEQ)   /* 4096 */
#define KVDIM (NKV*HD)      /* 512 */
#define NQKV (DIM + 2*KVDIM) /* 3072 */

// ---------------- scratch (static device allocations; no cudaMalloc) ----------------
__device__ __align__(16) __half g_ah[(size_t)MROWS * DIM];   // activations fp16
__device__ __align__(16) __half g_bh[(size_t)NQKV * DIM];    // Wq|Wk|Wv transposed
__device__ __align__(16) __half g_bho[(size_t)DIM * DIM];    // Wo transposed
// flash operands: fp16; Q pre-scaled by 0.125*log2(e)
__device__ __align__(16) __half g_qh[(size_t)BATCH * NH * SEQ * HD];
__device__ __align__(16) __half g_kh[(size_t)BATCH * NKV * SEQ * HD];
__device__ __align__(16) __half g_vth[(size_t)BATCH * NKV * HD * SEQ];  // [b,kv,d,s]
__device__ float2 g_cs[(size_t)SEQ * (HD / 2)];

#define QSCALE 0.18033688011112042f   /* 0.125 * log2(e) */

// ---------------- fused prep + weight transpose (one launch) ----------------
// z 0..3: transpose {Wq,Wk,Wv,Wo}; z 4..6: x->fp16 convert + sincos table.
#define SPLIT_BLOCKS ((MROWS * DIM) / 1024)          /* 8192 */
#define PREP_TOTAL (SPLIT_BLOCKS + (SEQ * 32) / 256) /* 8448 */

__global__ void prep_transpose_kernel(const float* __restrict__ x,
                                      __half* __restrict__ oh,
                                      const float* __restrict__ Wq,
                                      const float* __restrict__ Wk,
                                      const float* __restrict__ Wv,
                                      const float* __restrict__ Wo) {
    __shared__ float tile[32][33];
    const int z = blockIdx.z;
    if (z < 4) {
        const int nx = (z == 1 || z == 2) ? (KVDIM / 32) : (DIM / 32);
        if (blockIdx.x >= nx) return;
        const float* in = (z == 0) ? Wq : (z == 1) ? Wk : (z == 2) ? Wv : Wo;
        __half* out = (z == 0) ? g_bh
                    : (z == 1) ? g_bh + (size_t)DIM * DIM
                    : (z == 2) ? g_bh + (size_t)(DIM + KVDIM) * DIM
                    : g_bho;
        const int Ccols = (z == 1 || z == 2) ? KVDIM : DIM;
        const int R = DIM;
        int bx = blockIdx.x * 32, by = blockIdx.y * 32;
        int xx = bx + threadIdx.x;
        #pragma unroll
        for (int i = 0; i < 32; i += 8)
            tile[threadIdx.y + i][threadIdx.x] = in[(size_t)(by + threadIdx.y + i) * Ccols + xx];
        __syncthreads();
        int ox = by + threadIdx.x;
        #pragma unroll
        for (int i = 0; i < 32; i += 8)
            out[(size_t)(bx + threadIdx.y + i) * R + ox] =
                __float2half_rn(tile[threadIdx.x][threadIdx.y + i]);
        return;
    }
    // prep region
    const int bid = (z - 4) * 4096 + blockIdx.y * 64 + blockIdx.x;
    if (bid >= PREP_TOTAL) return;
    const int t = threadIdx.y * 32 + threadIdx.x;
    if (bid < SPLIT_BLOCKS) {
        const int i = bid * 256 + t;
        const float4 v = *(const float4*)(x + (size_t)i * 4);
        __half h[4];
        h[0] = __float2half_rn(v.x);
        h[1] = __float2half_rn(v.y);
        h[2] = __float2half_rn(v.z);
        h[3] = __float2half_rn(v.w);
        *(uint2*)(oh + (size_t)i * 4) = *(uint2*)h;
    } else {
        const int idx = (bid - SPLIT_BLOCKS) * 256 + t;   // SEQ*32
        const int s = idx >> 5, p = idx & 31;
        double theta = pow(10000.0, -(double)p / 32.0);
        float ang = (float)((double)s * theta);
        float sv, cv;
        sincosf(ang, &sv, &cv);
        g_cs[idx] = make_float2(cv, sv);
    }
}

// ================= mma.sync / async helpers =================
__device__ __forceinline__ uint32_t smem_u32(const void* p) {
    uint32_t a;
    asm("{ .reg .u64 t; cvta.to.shared.u64 t, %1; cvt.u32.u64 %0, t; }" : "=r"(a) : "l"(p));
    return a;
}
__device__ __forceinline__ void cp16(uint32_t dst, const void* src) {
    asm volatile("cp.async.cg.shared.global [%0], [%1], 16;" :: "r"(dst), "l"(src));
}
#define CP_COMMIT() asm volatile("cp.async.commit_group;" ::: "memory")
#define CP_WAIT1()  asm volatile("cp.async.wait_group 1;" ::: "memory")

__device__ __forceinline__ void ldsm4(uint32_t* r, uint32_t addr) {
    asm volatile("ldmatrix.sync.aligned.m8n8.x4.shared.b16 {%0,%1,%2,%3}, [%4];"
                 : "=r"(r[0]), "=r"(r[1]), "=r"(r[2]), "=r"(r[3]) : "r"(addr));
}
__device__ __forceinline__ void mma_fp16(float* d, const uint32_t* a, const uint32_t* b) {
    asm volatile(
        "mma.sync.aligned.m16n8k16.row.col.f32.f16.f16.f32 "
        "{%0,%1,%2,%3}, {%4,%5,%6,%7}, {%8,%9}, {%0,%1,%2,%3};\n"
        : "+f"(d[0]), "+f"(d[1]), "+f"(d[2]), "+f"(d[3])
        : "r"(a[0]), "r"(a[1]), "r"(a[2]), "r"(a[3]), "r"(b[0]), "r"(b[1]));
}
__device__ __forceinline__ uint32_t pack_hf2(float x0, float x1) {
    __half2 v = __floats2half2_rn(x0, x1);
    return *(uint32_t*)&v;
}
// hardware 2^y (MUFU): 1 issued instruction; underflow flushes to 0 which is
// exactly the masked / first-tile semantics (y ~ -1e30 -> 0)
__device__ __forceinline__ float ex2(float y) {
    float r;
    asm("ex2.approx.ftz.f32 %0, %1;" : "=f"(r) : "f"(y));
    return r;
}

// ---------------- fp16 1-term GEMM, 3-stage pipeline ----------------
#define BPAD 40
#define G_ARRB (128 * BPAD * 2)     /* 10240 B */
#define G_BUFB (2 * G_ARRB)         /* 20480 B per stage (A, B) */
#define G_SMEM (3 * G_BUFB)         /* 61440 B, 3 stages */

__global__ void __launch_bounds__(256, 2) mma_gemm_fp16(
    const __half* __restrict__ Ah, const __half* __restrict__ Bh,
    const float* __restrict__ bias, float* __restrict__ C, int N, int K,
    int qkv_mode)
{
    extern __shared__ char smem[];
    const uint32_t smbase = smem_u32(smem);

    const int t    = threadIdx.x;
    const int lane = t & 31;
    const int wid  = t >> 5;
    const int wr   = wid & 3;
    const int wc   = wid >> 2;
    const int qid  = lane >> 2;
    const int tid4 = lane & 3;

    const size_t m0 = (size_t)blockIdx.y * 128;
    const size_t n0 = (size_t)blockIdx.x * 128;
    const __half* Abh = Ah + m0 * K;
    const __half* Bbh = Bh + n0 * K;

    const uint32_t a_off = (uint32_t)(((wr * 32 + (lane & 15)) * BPAD + ((lane >> 4) << 3)) * 2);
    const uint32_t b_off = (uint32_t)(((wc * 64 + (lane & 7) + ((lane & 16) >> 1)) * BPAD + (lane & 8)) * 2);

    float acc[2][8][4];
    #pragma unroll
    for (int mf = 0; mf < 2; ++mf)
        #pragma unroll
        for (int nf = 0; nf < 8; ++nf)
            #pragma unroll
            for (int r = 0; r < 4; ++r) acc[mf][nf][r] = 0.f;

    const int nchunks = K / 32;   // 64

    #pragma unroll
    for (int pc = 0; pc < 2; ++pc) {
        const uint32_t dst = smbase + (uint32_t)(pc * G_BUFB);
        #pragma unroll
        for (int i = 0; i < 4; ++i) {
            const int o = t + i * 256;
            const int arr = o >> 9;
            const int r = (o & 511) >> 2, c = (o & 3) * 8;
            const __half* src = ((arr == 0) ? Abh : Bbh) + (size_t)r * K + pc * 32 + c;
            cp16(dst + (uint32_t)(arr * G_ARRB) + (uint32_t)((r * BPAD + c) * 2), src);
        }
        CP_COMMIT();
    }

    for (int cch = 0; cch < nchunks; ++cch) {
        CP_WAIT1();
        __syncthreads();

        const uint32_t sb = smbase + (uint32_t)((cch % 3) * G_BUFB);
        #pragma unroll
        for (int ks = 0; ks < 2; ++ks) {
            const uint32_t kb = (uint32_t)(ks * 32);
            uint32_t ah[2][4];
            #pragma unroll
            for (int mf = 0; mf < 2; ++mf) {
                const uint32_t ro = (uint32_t)(mf * 16 * BPAD * 2);
                ldsm4(ah[mf], sb + a_off + ro + kb);
            }
            uint32_t bh[8][2];
            #pragma unroll
            for (int p = 0; p < 4; ++p) {
                const uint32_t ro = (uint32_t)(p * 16 * BPAD * 2);
                uint32_t r[4];
                ldsm4(r, sb + G_ARRB + b_off + ro + kb);
                bh[2 * p][0] = r[0]; bh[2 * p][1] = r[1];
                bh[2 * p + 1][0] = r[2]; bh[2 * p + 1][1] = r[3];
            }
            #pragma unroll
            for (int nf = 0; nf < 8; ++nf)
                #pragma unroll
                for (int mf = 0; mf < 2; ++mf)
                    mma_fp16(acc[mf][nf], ah[mf], bh[nf]);
        }

        if (cch + 2 < nchunks) {
            const uint32_t dst = smbase + (uint32_t)(((cch + 2) % 3) * G_BUFB);
            const int k0 = (cch + 2) * 32;
            #pragma unroll
            for (int i = 0; i < 4; ++i) {
                const int o = t + i * 256;
                const int arr = o >> 9;
                const int r = (o & 511) >> 2, c = (o & 3) * 8;
                const __half* src = ((arr == 0) ? Abh : Bbh) + (size_t)r * K + k0 + c;
                cp16(dst + (uint32_t)(arr * G_ARRB) + (uint32_t)((r * BPAD + c) * 2), src);
            }
        }
        CP_COMMIT();
    }

    // ---------------- epilogue ----------------
    const int trow = qid;
    const int tcol = tid4 * 2;
    if (!qkv_mode) {
        #pragma unroll
        for (int mf = 0; mf < 2; ++mf) {
            const size_t m = m0 + wr * 32 + mf * 16 + trow;
            #pragma unroll
            for (int nf = 0; nf < 8; ++nf) {
                const int ncol = (int)n0 + wc * 64 + nf * 8 + tcol;
                float2 v0 = make_float2(acc[mf][nf][0], acc[mf][nf][1]);
                float2 v1 = make_float2(acc[mf][nf][2], acc[mf][nf][3]);
                const float bx = bias[ncol], by = bias[ncol + 1];
                v0.x += bx; v0.y += by;
                v1.x += bx; v1.y += by;
                *(float2*)(C + m * N + ncol)       = v0;
                *(float2*)(C + (m + 8) * N + ncol) = v1;
            }
        }
        return;
    }

    // fused QKV epilogue: rope + fp16 + layout (Q pre-scaled by QSCALE)
    #pragma unroll
    for (int mf = 0; mf < 2; ++mf) {
        const size_t m = m0 + wr * 32 + mf * 16 + trow;
        const int b = (int)(m >> 11);
        const int s = (int)(m & 2047);
        #pragma unroll
        for (int nf = 0; nf < 8; ++nf) {
            const int ncol = (int)n0 + wc * 64 + nf * 8 + tcol;
            float2 v0 = make_float2(acc[mf][nf][0], acc[mf][nf][1]);
            float2 v1 = make_float2(acc[mf][nf][2], acc[mf][nf][3]);
            if (ncol < DIM + KVDIM) {
                const bool isQ = (ncol < DIM);
                const int cc = isQ ? ncol : (ncol - DIM);
                const int hh = cc >> 6, d = cc & 63, p = d >> 1;
                const float2 c0 = g_cs[s * 32 + p];
                const float2 c1 = g_cs[(s + 8) * 32 + p];
                float r0x = v0.x * c0.x - v0.y * c0.y;
                float r0y = v0.x * c0.y + v0.y * c0.x;
                float r1x = v1.x * c1.x - v1.y * c1.y;
                float r1y = v1.x * c1.y + v1.y * c1.x;
                if (isQ) {
                    r0x *= QSCALE; r0y *= QSCALE;
                    r1x *= QSCALE; r1y *= QSCALE;
                }
                __half* dst = isQ ? g_qh : g_kh;
                const int nheads = isQ ? NH : NKV;
                const size_t o0 = (((size_t)(b * nheads + hh)) * SEQ + s) * HD + d;
                const size_t o1 = o0 + 8 * HD;
                *(__half2*)(dst + o0) = __floats2half2_rn(r0x, r0y);
                *(__half2*)(dst + o1) = __floats2half2_rn(r1x, r1y);
            } else {
                const int vc = ncol - DIM - KVDIM;
                const int kv = vc >> 6, d = vc & 63;
                const float bx = bias[vc], by = bias[vc + 1];
                const size_t base = ((size_t)(b * NKV + kv) * HD + d) * SEQ;
                g_vth[base + s]           = __float2half_rn(v0.x + bx);
                g_vth[base + SEQ + s]     = __float2half_rn(v0.y + by);
                g_vth[base + s + 8]       = __float2half_rn(v1.x + bx);
                g_vth[base + SEQ + s + 8] = __float2half_rn(v1.y + by);
            }
        }
    }
}

// ---------------- flash attention v8: 1-term fp16, MUFU ex2 ----------------
#define FQ 128
#define FK 64
#define SP 72
#define F_QARR (FQ * SP * 2)
#define QOFF   F_QARR
#define F_ARR  (FK * SP * 2)
#define F_BUF  (2 * F_ARR)
#define F_SMEM (QOFF + 3 * F_BUF)

__global__ void __launch_bounds__(256, 2) flash_mma_kernel(
    const __half* __restrict__ Qh,
    const __half* __restrict__ Kh, const __half* __restrict__ Vth,
    __half* __restrict__ Oh)
{
    extern __shared__ char smem[];
    const uint32_t smbase = smem_u32(smem);

    const int qt  = (SEQ / FQ - 1) - blockIdx.x;
    const int h   = blockIdx.y;
    const int b   = blockIdx.z;
    const int kvh = h >> 2;
    const int t    = threadIdx.x;
    const int lane = t & 31;
    const int w    = t >> 5;
    const int qid  = lane >> 2;
    const int tid4 = lane & 3;
    const int q0   = qt * FQ;
    const int wrow = w * 16;

    const __half* Qhb = Qh + (((size_t)(b * NH + h)) * SEQ + q0) * HD;
    const __half* Khb = Kh + ((size_t)(b * NKV + kvh)) * SEQ * HD;
    const __half* Vhb = Vth + ((size_t)(b * NKV + kvh)) * HD * SEQ;

    #pragma unroll
    for (int i = 0; i < 4; ++i) {
        const int idx = t + i * 256;
        const int r = idx >> 3, c = (idx & 7) * 8;
        *(uint4*)(smem + (r * SP + c) * 2) = *(const uint4*)(Qhb + (size_t)r * HD + c);
    }

    const uint32_t a_off = (uint32_t)(((wrow + (lane & 15)) * SP + ((lane >> 4) << 3)) * 2);
    const uint32_t b_off = (uint32_t)((((lane & 7) + ((lane & 16) >> 1)) * SP + (lane & 8)) * 2);

    const int ga  = t >> 7;
    const int sub = t & 127;
    const __half* gsrc = (ga == 0) ? Khb : Vhb;
    const bool isK = (ga == 0);

    float oacc[8][4];
    #pragma unroll
    for (int nf = 0; nf < 8; ++nf)
        #pragma unroll
        for (int j = 0; j < 4; ++j) oacc[nf][j] = 0.f;
    float m[2] = {-1e30f, -1e30f};
    float l[2] = {0.f, 0.f};

    const int row_a = q0 + wrow + qid;
    const int row_b = row_a + 8;

    const int ntiles = (q0 + FQ) / FK;
    const int qdiag  = q0 / FK;

    #pragma unroll
    for (int pt = 0; pt < 2; ++pt) {
        const uint32_t dst = smbase + QOFF + (uint32_t)(pt * F_BUF) + (uint32_t)(ga * F_ARR);
        #pragma unroll
        for (int i = 0; i < 4; ++i) {
            const int idx = sub + i * 128;
            const int row = idx >> 3, col = (idx & 7) * 8;
            const __half* s = isK ? (gsrc + (size_t)(pt * FK + row) * HD + col)
                                  : (gsrc + (size_t)row * SEQ + pt * FK + col);
            cp16(dst + (uint32_t)((row * SP + col) * 2), s);
        }
        CP_COMMIT();
    }
    __syncthreads();

    for (int kt = 0; kt < ntiles; ++kt) {
        CP_WAIT1();
        __syncthreads();

        const uint32_t sb = smbase + QOFF + (uint32_t)((kt % 3) * F_BUF);

        float sacc[8][4];
        #pragma unroll
        for (int nf = 0; nf < 8; ++nf)
            #pragma unroll
            for (int j = 0; j < 4; ++j) sacc[nf][j] = 0.f;

        #pragma unroll
        for (int g2 = 0; g2 < 4; ++g2) {
            const uint32_t kb = (uint32_t)(g2 * 32);
            uint32_t qh4[4];
            ldsm4(qh4, smbase + a_off + kb);
            uint32_t bh[8][2];
            #pragma unroll
            for (int p = 0; p < 4; ++p) {
                const uint32_t ro = (uint32_t)(p * 16 * SP * 2);
                uint32_t r[4];
                ldsm4(r, sb + 0 * F_ARR + b_off + ro + kb);
                bh[2 * p][0] = r[0]; bh[2 * p][1] = r[1];
                bh[2 * p + 1][0] = r[2]; bh[2 * p + 1][1] = r[3];
            }
            #pragma unroll
            for (int nf = 0; nf < 8; ++nf)
                mma_fp16(sacc[nf], qh4, bh[nf]);
        }

        float tmax[2] = {-1e30f, -1e30f};
        if (kt >= qdiag) {
            #pragma unroll
            for (int nf = 0; nf < 8; ++nf) {
                const int colbase = kt * FK + nf * 8 + tid4 * 2;
                #pragma unroll
                for (int j = 0; j < 4; ++j) {
                    const int col = colbase + (j & 1);
                    const int row = (j < 2) ? row_a : row_b;
                    float v = sacc[nf][j];
                    if (col > row) v = -1e30f;
                    sacc[nf][j] = v;
                    tmax[j >> 1] = fmaxf(tmax[j >> 1], v);
                }
            }
        } else {
            #pragma unroll
            for (int nf = 0; nf < 8; ++nf)
                #pragma unroll
                for (int j = 0; j < 4; ++j)
                    tmax[j >> 1] = fmaxf(tmax[j >> 1], sacc[nf][j]);
        }

        float corr[2];
        #pragma unroll
        for (int hh = 0; hh < 2; ++hh) {
            tmax[hh] = fmaxf(tmax[hh], __shfl_xor_sync(0xffffffffu, tmax[hh], 1));
            tmax[hh] = fmaxf(tmax[hh], __shfl_xor_sync(0xffffffffu, tmax[hh], 2));
            const float mnew = fmaxf(m[hh], tmax[hh]);
            corr[hh] = ex2(m[hh] - mnew);
            m[hh] = mnew;
            l[hh] *= corr[hh];
        }
        #pragma unroll
        for (int nf = 0; nf < 8; ++nf) {
            oacc[nf][0] *= corr[0]; oacc[nf][1] *= corr[0];
            oacc[nf][2] *= corr[1]; oacc[nf][3] *= corr[1];
        }
        float rsum[2] = {0.f, 0.f};
        #pragma unroll
        for (int nf = 0; nf < 8; ++nf) {
            #pragma unroll
            for (int j = 0; j < 4; ++j) {
                const float p = ex2(sacc[nf][j] - m[j >> 1]);
                sacc[nf][j] = p;
                rsum[j >> 1] += p;
            }
        }
        #pragma unroll
        for (int hh = 0; hh < 2; ++hh) {
            rsum[hh] += __shfl_xor_sync(0xffffffffu, rsum[hh], 1);
            rsum[hh] += __shfl_xor_sync(0xffffffffu, rsum[hh], 2);
            l[hh] += rsum[hh];
        }

        uint32_t pfh[4][4];
        #pragma unroll
        for (int g2 = 0; g2 < 4; ++g2) {
            const float* s0 = sacc[2 * g2];
            const float* s1 = sacc[2 * g2 + 1];
            pfh[g2][0] = pack_hf2(s0[0], s0[1]);
            pfh[g2][1] = pack_hf2(s0[2], s0[3]);
            pfh[g2][2] = pack_hf2(s1[0], s1[1]);
            pfh[g2][3] = pack_hf2(s1[2], s1[3]);
        }

        #pragma unroll
        for (int g2 = 0; g2 < 4; ++g2) {
            const uint32_t kb = (uint32_t)(g2 * 32);
            uint32_t vh[8][2];
            #pragma unroll
            for (int p = 0; p < 4; ++p) {
                const uint32_t ro = (uint32_t)(p * 16 * SP * 2);
                uint32_t r[4];
                ldsm4(r, sb + 1 * F_ARR + b_off + ro + kb);
                vh[2 * p][0] = r[0]; vh[2 * p][1] = r[1];
                vh[2 * p + 1][0] = r[2]; vh[2 * p + 1][1] = r[3];
            }
            #pragma unroll
            for (int nf = 0; nf < 8; ++nf)
                mma_fp16(oacc[nf], pfh[g2], vh[nf]);
        }

        if (kt + 2 < ntiles) {
            const uint32_t dst = smbase + QOFF + (uint32_t)(((kt + 2) % 3) * F_BUF) + (uint32_t)(ga * F_ARR);
            #pragma unroll
            for (int i = 0; i < 4; ++i) {
                const int idx = sub + i * 128;
                const int row = idx >> 3, col = (idx & 7) * 8;
                const __half* s = isK
                    ? (gsrc + (size_t)((kt + 2) * FK + row) * HD + col)
                    : (gsrc + (size_t)row * SEQ + (kt + 2) * FK + col);
                cp16(dst + (uint32_t)((row * SP + col) * 2), s);
            }
        }
        CP_COMMIT();
    }

    const float inv_a = 1.0f / l[0];
    const float inv_b = 1.0f / l[1];
    const size_t rA = ((size_t)(b * SEQ) + row_a) * DIM + h * HD;
    const size_t rB = rA + 8 * DIM;
    #pragma unroll
    for (int nf = 0; nf < 8; ++nf) {
        const int col = nf * 8 + tid4 * 2;
        *(__half2*)(Oh + rA + col) = __floats2half2_rn(oacc[nf][0] * inv_a, oacc[nf][1] * inv_a);
        *(__half2*)(Oh + rB + col) = __floats2half2_rn(oacc[nf][2] * inv_b, oacc[nf][3] * inv_b);
    }
}

// ---------------- host launcher ----------------
extern "C" void kernel_launch(void* const* d_in, const int* in_sizes, int n_in,
                              void* d_out, int out_size) {
    (void)in_sizes; (void)n_in; (void)out_size;
    const float* x  = (const float*)d_in[0];
    const float* Wq = (const float*)d_in[1];
    const float* Wk = (const float*)d_in[2];
    const float* Wv = (const float*)d_in[3];
    const float* bv = (const float*)d_in[4];
    const float* Wo = (const float*)d_in[5];
    const float* bo = (const float*)d_in[6];
    float* out = (float*)d_out;

    __half *ah, *bh, *bho, *qh, *kh, *vth;
    cudaGetSymbolAddress((void**)&ah,  g_ah);
    cudaGetSymbolAddress((void**)&bh,  g_bh);
    cudaGetSymbolAddress((void**)&bho, g_bho);
    cudaGetSymbolAddress((void**)&qh,  g_qh);
    cudaGetSymbolAddress((void**)&kh,  g_kh);
    cudaGetSymbolAddress((void**)&vth, g_vth);

    cudaFuncSetAttribute(mma_gemm_fp16, cudaFuncAttributeMaxDynamicSharedMemorySize, G_SMEM);
    cudaFuncSetAttribute(flash_mma_kernel, cudaFuncAttributeMaxDynamicSharedMemorySize, F_SMEM);

    // prep (x convert + sincos) and all weight transposes: one launch
    prep_transpose_kernel<<<dim3(64, 64, 7), dim3(32, 8)>>>(x, ah, Wq, Wk, Wv, Wo);

    // merged QKV projection (N = 3072), 1-term, fused rope epilogue
    mma_gemm_fp16<<<dim3(NQKV / 128, MROWS / 128), 256, G_SMEM>>>(
        ah, bh, bv, nullptr, NQKV, DIM, 1);

    // flash writes fp16 ah for the O projection
    flash_mma_kernel<<<dim3(SEQ / FQ, NH, BATCH), 256, F_SMEM>>>(qh, kh, vth, ah);

    // O projection: 1-term
    mma_gemm_fp16<<<dim3(DIM / 128, MROWS / 128), 256, G_SMEM>>>(
        ah, bho, bo, out, DIM, DIM, 0);
}

// round 17
// speedup vs baseline: 8.1845x; 1.0895x over previous
#include <cuda_runtime.h>
#include <cuda_fp16.h>
#include <math.h>
#include <stdint.h>

#define DIM 2048
#define NH 32
#define NKV 8
#define HD 64
#define BATCH 2
#define SEQ 2048
#define MROWS (BATCH*SEQ)   /* 4096 */
#define KVDIM (NKV*HD)      /* 512 */
#define NQKV (DIM + 2*KVDIM) /* 3072 */

// ---------------- scratch (static device allocations; no cudaMalloc) ----------------
__device__ __align__(16) __half g_ah[(size_t)MROWS * DIM];   // activations fp16
__device__ __align__(16) __half g_bh[(size_t)NQKV * DIM];    // Wq|Wk|Wv transposed
__device__ __align__(16) __half g_bho[(size_t)DIM * DIM];    // Wo transposed
// flash operands: fp16; Q pre-scaled by 0.125*log2(e)
__device__ __align__(16) __half g_qh[(size_t)BATCH * NH * SEQ * HD];
__device__ __align__(16) __half g_kh[(size_t)BATCH * NKV * SEQ * HD];
__device__ __align__(16) __half g_vth[(size_t)BATCH * NKV * HD * SEQ];  // [b,kv,d,s]
__device__ float2 g_cs[(size_t)SEQ * (HD / 2)];

#define QSCALE 0.18033688011112042f   /* 0.125 * log2(e) */

// ---------------- fused prep + weight transpose (one launch) ----------------
#define SPLIT_BLOCKS ((MROWS * DIM) / 1024)          /* 8192 */
#define PREP_TOTAL (SPLIT_BLOCKS + (SEQ * 32) / 256) /* 8448 */

__global__ void prep_transpose_kernel(const float* __restrict__ x,
                                      __half* __restrict__ oh,
                                      const float* __restrict__ Wq,
                                      const float* __restrict__ Wk,
                                      const float* __restrict__ Wv,
                                      const float* __restrict__ Wo) {
    __shared__ float tile[32][33];
    const int z = blockIdx.z;
    if (z < 4) {
        const int nx = (z == 1 || z == 2) ? (KVDIM / 32) : (DIM / 32);
        if (blockIdx.x >= nx) return;
        const float* in = (z == 0) ? Wq : (z == 1) ? Wk : (z == 2) ? Wv : Wo;
        __half* out = (z == 0) ? g_bh
                    : (z == 1) ? g_bh + (size_t)DIM * DIM
                    : (z == 2) ? g_bh + (size_t)(DIM + KVDIM) * DIM
                    : g_bho;
        const int Ccols = (z == 1 || z == 2) ? KVDIM : DIM;
        const int R = DIM;
        int bx = blockIdx.x * 32, by = blockIdx.y * 32;
        int xx = bx + threadIdx.x;
        #pragma unroll
        for (int i = 0; i < 32; i += 8)
            tile[threadIdx.y + i][threadIdx.x] = in[(size_t)(by + threadIdx.y + i) * Ccols + xx];
        __syncthreads();
        int ox = by + threadIdx.x;
        #pragma unroll
        for (int i = 0; i < 32; i += 8)
            out[(size_t)(bx + threadIdx.y + i) * R + ox] =
                __float2half_rn(tile[threadIdx.x][threadIdx.y + i]);
        return;
    }
    const int bid = (z - 4) * 4096 + blockIdx.y * 64 + blockIdx.x;
    if (bid >= PREP_TOTAL) return;
    const int t = threadIdx.y * 32 + threadIdx.x;
    if (bid < SPLIT_BLOCKS) {
        const int i = bid * 256 + t;
        const float4 v = *(const float4*)(x + (size_t)i * 4);
        __half h[4];
        h[0] = __float2half_rn(v.x);
        h[1] = __float2half_rn(v.y);
        h[2] = __float2half_rn(v.z);
        h[3] = __float2half_rn(v.w);
        *(uint2*)(oh + (size_t)i * 4) = *(uint2*)h;
    } else {
        const int idx = (bid - SPLIT_BLOCKS) * 256 + t;   // SEQ*32
        const int s = idx >> 5, p = idx & 31;
        double theta = pow(10000.0, -(double)p / 32.0);
        float ang = (float)((double)s * theta);
        float sv, cv;
        sincosf(ang, &sv, &cv);
        g_cs[idx] = make_float2(cv, sv);
    }
}

// ================= mma.sync / async helpers =================
__device__ __forceinline__ uint32_t smem_u32(const void* p) {
    uint32_t a;
    asm("{ .reg .u64 t; cvta.to.shared.u64 t, %1; cvt.u32.u64 %0, t; }" : "=r"(a) : "l"(p));
    return a;
}
__device__ __forceinline__ void cp16(uint32_t dst, const void* src) {
    asm volatile("cp.async.cg.shared.global [%0], [%1], 16;" :: "r"(dst), "l"(src));
}
#define CP_COMMIT() asm volatile("cp.async.commit_group;" ::: "memory")
#define CP_WAIT1()  asm volatile("cp.async.wait_group 1;" ::: "memory")

__device__ __forceinline__ void ldsm4(uint32_t* r, uint32_t addr) {
    asm volatile("ldmatrix.sync.aligned.m8n8.x4.shared.b16 {%0,%1,%2,%3}, [%4];"
                 : "=r"(r[0]), "=r"(r[1]), "=r"(r[2]), "=r"(r[3]) : "r"(addr));
}
__device__ __forceinline__ void mma_fp16(float* d, const uint32_t* a, const uint32_t* b) {
    asm volatile(
        "mma.sync.aligned.m16n8k16.row.col.f32.f16.f16.f32 "
        "{%0,%1,%2,%3}, {%4,%5,%6,%7}, {%8,%9}, {%0,%1,%2,%3};\n"
        : "+f"(d[0]), "+f"(d[1]), "+f"(d[2]), "+f"(d[3])
        : "r"(a[0]), "r"(a[1]), "r"(a[2]), "r"(a[3]), "r"(b[0]), "r"(b[1]));
}
__device__ __forceinline__ uint32_t pack_hf2(float x0, float x1) {
    __half2 v = __floats2half2_rn(x0, x1);
    return *(uint32_t*)&v;
}
__device__ __forceinline__ float ex2(float y) {
    float r;
    asm("ex2.approx.ftz.f32 %0, %1;" : "=f"(r) : "f"(y));
    return r;
}

// ---------------- fp16 1-term GEMM, K-chunk 64, 3-stage pipeline ----------------
#define BPAD 72                     /* halfs per row (144 B, conflict-free like SP=72) */
#define G_ARRB (128 * BPAD * 2)     /* 18432 B */
#define G_BUFB (2 * G_ARRB)         /* 36864 B per stage (A, B) */
#define G_SMEM (3 * G_BUFB)         /* 110592 B, 3 stages, 2 CTAs/SM */

__global__ void __launch_bounds__(256, 2) mma_gemm_fp16(
    const __half* __restrict__ Ah, const __half* __restrict__ Bh,
    const float* __restrict__ bias, float* __restrict__ C, int N, int K,
    int qkv_mode)
{
    extern __shared__ char smem[];
    const uint32_t smbase = smem_u32(smem);

    const int t    = threadIdx.x;
    const int lane = t & 31;
    const int wid  = t >> 5;
    const int wr   = wid & 3;
    const int wc   = wid >> 2;
    const int qid  = lane >> 2;
    const int tid4 = lane & 3;

    const size_t m0 = (size_t)blockIdx.y * 128;
    const size_t n0 = (size_t)blockIdx.x * 128;
    const __half* Abh = Ah + m0 * K;
    const __half* Bbh = Bh + n0 * K;

    const uint32_t a_off = (uint32_t)(((wr * 32 + (lane & 15)) * BPAD + ((lane >> 4) << 3)) * 2);
    const uint32_t b_off = (uint32_t)(((wc * 64 + (lane & 7) + ((lane & 16) >> 1)) * BPAD + (lane & 8)) * 2);

    float acc[2][8][4];
    #pragma unroll
    for (int mf = 0; mf < 2; ++mf)
        #pragma unroll
        for (int nf = 0; nf < 8; ++nf)
            #pragma unroll
            for (int r = 0; r < 4; ++r) acc[mf][nf][r] = 0.f;

    const int nchunks = K / 64;   // 32

    // prologue: chunks 0,1 -> stages 0,1. 2 arrays x 1024 x 16B = 8 per thread.
    #pragma unroll
    for (int pc = 0; pc < 2; ++pc) {
        const uint32_t dst = smbase + (uint32_t)(pc * G_BUFB);
        #pragma unroll
        for (int i = 0; i < 8; ++i) {
            const int o = t + i * 256;
            const int arr = o >> 10;
            const int r = (o & 1023) >> 3, c = (o & 7) * 8;
            const __half* src = ((arr == 0) ? Abh : Bbh) + (size_t)r * K + pc * 64 + c;
            cp16(dst + (uint32_t)(arr * G_ARRB) + (uint32_t)((r * BPAD + c) * 2), src);
        }
        CP_COMMIT();
    }

    for (int cch = 0; cch < nchunks; ++cch) {
        CP_WAIT1();
        __syncthreads();

        const uint32_t sb = smbase + (uint32_t)((cch % 3) * G_BUFB);
        #pragma unroll
        for (int ks = 0; ks < 4; ++ks) {
            const uint32_t kb = (uint32_t)(ks * 32);   // 16 halfs per step
            uint32_t ah[2][4];
            #pragma unroll
            for (int mf = 0; mf < 2; ++mf) {
                const uint32_t ro = (uint32_t)(mf * 16 * BPAD * 2);
                ldsm4(ah[mf], sb + a_off + ro + kb);
            }
            uint32_t bh[8][2];
            #pragma unroll
            for (int p = 0; p < 4; ++p) {
                const uint32_t ro = (uint32_t)(p * 16 * BPAD * 2);
                uint32_t r[4];
                ldsm4(r, sb + G_ARRB + b_off + ro + kb);
                bh[2 * p][0] = r[0]; bh[2 * p][1] = r[1];
                bh[2 * p + 1][0] = r[2]; bh[2 * p + 1][1] = r[3];
            }
            #pragma unroll
            for (int nf = 0; nf < 8; ++nf)
                #pragma unroll
                for (int mf = 0; mf < 2; ++mf)
                    mma_fp16(acc[mf][nf], ah[mf], bh[nf]);
        }

        if (cch + 2 < nchunks) {
            const uint32_t dst = smbase + (uint32_t)(((cch + 2) % 3) * G_BUFB);
            const int k0 = (cch + 2) * 64;
            #pragma unroll
            for (int i = 0; i < 8; ++i) {
                const int o = t + i * 256;
                const int arr = o >> 10;
                const int r = (o & 1023) >> 3, c = (o & 7) * 8;
                const __half* src = ((arr == 0) ? Abh : Bbh) + (size_t)r * K + k0 + c;
                cp16(dst + (uint32_t)(arr * G_ARRB) + (uint32_t)((r * BPAD + c) * 2), src);
            }
        }
        CP_COMMIT();
    }

    // ---------------- epilogue ----------------
    const int trow = qid;
    const int tcol = tid4 * 2;
    if (!qkv_mode) {
        #pragma unroll
        for (int mf = 0; mf < 2; ++mf) {
            const size_t m = m0 + wr * 32 + mf * 16 + trow;
            #pragma unroll
            for (int nf = 0; nf < 8; ++nf) {
                const int ncol = (int)n0 + wc * 64 + nf * 8 + tcol;
                float2 v0 = make_float2(acc[mf][nf][0], acc[mf][nf][1]);
                float2 v1 = make_float2(acc[mf][nf][2], acc[mf][nf][3]);
                const float bx = bias[ncol], by = bias[ncol + 1];
                v0.x += bx; v0.y += by;
                v1.x += bx; v1.y += by;
                *(float2*)(C + m * N + ncol)       = v0;
                *(float2*)(C + (m + 8) * N + ncol) = v1;
            }
        }
        return;
    }

    // fused QKV epilogue: rope + fp16 + layout (Q pre-scaled by QSCALE)
    #pragma unroll
    for (int mf = 0; mf < 2; ++mf) {
        const size_t m = m0 + wr * 32 + mf * 16 + trow;
        const int b = (int)(m >> 11);
        const int s = (int)(m & 2047);
        #pragma unroll
        for (int nf = 0; nf < 8; ++nf) {
            const int ncol = (int)n0 + wc * 64 + nf * 8 + tcol;
            float2 v0 = make_float2(acc[mf][nf][0], acc[mf][nf][1]);
            float2 v1 = make_float2(acc[mf][nf][2], acc[mf][nf][3]);
            if (ncol < DIM + KVDIM) {
                const bool isQ = (ncol < DIM);
                const int cc = isQ ? ncol : (ncol - DIM);
                const int hh = cc >> 6, d = cc & 63, p = d >> 1;
                const float2 c0 = g_cs[s * 32 + p];
                const float2 c1 = g_cs[(s + 8) * 32 + p];
                float r0x = v0.x * c0.x - v0.y * c0.y;
                float r0y = v0.x * c0.y + v0.y * c0.x;
                float r1x = v1.x * c1.x - v1.y * c1.y;
                float r1y = v1.x * c1.y + v1.y * c1.x;
                if (isQ) {
                    r0x *= QSCALE; r0y *= QSCALE;
                    r1x *= QSCALE; r1y *= QSCALE;
                }
                __half* dst = isQ ? g_qh : g_kh;
                const int nheads = isQ ? NH : NKV;
                const size_t o0 = (((size_t)(b * nheads + hh)) * SEQ + s) * HD + d;
                const size_t o1 = o0 + 8 * HD;
                *(__half2*)(dst + o0) = __floats2half2_rn(r0x, r0y);
                *(__half2*)(dst + o1) = __floats2half2_rn(r1x, r1y);
            } else {
                const int vc = ncol - DIM - KVDIM;
                const int kv = vc >> 6, d = vc & 63;
                const float bx = bias[vc], by = bias[vc + 1];
                const size_t base = ((size_t)(b * NKV + kv) * HD + d) * SEQ;
                g_vth[base + s]           = __float2half_rn(v0.x + bx);
                g_vth[base + SEQ + s]     = __float2half_rn(v0.y + by);
                g_vth[base + s + 8]       = __float2half_rn(v1.x + bx);
                g_vth[base + SEQ + s + 8] = __float2half_rn(v1.y + by);
            }
        }
    }
}

// ---------------- flash attention v8 (unchanged from R16) ----------------
#define FQ 128
#define FK 64
#define SP 72
#define F_QARR (FQ * SP * 2)
#define QOFF   F_QARR
#define F_ARR  (FK * SP * 2)
#define F_BUF  (2 * F_ARR)
#define F_SMEM (QOFF + 3 * F_BUF)

__global__ void __launch_bounds__(256, 2) flash_mma_kernel(
    const __half* __restrict__ Qh,
    const __half* __restrict__ Kh, const __half* __restrict__ Vth,
    __half* __restrict__ Oh)
{
    extern __shared__ char smem[];
    const uint32_t smbase = smem_u32(smem);

    const int qt  = (SEQ / FQ - 1) - blockIdx.x;
    const int h   = blockIdx.y;
    const int b   = blockIdx.z;
    const int kvh = h >> 2;
    const int t    = threadIdx.x;
    const int lane = t & 31;
    const int w    = t >> 5;
    const int qid  = lane >> 2;
    const int tid4 = lane & 3;
    const int q0   = qt * FQ;
    const int wrow = w * 16;

    const __half* Qhb = Qh + (((size_t)(b * NH + h)) * SEQ + q0) * HD;
    const __half* Khb = Kh + ((size_t)(b * NKV + kvh)) * SEQ * HD;
    const __half* Vhb = Vth + ((size_t)(b * NKV + kvh)) * HD * SEQ;

    #pragma unroll
    for (int i = 0; i < 4; ++i) {
        const int idx = t + i * 256;
        const int r = idx >> 3, c = (idx & 7) * 8;
        *(uint4*)(smem + (r * SP + c) * 2) = *(const uint4*)(Qhb + (size_t)r * HD + c);
    }

    const uint32_t a_off = (uint32_t)(((wrow + (lane & 15)) * SP + ((lane >> 4) << 3)) * 2);
    const uint32_t b_off = (uint32_t)((((lane & 7) + ((lane & 16) >> 1)) * SP + (lane & 8)) * 2);

    const int ga  = t >> 7;
    const int sub = t & 127;
    const __half* gsrc = (ga == 0) ? Khb : Vhb;
    const bool isK = (ga == 0);

    float oacc[8][4];
    #pragma unroll
    for (int nf = 0; nf < 8; ++nf)
        #pragma unroll
        for (int j = 0; j < 4; ++j) oacc[nf][j] = 0.f;
    float m[2] = {-1e30f, -1e30f};
    float l[2] = {0.f, 0.f};

    const int row_a = q0 + wrow + qid;
    const int row_b = row_a + 8;

    const int ntiles = (q0 + FQ) / FK;
    const int qdiag  = q0 / FK;

    #pragma unroll
    for (int pt = 0; pt < 2; ++pt) {
        const uint32_t dst = smbase + QOFF + (uint32_t)(pt * F_BUF) + (uint32_t)(ga * F_ARR);
        #pragma unroll
        for (int i = 0; i < 4; ++i) {
            const int idx = sub + i * 128;
            const int row = idx >> 3, col = (idx & 7) * 8;
            const __half* s = isK ? (gsrc + (size_t)(pt * FK + row) * HD + col)
                                  : (gsrc + (size_t)row * SEQ + pt * FK + col);
            cp16(dst + (uint32_t)((row * SP + col) * 2), s);
        }
        CP_COMMIT();
    }
    __syncthreads();

    for (int kt = 0; kt < ntiles; ++kt) {
        CP_WAIT1();
        __syncthreads();

        const uint32_t sb = smbase + QOFF + (uint32_t)((kt % 3) * F_BUF);

        float sacc[8][4];
        #pragma unroll
        for (int nf = 0; nf < 8; ++nf)
            #pragma unroll
            for (int j = 0; j < 4; ++j) sacc[nf][j] = 0.f;

        #pragma unroll
        for (int g2 = 0; g2 < 4; ++g2) {
            const uint32_t kb = (uint32_t)(g2 * 32);
            uint32_t qh4[4];
            ldsm4(qh4, smbase + a_off + kb);
            uint32_t bh[8][2];
            #pragma unroll
            for (int p = 0; p < 4; ++p) {
                const uint32_t ro = (uint32_t)(p * 16 * SP * 2);
                uint32_t r[4];
                ldsm4(r, sb + 0 * F_ARR + b_off + ro + kb);
                bh[2 * p][0] = r[0]; bh[2 * p][1] = r[1];
                bh[2 * p + 1][0] = r[2]; bh[2 * p + 1][1] = r[3];
            }
            #pragma unroll
            for (int nf = 0; nf < 8; ++nf)
                mma_fp16(sacc[nf], qh4, bh[nf]);
        }

        float tmax[2] = {-1e30f, -1e30f};
        if (kt >= qdiag) {
            #pragma unroll
            for (int nf = 0; nf < 8; ++nf) {
                const int colbase = kt * FK + nf * 8 + tid4 * 2;
                #pragma unroll
                for (int j = 0; j < 4; ++j) {
                    const int col = colbase + (j & 1);
                    const int row = (j < 2) ? row_a : row_b;
                    float v = sacc[nf][j];
                    if (col > row) v = -1e30f;
                    sacc[nf][j] = v;
                    tmax[j >> 1] = fmaxf(tmax[j >> 1], v);
                }
            }
        } else {
            #pragma unroll
            for (int nf = 0; nf < 8; ++nf)
                #pragma unroll
                for (int j = 0; j < 4; ++j)
                    tmax[j >> 1] = fmaxf(tmax[j >> 1], sacc[nf][j]);
        }

        float corr[2];
        #pragma unroll
        for (int hh = 0; hh < 2; ++hh) {
            tmax[hh] = fmaxf(tmax[hh], __shfl_xor_sync(0xffffffffu, tmax[hh], 1));
            tmax[hh] = fmaxf(tmax[hh], __shfl_xor_sync(0xffffffffu, tmax[hh], 2));
            const float mnew = fmaxf(m[hh], tmax[hh]);
            corr[hh] = ex2(m[hh] - mnew);
            m[hh] = mnew;
            l[hh] *= corr[hh];
        }
        #pragma unroll
        for (int nf = 0; nf < 8; ++nf) {
            oacc[nf][0] *= corr[0]; oacc[nf][1] *= corr[0];
            oacc[nf][2] *= corr[1]; oacc[nf][3] *= corr[1];
        }
        float rsum[2] = {0.f, 0.f};
        #pragma unroll
        for (int nf = 0; nf < 8; ++nf) {
            #pragma unroll
            for (int j = 0; j < 4; ++j) {
                const float p = ex2(sacc[nf][j] - m[j >> 1]);
                sacc[nf][j] = p;
                rsum[j >> 1] += p;
            }
        }
        #pragma unroll
        for (int hh = 0; hh < 2; ++hh) {
            rsum[hh] += __shfl_xor_sync(0xffffffffu, rsum[hh], 1);
            rsum[hh] += __shfl_xor_sync(0xffffffffu, rsum[hh], 2);
            l[hh] += rsum[hh];
        }

        uint32_t pfh[4][4];
        #pragma unroll
        for (int g2 = 0; g2 < 4; ++g2) {
            const float* s0 = sacc[2 * g2];
            const float* s1 = sacc[2 * g2 + 1];
            pfh[g2][0] = pack_hf2(s0[0], s0[1]);
            pfh[g2][1] = pack_hf2(s0[2], s0[3]);
            pfh[g2][2] = pack_hf2(s1[0], s1[1]);
            pfh[g2][3] = pack_hf2(s1[2], s1[3]);
        }

        #pragma unroll
        for (int g2 = 0; g2 < 4; ++g2) {
            const uint32_t kb = (uint32_t)(g2 * 32);
            uint32_t vh[8][2];
            #pragma unroll
            for (int p = 0; p < 4; ++p) {
                const uint32_t ro = (uint32_t)(p * 16 * SP * 2);
                uint32_t r[4];
                ldsm4(r, sb + 1 * F_ARR + b_off + ro + kb);
                vh[2 * p][0] = r[0]; vh[2 * p][1] = r[1];
                vh[2 * p + 1][0] = r[2]; vh[2 * p + 1][1] = r[3];
            }
            #pragma unroll
            for (int nf = 0; nf < 8; ++nf)
                mma_fp16(oacc[nf], pfh[g2], vh[nf]);
        }

        if (kt + 2 < ntiles) {
            const uint32_t dst = smbase + QOFF + (uint32_t)(((kt + 2) % 3) * F_BUF) + (uint32_t)(ga * F_ARR);
            #pragma unroll
            for (int i = 0; i < 4; ++i) {
                const int idx = sub + i * 128;
                const int row = idx >> 3, col = (idx & 7) * 8;
                const __half* s = isK
                    ? (gsrc + (size_t)((kt + 2) * FK + row) * HD + col)
                    : (gsrc + (size_t)row * SEQ + (kt + 2) * FK + col);
                cp16(dst + (uint32_t)((row * SP + col) * 2), s);
            }
        }
        CP_COMMIT();
    }

    const float inv_a = 1.0f / l[0];
    const float inv_b = 1.0f / l[1];
    const size_t rA = ((size_t)(b * SEQ) + row_a) * DIM + h * HD;
    const size_t rB = rA + 8 * DIM;
    #pragma unroll
    for (int nf = 0; nf < 8; ++nf) {
        const int col = nf * 8 + tid4 * 2;
        *(__half2*)(Oh + rA + col) = __floats2half2_rn(oacc[nf][0] * inv_a, oacc[nf][1] * inv_a);
        *(__half2*)(Oh + rB + col) = __floats2half2_rn(oacc[nf][2] * inv_b, oacc[nf][3] * inv_b);
    }
}

// ---------------- host launcher ----------------
extern "C" void kernel_launch(void* const* d_in, const int* in_sizes, int n_in,
                              void* d_out, int out_size) {
    (void)in_sizes; (void)n_in; (void)out_size;
    const float* x  = (const float*)d_in[0];
    const float* Wq = (const float*)d_in[1];
    const float* Wk = (const float*)d_in[2];
    const float* Wv = (const float*)d_in[3];
    const float* bv = (const float*)d_in[4];
    const float* Wo = (const float*)d_in[5];
    const float* bo = (const float*)d_in[6];
    float* out = (float*)d_out;

    __half *ah, *bh, *bho, *qh, *kh, *vth;
    cudaGetSymbolAddress((void**)&ah,  g_ah);
    cudaGetSymbolAddress((void**)&bh,  g_bh);
    cudaGetSymbolAddress((void**)&bho, g_bho);
    cudaGetSymbolAddress((void**)&qh,  g_qh);
    cudaGetSymbolAddress((void**)&kh,  g_kh);
    cudaGetSymbolAddress((void**)&vth, g_vth);

    cudaFuncSetAttribute(mma_gemm_fp16, cudaFuncAttributeMaxDynamicSharedMemorySize, G_SMEM);
    cudaFuncSetAttribute(flash_mma_kernel, cudaFuncAttributeMaxDynamicSharedMemorySize, F_SMEM);

    prep_transpose_kernel<<<dim3(64, 64, 7), dim3(32, 8)>>>(x, ah, Wq, Wk, Wv, Wo);

    mma_gemm_fp16<<<dim3(NQKV / 128, MROWS / 128), 256, G_SMEM>>>(
        ah, bh, bv, nullptr, NQKV, DIM, 1);

    flash_mma_kernel<<<dim3(SEQ / FQ, NH, BATCH), 256, F_SMEM>>>(qh, kh, vth, ah);

    mma_gemm_fp16<<<dim3(DIM / 128, MROWS / 128), 256, G_SMEM>>>(
        ah, bho, bo, out, DIM, DIM, 0);
}